// round 2
// baseline (speedup 1.0000x reference)
#include <cuda_runtime.h>
#include <math.h>

// ---------------------------------------------------------------------------
// MSDeformAttn transformer encoder (6 layers), fp32 reference-accurate path.
// D=256, NH=8, NL=4, NP=4, DH=32, DFF=1024, B=2, S=21760.
// ---------------------------------------------------------------------------

#define D_MODEL 256
#define NH 8
#define NL 4
#define NP 4
#define DH 32
#define DFF 1024
#define NLAYERS 6
#define BATCH 2
#define S_TOTAL 21760
#define M_TOT (BATCH * S_TOTAL)   // 43520 rows; divisible by 128

// Scratch (allocation-free: __device__ globals)
__device__ float g_pos[M_TOT * D_MODEL];
__device__ float g_q[M_TOT * D_MODEL];
__device__ float g_val[M_TOT * D_MODEL];
__device__ float g_off[M_TOT * 256];
__device__ float g_awl[M_TOT * 128];
__device__ float g_samp[M_TOT * D_MODEL];
__device__ float g_tmp[M_TOT * D_MODEL];
__device__ float g_ffh[M_TOT * DFF];

// ---------------------------------------------------------------------------
// Flatten: src [B, D, h, w] -> out [B, S, D] slice ; pos likewise + level_embed
// 32x32 shared-memory transpose tiles, coalesced both sides.
// ---------------------------------------------------------------------------
__global__ void flatten_kernel(const float* __restrict__ src,
                               const float* __restrict__ pos,
                               const float* __restrict__ lemb,
                               float* __restrict__ out,
                               float* __restrict__ posout,
                               int hw, int start, int level) {
    __shared__ float ts[32][33];
    __shared__ float tp[32][33];
    int b  = blockIdx.z;
    int p0 = blockIdx.x * 32;
    int d0 = blockIdx.y * 32;
    int tx = threadIdx.x, ty = threadIdx.y;

    const float* sp = src + ((size_t)b * D_MODEL + d0 + ty) * hw + p0;
    const float* pp = pos + ((size_t)b * D_MODEL + d0 + ty) * hw + p0;
    ts[ty][tx] = sp[tx];
    tp[ty][tx] = pp[tx];
    __syncthreads();

    int d = d0 + tx;
    float le = lemb[level * D_MODEL + d];
    size_t srow = (size_t)b * S_TOTAL + start + p0 + ty;
    out[srow * D_MODEL + d]    = ts[tx][ty];
    posout[srow * D_MODEL + d] = tp[tx][ty] + le;
}

// ---------------------------------------------------------------------------
// q = a + b elementwise (float4)
// ---------------------------------------------------------------------------
__global__ void add_kernel(const float* __restrict__ a, const float* __restrict__ b,
                           float* __restrict__ c, int n4) {
    int i = blockIdx.x * blockDim.x + threadIdx.x;
    if (i < n4) {
        float4 x = ((const float4*)a)[i];
        float4 y = ((const float4*)b)[i];
        x.x += y.x; x.y += y.y; x.z += y.z; x.w += y.w;
        ((float4*)c)[i] = x;
    }
}

// ---------------------------------------------------------------------------
// SGEMM: C[M,N] = A[M,K] @ W[K,N] + bias (optional ReLU)
// BM=BN=128, BK=16, 256 threads, 8x8 per thread. All dims divisible.
// ---------------------------------------------------------------------------
template <int RELU>
__global__ __launch_bounds__(256, 2)
void sgemm_kernel(const float* __restrict__ A, const float* __restrict__ W,
                  const float* __restrict__ bias, float* __restrict__ C,
                  int M, int N, int K) {
    __shared__ float As[16][128];
    __shared__ float Bs[16][128];

    int tid  = threadIdx.x;
    int brow = blockIdx.x * 128;
    int bcol = blockIdx.y * 128;

    int ar  = tid >> 2;          // 0..63   A row within tile (and +64)
    int ac  = (tid & 3) * 4;     // 0,4,8,12 A col (k) start
    int bkr = tid >> 4;          // 0..15   W k-row
    int bc  = (tid & 15) * 4;    // 0..60   W col start (and +64)

    float acc[8][8];
#pragma unroll
    for (int i = 0; i < 8; i++)
#pragma unroll
        for (int j = 0; j < 8; j++) acc[i][j] = 0.f;

    const float* Aptr = A + (size_t)(brow + ar) * K + ac;
    const float* Wptr = W + (size_t)bkr * N + bcol + bc;

    int ty = (tid >> 4) * 8;
    int tx = (tid & 15) * 8;

    for (int k0 = 0; k0 < K; k0 += 16) {
        float4 a0 = *(const float4*)(Aptr);
        float4 a1 = *(const float4*)(Aptr + (size_t)64 * K);
        float4 b0 = *(const float4*)(Wptr);
        float4 b1 = *(const float4*)(Wptr + 64);
        __syncthreads();
        As[ac + 0][ar] = a0.x; As[ac + 1][ar] = a0.y;
        As[ac + 2][ar] = a0.z; As[ac + 3][ar] = a0.w;
        As[ac + 0][ar + 64] = a1.x; As[ac + 1][ar + 64] = a1.y;
        As[ac + 2][ar + 64] = a1.z; As[ac + 3][ar + 64] = a1.w;
        *(float4*)&Bs[bkr][bc]      = b0;
        *(float4*)&Bs[bkr][bc + 64] = b1;
        __syncthreads();
        Aptr += 16;
        Wptr += (size_t)16 * N;

#pragma unroll
        for (int k = 0; k < 16; k++) {
            float4 x0 = *(const float4*)&As[k][ty];
            float4 x1 = *(const float4*)&As[k][ty + 4];
            float4 y0 = *(const float4*)&Bs[k][tx];
            float4 y1 = *(const float4*)&Bs[k][tx + 4];
            float av[8] = {x0.x, x0.y, x0.z, x0.w, x1.x, x1.y, x1.z, x1.w};
            float bv[8] = {y0.x, y0.y, y0.z, y0.w, y1.x, y1.y, y1.z, y1.w};
#pragma unroll
            for (int i = 0; i < 8; i++)
#pragma unroll
                for (int j = 0; j < 8; j++)
                    acc[i][j] += av[i] * bv[j];
        }
    }

    int row = brow + ty;
    int col = bcol + tx;
    float bb[8];
#pragma unroll
    for (int j = 0; j < 8; j++) bb[j] = bias[col + j];
#pragma unroll
    for (int i = 0; i < 8; i++) {
        float4 o0, o1;
        float v[8];
#pragma unroll
        for (int j = 0; j < 8; j++) {
            v[j] = acc[i][j] + bb[j];
            if (RELU) v[j] = fmaxf(v[j], 0.f);
        }
        o0.x = v[0]; o0.y = v[1]; o0.z = v[2]; o0.w = v[3];
        o1.x = v[4]; o1.y = v[5]; o1.z = v[6]; o1.w = v[7];
        *(float4*)&C[(size_t)(row + i) * N + col]     = o0;
        *(float4*)&C[(size_t)(row + i) * N + col + 4] = o1;
    }
}

// ---------------------------------------------------------------------------
// Residual + LayerNorm: out = LN(x + r) * gamma + beta. One warp per row (D=256).
// ---------------------------------------------------------------------------
__global__ void resid_ln_kernel(const float* __restrict__ X, const float* __restrict__ R,
                                const float* __restrict__ g, const float* __restrict__ bt,
                                float* __restrict__ O, int rows) {
    int warp = (blockIdx.x * blockDim.x + threadIdx.x) >> 5;
    int lane = threadIdx.x & 31;
    if (warp >= rows) return;
    const float* xr = X + (size_t)warp * D_MODEL;
    const float* rr = R + (size_t)warp * D_MODEL;

    float v[8];
    float s = 0.f, s2 = 0.f;
#pragma unroll
    for (int u = 0; u < 2; u++) {
        float4 a = *(const float4*)(xr + lane * 4 + u * 128);
        float4 c = *(const float4*)(rr + lane * 4 + u * 128);
        float t0 = a.x + c.x, t1 = a.y + c.y, t2 = a.z + c.z, t3 = a.w + c.w;
        v[u * 4 + 0] = t0; v[u * 4 + 1] = t1; v[u * 4 + 2] = t2; v[u * 4 + 3] = t3;
        s += t0 + t1 + t2 + t3;
        s2 += t0 * t0 + t1 * t1 + t2 * t2 + t3 * t3;
    }
#pragma unroll
    for (int o = 16; o > 0; o >>= 1) {
        s  += __shfl_xor_sync(0xffffffffu, s, o);
        s2 += __shfl_xor_sync(0xffffffffu, s2, o);
    }
    float mean = s * (1.f / D_MODEL);
    float var  = s2 * (1.f / D_MODEL) - mean * mean;
    float inv  = rsqrtf(var + 1e-5f);
#pragma unroll
    for (int u = 0; u < 2; u++) {
        int d = lane * 4 + u * 128;
        float4 o4;
        o4.x = (v[u * 4 + 0] - mean) * inv * g[d + 0] + bt[d + 0];
        o4.y = (v[u * 4 + 1] - mean) * inv * g[d + 1] + bt[d + 1];
        o4.z = (v[u * 4 + 2] - mean) * inv * g[d + 2] + bt[d + 2];
        o4.w = (v[u * 4 + 3] - mean) * inv * g[d + 3] + bt[d + 3];
        *(float4*)(O + (size_t)warp * D_MODEL + d) = o4;
    }
}

// ---------------------------------------------------------------------------
// Deformable sampling. One warp per (token, head); lane = channel (DH=32).
// Lanes 0..15 each own one of the 16 (level,point) samples: compute softmax
// weight + 4 bilinear taps, then broadcast (idx, w) to all lanes for gather.
// ---------------------------------------------------------------------------
__constant__ int c_lw[4]    = {128, 64, 32, 16};
__constant__ int c_lstart[4] = {0, 16384, 20480, 21504};

__global__ void sample_kernel(const float* __restrict__ Val, const float* __restrict__ Off,
                              const float* __restrict__ Awl, float* __restrict__ Samp) {
    int gw   = (blockIdx.x * blockDim.x + threadIdx.x) >> 5;
    int lane = threadIdx.x & 31;
    if (gw >= M_TOT * NH) return;
    int h   = gw & 7;
    int tok = gw >> 3;           // b*S + s
    int s   = tok % S_TOTAL;
    int b   = tok / S_TOTAL;

    // token's own level -> reference point
    int wt, st, sh;
    if (s < 16384)      { wt = 128; st = 0;     sh = 7; }
    else if (s < 20480) { wt = 64;  st = 16384; sh = 6; }
    else if (s < 21504) { wt = 32;  st = 20480; sh = 5; }
    else                { wt = 16;  st = 21504; sh = 4; }
    int sl = s - st;
    int iy = sl >> sh;
    int ix = sl - (iy << sh);
    float refx = (ix + 0.5f) / (float)wt;
    float refy = (iy + 0.5f) / (float)wt;   // square levels: h == w

    size_t rb = (size_t)tok;

    // softmax over the 16 sampling logits of this head
    float lv = (lane < 16) ? Awl[rb * 128 + h * 16 + lane] : -1e30f;
    float m = lv;
#pragma unroll
    for (int o = 8; o > 0; o >>= 1) m = fmaxf(m, __shfl_xor_sync(0xffffffffu, m, o));
    float e = (lane < 16) ? expf(lv - m) : 0.f;
    float ssum = e;
#pragma unroll
    for (int o = 8; o > 0; o >>= 1) ssum += __shfl_xor_sync(0xffffffffu, ssum, o);
    float aw = e / ssum;   // lanes >= 16 produce 0

    // per-sample taps (lanes 0..15)
    int idx0 = 0, idx1 = 0, idx2 = 0, idx3 = 0;
    float w0 = 0.f, w1 = 0.f, w2 = 0.f, w3 = 0.f;
    if (lane < 16) {
        int l   = lane >> 2;
        int wl  = c_lw[l];
        int stl = c_lstart[l];
        float ox = Off[rb * 256 + (size_t)(h * 16 + lane) * 2 + 0];
        float oy = Off[rb * 256 + (size_t)(h * 16 + lane) * 2 + 1];
        float x = refx * (float)wl + ox - 0.5f;
        float y = refy * (float)wl + oy - 0.5f;
        float xf = floorf(x), yf = floorf(y);
        float lx = x - xf, ly = y - yf;
        int x0 = (int)xf, y0 = (int)yf;
        int x1 = x0 + 1, y1 = y0 + 1;
        bool okx0 = (x0 >= 0) & (x0 < wl);
        bool okx1 = (x1 >= 0) & (x1 < wl);
        bool oky0 = (y0 >= 0) & (y0 < wl);
        bool oky1 = (y1 >= 0) & (y1 < wl);
        int cx0 = min(max(x0, 0), wl - 1), cx1 = min(max(x1, 0), wl - 1);
        int cy0 = min(max(y0, 0), wl - 1), cy1 = min(max(y1, 0), wl - 1);
        idx0 = stl + cy0 * wl + cx0;
        idx1 = stl + cy0 * wl + cx1;
        idx2 = stl + cy1 * wl + cx0;
        idx3 = stl + cy1 * wl + cx1;
        w0 = (1.f - lx) * (1.f - ly) * aw * ((okx0 && oky0) ? 1.f : 0.f);
        w1 = lx * (1.f - ly) * aw * ((okx1 && oky0) ? 1.f : 0.f);
        w2 = (1.f - lx) * ly * aw * ((okx0 && oky1) ? 1.f : 0.f);
        w3 = lx * ly * aw * ((okx1 && oky1) ? 1.f : 0.f);
    }

    const float* vb = Val + (size_t)b * S_TOTAL * 256 + h * 32 + lane;
    float acc = 0.f;
#pragma unroll
    for (int j = 0; j < 16; j++) {
        int   i0 = __shfl_sync(0xffffffffu, idx0, j);
        int   i1 = __shfl_sync(0xffffffffu, idx1, j);
        int   i2 = __shfl_sync(0xffffffffu, idx2, j);
        int   i3 = __shfl_sync(0xffffffffu, idx3, j);
        float f0 = __shfl_sync(0xffffffffu, w0, j);
        float f1 = __shfl_sync(0xffffffffu, w1, j);
        float f2 = __shfl_sync(0xffffffffu, w2, j);
        float f3 = __shfl_sync(0xffffffffu, w3, j);
        acc += f0 * vb[(size_t)i0 * 256];
        acc += f1 * vb[(size_t)i1 * 256];
        acc += f2 * vb[(size_t)i2 * 256];
        acc += f3 * vb[(size_t)i3 * 256];
    }
    Samp[(size_t)tok * 256 + h * 32 + lane] = acc;
}

// ---------------------------------------------------------------------------
// Host orchestration
// ---------------------------------------------------------------------------
extern "C" void kernel_launch(void* const* d_in, const int* in_sizes, int n_in,
                              void* d_out, int out_size) {
    // Input ordering: setup_inputs() inserts src0,pos0,src1,pos1,... (interleaved).
    // Detect at runtime via sizes: interleaved => in_sizes[1] == in_sizes[0]
    // (pos0 same size as src0); grouped => in_sizes[1] == in_sizes[0]/4 (src1).
    const float* src[4];
    const float* posin[4];
    bool interleaved = (in_sizes[1] == in_sizes[0]);
    for (int l = 0; l < 4; l++) {
        if (interleaved) {
            src[l]   = (const float*)d_in[2 * l];
            posin[l] = (const float*)d_in[2 * l + 1];
        } else {
            src[l]   = (const float*)d_in[l];
            posin[l] = (const float*)d_in[4 + l];
        }
    }
    const float* lemb  = (const float*)d_in[8];
    const float* Woff  = (const float*)d_in[9];
    const float* boff  = (const float*)d_in[10];
    const float* Wattn = (const float*)d_in[11];
    const float* battn = (const float*)d_in[12];
    const float* Wval  = (const float*)d_in[13];
    const float* bval  = (const float*)d_in[14];
    const float* Wout  = (const float*)d_in[15];
    const float* bout  = (const float*)d_in[16];
    const float* ln1s  = (const float*)d_in[17];
    const float* ln1b  = (const float*)d_in[18];
    const float* W1    = (const float*)d_in[19];
    const float* b1    = (const float*)d_in[20];
    const float* W2    = (const float*)d_in[21];
    const float* b2    = (const float*)d_in[22];
    const float* ln2s  = (const float*)d_in[23];
    const float* ln2b  = (const float*)d_in[24];

    float* out = (float*)d_out;

    float *pos, *q, *val, *off, *awl, *samp, *tmp, *ffh;
    cudaGetSymbolAddress((void**)&pos,  g_pos);
    cudaGetSymbolAddress((void**)&q,    g_q);
    cudaGetSymbolAddress((void**)&val,  g_val);
    cudaGetSymbolAddress((void**)&off,  g_off);
    cudaGetSymbolAddress((void**)&awl,  g_awl);
    cudaGetSymbolAddress((void**)&samp, g_samp);
    cudaGetSymbolAddress((void**)&tmp,  g_tmp);
    cudaGetSymbolAddress((void**)&ffh,  g_ffh);

    const int hw[4]    = {16384, 4096, 1024, 256};
    const int start[4] = {0, 16384, 20480, 21504};

    for (int l = 0; l < 4; l++) {
        dim3 grid(hw[l] / 32, D_MODEL / 32, BATCH);
        flatten_kernel<<<grid, dim3(32, 32)>>>(src[l], posin[l], lemb, out, pos,
                                               hw[l], start[l], l);
    }

    const int n4 = M_TOT * D_MODEL / 4;
    const int MB = M_TOT / 128;     // 340

    for (int i = 0; i < NLAYERS; i++) {
        // q = out + pos_flat
        add_kernel<<<(n4 + 255) / 256, 256>>>(out, pos, q, n4);
        // value = out @ Wval + bval
        sgemm_kernel<0><<<dim3(MB, 2), 256>>>(out, Wval + (size_t)i * 256 * 256,
                                              bval + i * 256, val, M_TOT, 256, 256);
        // off = q @ Woff + boff
        sgemm_kernel<0><<<dim3(MB, 2), 256>>>(q, Woff + (size_t)i * 256 * 256,
                                              boff + i * 256, off, M_TOT, 256, 256);
        // attn logits = q @ Wattn + battn
        sgemm_kernel<0><<<dim3(MB, 1), 256>>>(q, Wattn + (size_t)i * 256 * 128,
                                              battn + i * 128, awl, M_TOT, 128, 256);
        // deformable sampling
        sample_kernel<<<M_TOT * NH / 8, 256>>>(val, off, awl, samp);
        // attn out = samp @ Wout + bout
        sgemm_kernel<0><<<dim3(MB, 2), 256>>>(samp, Wout + (size_t)i * 256 * 256,
                                              bout + i * 256, tmp, M_TOT, 256, 256);
        // out = LN(out + attn)
        resid_ln_kernel<<<(M_TOT + 7) / 8, 256>>>(tmp, out, ln1s + i * 256,
                                                  ln1b + i * 256, out, M_TOT);
        // h = relu(out @ W1 + b1)
        sgemm_kernel<1><<<dim3(MB, 8), 256>>>(out, W1 + (size_t)i * 256 * 1024,
                                              b1 + i * 1024, ffh, M_TOT, 1024, 256);
        // ff = h @ W2 + b2
        sgemm_kernel<0><<<dim3(MB, 2), 256>>>(ffh, W2 + (size_t)i * 1024 * 256,
                                              b2 + i * 256, tmp, M_TOT, 256, 1024);
        // out = LN(out + ff)
        resid_ln_kernel<<<(M_TOT + 7) / 8, 256>>>(tmp, out, ln2s + i * 256,
                                                  ln2b + i * 256, out, M_TOT);
    }
}

// round 4
// speedup vs baseline: 1.9016x; 1.9016x over previous
#include <cuda_runtime.h>
#include <math.h>
#include <stdint.h>

// ---------------------------------------------------------------------------
// MSDeformAttn transformer encoder (6 layers).
// GEMMs on tcgen05 kind::tf32 with 3xTF32 split (fp32-class accuracy),
// guarded by the sm_103a arch-feature macro; SIMT fallback otherwise.
// D=256, NH=8, NL=4, NP=4, DH=32, DFF=1024, B=2, S=21760.
// ---------------------------------------------------------------------------

#define D_MODEL 256
#define NH 8
#define DFF 1024
#define NLAYERS 6
#define BATCH 2
#define S_TOTAL 21760
#define M_TOT (BATCH * S_TOTAL)   // 43520 rows; divisible by 128

#if defined(__CUDA_ARCH_FEAT_SM103_ALL) || defined(__CUDA_ARCH_FEAT_SM100_ALL) || defined(__CUDA_ARCH_FEAT_SM101_ALL)
#define HAS_TCGEN05 1
#else
#define HAS_TCGEN05 0
#endif

// Scratch (allocation-free: __device__ globals)
__device__ float g_pos[M_TOT * D_MODEL];
__device__ float g_q[M_TOT * D_MODEL];
__device__ float g_val[M_TOT * D_MODEL];
__device__ float g_off[M_TOT * 256];
__device__ float g_awl[M_TOT * 128];
__device__ float g_samp[M_TOT * D_MODEL];
__device__ float g_tmp[M_TOT * D_MODEL];
__device__ float g_ffh[M_TOT * DFF];

// Transposed weights: per layer 753664 floats
#define WT_LAYER 753664
__device__ float g_wt[NLAYERS * WT_LAYER];
#define WT_VAL  0
#define WT_OFF  65536
#define WT_ATTN 131072
#define WT_OUT  163840
#define WT_W1   229376
#define WT_W2   491520

// ---------------------------------------------------------------------------
// PTX helpers (only instantiated inside HAS_TCGEN05 blocks)
// ---------------------------------------------------------------------------
__device__ __forceinline__ uint32_t elect_one_pred() {
    uint32_t pred;
    asm volatile(
        "{\n\t.reg .pred p;\n\telect.sync _|p, 0xFFFFFFFF;\n\t"
        "selp.b32 %0, 1, 0, p;\n\t}" : "=r"(pred));
    return pred;
}
__device__ __forceinline__ uint32_t smem_to_u32(const void* p) {
    uint32_t a;
    asm("{ .reg .u64 t; cvta.to.shared.u64 t, %1; cvt.u32.u64 %0, t; }"
        : "=r"(a) : "l"(p));
    return a;
}

#define TCGEN05_ALLOC(addr, n) \
    asm volatile("tcgen05.alloc.cta_group::1.sync.aligned.shared::cta.b32 [%0], %1;" \
                 :: "r"((uint32_t)(addr)), "r"((uint32_t)(n)) : "memory")
#define TCGEN05_DEALLOC(tmem, n) \
    asm volatile("tcgen05.dealloc.cta_group::1.sync.aligned.b32 %0, %1;" \
                 :: "r"(tmem), "r"((uint32_t)(n)))
#define TCGEN05_RELINQ() \
    asm volatile("tcgen05.relinquish_alloc_permit.cta_group::1.sync.aligned;")
#define TCGEN05_COMMIT(mbar) \
    asm volatile("tcgen05.commit.cta_group::1.mbarrier::arrive::one.shared::cluster.b64 [%0];" \
                 :: "r"((uint32_t)(mbar)) : "memory")
#define TCGEN05_FENCE_AFTER() \
    asm volatile("tcgen05.fence::after_thread_sync;" ::: "memory")
#define TCGEN05_FENCE_BEFORE() \
    asm volatile("tcgen05.fence::before_thread_sync;" ::: "memory")
#define TCGEN05_WAIT_LD() \
    asm volatile("tcgen05.wait::ld.sync.aligned;" ::: "memory")
#define FENCE_PROXY_ASYNC() \
    asm volatile("fence.proxy.async.shared::cta;" ::: "memory")
#define MBARRIER_INIT(mbar, cnt) \
    asm volatile("mbarrier.init.shared.b64 [%0], %1;" \
                 :: "r"((uint32_t)(mbar)), "r"((uint32_t)(cnt)) : "memory")
#define MBARRIER_INVAL(mbar) \
    asm volatile("mbarrier.inval.shared.b64 [%0];" :: "r"((uint32_t)(mbar)) : "memory")

#define MBARRIER_WAIT_PARITY(mbar, parity) do {                               \
    uint32_t _m = (uint32_t)(mbar);                                           \
    uint32_t _p = (uint32_t)(parity);                                         \
    asm volatile(                                                             \
        "{\n\t.reg .pred P1;\n\t"                                             \
        "WAIT_LOOP_%=:\n\t"                                                   \
        "mbarrier.try_wait.parity.acquire.cta.shared::cta.b64 P1, [%0], %1, 0x989680;\n\t" \
        "@P1 bra.uni WAIT_DONE_%=;\n\t"                                       \
        "bra.uni WAIT_LOOP_%=;\n\t"                                           \
        "WAIT_DONE_%=:\n\t}"                                                  \
        :: "r"(_m), "r"(_p) : "memory");                                      \
} while (0)

#define TCGEN05_MMA_TF32_SS(d, ad, bd, id, en) do {                           \
    uint32_t _e = (en) ? 1u : 0u; uint32_t _z = 0;                            \
    asm volatile(                                                             \
        "{\n\t.reg .pred p;\n\tsetp.ne.u32 p, %5, 0;\n\t"                     \
        "tcgen05.mma.cta_group::1.kind::tf32 [%0], %1, %2, %3, {%4,%4,%4,%4}, p;\n\t}" \
        :: "r"(d), "l"(ad), "l"(bd), "r"(id), "r"(_z), "r"(_e) : "memory");   \
} while (0)

#define TCGEN05_LD32(r, addr)                                                 \
    asm volatile(                                                             \
        "tcgen05.ld.sync.aligned.32x32b.x32.b32 "                             \
        "{%0, %1, %2, %3, %4, %5, %6, %7, "                                   \
        " %8, %9, %10, %11, %12, %13, %14, %15, "                             \
        " %16, %17, %18, %19, %20, %21, %22, %23, "                           \
        " %24, %25, %26, %27, %28, %29, %30, %31}, [%32];"                    \
        : "=r"((r)[0]),  "=r"((r)[1]),  "=r"((r)[2]),  "=r"((r)[3]),          \
          "=r"((r)[4]),  "=r"((r)[5]),  "=r"((r)[6]),  "=r"((r)[7]),          \
          "=r"((r)[8]),  "=r"((r)[9]),  "=r"((r)[10]), "=r"((r)[11]),         \
          "=r"((r)[12]), "=r"((r)[13]), "=r"((r)[14]), "=r"((r)[15]),         \
          "=r"((r)[16]), "=r"((r)[17]), "=r"((r)[18]), "=r"((r)[19]),         \
          "=r"((r)[20]), "=r"((r)[21]), "=r"((r)[22]), "=r"((r)[23]),         \
          "=r"((r)[24]), "=r"((r)[25]), "=r"((r)[26]), "=r"((r)[27]),         \
          "=r"((r)[28]), "=r"((r)[29]), "=r"((r)[30]), "=r"((r)[31])          \
        : "r"(addr))

// SW128 K-major smem descriptor: layout=2, version=1, SBO=64, LBO=1
__device__ __forceinline__ uint64_t make_sw128_desc(uint32_t addr) {
    const uint64_t base = (uint64_t(2) << 61) | (uint64_t(1) << 46)
                        | (uint64_t(64) << 32) | (uint64_t(1) << 16);
    return base | ((uint64_t)(addr >> 4) & 0x3FFF);
}

__device__ __forceinline__ float tf32_hi(float x) {
    return __uint_as_float(__float_as_uint(x) & 0xffffe000u);
}

// ---------------------------------------------------------------------------
// GEMM: C[M,N] = A[M,K] @ Wt[N,K]^T + bias (opt ReLU)
// Tensor path: tcgen05 tf32 3-split, 128x128 tile, BK=32. 256 threads.
// Fallback: SIMT NT-GEMM, same tile/thread shape.
// ---------------------------------------------------------------------------
#define TCG_IDESC 0x8200910u  // cF32 | aTF32 | bTF32 | N=128 | M=128
#define STAGE_BYTES 65536
#define OFF_AH 0
#define OFF_AL 16384
#define OFF_BH 32768
#define OFF_BL 49152
#define TCG_SMEM (1024 + 2 * STAGE_BYTES)   // 132096

template <int RELU>
__global__ __launch_bounds__(256, 1)
void tc_gemm(const float* __restrict__ A, const float* __restrict__ Wt,
             const float* __restrict__ bias, float* __restrict__ C,
             int M, int N, int K) {
    extern __shared__ char smem[];
    const int tid  = threadIdx.x;
    const int brow = blockIdx.x * 128;
    const int bcol = blockIdx.y * 128;

    // common coalesced load mapping: instr i covers row i*32 + (tid>>3),
    // k-cols (tid&7)*4 .. +3
    const int lr = tid >> 3;
    const int c4 = tid & 7;
    const float* Abase = A  + (size_t)(brow + lr) * K + c4 * 4;
    const float* Bbase = Wt + (size_t)(bcol + lr) * K + c4 * 4;
    const int KT = K >> 5;
    float4 a_reg[4], b_reg[4];

#define LDG_TILE(kt) do {                                                     \
    int _k = (kt) * 32;                                                       \
    _Pragma("unroll")                                                         \
    for (int i = 0; i < 4; i++) {                                             \
        a_reg[i] = *(const float4*)(Abase + (size_t)(i * 32) * K + _k);       \
        b_reg[i] = *(const float4*)(Bbase + (size_t)(i * 32) * K + _k);       \
    }                                                                         \
} while (0)

#if HAS_TCGEN05
    const uint32_t sbase = smem_to_u32(smem);
    const int wid  = tid >> 5;
    const int lane = tid & 31;

    const uint32_t TMEMP = sbase;
    const uint32_t MBAR0 = sbase + 8;
    const uint32_t MBAR1 = sbase + 16;
    const uint32_t STG0  = sbase + 1024;

    if (wid == 0) TCGEN05_ALLOC(TMEMP, 128);
    if (tid == 0) { MBARRIER_INIT(MBAR0, 1); MBARRIER_INIT(MBAR1, 1); }
    __syncthreads();
    uint32_t tmem;
    asm volatile("ld.shared.b32 %0, [%1];" : "=r"(tmem) : "r"(TMEMP));
    if (wid == 0) TCGEN05_RELINQ();

    uint32_t swoff[4];
#pragma unroll
    for (int i = 0; i < 4; i++) {
        uint32_t off = (uint32_t)(i * 32 + lr) * 128 + c4 * 16;
        swoff[i] = off ^ ((off >> 3) & 0x70);
    }

    int ph0 = 0, ph1 = 0;

#define STS_TILE(stoff) do {                                                  \
    char* _sb = smem + 1024 + (stoff);                                        \
    _Pragma("unroll")                                                         \
    for (int i = 0; i < 4; i++) {                                             \
        float4 a = a_reg[i], b = b_reg[i];                                    \
        float4 ah = make_float4(tf32_hi(a.x), tf32_hi(a.y), tf32_hi(a.z), tf32_hi(a.w)); \
        float4 al = make_float4(a.x - ah.x, a.y - ah.y, a.z - ah.z, a.w - ah.w); \
        float4 bh = make_float4(tf32_hi(b.x), tf32_hi(b.y), tf32_hi(b.z), tf32_hi(b.w)); \
        float4 bl = make_float4(b.x - bh.x, b.y - bh.y, b.z - bh.z, b.w - bh.w); \
        *(float4*)(_sb + OFF_AH + swoff[i]) = ah;                             \
        *(float4*)(_sb + OFF_AL + swoff[i]) = al;                             \
        *(float4*)(_sb + OFF_BH + swoff[i]) = bh;                             \
        *(float4*)(_sb + OFF_BL + swoff[i]) = bl;                             \
    }                                                                         \
} while (0)

    LDG_TILE(0);
    STS_TILE(0);
    FENCE_PROXY_ASYNC();
    __syncthreads();

    for (int kt = 0; kt < KT; kt++) {
        int s = kt & 1;
        bool have_next = (kt + 1 < KT);
        if (have_next) LDG_TILE(kt + 1);

        if (wid == 0) {
            if (elect_one_pred()) {
                uint32_t sb = STG0 + s * STAGE_BYTES;
                uint64_t dah = make_sw128_desc(sb + OFF_AH);
                uint64_t dal = make_sw128_desc(sb + OFF_AL);
                uint64_t dbh = make_sw128_desc(sb + OFF_BH);
                uint64_t dbl = make_sw128_desc(sb + OFF_BL);
#pragma unroll
                for (int ks = 0; ks < 4; ks++) {
                    TCGEN05_MMA_TF32_SS(tmem, dah + ks * 2, dbh + ks * 2,
                                        TCG_IDESC, (kt > 0) || (ks > 0));
                    TCGEN05_MMA_TF32_SS(tmem, dah + ks * 2, dbl + ks * 2,
                                        TCG_IDESC, 1);
                    TCGEN05_MMA_TF32_SS(tmem, dal + ks * 2, dbh + ks * 2,
                                        TCG_IDESC, 1);
                }
                TCGEN05_COMMIT(s == 0 ? MBAR0 : MBAR1);
            }
        }

        if (have_next) {
            int ns = s ^ 1;
            if (kt >= 1) {   // MMA of iter kt-1 read stage ns; wait before reuse
                if (ns == 0) { MBARRIER_WAIT_PARITY(MBAR0, ph0); ph0 ^= 1; }
                else         { MBARRIER_WAIT_PARITY(MBAR1, ph1); ph1 ^= 1; }
            }
            STS_TILE(ns * STAGE_BYTES);
            FENCE_PROXY_ASYNC();
            __syncthreads();
        }
    }

    if (((KT - 1) & 1) == 0) { MBARRIER_WAIT_PARITY(MBAR0, ph0); }
    else                     { MBARRIER_WAIT_PARITY(MBAR1, ph1); }
    TCGEN05_FENCE_AFTER();

    // Epilogue: warp w -> rows (w&3)*32+lane, cols (w>>2)*64 .. +63
    {
        int colbase = (wid >> 2) * 64;
        uint32_t d0[32], d1[32];
        TCGEN05_LD32(d0, tmem + colbase);
        TCGEN05_LD32(d1, tmem + colbase + 32);
        TCGEN05_WAIT_LD();
        TCGEN05_FENCE_BEFORE();

        int r = brow + (wid & 3) * 32 + lane;
        float* Crow = C + (size_t)r * N + bcol + colbase;
        const float* brow_b = bias + bcol + colbase;
#pragma unroll
        for (int c = 0; c < 32; c += 4) {
            float4 o;
            o.x = __uint_as_float(d0[c + 0]) + brow_b[c + 0];
            o.y = __uint_as_float(d0[c + 1]) + brow_b[c + 1];
            o.z = __uint_as_float(d0[c + 2]) + brow_b[c + 2];
            o.w = __uint_as_float(d0[c + 3]) + brow_b[c + 3];
            if (RELU) {
                o.x = fmaxf(o.x, 0.f); o.y = fmaxf(o.y, 0.f);
                o.z = fmaxf(o.z, 0.f); o.w = fmaxf(o.w, 0.f);
            }
            *(float4*)(Crow + c) = o;
        }
#pragma unroll
        for (int c = 0; c < 32; c += 4) {
            float4 o;
            o.x = __uint_as_float(d1[c + 0]) + brow_b[32 + c + 0];
            o.y = __uint_as_float(d1[c + 1]) + brow_b[32 + c + 1];
            o.z = __uint_as_float(d1[c + 2]) + brow_b[32 + c + 2];
            o.w = __uint_as_float(d1[c + 3]) + brow_b[32 + c + 3];
            if (RELU) {
                o.x = fmaxf(o.x, 0.f); o.y = fmaxf(o.y, 0.f);
                o.z = fmaxf(o.z, 0.f); o.w = fmaxf(o.w, 0.f);
            }
            *(float4*)(Crow + 32 + c) = o;
        }
    }

    __syncthreads();
    if (tid == 0) { MBARRIER_INVAL(MBAR0); MBARRIER_INVAL(MBAR1); }
    __syncthreads();
    if (wid == 0) TCGEN05_DEALLOC(tmem, 128);

#else  // ------------------- SIMT fallback (plain sm_103 pass) -------------
    float (*As)[132] = (float(*)[132])(smem);
    float (*Bs)[132] = (float(*)[132])(smem + 32 * 132 * 4);

    int ty = (tid >> 4) * 8;
    int tx = (tid & 15) * 8;

    float acc[8][8];
#pragma unroll
    for (int i = 0; i < 8; i++)
#pragma unroll
        for (int j = 0; j < 8; j++) acc[i][j] = 0.f;

    for (int kt = 0; kt < KT; kt++) {
        LDG_TILE(kt);
        __syncthreads();
#pragma unroll
        for (int i = 0; i < 4; i++) {
            int r = i * 32 + lr;
            As[c4 * 4 + 0][r] = a_reg[i].x; As[c4 * 4 + 1][r] = a_reg[i].y;
            As[c4 * 4 + 2][r] = a_reg[i].z; As[c4 * 4 + 3][r] = a_reg[i].w;
            Bs[c4 * 4 + 0][r] = b_reg[i].x; Bs[c4 * 4 + 1][r] = b_reg[i].y;
            Bs[c4 * 4 + 2][r] = b_reg[i].z; Bs[c4 * 4 + 3][r] = b_reg[i].w;
        }
        __syncthreads();
#pragma unroll
        for (int k = 0; k < 32; k++) {
            float av[8], bv[8];
#pragma unroll
            for (int i = 0; i < 8; i++) { av[i] = As[k][ty + i]; bv[i] = Bs[k][tx + i]; }
#pragma unroll
            for (int i = 0; i < 8; i++)
#pragma unroll
                for (int j = 0; j < 8; j++)
                    acc[i][j] += av[i] * bv[j];
        }
    }

    int row = brow + ty;
    int col = bcol + tx;
#pragma unroll
    for (int i = 0; i < 8; i++) {
#pragma unroll
        for (int j = 0; j < 8; j++) {
            float v = acc[i][j] + bias[col + j];
            if (RELU) v = fmaxf(v, 0.f);
            C[(size_t)(row + i) * N + col + j] = v;
        }
    }
#endif
}

// ---------------------------------------------------------------------------
// Weight transpose: W[K,N] -> Wt[N,K]
// ---------------------------------------------------------------------------
__global__ void transpose_kernel(const float* __restrict__ W, float* __restrict__ Wt,
                                 int K, int N) {
    __shared__ float t[32][33];
    int k0 = blockIdx.x * 32, n0 = blockIdx.y * 32;
    t[threadIdx.y][threadIdx.x] = W[(size_t)(k0 + threadIdx.y) * N + n0 + threadIdx.x];
    __syncthreads();
    Wt[(size_t)(n0 + threadIdx.y) * K + k0 + threadIdx.x] = t[threadIdx.x][threadIdx.y];
}

// ---------------------------------------------------------------------------
// Flatten: src [B, D, h, w] -> out [B, S, D] slice ; pos likewise + level_embed
// ---------------------------------------------------------------------------
__global__ void flatten_kernel(const float* __restrict__ src,
                               const float* __restrict__ pos,
                               const float* __restrict__ lemb,
                               float* __restrict__ out,
                               float* __restrict__ posout,
                               int hw, int start, int level) {
    __shared__ float ts[32][33];
    __shared__ float tp[32][33];
    int b  = blockIdx.z;
    int p0 = blockIdx.x * 32;
    int d0 = blockIdx.y * 32;
    int tx = threadIdx.x, ty = threadIdx.y;

    const float* sp = src + ((size_t)b * D_MODEL + d0 + ty) * hw + p0;
    const float* pp = pos + ((size_t)b * D_MODEL + d0 + ty) * hw + p0;
    ts[ty][tx] = sp[tx];
    tp[ty][tx] = pp[tx];
    __syncthreads();

    int d = d0 + tx;
    float le = lemb[level * D_MODEL + d];
    size_t srow = (size_t)b * S_TOTAL + start + p0 + ty;
    out[srow * D_MODEL + d]    = ts[tx][ty];
    posout[srow * D_MODEL + d] = tp[tx][ty] + le;
}

__global__ void add_kernel(const float* __restrict__ a, const float* __restrict__ b,
                           float* __restrict__ c, int n4) {
    int i = blockIdx.x * blockDim.x + threadIdx.x;
    if (i < n4) {
        float4 x = ((const float4*)a)[i];
        float4 y = ((const float4*)b)[i];
        x.x += y.x; x.y += y.y; x.z += y.z; x.w += y.w;
        ((float4*)c)[i] = x;
    }
}

// ---------------------------------------------------------------------------
// Residual + LayerNorm: out = LN(x + r) * gamma + beta. One warp per row.
// ---------------------------------------------------------------------------
__global__ void resid_ln_kernel(const float* __restrict__ X, const float* __restrict__ R,
                                const float* __restrict__ g, const float* __restrict__ bt,
                                float* __restrict__ O, int rows) {
    int warp = (blockIdx.x * blockDim.x + threadIdx.x) >> 5;
    int lane = threadIdx.x & 31;
    if (warp >= rows) return;
    const float* xr = X + (size_t)warp * D_MODEL;
    const float* rr = R + (size_t)warp * D_MODEL;

    float v[8];
    float s = 0.f, s2 = 0.f;
#pragma unroll
    for (int u = 0; u < 2; u++) {
        float4 a = *(const float4*)(xr + lane * 4 + u * 128);
        float4 c = *(const float4*)(rr + lane * 4 + u * 128);
        float t0 = a.x + c.x, t1 = a.y + c.y, t2 = a.z + c.z, t3 = a.w + c.w;
        v[u * 4 + 0] = t0; v[u * 4 + 1] = t1; v[u * 4 + 2] = t2; v[u * 4 + 3] = t3;
        s += t0 + t1 + t2 + t3;
        s2 += t0 * t0 + t1 * t1 + t2 * t2 + t3 * t3;
    }
#pragma unroll
    for (int o = 16; o > 0; o >>= 1) {
        s  += __shfl_xor_sync(0xffffffffu, s, o);
        s2 += __shfl_xor_sync(0xffffffffu, s2, o);
    }
    float mean = s * (1.f / D_MODEL);
    float var  = s2 * (1.f / D_MODEL) - mean * mean;
    float inv  = rsqrtf(var + 1e-5f);
#pragma unroll
    for (int u = 0; u < 2; u++) {
        int d = lane * 4 + u * 128;
        float4 o4;
        o4.x = (v[u * 4 + 0] - mean) * inv * g[d + 0] + bt[d + 0];
        o4.y = (v[u * 4 + 1] - mean) * inv * g[d + 1] + bt[d + 1];
        o4.z = (v[u * 4 + 2] - mean) * inv * g[d + 2] + bt[d + 2];
        o4.w = (v[u * 4 + 3] - mean) * inv * g[d + 3] + bt[d + 3];
        *(float4*)(O + (size_t)warp * D_MODEL + d) = o4;
    }
}

// ---------------------------------------------------------------------------
// Deformable sampling. One warp per (token, head); lane = channel (DH=32).
// ---------------------------------------------------------------------------
__constant__ int c_lw[4]     = {128, 64, 32, 16};
__constant__ int c_lstart[4] = {0, 16384, 20480, 21504};

__global__ void sample_kernel(const float* __restrict__ Val, const float* __restrict__ Off,
                              const float* __restrict__ Awl, float* __restrict__ Samp) {
    int gw   = (blockIdx.x * blockDim.x + threadIdx.x) >> 5;
    int lane = threadIdx.x & 31;
    if (gw >= M_TOT * NH) return;
    int h   = gw & 7;
    int tok = gw >> 3;
    int s   = tok % S_TOTAL;
    int b   = tok / S_TOTAL;

    int wt, st, sh;
    if (s < 16384)      { wt = 128; st = 0;     sh = 7; }
    else if (s < 20480) { wt = 64;  st = 16384; sh = 6; }
    else if (s < 21504) { wt = 32;  st = 20480; sh = 5; }
    else                { wt = 16;  st = 21504; sh = 4; }
    int sl = s - st;
    int iy = sl >> sh;
    int ix = sl - (iy << sh);
    float refx = (ix + 0.5f) / (float)wt;
    float refy = (iy + 0.5f) / (float)wt;

    size_t rb = (size_t)tok;

    float lv = (lane < 16) ? Awl[rb * 128 + h * 16 + lane] : -1e30f;
    float m = lv;
#pragma unroll
    for (int o = 8; o > 0; o >>= 1) m = fmaxf(m, __shfl_xor_sync(0xffffffffu, m, o));
    float e = (lane < 16) ? expf(lv - m) : 0.f;
    float ssum = e;
#pragma unroll
    for (int o = 8; o > 0; o >>= 1) ssum += __shfl_xor_sync(0xffffffffu, ssum, o);
    float aw = e / ssum;

    int idx0 = 0, idx1 = 0, idx2 = 0, idx3 = 0;
    float w0 = 0.f, w1 = 0.f, w2 = 0.f, w3 = 0.f;
    if (lane < 16) {
        int l   = lane >> 2;
        int wl  = c_lw[l];
        int stl = c_lstart[l];
        float ox = Off[rb * 256 + (size_t)(h * 16 + lane) * 2 + 0];
        float oy = Off[rb * 256 + (size_t)(h * 16 + lane) * 2 + 1];
        float x = refx * (float)wl + ox - 0.5f;
        float y = refy * (float)wl + oy - 0.5f;
        float xf = floorf(x), yf = floorf(y);
        float lx = x - xf, ly = y - yf;
        int x0 = (int)xf, y0 = (int)yf;
        int x1 = x0 + 1, y1 = y0 + 1;
        bool okx0 = (x0 >= 0) & (x0 < wl);
        bool okx1 = (x1 >= 0) & (x1 < wl);
        bool oky0 = (y0 >= 0) & (y0 < wl);
        bool oky1 = (y1 >= 0) & (y1 < wl);
        int cx0 = min(max(x0, 0), wl - 1), cx1 = min(max(x1, 0), wl - 1);
        int cy0 = min(max(y0, 0), wl - 1), cy1 = min(max(y1, 0), wl - 1);
        idx0 = stl + cy0 * wl + cx0;
        idx1 = stl + cy0 * wl + cx1;
        idx2 = stl + cy1 * wl + cx0;
        idx3 = stl + cy1 * wl + cx1;
        w0 = (1.f - lx) * (1.f - ly) * aw * ((okx0 && oky0) ? 1.f : 0.f);
        w1 = lx * (1.f - ly) * aw * ((okx1 && oky0) ? 1.f : 0.f);
        w2 = (1.f - lx) * ly * aw * ((okx0 && oky1) ? 1.f : 0.f);
        w3 = lx * ly * aw * ((okx1 && oky1) ? 1.f : 0.f);
    }

    const float* vb = Val + (size_t)b * S_TOTAL * 256 + h * 32 + lane;
    float acc = 0.f;
#pragma unroll
    for (int j = 0; j < 16; j++) {
        int   i0 = __shfl_sync(0xffffffffu, idx0, j);
        int   i1 = __shfl_sync(0xffffffffu, idx1, j);
        int   i2 = __shfl_sync(0xffffffffu, idx2, j);
        int   i3 = __shfl_sync(0xffffffffu, idx3, j);
        float f0 = __shfl_sync(0xffffffffu, w0, j);
        float f1 = __shfl_sync(0xffffffffu, w1, j);
        float f2 = __shfl_sync(0xffffffffu, w2, j);
        float f3 = __shfl_sync(0xffffffffu, w3, j);
        acc += f0 * vb[(size_t)i0 * 256];
        acc += f1 * vb[(size_t)i1 * 256];
        acc += f2 * vb[(size_t)i2 * 256];
        acc += f3 * vb[(size_t)i3 * 256];
    }
    Samp[(size_t)tok * 256 + h * 32 + lane] = acc;
}

// ---------------------------------------------------------------------------
// Host orchestration
// ---------------------------------------------------------------------------
extern "C" void kernel_launch(void* const* d_in, const int* in_sizes, int n_in,
                              void* d_out, int out_size) {
    const float* src[4];
    const float* posin[4];
    bool interleaved = (in_sizes[1] == in_sizes[0]);
    for (int l = 0; l < 4; l++) {
        if (interleaved) {
            src[l]   = (const float*)d_in[2 * l];
            posin[l] = (const float*)d_in[2 * l + 1];
        } else {
            src[l]   = (const float*)d_in[l];
            posin[l] = (const float*)d_in[4 + l];
        }
    }
    const float* lemb  = (const float*)d_in[8];
    const float* Woff  = (const float*)d_in[9];
    const float* boff  = (const float*)d_in[10];
    const float* Wattn = (const float*)d_in[11];
    const float* battn = (const float*)d_in[12];
    const float* Wval  = (const float*)d_in[13];
    const float* bval  = (const float*)d_in[14];
    const float* Wout  = (const float*)d_in[15];
    const float* bout  = (const float*)d_in[16];
    const float* ln1s  = (const float*)d_in[17];
    const float* ln1b  = (const float*)d_in[18];
    const float* W1    = (const float*)d_in[19];
    const float* b1    = (const float*)d_in[20];
    const float* W2    = (const float*)d_in[21];
    const float* b2    = (const float*)d_in[22];
    const float* ln2s  = (const float*)d_in[23];
    const float* ln2b  = (const float*)d_in[24];

    float* out = (float*)d_out;

    float *pos, *q, *val, *off, *awl, *samp, *tmp, *ffh, *wt;
    cudaGetSymbolAddress((void**)&pos,  g_pos);
    cudaGetSymbolAddress((void**)&q,    g_q);
    cudaGetSymbolAddress((void**)&val,  g_val);
    cudaGetSymbolAddress((void**)&off,  g_off);
    cudaGetSymbolAddress((void**)&awl,  g_awl);
    cudaGetSymbolAddress((void**)&samp, g_samp);
    cudaGetSymbolAddress((void**)&tmp,  g_tmp);
    cudaGetSymbolAddress((void**)&ffh,  g_ffh);
    cudaGetSymbolAddress((void**)&wt,   g_wt);

    cudaFuncSetAttribute(tc_gemm<0>, cudaFuncAttributeMaxDynamicSharedMemorySize, TCG_SMEM);
    cudaFuncSetAttribute(tc_gemm<1>, cudaFuncAttributeMaxDynamicSharedMemorySize, TCG_SMEM);

    // Transpose all weights: W[K,N] -> Wt[N,K]
    for (int i = 0; i < NLAYERS; i++) {
        float* base = wt + (size_t)i * WT_LAYER;
        transpose_kernel<<<dim3(256/32, 256/32),  dim3(32, 32)>>>(Wval + (size_t)i*256*256,  base + WT_VAL,  256, 256);
        transpose_kernel<<<dim3(256/32, 256/32),  dim3(32, 32)>>>(Woff + (size_t)i*256*256,  base + WT_OFF,  256, 256);
        transpose_kernel<<<dim3(256/32, 128/32),  dim3(32, 32)>>>(Wattn + (size_t)i*256*128, base + WT_ATTN, 256, 128);
        transpose_kernel<<<dim3(256/32, 256/32),  dim3(32, 32)>>>(Wout + (size_t)i*256*256,  base + WT_OUT,  256, 256);
        transpose_kernel<<<dim3(256/32, 1024/32), dim3(32, 32)>>>(W1 + (size_t)i*256*1024,   base + WT_W1,   256, 1024);
        transpose_kernel<<<dim3(1024/32, 256/32), dim3(32, 32)>>>(W2 + (size_t)i*1024*256,   base + WT_W2,   1024, 256);
    }

    const int hw[4]    = {16384, 4096, 1024, 256};
    const int start[4] = {0, 16384, 20480, 21504};
    for (int l = 0; l < 4; l++) {
        dim3 grid(hw[l] / 32, D_MODEL / 32, BATCH);
        flatten_kernel<<<grid, dim3(32, 32)>>>(src[l], posin[l], lemb, out, pos,
                                               hw[l], start[l], l);
    }

    const int n4 = M_TOT * D_MODEL / 4;
    const int MB = M_TOT / 128;     // 340

    for (int i = 0; i < NLAYERS; i++) {
        float* base = wt + (size_t)i * WT_LAYER;
        add_kernel<<<(n4 + 255) / 256, 256>>>(out, pos, q, n4);
        tc_gemm<0><<<dim3(MB, 2), 256, TCG_SMEM>>>(out, base + WT_VAL,
                                                   bval + i * 256, val, M_TOT, 256, 256);
        tc_gemm<0><<<dim3(MB, 2), 256, TCG_SMEM>>>(q, base + WT_OFF,
                                                   boff + i * 256, off, M_TOT, 256, 256);
        tc_gemm<0><<<dim3(MB, 1), 256, TCG_SMEM>>>(q, base + WT_ATTN,
                                                   battn + i * 128, awl, M_TOT, 128, 256);
        sample_kernel<<<M_TOT * NH / 8, 256>>>(val, off, awl, samp);
        tc_gemm<0><<<dim3(MB, 2), 256, TCG_SMEM>>>(samp, base + WT_OUT,
                                                   bout + i * 256, tmp, M_TOT, 256, 256);
        resid_ln_kernel<<<(M_TOT + 7) / 8, 256>>>(tmp, out, ln1s + i * 256,
                                                  ln1b + i * 256, out, M_TOT);
        tc_gemm<1><<<dim3(MB, 8), 256, TCG_SMEM>>>(out, base + WT_W1,
                                                   b1 + i * 1024, ffh, M_TOT, 1024, 256);
        tc_gemm<0><<<dim3(MB, 2), 256, TCG_SMEM>>>(ffh, base + WT_W2,
                                                   b2 + i * 256, tmp, M_TOT, 256, 1024);
        resid_ln_kernel<<<(M_TOT + 7) / 8, 256>>>(tmp, out, ln2s + i * 256,
                                                  ln2b + i * 256, out, M_TOT);
    }
}

// round 5
// speedup vs baseline: 2.2462x; 1.1812x over previous
#include <cuda_runtime.h>
#include <cuda_fp16.h>
#include <math.h>
#include <stdint.h>

// ---------------------------------------------------------------------------
// MSDeformAttn transformer encoder (6 layers).
// GEMMs on tcgen05 kind::f16 with 3xFP16 split (fp32-class accuracy),
// guarded by the sm_103a arch-feature macro; SIMT fallback otherwise.
// D=256, NH=8, NL=4, NP=4, DH=32, DFF=1024, B=2, S=21760.
// ---------------------------------------------------------------------------

#define D_MODEL 256
#define NH 8
#define DFF 1024
#define NLAYERS 6
#define BATCH 2
#define S_TOTAL 21760
#define M_TOT (BATCH * S_TOTAL)   // 43520 rows; divisible by 128

#if defined(__CUDA_ARCH_FEAT_SM103_ALL) || defined(__CUDA_ARCH_FEAT_SM100_ALL) || defined(__CUDA_ARCH_FEAT_SM101_ALL)
#define HAS_TCGEN05 1
#else
#define HAS_TCGEN05 0
#endif

// Scratch (allocation-free: __device__ globals)
__device__ float g_pos[M_TOT * D_MODEL];
__device__ float g_val[M_TOT * D_MODEL];
__device__ float g_off[M_TOT * 256];
__device__ float g_awl[M_TOT * 128];
__device__ float g_samp[M_TOT * D_MODEL];
__device__ float g_tmp[M_TOT * D_MODEL];
__device__ float g_ffh[M_TOT * DFF];

// Transposed + fp16-split weights: per layer 753664 elements
#define WT_LAYER 753664
__device__ __half g_wth[NLAYERS * WT_LAYER];
__device__ __half g_wtl[NLAYERS * WT_LAYER];
#define WT_VAL  0
#define WT_OFF  65536
#define WT_ATTN 131072
#define WT_OUT  163840
#define WT_W1   229376
#define WT_W2   491520

// ---------------------------------------------------------------------------
// PTX helpers
// ---------------------------------------------------------------------------
__device__ __forceinline__ uint32_t elect_one_pred() {
    uint32_t pred;
    asm volatile(
        "{\n\t.reg .pred p;\n\telect.sync _|p, 0xFFFFFFFF;\n\t"
        "selp.b32 %0, 1, 0, p;\n\t}" : "=r"(pred));
    return pred;
}
__device__ __forceinline__ uint32_t smem_to_u32(const void* p) {
    uint32_t a;
    asm("{ .reg .u64 t; cvta.to.shared.u64 t, %1; cvt.u32.u64 %0, t; }"
        : "=r"(a) : "l"(p));
    return a;
}

#define TCGEN05_ALLOC(addr, n) \
    asm volatile("tcgen05.alloc.cta_group::1.sync.aligned.shared::cta.b32 [%0], %1;" \
                 :: "r"((uint32_t)(addr)), "r"((uint32_t)(n)) : "memory")
#define TCGEN05_DEALLOC(tmem, n) \
    asm volatile("tcgen05.dealloc.cta_group::1.sync.aligned.b32 %0, %1;" \
                 :: "r"(tmem), "r"((uint32_t)(n)))
#define TCGEN05_RELINQ() \
    asm volatile("tcgen05.relinquish_alloc_permit.cta_group::1.sync.aligned;")
#define TCGEN05_COMMIT(mbar) \
    asm volatile("tcgen05.commit.cta_group::1.mbarrier::arrive::one.shared::cluster.b64 [%0];" \
                 :: "r"((uint32_t)(mbar)) : "memory")
#define TCGEN05_FENCE_AFTER() \
    asm volatile("tcgen05.fence::after_thread_sync;" ::: "memory")
#define TCGEN05_FENCE_BEFORE() \
    asm volatile("tcgen05.fence::before_thread_sync;" ::: "memory")
#define TCGEN05_WAIT_LD() \
    asm volatile("tcgen05.wait::ld.sync.aligned;" ::: "memory")
#define FENCE_PROXY_ASYNC() \
    asm volatile("fence.proxy.async.shared::cta;" ::: "memory")
#define MBARRIER_INIT(mbar, cnt) \
    asm volatile("mbarrier.init.shared.b64 [%0], %1;" \
                 :: "r"((uint32_t)(mbar)), "r"((uint32_t)(cnt)) : "memory")
#define MBARRIER_INVAL(mbar) \
    asm volatile("mbarrier.inval.shared.b64 [%0];" :: "r"((uint32_t)(mbar)) : "memory")

#define MBARRIER_WAIT_PARITY(mbar, parity) do {                               \
    uint32_t _m = (uint32_t)(mbar);                                           \
    uint32_t _p = (uint32_t)(parity);                                         \
    asm volatile(                                                             \
        "{\n\t.reg .pred P1;\n\t"                                             \
        "WAIT_LOOP_%=:\n\t"                                                   \
        "mbarrier.try_wait.parity.acquire.cta.shared::cta.b64 P1, [%0], %1, 0x989680;\n\t" \
        "@P1 bra.uni WAIT_DONE_%=;\n\t"                                       \
        "bra.uni WAIT_LOOP_%=;\n\t"                                           \
        "WAIT_DONE_%=:\n\t}"                                                  \
        :: "r"(_m), "r"(_p) : "memory");                                      \
} while (0)

// fp16 SS MMA (fp32 accum), cta_group::1
#define TCGEN05_MMA_F16_SS(d, ad, bd, id, en) do {                            \
    uint32_t _e = (en) ? 1u : 0u; uint32_t _z = 0;                            \
    asm volatile(                                                             \
        "{\n\t.reg .pred p;\n\tsetp.ne.u32 p, %5, 0;\n\t"                     \
        "tcgen05.mma.cta_group::1.kind::f16 [%0], %1, %2, %3, {%4,%4,%4,%4}, p;\n\t}" \
        :: "r"(d), "l"(ad), "l"(bd), "r"(id), "r"(_z), "r"(_e) : "memory");   \
} while (0)

#define TCGEN05_LD32(r, addr)                                                 \
    asm volatile(                                                             \
        "tcgen05.ld.sync.aligned.32x32b.x32.b32 "                             \
        "{%0, %1, %2, %3, %4, %5, %6, %7, "                                   \
        " %8, %9, %10, %11, %12, %13, %14, %15, "                             \
        " %16, %17, %18, %19, %20, %21, %22, %23, "                           \
        " %24, %25, %26, %27, %28, %29, %30, %31}, [%32];"                    \
        : "=r"((r)[0]),  "=r"((r)[1]),  "=r"((r)[2]),  "=r"((r)[3]),          \
          "=r"((r)[4]),  "=r"((r)[5]),  "=r"((r)[6]),  "=r"((r)[7]),          \
          "=r"((r)[8]),  "=r"((r)[9]),  "=r"((r)[10]), "=r"((r)[11]),         \
          "=r"((r)[12]), "=r"((r)[13]), "=r"((r)[14]), "=r"((r)[15]),         \
          "=r"((r)[16]), "=r"((r)[17]), "=r"((r)[18]), "=r"((r)[19]),         \
          "=r"((r)[20]), "=r"((r)[21]), "=r"((r)[22]), "=r"((r)[23]),         \
          "=r"((r)[24]), "=r"((r)[25]), "=r"((r)[26]), "=r"((r)[27]),         \
          "=r"((r)[28]), "=r"((r)[29]), "=r"((r)[30]), "=r"((r)[31])          \
        : "r"(addr))

// SW128 K-major smem descriptor: layout=2, version=1, SBO=64, LBO=1
__device__ __forceinline__ uint64_t make_sw128_desc(uint32_t addr) {
    const uint64_t base = (uint64_t(2) << 61) | (uint64_t(1) << 46)
                        | (uint64_t(64) << 32) | (uint64_t(1) << 16);
    return base | ((uint64_t)(addr >> 4) & 0x3FFF);
}

// ---------------------------------------------------------------------------
// GEMM: C[M,N] = (A [+ A2])[M,K] @ Wt[N,K]^T + bias (opt ReLU)
// fp16 3-split: C = AH*BH + AH*BL + AL*BH (lo*lo dropped, ~2^-22).
// Tile 128x128, BK=64 floats (rows of 64 halves = 128B = SW128 atom).
// idesc: dtype F32 (1<<4) | atype F16(0) | btype F16(0) | N=128 | M=128
// ---------------------------------------------------------------------------
#define TCG_IDESC 0x8200010u
#define STAGE_BYTES 65536
#define OFF_AH 0
#define OFF_AL 16384
#define OFF_BH 32768
#define OFF_BL 49152
#define TCG_SMEM (1024 + 2 * STAGE_BYTES)   // 132096

template <int RELU>
__global__ __launch_bounds__(256, 1)
void tc_gemm(const float* __restrict__ A, const float* __restrict__ A2,
             const __half* __restrict__ WH, const __half* __restrict__ WL,
             const float* __restrict__ bias, float* __restrict__ C,
             int M, int N, int K) {
    extern __shared__ char smem[];
    const int tid  = threadIdx.x;
    const int brow = blockIdx.x * 128;
    const int bcol = blockIdx.y * 128;

    // coalesced load mapping: row-group i covers row i*32 + (tid>>3),
    // element cols (tid&7)*8 .. +7 (floats for A, halves for B)
    const int lr = tid >> 3;
    const int c8 = (tid & 7) * 8;
    const float*  Ab  = A  + (size_t)(brow + lr) * K + c8;
    const float*  A2b = A2 ? A2 + (size_t)(brow + lr) * K + c8 : (const float*)0;
    const __half* BHb = WH + (size_t)(bcol + lr) * K + c8;
    const __half* BLb = WL + (size_t)(bcol + lr) * K + c8;
    const int KT = K >> 6;     // K64 tiles

    float4 a0[4], a1[4];
    uint4  bh[4], bl[4];

#define LDG_TILE(kt) do {                                                     \
    int _k = (kt) * 64;                                                       \
    _Pragma("unroll")                                                         \
    for (int i = 0; i < 4; i++) {                                             \
        size_t ro = (size_t)(i * 32) * K + _k;                                \
        a0[i] = *(const float4*)(Ab + ro);                                    \
        a1[i] = *(const float4*)(Ab + ro + 4);                                \
        if (A2b) {                                                            \
            float4 e0 = *(const float4*)(A2b + ro);                           \
            float4 e1 = *(const float4*)(A2b + ro + 4);                       \
            a0[i].x += e0.x; a0[i].y += e0.y; a0[i].z += e0.z; a0[i].w += e0.w; \
            a1[i].x += e1.x; a1[i].y += e1.y; a1[i].z += e1.z; a1[i].w += e1.w; \
        }                                                                     \
        bh[i] = *(const uint4*)(BHb + ro);                                    \
        bl[i] = *(const uint4*)(BLb + ro);                                    \
    }                                                                         \
} while (0)

#if HAS_TCGEN05
    const uint32_t sbase = smem_to_u32(smem);
    const int wid  = tid >> 5;
    const int lane = tid & 31;

    const uint32_t TMEMP = sbase;
    const uint32_t MBAR0 = sbase + 8;
    const uint32_t MBAR1 = sbase + 16;
    const uint32_t STG0  = sbase + 1024;

    if (wid == 0) TCGEN05_ALLOC(TMEMP, 128);
    if (tid == 0) { MBARRIER_INIT(MBAR0, 1); MBARRIER_INIT(MBAR1, 1); }
    __syncthreads();
    uint32_t tmem;
    asm volatile("ld.shared.b32 %0, [%1];" : "=r"(tmem) : "r"(TMEMP));
    if (wid == 0) TCGEN05_RELINQ();

    uint32_t swoff[4];
#pragma unroll
    for (int i = 0; i < 4; i++) {
        uint32_t off = (uint32_t)(i * 32 + lr) * 128 + (tid & 7) * 16;
        swoff[i] = off ^ ((off >> 3) & 0x70);
    }

    int ph0 = 0, ph1 = 0;

#define SPLIT8(x0, x1, hi, lo) do {                                           \
    float _v[8] = {x0.x, x0.y, x0.z, x0.w, x1.x, x1.y, x1.z, x1.w};           \
    _Pragma("unroll")                                                         \
    for (int j = 0; j < 4; j++) {                                             \
        __half hx = __float2half_rn(_v[2*j]);                                 \
        __half hy = __float2half_rn(_v[2*j+1]);                               \
        __half lx = __float2half_rn(_v[2*j]   - __half2float(hx));            \
        __half ly = __float2half_rn(_v[2*j+1] - __half2float(hy));            \
        __half2 hp = __halves2half2(hx, hy);                                  \
        __half2 lp = __halves2half2(lx, ly);                                  \
        (hi)[j] = *(uint32_t*)&hp;                                            \
        (lo)[j] = *(uint32_t*)&lp;                                            \
    }                                                                         \
} while (0)

#define STS_TILE(stoff) do {                                                  \
    char* _sb = smem + 1024 + (stoff);                                        \
    _Pragma("unroll")                                                         \
    for (int i = 0; i < 4; i++) {                                             \
        uint32_t ah[4], al[4];                                                \
        SPLIT8(a0[i], a1[i], ah, al);                                         \
        *(uint4*)(_sb + OFF_AH + swoff[i]) = make_uint4(ah[0], ah[1], ah[2], ah[3]); \
        *(uint4*)(_sb + OFF_AL + swoff[i]) = make_uint4(al[0], al[1], al[2], al[3]); \
        *(uint4*)(_sb + OFF_BH + swoff[i]) = bh[i];                           \
        *(uint4*)(_sb + OFF_BL + swoff[i]) = bl[i];                           \
    }                                                                         \
} while (0)

    LDG_TILE(0);
    STS_TILE(0);
    FENCE_PROXY_ASYNC();
    __syncthreads();

    for (int kt = 0; kt < KT; kt++) {
        int s = kt & 1;
        bool have_next = (kt + 1 < KT);
        if (have_next) LDG_TILE(kt + 1);

        if (wid == 0) {
            if (elect_one_pred()) {
                uint32_t sb = STG0 + s * STAGE_BYTES;
                uint64_t dah = make_sw128_desc(sb + OFF_AH);
                uint64_t dal = make_sw128_desc(sb + OFF_AL);
                uint64_t dbh = make_sw128_desc(sb + OFF_BH);
                uint64_t dbl = make_sw128_desc(sb + OFF_BL);
#pragma unroll
                for (int ks = 0; ks < 4; ks++) {   // K=16 halves per chunk
                    TCGEN05_MMA_F16_SS(tmem, dah + ks * 2, dbh + ks * 2,
                                       TCG_IDESC, (kt > 0) || (ks > 0));
                    TCGEN05_MMA_F16_SS(tmem, dah + ks * 2, dbl + ks * 2,
                                       TCG_IDESC, 1);
                    TCGEN05_MMA_F16_SS(tmem, dal + ks * 2, dbh + ks * 2,
                                       TCG_IDESC, 1);
                }
                TCGEN05_COMMIT(s == 0 ? MBAR0 : MBAR1);
            }
        }

        if (have_next) {
            int ns = s ^ 1;
            if (kt >= 1) {   // MMA of iter kt-1 read stage ns; wait before reuse
                if (ns == 0) { MBARRIER_WAIT_PARITY(MBAR0, ph0); ph0 ^= 1; }
                else         { MBARRIER_WAIT_PARITY(MBAR1, ph1); ph1 ^= 1; }
            }
            STS_TILE(ns * STAGE_BYTES);
            FENCE_PROXY_ASYNC();
            __syncthreads();
        }
    }

    if (((KT - 1) & 1) == 0) { MBARRIER_WAIT_PARITY(MBAR0, ph0); }
    else                     { MBARRIER_WAIT_PARITY(MBAR1, ph1); }
    TCGEN05_FENCE_AFTER();

    // Epilogue: warp w -> rows (w&3)*32+lane, cols (w>>2)*64 .. +63
    {
        int colbase = (wid >> 2) * 64;
        uint32_t d0[32], d1[32];
        TCGEN05_LD32(d0, tmem + colbase);
        TCGEN05_LD32(d1, tmem + colbase + 32);
        TCGEN05_WAIT_LD();
        TCGEN05_FENCE_BEFORE();

        int r = brow + (wid & 3) * 32 + lane;
        float* Crow = C + (size_t)r * N + bcol + colbase;
        const float* brow_b = bias + bcol + colbase;
#pragma unroll
        for (int c = 0; c < 32; c += 4) {
            float4 o;
            o.x = __uint_as_float(d0[c + 0]) + brow_b[c + 0];
            o.y = __uint_as_float(d0[c + 1]) + brow_b[c + 1];
            o.z = __uint_as_float(d0[c + 2]) + brow_b[c + 2];
            o.w = __uint_as_float(d0[c + 3]) + brow_b[c + 3];
            if (RELU) {
                o.x = fmaxf(o.x, 0.f); o.y = fmaxf(o.y, 0.f);
                o.z = fmaxf(o.z, 0.f); o.w = fmaxf(o.w, 0.f);
            }
            *(float4*)(Crow + c) = o;
        }
#pragma unroll
        for (int c = 0; c < 32; c += 4) {
            float4 o;
            o.x = __uint_as_float(d1[c + 0]) + brow_b[32 + c + 0];
            o.y = __uint_as_float(d1[c + 1]) + brow_b[32 + c + 1];
            o.z = __uint_as_float(d1[c + 2]) + brow_b[32 + c + 2];
            o.w = __uint_as_float(d1[c + 3]) + brow_b[32 + c + 3];
            if (RELU) {
                o.x = fmaxf(o.x, 0.f); o.y = fmaxf(o.y, 0.f);
                o.z = fmaxf(o.z, 0.f); o.w = fmaxf(o.w, 0.f);
            }
            *(float4*)(Crow + 32 + c) = o;
        }
    }

    __syncthreads();
    if (tid == 0) { MBARRIER_INVAL(MBAR0); MBARRIER_INVAL(MBAR1); }
    __syncthreads();
    if (wid == 0) TCGEN05_DEALLOC(tmem, 128);

#else  // ------------------- SIMT fallback (plain sm_103 pass) -------------
    float (*As)[132] = (float(*)[132])(smem);
    float (*Bs)[132] = (float(*)[132])(smem + 64 * 132 * 4);

    int ty = (tid >> 4) * 8;
    int tx = (tid & 15) * 8;

    float acc[8][8];
#pragma unroll
    for (int i = 0; i < 8; i++)
#pragma unroll
        for (int j = 0; j < 8; j++) acc[i][j] = 0.f;

    for (int kt = 0; kt < KT; kt++) {
        LDG_TILE(kt);
        __syncthreads();
#pragma unroll
        for (int i = 0; i < 4; i++) {
            int r = i * 32 + lr;
            float av[8] = {a0[i].x, a0[i].y, a0[i].z, a0[i].w,
                           a1[i].x, a1[i].y, a1[i].z, a1[i].w};
            const __half* hh = (const __half*)&bh[i];
            const __half* ll = (const __half*)&bl[i];
#pragma unroll
            for (int j = 0; j < 8; j++) {
                As[c8 + j][r] = av[j];
                Bs[c8 + j][r] = __half2float(hh[j]) + __half2float(ll[j]);
            }
        }
        __syncthreads();
#pragma unroll 16
        for (int k = 0; k < 64; k++) {
            float av[8], bv[8];
#pragma unroll
            for (int i = 0; i < 8; i++) { av[i] = As[k][ty + i]; bv[i] = Bs[k][tx + i]; }
#pragma unroll
            for (int i = 0; i < 8; i++)
#pragma unroll
                for (int j = 0; j < 8; j++)
                    acc[i][j] += av[i] * bv[j];
        }
    }

    int row = brow + ty;
    int col = bcol + tx;
#pragma unroll
    for (int i = 0; i < 8; i++) {
#pragma unroll
        for (int j = 0; j < 8; j++) {
            float v = acc[i][j] + bias[col + j];
            if (RELU) v = fmaxf(v, 0.f);
            C[(size_t)(row + i) * N + col + j] = v;
        }
    }
#endif
}

// ---------------------------------------------------------------------------
// Weight transpose + fp16 split: W[K,N] -> Ht[N,K], Lt[N,K]
// ---------------------------------------------------------------------------
__global__ void transplit_kernel(const float* __restrict__ W,
                                 __half* __restrict__ Ht, __half* __restrict__ Lt,
                                 int K, int N) {
    __shared__ float t[32][33];
    int k0 = blockIdx.x * 32, n0 = blockIdx.y * 32;
    t[threadIdx.y][threadIdx.x] = W[(size_t)(k0 + threadIdx.y) * N + n0 + threadIdx.x];
    __syncthreads();
    float v = t[threadIdx.x][threadIdx.y];
    __half h = __float2half_rn(v);
    size_t o = (size_t)(n0 + threadIdx.y) * K + k0 + threadIdx.x;
    Ht[o] = h;
    Lt[o] = __float2half_rn(v - __half2float(h));
}

// ---------------------------------------------------------------------------
// Flatten: src [B, D, h, w] -> out [B, S, D] slice ; pos likewise + level_embed
// ---------------------------------------------------------------------------
__global__ void flatten_kernel(const float* __restrict__ src,
                               const float* __restrict__ pos,
                               const float* __restrict__ lemb,
                               float* __restrict__ out,
                               float* __restrict__ posout,
                               int hw, int start, int level) {
    __shared__ float ts[32][33];
    __shared__ float tp[32][33];
    int b  = blockIdx.z;
    int p0 = blockIdx.x * 32;
    int d0 = blockIdx.y * 32;
    int tx = threadIdx.x, ty = threadIdx.y;

    const float* sp = src + ((size_t)b * D_MODEL + d0 + ty) * hw + p0;
    const float* pp = pos + ((size_t)b * D_MODEL + d0 + ty) * hw + p0;
    ts[ty][tx] = sp[tx];
    tp[ty][tx] = pp[tx];
    __syncthreads();

    int d = d0 + tx;
    float le = lemb[level * D_MODEL + d];
    size_t srow = (size_t)b * S_TOTAL + start + p0 + ty;
    out[srow * D_MODEL + d]    = ts[tx][ty];
    posout[srow * D_MODEL + d] = tp[tx][ty] + le;
}

// ---------------------------------------------------------------------------
// Residual + LayerNorm: out = LN(x + r) * gamma + beta. One warp per row.
// ---------------------------------------------------------------------------
__global__ void resid_ln_kernel(const float* __restrict__ X, const float* __restrict__ R,
                                const float* __restrict__ g, const float* __restrict__ bt,
                                float* __restrict__ O, int rows) {
    int warp = (blockIdx.x * blockDim.x + threadIdx.x) >> 5;
    int lane = threadIdx.x & 31;
    if (warp >= rows) return;
    const float* xr = X + (size_t)warp * D_MODEL;
    const float* rr = R + (size_t)warp * D_MODEL;

    float v[8];
    float s = 0.f, s2 = 0.f;
#pragma unroll
    for (int u = 0; u < 2; u++) {
        float4 a = *(const float4*)(xr + lane * 4 + u * 128);
        float4 c = *(const float4*)(rr + lane * 4 + u * 128);
        float t0 = a.x + c.x, t1 = a.y + c.y, t2 = a.z + c.z, t3 = a.w + c.w;
        v[u * 4 + 0] = t0; v[u * 4 + 1] = t1; v[u * 4 + 2] = t2; v[u * 4 + 3] = t3;
        s += t0 + t1 + t2 + t3;
        s2 += t0 * t0 + t1 * t1 + t2 * t2 + t3 * t3;
    }
#pragma unroll
    for (int o = 16; o > 0; o >>= 1) {
        s  += __shfl_xor_sync(0xffffffffu, s, o);
        s2 += __shfl_xor_sync(0xffffffffu, s2, o);
    }
    float mean = s * (1.f / D_MODEL);
    float var  = s2 * (1.f / D_MODEL) - mean * mean;
    float inv  = rsqrtf(var + 1e-5f);
#pragma unroll
    for (int u = 0; u < 2; u++) {
        int d = lane * 4 + u * 128;
        float4 o4;
        o4.x = (v[u * 4 + 0] - mean) * inv * g[d + 0] + bt[d + 0];
        o4.y = (v[u * 4 + 1] - mean) * inv * g[d + 1] + bt[d + 1];
        o4.z = (v[u * 4 + 2] - mean) * inv * g[d + 2] + bt[d + 2];
        o4.w = (v[u * 4 + 3] - mean) * inv * g[d + 3] + bt[d + 3];
        *(float4*)(O + (size_t)warp * D_MODEL + d) = o4;
    }
}

// ---------------------------------------------------------------------------
// Deformable sampling. One warp per (token, head); lane = channel (DH=32).
// ---------------------------------------------------------------------------
__constant__ int c_lw[4]     = {128, 64, 32, 16};
__constant__ int c_lstart[4] = {0, 16384, 20480, 21504};

__global__ void sample_kernel(const float* __restrict__ Val, const float* __restrict__ Off,
                              const float* __restrict__ Awl, float* __restrict__ Samp) {
    int gw   = (blockIdx.x * blockDim.x + threadIdx.x) >> 5;
    int lane = threadIdx.x & 31;
    if (gw >= M_TOT * NH) return;
    int h   = gw & 7;
    int tok = gw >> 3;
    int s   = tok % S_TOTAL;
    int b   = tok / S_TOTAL;

    int wt, st, sh;
    if (s < 16384)      { wt = 128; st = 0;     sh = 7; }
    else if (s < 20480) { wt = 64;  st = 16384; sh = 6; }
    else if (s < 21504) { wt = 32;  st = 20480; sh = 5; }
    else                { wt = 16;  st = 21504; sh = 4; }
    int sl = s - st;
    int iy = sl >> sh;
    int ix = sl - (iy << sh);
    float refx = (ix + 0.5f) / (float)wt;
    float refy = (iy + 0.5f) / (float)wt;

    size_t rb = (size_t)tok;

    float lv = (lane < 16) ? Awl[rb * 128 + h * 16 + lane] : -1e30f;
    float m = lv;
#pragma unroll
    for (int o = 8; o > 0; o >>= 1) m = fmaxf(m, __shfl_xor_sync(0xffffffffu, m, o));
    float e = (lane < 16) ? expf(lv - m) : 0.f;
    float ssum = e;
#pragma unroll
    for (int o = 8; o > 0; o >>= 1) ssum += __shfl_xor_sync(0xffffffffu, ssum, o);
    float aw = e / ssum;

    int idx0 = 0, idx1 = 0, idx2 = 0, idx3 = 0;
    float w0 = 0.f, w1 = 0.f, w2 = 0.f, w3 = 0.f;
    if (lane < 16) {
        int l   = lane >> 2;
        int wl  = c_lw[l];
        int stl = c_lstart[l];
        float ox = Off[rb * 256 + (size_t)(h * 16 + lane) * 2 + 0];
        float oy = Off[rb * 256 + (size_t)(h * 16 + lane) * 2 + 1];
        float x = refx * (float)wl + ox - 0.5f;
        float y = refy * (float)wl + oy - 0.5f;
        float xf = floorf(x), yf = floorf(y);
        float lx = x - xf, ly = y - yf;
        int x0 = (int)xf, y0 = (int)yf;
        int x1 = x0 + 1, y1 = y0 + 1;
        bool okx0 = (x0 >= 0) & (x0 < wl);
        bool okx1 = (x1 >= 0) & (x1 < wl);
        bool oky0 = (y0 >= 0) & (y0 < wl);
        bool oky1 = (y1 >= 0) & (y1 < wl);
        int cx0 = min(max(x0, 0), wl - 1), cx1 = min(max(x1, 0), wl - 1);
        int cy0 = min(max(y0, 0), wl - 1), cy1 = min(max(y1, 0), wl - 1);
        idx0 = stl + cy0 * wl + cx0;
        idx1 = stl + cy0 * wl + cx1;
        idx2 = stl + cy1 * wl + cx0;
        idx3 = stl + cy1 * wl + cx1;
        w0 = (1.f - lx) * (1.f - ly) * aw * ((okx0 && oky0) ? 1.f : 0.f);
        w1 = lx * (1.f - ly) * aw * ((okx1 && oky0) ? 1.f : 0.f);
        w2 = (1.f - lx) * ly * aw * ((okx0 && oky1) ? 1.f : 0.f);
        w3 = lx * ly * aw * ((okx1 && oky1) ? 1.f : 0.f);
    }

    const float* vb = Val + (size_t)b * S_TOTAL * 256 + h * 32 + lane;
    float acc = 0.f;
#pragma unroll
    for (int j = 0; j < 16; j++) {
        int   i0 = __shfl_sync(0xffffffffu, idx0, j);
        int   i1 = __shfl_sync(0xffffffffu, idx1, j);
        int   i2 = __shfl_sync(0xffffffffu, idx2, j);
        int   i3 = __shfl_sync(0xffffffffu, idx3, j);
        float f0 = __shfl_sync(0xffffffffu, w0, j);
        float f1 = __shfl_sync(0xffffffffu, w1, j);
        float f2 = __shfl_sync(0xffffffffu, w2, j);
        float f3 = __shfl_sync(0xffffffffu, w3, j);
        acc += f0 * vb[(size_t)i0 * 256];
        acc += f1 * vb[(size_t)i1 * 256];
        acc += f2 * vb[(size_t)i2 * 256];
        acc += f3 * vb[(size_t)i3 * 256];
    }
    Samp[(size_t)tok * 256 + h * 32 + lane] = acc;
}

// ---------------------------------------------------------------------------
// Host orchestration
// ---------------------------------------------------------------------------
extern "C" void kernel_launch(void* const* d_in, const int* in_sizes, int n_in,
                              void* d_out, int out_size) {
    const float* src[4];
    const float* posin[4];
    bool interleaved = (in_sizes[1] == in_sizes[0]);
    for (int l = 0; l < 4; l++) {
        if (interleaved) {
            src[l]   = (const float*)d_in[2 * l];
            posin[l] = (const float*)d_in[2 * l + 1];
        } else {
            src[l]   = (const float*)d_in[l];
            posin[l] = (const float*)d_in[4 + l];
        }
    }
    const float* lemb  = (const float*)d_in[8];
    const float* Woff  = (const float*)d_in[9];
    const float* boff  = (const float*)d_in[10];
    const float* Wattn = (const float*)d_in[11];
    const float* battn = (const float*)d_in[12];
    const float* Wval  = (const float*)d_in[13];
    const float* bval  = (const float*)d_in[14];
    const float* Wout  = (const float*)d_in[15];
    const float* bout  = (const float*)d_in[16];
    const float* ln1s  = (const float*)d_in[17];
    const float* ln1b  = (const float*)d_in[18];
    const float* W1    = (const float*)d_in[19];
    const float* b1    = (const float*)d_in[20];
    const float* W2    = (const float*)d_in[21];
    const float* b2    = (const float*)d_in[22];
    const float* ln2s  = (const float*)d_in[23];
    const float* ln2b  = (const float*)d_in[24];

    float* out = (float*)d_out;

    float *pos, *val, *off, *awl, *samp, *tmp, *ffh;
    __half *wth, *wtl;
    cudaGetSymbolAddress((void**)&pos,  g_pos);
    cudaGetSymbolAddress((void**)&val,  g_val);
    cudaGetSymbolAddress((void**)&off,  g_off);
    cudaGetSymbolAddress((void**)&awl,  g_awl);
    cudaGetSymbolAddress((void**)&samp, g_samp);
    cudaGetSymbolAddress((void**)&tmp,  g_tmp);
    cudaGetSymbolAddress((void**)&ffh,  g_ffh);
    cudaGetSymbolAddress((void**)&wth,  g_wth);
    cudaGetSymbolAddress((void**)&wtl,  g_wtl);

    cudaFuncSetAttribute(tc_gemm<0>, cudaFuncAttributeMaxDynamicSharedMemorySize, TCG_SMEM);
    cudaFuncSetAttribute(tc_gemm<1>, cudaFuncAttributeMaxDynamicSharedMemorySize, TCG_SMEM);

    // Transpose + fp16-split all weights: W[K,N] -> Ht/Lt[N,K]
    for (int i = 0; i < NLAYERS; i++) {
        __half* bh = wth + (size_t)i * WT_LAYER;
        __half* bl = wtl + (size_t)i * WT_LAYER;
        transplit_kernel<<<dim3(8, 8),   dim3(32, 32)>>>(Wval + (size_t)i*256*256,  bh + WT_VAL,  bl + WT_VAL,  256, 256);
        transplit_kernel<<<dim3(8, 8),   dim3(32, 32)>>>(Woff + (size_t)i*256*256,  bh + WT_OFF,  bl + WT_OFF,  256, 256);
        transplit_kernel<<<dim3(8, 4),   dim3(32, 32)>>>(Wattn + (size_t)i*256*128, bh + WT_ATTN, bl + WT_ATTN, 256, 128);
        transplit_kernel<<<dim3(8, 8),   dim3(32, 32)>>>(Wout + (size_t)i*256*256,  bh + WT_OUT,  bl + WT_OUT,  256, 256);
        transplit_kernel<<<dim3(8, 32),  dim3(32, 32)>>>(W1 + (size_t)i*256*1024,   bh + WT_W1,   bl + WT_W1,   256, 1024);
        transplit_kernel<<<dim3(32, 8),  dim3(32, 32)>>>(W2 + (size_t)i*1024*256,   bh + WT_W2,   bl + WT_W2,   1024, 256);
    }

    const int hw[4]    = {16384, 4096, 1024, 256};
    const int start[4] = {0, 16384, 20480, 21504};
    for (int l = 0; l < 4; l++) {
        dim3 grid(hw[l] / 32, D_MODEL / 32, BATCH);
        flatten_kernel<<<grid, dim3(32, 32)>>>(src[l], posin[l], lemb, out, pos,
                                               hw[l], start[l], l);
    }

    const int MB = M_TOT / 128;     // 340

    for (int i = 0; i < NLAYERS; i++) {
        const __half* bh = wth + (size_t)i * WT_LAYER;
        const __half* bl = wtl + (size_t)i * WT_LAYER;
        // value = out @ Wval + bval
        tc_gemm<0><<<dim3(MB, 2), 256, TCG_SMEM>>>(out, nullptr, bh + WT_VAL, bl + WT_VAL,
                                                   bval + i * 256, val, M_TOT, 256, 256);
        // off = (out + pos) @ Woff + boff   (q fused into A-load)
        tc_gemm<0><<<dim3(MB, 2), 256, TCG_SMEM>>>(out, pos, bh + WT_OFF, bl + WT_OFF,
                                                   boff + i * 256, off, M_TOT, 256, 256);
        // attn logits = (out + pos) @ Wattn + battn
        tc_gemm<0><<<dim3(MB, 1), 256, TCG_SMEM>>>(out, pos, bh + WT_ATTN, bl + WT_ATTN,
                                                   battn + i * 128, awl, M_TOT, 128, 256);
        // deformable sampling
        sample_kernel<<<M_TOT * NH / 8, 256>>>(val, off, awl, samp);
        // attn out = samp @ Wout + bout
        tc_gemm<0><<<dim3(MB, 2), 256, TCG_SMEM>>>(samp, nullptr, bh + WT_OUT, bl + WT_OUT,
                                                   bout + i * 256, tmp, M_TOT, 256, 256);
        // out = LN(out + attn)
        resid_ln_kernel<<<(M_TOT + 7) / 8, 256>>>(tmp, out, ln1s + i * 256,
                                                  ln1b + i * 256, out, M_TOT);
        // h = relu(out @ W1 + b1)
        tc_gemm<1><<<dim3(MB, 8), 256, TCG_SMEM>>>(out, nullptr, bh + WT_W1, bl + WT_W1,
                                                   b1 + i * 1024, ffh, M_TOT, 1024, 256);
        // ff = h @ W2 + b2
        tc_gemm<0><<<dim3(MB, 2), 256, TCG_SMEM>>>(ffh, nullptr, bh + WT_W2, bl + WT_W2,
                                                   b2 + i * 256, tmp, M_TOT, 256, 1024);
        // out = LN(out + ff)
        resid_ln_kernel<<<(M_TOT + 7) / 8, 256>>>(tmp, out, ln2s + i * 256,
                                                  ln2b + i * 256, out, M_TOT);
    }
}

// round 8
// speedup vs baseline: 2.5114x; 1.1181x over previous
#include <cuda_runtime.h>
#include <cuda_fp16.h>
#include <math.h>
#include <stdint.h>

// ---------------------------------------------------------------------------
// MSDeformAttn transformer encoder (6 layers).
// GEMMs on tcgen05 kind::f16 with 3xFP16 split (fp32-class accuracy),
// BN=128 tiles (round-5 proven), new vectorized sampler + fused prologue.
// D=256, NH=8, NL=4, NP=4, DH=32, DFF=1024, B=2, S=21760.
// ---------------------------------------------------------------------------

#define D_MODEL 256
#define NH 8
#define DFF 1024
#define NLAYERS 6
#define BATCH 2
#define S_TOTAL 21760
#define M_TOT (BATCH * S_TOTAL)   // 43520 rows; divisible by 128

#if defined(__CUDA_ARCH_FEAT_SM103_ALL) || defined(__CUDA_ARCH_FEAT_SM100_ALL) || defined(__CUDA_ARCH_FEAT_SM101_ALL)
#define HAS_TCGEN05 1
#else
#define HAS_TCGEN05 0
#endif

// Scratch (allocation-free: __device__ globals)
__device__ float g_pos[M_TOT * D_MODEL];
__device__ float g_val[M_TOT * D_MODEL];
__device__ float g_off[M_TOT * 256];
__device__ float g_awl[M_TOT * 128];
__device__ float g_samp[M_TOT * D_MODEL];
__device__ float g_tmp[M_TOT * D_MODEL];
__device__ float g_ffh[M_TOT * DFF];

// Transposed + fp16-split weights: per layer 753664 elements
#define WT_LAYER 753664
__device__ __half g_wth[NLAYERS * WT_LAYER];
__device__ __half g_wtl[NLAYERS * WT_LAYER];
#define WT_VAL  0
#define WT_OFF  65536
#define WT_ATTN 131072
#define WT_OUT  163840
#define WT_W1   229376
#define WT_W2   491520

// ---------------------------------------------------------------------------
// PTX helpers
// ---------------------------------------------------------------------------
__device__ __forceinline__ uint32_t elect_one_pred() {
    uint32_t pred;
    asm volatile(
        "{\n\t.reg .pred p;\n\telect.sync _|p, 0xFFFFFFFF;\n\t"
        "selp.b32 %0, 1, 0, p;\n\t}" : "=r"(pred));
    return pred;
}
__device__ __forceinline__ uint32_t smem_to_u32(const void* p) {
    uint32_t a;
    asm("{ .reg .u64 t; cvta.to.shared.u64 t, %1; cvt.u32.u64 %0, t; }"
        : "=r"(a) : "l"(p));
    return a;
}

#define TCGEN05_ALLOC(addr, n) \
    asm volatile("tcgen05.alloc.cta_group::1.sync.aligned.shared::cta.b32 [%0], %1;" \
                 :: "r"((uint32_t)(addr)), "r"((uint32_t)(n)) : "memory")
#define TCGEN05_DEALLOC(tmem, n) \
    asm volatile("tcgen05.dealloc.cta_group::1.sync.aligned.b32 %0, %1;" \
                 :: "r"(tmem), "r"((uint32_t)(n)))
#define TCGEN05_RELINQ() \
    asm volatile("tcgen05.relinquish_alloc_permit.cta_group::1.sync.aligned;")
#define TCGEN05_COMMIT(mbar) \
    asm volatile("tcgen05.commit.cta_group::1.mbarrier::arrive::one.shared::cluster.b64 [%0];" \
                 :: "r"((uint32_t)(mbar)) : "memory")
#define TCGEN05_FENCE_AFTER() \
    asm volatile("tcgen05.fence::after_thread_sync;" ::: "memory")
#define TCGEN05_FENCE_BEFORE() \
    asm volatile("tcgen05.fence::before_thread_sync;" ::: "memory")
#define TCGEN05_WAIT_LD() \
    asm volatile("tcgen05.wait::ld.sync.aligned;" ::: "memory")
#define FENCE_PROXY_ASYNC() \
    asm volatile("fence.proxy.async.shared::cta;" ::: "memory")
#define MBARRIER_INIT(mbar, cnt) \
    asm volatile("mbarrier.init.shared.b64 [%0], %1;" \
                 :: "r"((uint32_t)(mbar)), "r"((uint32_t)(cnt)) : "memory")
#define MBARRIER_INVAL(mbar) \
    asm volatile("mbarrier.inval.shared.b64 [%0];" :: "r"((uint32_t)(mbar)) : "memory")

#define MBARRIER_WAIT_PARITY(mbar, parity) do {                               \
    uint32_t _m = (uint32_t)(mbar);                                           \
    uint32_t _p = (uint32_t)(parity);                                         \
    asm volatile(                                                             \
        "{\n\t.reg .pred P1;\n\t"                                             \
        "WAIT_LOOP_%=:\n\t"                                                   \
        "mbarrier.try_wait.parity.acquire.cta.shared::cta.b64 P1, [%0], %1, 0x989680;\n\t" \
        "@P1 bra.uni WAIT_DONE_%=;\n\t"                                       \
        "bra.uni WAIT_LOOP_%=;\n\t"                                           \
        "WAIT_DONE_%=:\n\t}"                                                  \
        :: "r"(_m), "r"(_p) : "memory");                                      \
} while (0)

// fp16 SS MMA (fp32 accum), cta_group::1
#define TCGEN05_MMA_F16_SS(d, ad, bd, id, en) do {                            \
    uint32_t _e = (en) ? 1u : 0u; uint32_t _z = 0;                            \
    asm volatile(                                                             \
        "{\n\t.reg .pred p;\n\tsetp.ne.u32 p, %5, 0;\n\t"                     \
        "tcgen05.mma.cta_group::1.kind::f16 [%0], %1, %2, %3, {%4,%4,%4,%4}, p;\n\t}" \
        :: "r"(d), "l"(ad), "l"(bd), "r"(id), "r"(_z), "r"(_e) : "memory");   \
} while (0)

#define TCGEN05_LD32(r, addr)                                                 \
    asm volatile(                                                             \
        "tcgen05.ld.sync.aligned.32x32b.x32.b32 "                             \
        "{%0, %1, %2, %3, %4, %5, %6, %7, "                                   \
        " %8, %9, %10, %11, %12, %13, %14, %15, "                             \
        " %16, %17, %18, %19, %20, %21, %22, %23, "                           \
        " %24, %25, %26, %27, %28, %29, %30, %31}, [%32];"                    \
        : "=r"((r)[0]),  "=r"((r)[1]),  "=r"((r)[2]),  "=r"((r)[3]),          \
          "=r"((r)[4]),  "=r"((r)[5]),  "=r"((r)[6]),  "=r"((r)[7]),          \
          "=r"((r)[8]),  "=r"((r)[9]),  "=r"((r)[10]), "=r"((r)[11]),         \
          "=r"((r)[12]), "=r"((r)[13]), "=r"((r)[14]), "=r"((r)[15]),         \
          "=r"((r)[16]), "=r"((r)[17]), "=r"((r)[18]), "=r"((r)[19]),         \
          "=r"((r)[20]), "=r"((r)[21]), "=r"((r)[22]), "=r"((r)[23]),         \
          "=r"((r)[24]), "=r"((r)[25]), "=r"((r)[26]), "=r"((r)[27]),         \
          "=r"((r)[28]), "=r"((r)[29]), "=r"((r)[30]), "=r"((r)[31])          \
        : "r"(addr))

// SW128 K-major smem descriptor: layout=2, version=1, SBO=64, LBO=1
__device__ __forceinline__ uint64_t make_sw128_desc(uint32_t addr) {
    const uint64_t base = (uint64_t(2) << 61) | (uint64_t(1) << 46)
                        | (uint64_t(64) << 32) | (uint64_t(1) << 16);
    return base | ((uint64_t)(addr >> 4) & 0x3FFF);
}

// ---------------------------------------------------------------------------
// GEMM: C[M,N] = (A [+ A2])[M,K] @ Wt[N,K]^T + bias (opt ReLU)
// fp16 3-split: C = AH*BH + AH*BL + AL*BH (lo*lo dropped, ~2^-22).
// Tile 128x128, BK=64 floats (rows of 64 halves = 128B = SW128 atom).
// Exact round-5 kernel (proven clean at 4984 us).
// ---------------------------------------------------------------------------
#define TCG_IDESC 0x8200010u
#define STAGE_BYTES 65536
#define OFF_AH 0
#define OFF_AL 16384
#define OFF_BH 32768
#define OFF_BL 49152
#define TCG_SMEM (1024 + 2 * STAGE_BYTES)   // 132096

template <int RELU>
__global__ __launch_bounds__(256, 1)
void tc_gemm(const float* __restrict__ A, const float* __restrict__ A2,
             const __half* __restrict__ WH, const __half* __restrict__ WL,
             const float* __restrict__ bias, float* __restrict__ C,
             int M, int N, int K) {
    extern __shared__ char smem[];
    const int tid  = threadIdx.x;
    const int brow = blockIdx.x * 128;
    const int bcol = blockIdx.y * 128;

    const int lr = tid >> 3;
    const int c8 = (tid & 7) * 8;
    const float*  Ab  = A  + (size_t)(brow + lr) * K + c8;
    const float*  A2b = A2 ? A2 + (size_t)(brow + lr) * K + c8 : (const float*)0;
    const __half* BHb = WH + (size_t)(bcol + lr) * K + c8;
    const __half* BLb = WL + (size_t)(bcol + lr) * K + c8;
    const int KT = K >> 6;     // K64 tiles

    float4 a0[4], a1[4];
    uint4  bh[4], bl[4];

#define LDG_TILE(kt) do {                                                     \
    int _k = (kt) * 64;                                                       \
    _Pragma("unroll")                                                         \
    for (int i = 0; i < 4; i++) {                                             \
        size_t ro = (size_t)(i * 32) * K + _k;                                \
        a0[i] = *(const float4*)(Ab + ro);                                    \
        a1[i] = *(const float4*)(Ab + ro + 4);                                \
        if (A2b) {                                                            \
            float4 e0 = *(const float4*)(A2b + ro);                           \
            float4 e1 = *(const float4*)(A2b + ro + 4);                       \
            a0[i].x += e0.x; a0[i].y += e0.y; a0[i].z += e0.z; a0[i].w += e0.w; \
            a1[i].x += e1.x; a1[i].y += e1.y; a1[i].z += e1.z; a1[i].w += e1.w; \
        }                                                                     \
        bh[i] = *(const uint4*)(BHb + ro);                                    \
        bl[i] = *(const uint4*)(BLb + ro);                                    \
    }                                                                         \
} while (0)

#if HAS_TCGEN05
    const uint32_t sbase = smem_to_u32(smem);
    const int wid  = tid >> 5;
    const int lane = tid & 31;

    const uint32_t TMEMP = sbase;
    const uint32_t MBAR0 = sbase + 8;
    const uint32_t MBAR1 = sbase + 16;
    const uint32_t STG0  = sbase + 1024;

    if (wid == 0) TCGEN05_ALLOC(TMEMP, 128);
    if (tid == 0) { MBARRIER_INIT(MBAR0, 1); MBARRIER_INIT(MBAR1, 1); }
    __syncthreads();
    uint32_t tmem;
    asm volatile("ld.shared.b32 %0, [%1];" : "=r"(tmem) : "r"(TMEMP));
    if (wid == 0) TCGEN05_RELINQ();

    uint32_t swoff[4];
#pragma unroll
    for (int i = 0; i < 4; i++) {
        uint32_t off = (uint32_t)(i * 32 + lr) * 128 + (tid & 7) * 16;
        swoff[i] = off ^ ((off >> 3) & 0x70);
    }

    int ph0 = 0, ph1 = 0;

#define SPLIT8(x0, x1, hi, lo) do {                                           \
    float _v[8] = {x0.x, x0.y, x0.z, x0.w, x1.x, x1.y, x1.z, x1.w};           \
    _Pragma("unroll")                                                         \
    for (int j = 0; j < 4; j++) {                                             \
        __half hx = __float2half_rn(_v[2*j]);                                 \
        __half hy = __float2half_rn(_v[2*j+1]);                               \
        __half lx = __float2half_rn(_v[2*j]   - __half2float(hx));            \
        __half ly = __float2half_rn(_v[2*j+1] - __half2float(hy));            \
        __half2 hp = __halves2half2(hx, hy);                                  \
        __half2 lp = __halves2half2(lx, ly);                                  \
        (hi)[j] = *(uint32_t*)&hp;                                            \
        (lo)[j] = *(uint32_t*)&lp;                                            \
    }                                                                         \
} while (0)

#define STS_TILE(stoff) do {                                                  \
    char* _sb = smem + 1024 + (stoff);                                        \
    _Pragma("unroll")                                                         \
    for (int i = 0; i < 4; i++) {                                             \
        uint32_t ah[4], al[4];                                                \
        SPLIT8(a0[i], a1[i], ah, al);                                         \
        *(uint4*)(_sb + OFF_AH + swoff[i]) = make_uint4(ah[0], ah[1], ah[2], ah[3]); \
        *(uint4*)(_sb + OFF_AL + swoff[i]) = make_uint4(al[0], al[1], al[2], al[3]); \
        *(uint4*)(_sb + OFF_BH + swoff[i]) = bh[i];                           \
        *(uint4*)(_sb + OFF_BL + swoff[i]) = bl[i];                           \
    }                                                                         \
} while (0)

    LDG_TILE(0);
    STS_TILE(0);
    FENCE_PROXY_ASYNC();
    __syncthreads();

    for (int kt = 0; kt < KT; kt++) {
        int s = kt & 1;
        bool have_next = (kt + 1 < KT);
        if (have_next) LDG_TILE(kt + 1);

        if (wid == 0) {
            if (elect_one_pred()) {
                uint32_t sb = STG0 + s * STAGE_BYTES;
                uint64_t dah = make_sw128_desc(sb + OFF_AH);
                uint64_t dal = make_sw128_desc(sb + OFF_AL);
                uint64_t dbh = make_sw128_desc(sb + OFF_BH);
                uint64_t dbl = make_sw128_desc(sb + OFF_BL);
#pragma unroll
                for (int ks = 0; ks < 4; ks++) {   // K=16 halves per chunk
                    TCGEN05_MMA_F16_SS(tmem, dah + ks * 2, dbh + ks * 2,
                                       TCG_IDESC, (kt > 0) || (ks > 0));
                    TCGEN05_MMA_F16_SS(tmem, dah + ks * 2, dbl + ks * 2,
                                       TCG_IDESC, 1);
                    TCGEN05_MMA_F16_SS(tmem, dal + ks * 2, dbh + ks * 2,
                                       TCG_IDESC, 1);
                }
                TCGEN05_COMMIT(s == 0 ? MBAR0 : MBAR1);
            }
        }

        if (have_next) {
            int ns = s ^ 1;
            if (kt >= 1) {   // MMA of iter kt-1 read stage ns; wait before reuse
                if (ns == 0) { MBARRIER_WAIT_PARITY(MBAR0, ph0); ph0 ^= 1; }
                else         { MBARRIER_WAIT_PARITY(MBAR1, ph1); ph1 ^= 1; }
            }
            STS_TILE(ns * STAGE_BYTES);
            FENCE_PROXY_ASYNC();
            __syncthreads();
        }
    }

    if (((KT - 1) & 1) == 0) { MBARRIER_WAIT_PARITY(MBAR0, ph0); }
    else                     { MBARRIER_WAIT_PARITY(MBAR1, ph1); }
    TCGEN05_FENCE_AFTER();

    // Epilogue: warp w -> rows (w&3)*32+lane, cols (w>>2)*64 .. +63
    {
        int colbase = (wid >> 2) * 64;
        uint32_t d0[32], d1[32];
        TCGEN05_LD32(d0, tmem + colbase);
        TCGEN05_LD32(d1, tmem + colbase + 32);
        TCGEN05_WAIT_LD();
        TCGEN05_FENCE_BEFORE();

        int r = brow + (wid & 3) * 32 + lane;
        float* Crow = C + (size_t)r * N + bcol + colbase;
        const float* brow_b = bias + bcol + colbase;
#pragma unroll
        for (int c = 0; c < 32; c += 4) {
            float4 o;
            o.x = __uint_as_float(d0[c + 0]) + brow_b[c + 0];
            o.y = __uint_as_float(d0[c + 1]) + brow_b[c + 1];
            o.z = __uint_as_float(d0[c + 2]) + brow_b[c + 2];
            o.w = __uint_as_float(d0[c + 3]) + brow_b[c + 3];
            if (RELU) {
                o.x = fmaxf(o.x, 0.f); o.y = fmaxf(o.y, 0.f);
                o.z = fmaxf(o.z, 0.f); o.w = fmaxf(o.w, 0.f);
            }
            *(float4*)(Crow + c) = o;
        }
#pragma unroll
        for (int c = 0; c < 32; c += 4) {
            float4 o;
            o.x = __uint_as_float(d1[c + 0]) + brow_b[32 + c + 0];
            o.y = __uint_as_float(d1[c + 1]) + brow_b[32 + c + 1];
            o.z = __uint_as_float(d1[c + 2]) + brow_b[32 + c + 2];
            o.w = __uint_as_float(d1[c + 3]) + brow_b[32 + c + 3];
            if (RELU) {
                o.x = fmaxf(o.x, 0.f); o.y = fmaxf(o.y, 0.f);
                o.z = fmaxf(o.z, 0.f); o.w = fmaxf(o.w, 0.f);
            }
            *(float4*)(Crow + 32 + c) = o;
        }
    }

    __syncthreads();
    if (tid == 0) { MBARRIER_INVAL(MBAR0); MBARRIER_INVAL(MBAR1); }
    __syncthreads();
    if (wid == 0) TCGEN05_DEALLOC(tmem, 128);

#else  // ------------------- SIMT fallback (plain sm_103 pass) -------------
    float (*As)[132] = (float(*)[132])(smem);
    float (*Bs)[132] = (float(*)[132])(smem + 64 * 132 * 4);

    int ty = (tid >> 4) * 8;
    int tx = (tid & 15) * 8;

    float acc[8][8];
#pragma unroll
    for (int i = 0; i < 8; i++)
#pragma unroll
        for (int j = 0; j < 8; j++) acc[i][j] = 0.f;

    for (int kt = 0; kt < KT; kt++) {
        LDG_TILE(kt);
        __syncthreads();
#pragma unroll
        for (int i = 0; i < 4; i++) {
            int r = i * 32 + lr;
            float av[8] = {a0[i].x, a0[i].y, a0[i].z, a0[i].w,
                           a1[i].x, a1[i].y, a1[i].z, a1[i].w};
            const __half* hh = (const __half*)&bh[i];
            const __half* ll = (const __half*)&bl[i];
#pragma unroll
            for (int j = 0; j < 8; j++) {
                As[c8 + j][r] = av[j];
                Bs[c8 + j][r] = __half2float(hh[j]) + __half2float(ll[j]);
            }
        }
        __syncthreads();
#pragma unroll 16
        for (int k = 0; k < 64; k++) {
            float av[8], bv[8];
#pragma unroll
            for (int i = 0; i < 8; i++) { av[i] = As[k][ty + i]; bv[i] = Bs[k][tx + i]; }
#pragma unroll
            for (int i = 0; i < 8; i++)
#pragma unroll
                for (int j = 0; j < 8; j++)
                    acc[i][j] += av[i] * bv[j];
        }
    }

    int row = brow + ty;
    int col = bcol + tx;
#pragma unroll
    for (int i = 0; i < 8; i++) {
#pragma unroll
        for (int j = 0; j < 8; j++) {
            float v = acc[i][j] + bias[col + j];
            if (RELU) v = fmaxf(v, 0.f);
            C[(size_t)(row + i) * N + col + j] = v;
        }
    }
#endif
}

// ---------------------------------------------------------------------------
// Fused weight transpose + fp16 split (all 6 types, 3 layers per launch)
// W[K,N] -> Ht[N,K], Lt[N,K]
// ---------------------------------------------------------------------------
__global__ void transplit_all(const float* __restrict__ Wval, const float* __restrict__ Woff,
                              const float* __restrict__ Wattn, const float* __restrict__ Wout,
                              const float* __restrict__ W1, const float* __restrict__ W2,
                              __half* __restrict__ wth, __half* __restrict__ wtl,
                              int layer0) {
    int type  = blockIdx.y;
    int layer = layer0 + blockIdx.z;
    const float* W; int K, N, off;
    switch (type) {
        case 0: W = Wval  + (size_t)layer * 65536;  K = 256;  N = 256;  off = WT_VAL;  break;
        case 1: W = Woff  + (size_t)layer * 65536;  K = 256;  N = 256;  off = WT_OFF;  break;
        case 2: W = Wattn + (size_t)layer * 32768;  K = 256;  N = 128;  off = WT_ATTN; break;
        case 3: W = Wout  + (size_t)layer * 65536;  K = 256;  N = 256;  off = WT_OUT;  break;
        case 4: W = W1    + (size_t)layer * 262144; K = 256;  N = 1024; off = WT_W1;   break;
        default: W = W2   + (size_t)layer * 262144; K = 1024; N = 256;  off = WT_W2;   break;
    }
    int tK = K >> 5, tN = N >> 5;
    int t = blockIdx.x;
    if (t >= tK * tN) return;
    int k0 = (t % tK) * 32, n0 = (t / tK) * 32;

    __shared__ float tile[32][33];
    tile[threadIdx.y][threadIdx.x] = W[(size_t)(k0 + threadIdx.y) * N + n0 + threadIdx.x];
    __syncthreads();
    float v = tile[threadIdx.x][threadIdx.y];
    __half h = __float2half_rn(v);
    size_t o = (size_t)layer * WT_LAYER + off + (size_t)(n0 + threadIdx.y) * K + k0 + threadIdx.x;
    wth[o] = h;
    wtl[o] = __float2half_rn(v - __half2float(h));
}

// ---------------------------------------------------------------------------
// Flatten pair of levels: src [B, D, h, w] -> out [B, S, D]; pos + level_embed
// ---------------------------------------------------------------------------
__global__ void flatten_pair(const float* __restrict__ sA, const float* __restrict__ pA,
                             int hwA, int stA, int lvA,
                             const float* __restrict__ sB, const float* __restrict__ pB,
                             int hwB, int stB, int lvB,
                             const float* __restrict__ lemb,
                             float* __restrict__ out, float* __restrict__ posout) {
    __shared__ float ts[32][33];
    __shared__ float tp[32][33];
    int px = blockIdx.x;
    const float *src, *pos; int hw, start, level, p0;
    int tA = hwA >> 5;
    if (px < tA) { src = sA; pos = pA; hw = hwA; start = stA; level = lvA; p0 = px * 32; }
    else         { src = sB; pos = pB; hw = hwB; start = stB; level = lvB; p0 = (px - tA) * 32; }

    int b  = blockIdx.z;
    int d0 = blockIdx.y * 32;
    int tx = threadIdx.x, ty = threadIdx.y;

    const float* sp = src + ((size_t)b * D_MODEL + d0 + ty) * hw + p0;
    const float* pp = pos + ((size_t)b * D_MODEL + d0 + ty) * hw + p0;
    ts[ty][tx] = sp[tx];
    tp[ty][tx] = pp[tx];
    __syncthreads();

    int d = d0 + tx;
    float le = lemb[level * D_MODEL + d];
    size_t srow = (size_t)b * S_TOTAL + start + p0 + ty;
    out[srow * D_MODEL + d]    = ts[tx][ty];
    posout[srow * D_MODEL + d] = tp[tx][ty] + le;
}

// ---------------------------------------------------------------------------
// Residual + LayerNorm: out = LN(x + r) * gamma + beta. One warp per row.
// ---------------------------------------------------------------------------
__global__ void resid_ln_kernel(const float* __restrict__ X, const float* __restrict__ R,
                                const float* __restrict__ g, const float* __restrict__ bt,
                                float* __restrict__ O, int rows) {
    int warp = (blockIdx.x * blockDim.x + threadIdx.x) >> 5;
    int lane = threadIdx.x & 31;
    if (warp >= rows) return;
    const float* xr = X + (size_t)warp * D_MODEL;
    const float* rr = R + (size_t)warp * D_MODEL;

    float v[8];
    float s = 0.f, s2 = 0.f;
#pragma unroll
    for (int u = 0; u < 2; u++) {
        float4 a = *(const float4*)(xr + lane * 4 + u * 128);
        float4 c = *(const float4*)(rr + lane * 4 + u * 128);
        float t0 = a.x + c.x, t1 = a.y + c.y, t2 = a.z + c.z, t3 = a.w + c.w;
        v[u * 4 + 0] = t0; v[u * 4 + 1] = t1; v[u * 4 + 2] = t2; v[u * 4 + 3] = t3;
        s += t0 + t1 + t2 + t3;
        s2 += t0 * t0 + t1 * t1 + t2 * t2 + t3 * t3;
    }
#pragma unroll
    for (int o = 16; o > 0; o >>= 1) {
        s  += __shfl_xor_sync(0xffffffffu, s, o);
        s2 += __shfl_xor_sync(0xffffffffu, s2, o);
    }
    float mean = s * (1.f / D_MODEL);
    float var  = s2 * (1.f / D_MODEL) - mean * mean;
    float inv  = rsqrtf(var + 1e-5f);
#pragma unroll
    for (int u = 0; u < 2; u++) {
        int d = lane * 4 + u * 128;
        float4 o4;
        o4.x = (v[u * 4 + 0] - mean) * inv * g[d + 0] + bt[d + 0];
        o4.y = (v[u * 4 + 1] - mean) * inv * g[d + 1] + bt[d + 1];
        o4.z = (v[u * 4 + 2] - mean) * inv * g[d + 2] + bt[d + 2];
        o4.w = (v[u * 4 + 3] - mean) * inv * g[d + 3] + bt[d + 3];
        *(float4*)(O + (size_t)warp * D_MODEL + d) = o4;
    }
}

// ---------------------------------------------------------------------------
// Deformable sampling. One warp per (token, head).
// Lanes 0..15 compute the 16 samples' taps into a smem table; then lanes
// (tap = lane>>3, ch4 = lane&7) gather float4s and accumulate; cross-tap
// reduction via shfl; lanes 0..7 store float4.
// ---------------------------------------------------------------------------
__constant__ int c_lw[4]     = {128, 64, 32, 16};
__constant__ int c_lstart[4] = {0, 16384, 20480, 21504};

__global__ void sample_kernel(const float* __restrict__ Val, const float* __restrict__ Off,
                              const float* __restrict__ Awl, float* __restrict__ Samp) {
    __shared__ int2 tab[8][16][4];
    int gw   = (blockIdx.x * blockDim.x + threadIdx.x) >> 5;
    int lane = threadIdx.x & 31;
    int wpb  = threadIdx.x >> 5;
    if (gw >= M_TOT * NH) return;
    int h   = gw & 7;
    int tok = gw >> 3;
    int s   = tok % S_TOTAL;
    int b   = tok / S_TOTAL;

    int wt, st, sh;
    if (s < 16384)      { wt = 128; st = 0;     sh = 7; }
    else if (s < 20480) { wt = 64;  st = 16384; sh = 6; }
    else if (s < 21504) { wt = 32;  st = 20480; sh = 5; }
    else                { wt = 16;  st = 21504; sh = 4; }
    int sl = s - st;
    int iy = sl >> sh;
    int ix = sl - (iy << sh);
    float refx = (ix + 0.5f) / (float)wt;
    float refy = (iy + 0.5f) / (float)wt;

    size_t rb = (size_t)tok;

    float lv = (lane < 16) ? Awl[rb * 128 + h * 16 + lane] : -1e30f;
    float m = lv;
#pragma unroll
    for (int o = 8; o > 0; o >>= 1) m = fmaxf(m, __shfl_xor_sync(0xffffffffu, m, o));
    float e = (lane < 16) ? expf(lv - m) : 0.f;
    float ssum = e;
#pragma unroll
    for (int o = 8; o > 0; o >>= 1) ssum += __shfl_xor_sync(0xffffffffu, ssum, o);
    float aw = e / ssum;

    if (lane < 16) {
        int l   = lane >> 2;
        int wl  = c_lw[l];
        int stl = c_lstart[l];
        float ox = Off[rb * 256 + (size_t)(h * 16 + lane) * 2 + 0];
        float oy = Off[rb * 256 + (size_t)(h * 16 + lane) * 2 + 1];
        float x = refx * (float)wl + ox - 0.5f;
        float y = refy * (float)wl + oy - 0.5f;
        float xf = floorf(x), yf = floorf(y);
        float lx = x - xf, ly = y - yf;
        int x0 = (int)xf, y0 = (int)yf;
        int x1 = x0 + 1, y1 = y0 + 1;
        bool okx0 = (x0 >= 0) & (x0 < wl);
        bool okx1 = (x1 >= 0) & (x1 < wl);
        bool oky0 = (y0 >= 0) & (y0 < wl);
        bool oky1 = (y1 >= 0) & (y1 < wl);
        int cx0 = min(max(x0, 0), wl - 1), cx1 = min(max(x1, 0), wl - 1);
        int cy0 = min(max(y0, 0), wl - 1), cy1 = min(max(y1, 0), wl - 1);
        float w0 = (1.f - lx) * (1.f - ly) * aw * ((okx0 && oky0) ? 1.f : 0.f);
        float w1 = lx * (1.f - ly) * aw * ((okx1 && oky0) ? 1.f : 0.f);
        float w2 = (1.f - lx) * ly * aw * ((okx0 && oky1) ? 1.f : 0.f);
        float w3 = lx * ly * aw * ((okx1 && oky1) ? 1.f : 0.f);
        tab[wpb][lane][0] = make_int2(stl + cy0 * wl + cx0, __float_as_int(w0));
        tab[wpb][lane][1] = make_int2(stl + cy0 * wl + cx1, __float_as_int(w1));
        tab[wpb][lane][2] = make_int2(stl + cy1 * wl + cx0, __float_as_int(w2));
        tab[wpb][lane][3] = make_int2(stl + cy1 * wl + cx1, __float_as_int(w3));
    }
    __syncwarp();

    int t   = lane >> 3;
    int ch4 = lane & 7;
    const float4* base = (const float4*)Val + (size_t)b * S_TOTAL * 64 + h * 8 + ch4;
    float4 acc = make_float4(0.f, 0.f, 0.f, 0.f);
#pragma unroll
    for (int j = 0; j < 16; j++) {
        int2 ee = tab[wpb][j][t];
        float4 v = base[(size_t)ee.x * 64];
        float f = __int_as_float(ee.y);
        acc.x += f * v.x; acc.y += f * v.y; acc.z += f * v.z; acc.w += f * v.w;
    }
#pragma unroll
    for (int msk = 8; msk <= 16; msk <<= 1) {
        acc.x += __shfl_xor_sync(0xffffffffu, acc.x, msk);
        acc.y += __shfl_xor_sync(0xffffffffu, acc.y, msk);
        acc.z += __shfl_xor_sync(0xffffffffu, acc.z, msk);
        acc.w += __shfl_xor_sync(0xffffffffu, acc.w, msk);
    }
    if (lane < 8)
        ((float4*)(Samp + (size_t)tok * 256 + h * 32))[ch4] = acc;
}

// ---------------------------------------------------------------------------
// Host orchestration
// ---------------------------------------------------------------------------
extern "C" void kernel_launch(void* const* d_in, const int* in_sizes, int n_in,
                              void* d_out, int out_size) {
    const float* src[4];
    const float* posin[4];
    bool interleaved = (in_sizes[1] == in_sizes[0]);
    for (int l = 0; l < 4; l++) {
        if (interleaved) {
            src[l]   = (const float*)d_in[2 * l];
            posin[l] = (const float*)d_in[2 * l + 1];
        } else {
            src[l]   = (const float*)d_in[l];
            posin[l] = (const float*)d_in[4 + l];
        }
    }
    const float* lemb  = (const float*)d_in[8];
    const float* Woff  = (const float*)d_in[9];
    const float* boff  = (const float*)d_in[10];
    const float* Wattn = (const float*)d_in[11];
    const float* battn = (const float*)d_in[12];
    const float* Wval  = (const float*)d_in[13];
    const float* bval  = (const float*)d_in[14];
    const float* Wout  = (const float*)d_in[15];
    const float* bout  = (const float*)d_in[16];
    const float* ln1s  = (const float*)d_in[17];
    const float* ln1b  = (const float*)d_in[18];
    const float* W1    = (const float*)d_in[19];
    const float* b1    = (const float*)d_in[20];
    const float* W2    = (const float*)d_in[21];
    const float* b2    = (const float*)d_in[22];
    const float* ln2s  = (const float*)d_in[23];
    const float* ln2b  = (const float*)d_in[24];

    float* out = (float*)d_out;

    float *pos, *val, *off, *awl, *samp, *tmp, *ffh;
    __half *wth, *wtl;
    cudaGetSymbolAddress((void**)&pos,  g_pos);
    cudaGetSymbolAddress((void**)&val,  g_val);
    cudaGetSymbolAddress((void**)&off,  g_off);
    cudaGetSymbolAddress((void**)&awl,  g_awl);
    cudaGetSymbolAddress((void**)&samp, g_samp);
    cudaGetSymbolAddress((void**)&tmp,  g_tmp);
    cudaGetSymbolAddress((void**)&ffh,  g_ffh);
    cudaGetSymbolAddress((void**)&wth,  g_wth);
    cudaGetSymbolAddress((void**)&wtl,  g_wtl);

    cudaFuncSetAttribute(tc_gemm<0>, cudaFuncAttributeMaxDynamicSharedMemorySize, TCG_SMEM);
    cudaFuncSetAttribute(tc_gemm<1>, cudaFuncAttributeMaxDynamicSharedMemorySize, TCG_SMEM);

    // Prologue: exactly 4 launches (so ncu -s 5 profiles a main-loop GEMM)
    transplit_all<<<dim3(256, 6, 3), dim3(32, 32)>>>(Wval, Woff, Wattn, Wout, W1, W2,
                                                     wth, wtl, 0);
    transplit_all<<<dim3(256, 6, 3), dim3(32, 32)>>>(Wval, Woff, Wattn, Wout, W1, W2,
                                                     wth, wtl, 3);
    flatten_pair<<<dim3(16384/32 + 4096/32, 8, BATCH), dim3(32, 32)>>>(
        src[0], posin[0], 16384, 0, 0, src[1], posin[1], 4096, 16384, 1,
        lemb, out, pos);
    flatten_pair<<<dim3(1024/32 + 256/32, 8, BATCH), dim3(32, 32)>>>(
        src[2], posin[2], 1024, 20480, 2, src[3], posin[3], 256, 21504, 3,
        lemb, out, pos);

    const int MB = M_TOT / 128;     // 340

    for (int i = 0; i < NLAYERS; i++) {
        const __half* bh = wth + (size_t)i * WT_LAYER;
        const __half* bl = wtl + (size_t)i * WT_LAYER;
        // value = out @ Wval + bval
        tc_gemm<0><<<dim3(MB, 2), 256, TCG_SMEM>>>(out, nullptr, bh + WT_VAL, bl + WT_VAL,
                                                   bval + i * 256, val, M_TOT, 256, 256);
        // off = (out + pos) @ Woff + boff   (q fused into A-load)
        tc_gemm<0><<<dim3(MB, 2), 256, TCG_SMEM>>>(out, pos, bh + WT_OFF, bl + WT_OFF,
                                                   boff + i * 256, off, M_TOT, 256, 256);
        // attn logits = (out + pos) @ Wattn + battn
        tc_gemm<0><<<dim3(MB, 1), 256, TCG_SMEM>>>(out, pos, bh + WT_ATTN, bl + WT_ATTN,
                                                   battn + i * 128, awl, M_TOT, 128, 256);
        // deformable sampling
        sample_kernel<<<M_TOT * NH / 8, 256>>>(val, off, awl, samp);
        // attn out = samp @ Wout + bout
        tc_gemm<0><<<dim3(MB, 2), 256, TCG_SMEM>>>(samp, nullptr, bh + WT_OUT, bl + WT_OUT,
                                                   bout + i * 256, tmp, M_TOT, 256, 256);
        // out = LN(out + attn)
        resid_ln_kernel<<<(M_TOT + 7) / 8, 256>>>(tmp, out, ln1s + i * 256,
                                                  ln1b + i * 256, out, M_TOT);
        // h = relu(out @ W1 + b1)
        tc_gemm<1><<<dim3(MB, 8), 256, TCG_SMEM>>>(out, nullptr, bh + WT_W1, bl + WT_W1,
                                                   b1 + i * 1024, ffh, M_TOT, 1024, 256);
        // ff = h @ W2 + b2
        tc_gemm<0><<<dim3(MB, 2), 256, TCG_SMEM>>>(ffh, nullptr, bh + WT_W2, bl + WT_W2,
                                                   b2 + i * 256, tmp, M_TOT, 256, 1024);
        // out = LN(out + ff)
        resid_ln_kernel<<<(M_TOT + 7) / 8, 256>>>(tmp, out, ln2s + i * 256,
                                                  ln2b + i * 256, out, M_TOT);
    }
}

// round 9
// speedup vs baseline: 2.5460x; 1.0137x over previous
#include <cuda_runtime.h>
#include <cuda_fp16.h>
#include <math.h>
#include <stdint.h>

// ---------------------------------------------------------------------------
// MSDeformAttn transformer encoder (6 layers).
// K=256 GEMMs: persistent-B tcgen05 kind::f16 3-split kernel (B resident in
// SMEM, A double-buffered, TMEM alloc 128 only). W2 (K=1024): proven
// streaming kernel. sm_103a arch-feature guarded; SIMT fallback otherwise.
// D=256, NH=8, NL=4, NP=4, DH=32, DFF=1024, B=2, S=21760.
// ---------------------------------------------------------------------------

#define D_MODEL 256
#define NH 8
#define DFF 1024
#define NLAYERS 6
#define BATCH 2
#define S_TOTAL 21760
#define M_TOT (BATCH * S_TOTAL)   // 43520 rows; 340 M-tiles of 128

#if defined(__CUDA_ARCH_FEAT_SM103_ALL) || defined(__CUDA_ARCH_FEAT_SM100_ALL) || defined(__CUDA_ARCH_FEAT_SM101_ALL)
#define HAS_TCGEN05 1
#else
#define HAS_TCGEN05 0
#endif

// Scratch (allocation-free: __device__ globals)
__device__ float g_pos[M_TOT * D_MODEL];
__device__ float g_val[M_TOT * D_MODEL];
__device__ float g_off[M_TOT * 256];
__device__ float g_awl[M_TOT * 128];
__device__ float g_samp[M_TOT * D_MODEL];
__device__ float g_tmp[M_TOT * D_MODEL];
__device__ float g_ffh[M_TOT * DFF];

// Transposed + fp16-split weights: per layer 753664 elements
#define WT_LAYER 753664
__device__ __half g_wth[NLAYERS * WT_LAYER];
__device__ __half g_wtl[NLAYERS * WT_LAYER];
#define WT_VAL  0
#define WT_OFF  65536
#define WT_ATTN 131072
#define WT_OUT  163840
#define WT_W1   229376
#define WT_W2   491520

// ---------------------------------------------------------------------------
// PTX helpers
// ---------------------------------------------------------------------------
__device__ __forceinline__ uint32_t elect_one_pred() {
    uint32_t pred;
    asm volatile(
        "{\n\t.reg .pred p;\n\telect.sync _|p, 0xFFFFFFFF;\n\t"
        "selp.b32 %0, 1, 0, p;\n\t}" : "=r"(pred));
    return pred;
}
__device__ __forceinline__ uint32_t smem_to_u32(const void* p) {
    uint32_t a;
    asm("{ .reg .u64 t; cvta.to.shared.u64 t, %1; cvt.u32.u64 %0, t; }"
        : "=r"(a) : "l"(p));
    return a;
}

#define TCGEN05_ALLOC(addr, n) \
    asm volatile("tcgen05.alloc.cta_group::1.sync.aligned.shared::cta.b32 [%0], %1;" \
                 :: "r"((uint32_t)(addr)), "r"((uint32_t)(n)) : "memory")
#define TCGEN05_DEALLOC(tmem, n) \
    asm volatile("tcgen05.dealloc.cta_group::1.sync.aligned.b32 %0, %1;" \
                 :: "r"(tmem), "r"((uint32_t)(n)))
#define TCGEN05_RELINQ() \
    asm volatile("tcgen05.relinquish_alloc_permit.cta_group::1.sync.aligned;")
#define TCGEN05_COMMIT(mbar) \
    asm volatile("tcgen05.commit.cta_group::1.mbarrier::arrive::one.shared::cluster.b64 [%0];" \
                 :: "r"((uint32_t)(mbar)) : "memory")
#define TCGEN05_FENCE_AFTER() \
    asm volatile("tcgen05.fence::after_thread_sync;" ::: "memory")
#define TCGEN05_FENCE_BEFORE() \
    asm volatile("tcgen05.fence::before_thread_sync;" ::: "memory")
#define TCGEN05_WAIT_LD() \
    asm volatile("tcgen05.wait::ld.sync.aligned;" ::: "memory")
#define FENCE_PROXY_ASYNC() \
    asm volatile("fence.proxy.async.shared::cta;" ::: "memory")
#define MBARRIER_INIT(mbar, cnt) \
    asm volatile("mbarrier.init.shared.b64 [%0], %1;" \
                 :: "r"((uint32_t)(mbar)), "r"((uint32_t)(cnt)) : "memory")
#define MBARRIER_INVAL(mbar) \
    asm volatile("mbarrier.inval.shared.b64 [%0];" :: "r"((uint32_t)(mbar)) : "memory")

#define MBARRIER_WAIT_PARITY(mbar, parity) do {                               \
    uint32_t _m = (uint32_t)(mbar);                                           \
    uint32_t _p = (uint32_t)(parity);                                         \
    asm volatile(                                                             \
        "{\n\t.reg .pred P1;\n\t"                                             \
        "WAIT_LOOP_%=:\n\t"                                                   \
        "mbarrier.try_wait.parity.acquire.cta.shared::cta.b64 P1, [%0], %1, 0x989680;\n\t" \
        "@P1 bra.uni WAIT_DONE_%=;\n\t"                                       \
        "bra.uni WAIT_LOOP_%=;\n\t"                                           \
        "WAIT_DONE_%=:\n\t}"                                                  \
        :: "r"(_m), "r"(_p) : "memory");                                      \
} while (0)

// fp16 SS MMA (fp32 accum), cta_group::1
#define TCGEN05_MMA_F16_SS(d, ad, bd, id, en) do {                            \
    uint32_t _e = (en) ? 1u : 0u; uint32_t _z = 0;                            \
    asm volatile(                                                             \
        "{\n\t.reg .pred p;\n\tsetp.ne.u32 p, %5, 0;\n\t"                     \
        "tcgen05.mma.cta_group::1.kind::f16 [%0], %1, %2, %3, {%4,%4,%4,%4}, p;\n\t}" \
        :: "r"(d), "l"(ad), "l"(bd), "r"(id), "r"(_z), "r"(_e) : "memory");   \
} while (0)

#define TCGEN05_LD32(r, addr)                                                 \
    asm volatile(                                                             \
        "tcgen05.ld.sync.aligned.32x32b.x32.b32 "                             \
        "{%0, %1, %2, %3, %4, %5, %6, %7, "                                   \
        " %8, %9, %10, %11, %12, %13, %14, %15, "                             \
        " %16, %17, %18, %19, %20, %21, %22, %23, "                           \
        " %24, %25, %26, %27, %28, %29, %30, %31}, [%32];"                    \
        : "=r"((r)[0]),  "=r"((r)[1]),  "=r"((r)[2]),  "=r"((r)[3]),          \
          "=r"((r)[4]),  "=r"((r)[5]),  "=r"((r)[6]),  "=r"((r)[7]),          \
          "=r"((r)[8]),  "=r"((r)[9]),  "=r"((r)[10]), "=r"((r)[11]),         \
          "=r"((r)[12]), "=r"((r)[13]), "=r"((r)[14]), "=r"((r)[15]),         \
          "=r"((r)[16]), "=r"((r)[17]), "=r"((r)[18]), "=r"((r)[19]),         \
          "=r"((r)[20]), "=r"((r)[21]), "=r"((r)[22]), "=r"((r)[23]),         \
          "=r"((r)[24]), "=r"((r)[25]), "=r"((r)[26]), "=r"((r)[27]),         \
          "=r"((r)[28]), "=r"((r)[29]), "=r"((r)[30]), "=r"((r)[31])          \
        : "r"(addr))

// SW128 K-major smem descriptor: layout=2, version=1, SBO=64, LBO=1
__device__ __forceinline__ uint64_t make_sw128_desc(uint32_t addr) {
    const uint64_t base = (uint64_t(2) << 61) | (uint64_t(1) << 46)
                        | (uint64_t(64) << 32) | (uint64_t(1) << 16);
    return base | ((uint64_t)(addr >> 4) & 0x3FFF);
}

#define SPLIT8(x0, x1, hi, lo) do {                                           \
    float _v[8] = {x0.x, x0.y, x0.z, x0.w, x1.x, x1.y, x1.z, x1.w};           \
    _Pragma("unroll")                                                         \
    for (int _j = 0; _j < 4; _j++) {                                          \
        __half hx = __float2half_rn(_v[2*_j]);                                \
        __half hy = __float2half_rn(_v[2*_j+1]);                              \
        __half lx = __float2half_rn(_v[2*_j]   - __half2float(hx));           \
        __half ly = __float2half_rn(_v[2*_j+1] - __half2float(hy));           \
        __half2 hp = __halves2half2(hx, hy);                                  \
        __half2 lp = __halves2half2(lx, ly);                                  \
        (hi)[_j] = *(uint32_t*)&hp;                                           \
        (lo)[_j] = *(uint32_t*)&lp;                                           \
    }                                                                         \
} while (0)

#define TCG_IDESC 0x8200010u

// ---------------------------------------------------------------------------
// Streaming GEMM (round-8 proven): used for W2 (K=1024).
// C[M,N] = A[M,K] @ Wt[N,K]^T + bias. Tile 128x128, BK=64 floats.
// ---------------------------------------------------------------------------
#define STAGE_BYTES 65536
#define OFF_AH 0
#define OFF_AL 16384
#define OFF_BH 32768
#define OFF_BL 49152
#define TCG_SMEM (1024 + 2 * STAGE_BYTES)   // 132096

template <int RELU>
__global__ __launch_bounds__(256, 1)
void tc_gemm(const float* __restrict__ A, const float* __restrict__ A2,
             const __half* __restrict__ WH, const __half* __restrict__ WL,
             const float* __restrict__ bias, float* __restrict__ C,
             int M, int N, int K) {
    extern __shared__ char smem[];
    const int tid  = threadIdx.x;
    const int brow = blockIdx.x * 128;
    const int bcol = blockIdx.y * 128;

    const int lr = tid >> 3;
    const int c8 = (tid & 7) * 8;
    const float*  Ab  = A  + (size_t)(brow + lr) * K + c8;
    const float*  A2b = A2 ? A2 + (size_t)(brow + lr) * K + c8 : (const float*)0;
    const __half* BHb = WH + (size_t)(bcol + lr) * K + c8;
    const __half* BLb = WL + (size_t)(bcol + lr) * K + c8;
    const int KT = K >> 6;

    float4 a0[4], a1[4];
    uint4  bh[4], bl[4];

#define LDG_TILE(kt) do {                                                     \
    int _k = (kt) * 64;                                                       \
    _Pragma("unroll")                                                         \
    for (int i = 0; i < 4; i++) {                                             \
        size_t ro = (size_t)(i * 32) * K + _k;                                \
        a0[i] = *(const float4*)(Ab + ro);                                    \
        a1[i] = *(const float4*)(Ab + ro + 4);                                \
        if (A2b) {                                                            \
            float4 e0 = *(const float4*)(A2b + ro);                           \
            float4 e1 = *(const float4*)(A2b + ro + 4);                       \
            a0[i].x += e0.x; a0[i].y += e0.y; a0[i].z += e0.z; a0[i].w += e0.w; \
            a1[i].x += e1.x; a1[i].y += e1.y; a1[i].z += e1.z; a1[i].w += e1.w; \
        }                                                                     \
        bh[i] = *(const uint4*)(BHb + ro);                                    \
        bl[i] = *(const uint4*)(BLb + ro);                                    \
    }                                                                         \
} while (0)

#if HAS_TCGEN05
    const uint32_t sbase = smem_to_u32(smem);
    const int wid  = tid >> 5;
    const int lane = tid & 31;

    const uint32_t TMEMP = sbase;
    const uint32_t MBAR0 = sbase + 8;
    const uint32_t MBAR1 = sbase + 16;
    const uint32_t STG0  = sbase + 1024;

    if (wid == 0) TCGEN05_ALLOC(TMEMP, 128);
    if (tid == 0) { MBARRIER_INIT(MBAR0, 1); MBARRIER_INIT(MBAR1, 1); }
    __syncthreads();
    uint32_t tmem;
    asm volatile("ld.shared.b32 %0, [%1];" : "=r"(tmem) : "r"(TMEMP));
    if (wid == 0) TCGEN05_RELINQ();

    uint32_t swoff[4];
#pragma unroll
    for (int i = 0; i < 4; i++) {
        uint32_t off = (uint32_t)(i * 32 + lr) * 128 + (tid & 7) * 16;
        swoff[i] = off ^ ((off >> 3) & 0x70);
    }

    int ph0 = 0, ph1 = 0;

#define STS_TILE(stoff) do {                                                  \
    char* _sb = smem + 1024 + (stoff);                                        \
    _Pragma("unroll")                                                         \
    for (int i = 0; i < 4; i++) {                                             \
        uint32_t ah[4], al[4];                                                \
        SPLIT8(a0[i], a1[i], ah, al);                                         \
        *(uint4*)(_sb + OFF_AH + swoff[i]) = make_uint4(ah[0], ah[1], ah[2], ah[3]); \
        *(uint4*)(_sb + OFF_AL + swoff[i]) = make_uint4(al[0], al[1], al[2], al[3]); \
        *(uint4*)(_sb + OFF_BH + swoff[i]) = bh[i];                           \
        *(uint4*)(_sb + OFF_BL + swoff[i]) = bl[i];                           \
    }                                                                         \
} while (0)

    LDG_TILE(0);
    STS_TILE(0);
    FENCE_PROXY_ASYNC();
    __syncthreads();

    for (int kt = 0; kt < KT; kt++) {
        int s = kt & 1;
        bool have_next = (kt + 1 < KT);
        if (have_next) LDG_TILE(kt + 1);

        if (wid == 0) {
            if (elect_one_pred()) {
                uint32_t sb = STG0 + s * STAGE_BYTES;
                uint64_t dah = make_sw128_desc(sb + OFF_AH);
                uint64_t dal = make_sw128_desc(sb + OFF_AL);
                uint64_t dbh = make_sw128_desc(sb + OFF_BH);
                uint64_t dbl = make_sw128_desc(sb + OFF_BL);
#pragma unroll
                for (int ks = 0; ks < 4; ks++) {
                    TCGEN05_MMA_F16_SS(tmem, dah + ks * 2, dbh + ks * 2,
                                       TCG_IDESC, (kt > 0) || (ks > 0));
                    TCGEN05_MMA_F16_SS(tmem, dah + ks * 2, dbl + ks * 2,
                                       TCG_IDESC, 1);
                    TCGEN05_MMA_F16_SS(tmem, dal + ks * 2, dbh + ks * 2,
                                       TCG_IDESC, 1);
                }
                TCGEN05_COMMIT(s == 0 ? MBAR0 : MBAR1);
            }
        }

        if (have_next) {
            int ns = s ^ 1;
            if (kt >= 1) {
                if (ns == 0) { MBARRIER_WAIT_PARITY(MBAR0, ph0); ph0 ^= 1; }
                else         { MBARRIER_WAIT_PARITY(MBAR1, ph1); ph1 ^= 1; }
            }
            STS_TILE(ns * STAGE_BYTES);
            FENCE_PROXY_ASYNC();
            __syncthreads();
        }
    }

    if (((KT - 1) & 1) == 0) { MBARRIER_WAIT_PARITY(MBAR0, ph0); }
    else                     { MBARRIER_WAIT_PARITY(MBAR1, ph1); }
    TCGEN05_FENCE_AFTER();

    {
        int colbase = (wid >> 2) * 64;
        uint32_t d0[32], d1[32];
        TCGEN05_LD32(d0, tmem + colbase);
        TCGEN05_LD32(d1, tmem + colbase + 32);
        TCGEN05_WAIT_LD();
        TCGEN05_FENCE_BEFORE();

        int r = brow + (wid & 3) * 32 + lane;
        float* Crow = C + (size_t)r * N + bcol + colbase;
        const float* brow_b = bias + bcol + colbase;
#pragma unroll
        for (int c = 0; c < 32; c += 4) {
            float4 o;
            o.x = __uint_as_float(d0[c + 0]) + brow_b[c + 0];
            o.y = __uint_as_float(d0[c + 1]) + brow_b[c + 1];
            o.z = __uint_as_float(d0[c + 2]) + brow_b[c + 2];
            o.w = __uint_as_float(d0[c + 3]) + brow_b[c + 3];
            if (RELU) {
                o.x = fmaxf(o.x, 0.f); o.y = fmaxf(o.y, 0.f);
                o.z = fmaxf(o.z, 0.f); o.w = fmaxf(o.w, 0.f);
            }
            *(float4*)(Crow + c) = o;
        }
#pragma unroll
        for (int c = 0; c < 32; c += 4) {
            float4 o;
            o.x = __uint_as_float(d1[c + 0]) + brow_b[32 + c + 0];
            o.y = __uint_as_float(d1[c + 1]) + brow_b[32 + c + 1];
            o.z = __uint_as_float(d1[c + 2]) + brow_b[32 + c + 2];
            o.w = __uint_as_float(d1[c + 3]) + brow_b[32 + c + 3];
            if (RELU) {
                o.x = fmaxf(o.x, 0.f); o.y = fmaxf(o.y, 0.f);
                o.z = fmaxf(o.z, 0.f); o.w = fmaxf(o.w, 0.f);
            }
            *(float4*)(Crow + 32 + c) = o;
        }
    }

    __syncthreads();
    if (tid == 0) { MBARRIER_INVAL(MBAR0); MBARRIER_INVAL(MBAR1); }
    __syncthreads();
    if (wid == 0) TCGEN05_DEALLOC(tmem, 128);

#else  // SIMT fallback
    float (*As)[132] = (float(*)[132])(smem);
    float (*Bs)[132] = (float(*)[132])(smem + 64 * 132 * 4);

    int ty = (tid >> 4) * 8;
    int tx = (tid & 15) * 8;

    float acc[8][8];
#pragma unroll
    for (int i = 0; i < 8; i++)
#pragma unroll
        for (int j = 0; j < 8; j++) acc[i][j] = 0.f;

    for (int kt = 0; kt < KT; kt++) {
        LDG_TILE(kt);
        __syncthreads();
#pragma unroll
        for (int i = 0; i < 4; i++) {
            int r = i * 32 + lr;
            float av[8] = {a0[i].x, a0[i].y, a0[i].z, a0[i].w,
                           a1[i].x, a1[i].y, a1[i].z, a1[i].w};
            const __half* hh = (const __half*)&bh[i];
            const __half* ll = (const __half*)&bl[i];
#pragma unroll
            for (int j = 0; j < 8; j++) {
                As[c8 + j][r] = av[j];
                Bs[c8 + j][r] = __half2float(hh[j]) + __half2float(ll[j]);
            }
        }
        __syncthreads();
#pragma unroll 16
        for (int k = 0; k < 64; k++) {
            float av[8], bv[8];
#pragma unroll
            for (int i = 0; i < 8; i++) { av[i] = As[k][ty + i]; bv[i] = Bs[k][tx + i]; }
#pragma unroll
            for (int i = 0; i < 8; i++)
#pragma unroll
                for (int j = 0; j < 8; j++)
                    acc[i][j] += av[i] * bv[j];
        }
    }

    int row = brow + ty;
    int col = bcol + tx;
#pragma unroll
    for (int i = 0; i < 8; i++) {
#pragma unroll
        for (int j = 0; j < 8; j++) {
            float v = acc[i][j] + bias[col + j];
            if (RELU) v = fmaxf(v, 0.f);
            C[(size_t)(row + i) * N + col + j] = v;
        }
    }
#endif
}

// ---------------------------------------------------------------------------
// Persistent-B GEMM for K=256: each CTA owns one 128-col B slice, keeps B
// hi/lo resident in SMEM (4 x 16KB SW128 sub-tiles per plane), and loops over
// M-tiles m = cid, cid+CPC, ... A is split+staged per K64 chunk, double-
// buffered. TMEM alloc 128 only; single D buffer; proven MMA triple.
// SMEM: [0 hdr 1024][BH 65536][BL 65536][A stages 2x32768] = 197632.
// ---------------------------------------------------------------------------
#define PERS_SMEM 197632
#define MT_TILES (M_TOT / 128)   // 340

template <int RELU>
__global__ __launch_bounds__(256, 1)
void tc_gemm_pers(const float* __restrict__ A, const float* __restrict__ A2,
                  const __half* __restrict__ WH, const __half* __restrict__ WL,
                  const float* __restrict__ bias, float* __restrict__ C,
                  int N, int CPC) {
    extern __shared__ char smem[];
    const int tid = threadIdx.x;
    const int K = 256;
    const int col = blockIdx.x / CPC;
    const int cid = blockIdx.x % CPC;
    const int bcol = col * 128;

    const int lr  = tid >> 3;
    const int c16 = tid & 7;
    const uint32_t swr = (uint32_t)lr * 128 + (uint32_t)((c16 ^ (lr & 7)) * 16);

#if HAS_TCGEN05
    const uint32_t sbase = smem_to_u32(smem);
    const int wid = tid >> 5, lane = tid & 31;
    const uint32_t TMEMP = sbase;
    const uint32_t MBAR0 = sbase + 8;
    const uint32_t MBAR1 = sbase + 16;
    const uint32_t BH_S  = sbase + 1024;
    const uint32_t BL_S  = BH_S + 65536;
    const uint32_t AST   = BL_S + 65536;

    if (wid == 0) TCGEN05_ALLOC(TMEMP, 128);
    if (tid == 0) { MBARRIER_INIT(MBAR0, 1); MBARRIER_INIT(MBAR1, 1); }
    __syncthreads();
    uint32_t tmem;
    asm volatile("ld.shared.b32 %0, [%1];" : "=r"(tmem) : "r"(TMEMP));
    if (wid == 0) TCGEN05_RELINQ();

    // Load resident B hi/lo: 4 K64 sub-tiles of 16KB per plane
    {
        const __half* BHb = WH + (size_t)(bcol + lr) * K + c16 * 8;
        const __half* BLb = WL + (size_t)(bcol + lr) * K + c16 * 8;
#pragma unroll
        for (int kt = 0; kt < 4; kt++) {
#pragma unroll
            for (int i = 0; i < 4; i++) {
                size_t ro = (size_t)(i * 32) * K + kt * 64;
                uint32_t so = (uint32_t)kt * 16384 + swr + (uint32_t)i * 4096;
                *(uint4*)(smem + 1024 + so)         = *(const uint4*)(BHb + ro);
                *(uint4*)(smem + 1024 + 65536 + so) = *(const uint4*)(BLb + ro);
            }
        }
    }
    FENCE_PROXY_ASYNC();
    __syncthreads();

    int g = 0;   // global K-chunk step; commit per step to mbar[g&1]
    for (int m = cid; m < MT_TILES; m += CPC) {
        const int brow = m * 128;
        const float* Ab  = A  + (size_t)(brow + lr) * K + c16 * 8;
        const float* A2b = A2 ? A2 + (size_t)(brow + lr) * K + c16 * 8 : (const float*)0;

#pragma unroll 1
        for (int kt = 0; kt < 4; kt++, g++) {
            const int s = g & 1;
            float4 a0[4], a1[4];
#pragma unroll
            for (int i = 0; i < 4; i++) {
                size_t ro = (size_t)(i * 32) * K + kt * 64;
                a0[i] = *(const float4*)(Ab + ro);
                a1[i] = *(const float4*)(Ab + ro + 4);
                if (A2b) {
                    float4 e0 = *(const float4*)(A2b + ro);
                    float4 e1 = *(const float4*)(A2b + ro + 4);
                    a0[i].x += e0.x; a0[i].y += e0.y; a0[i].z += e0.z; a0[i].w += e0.w;
                    a1[i].x += e1.x; a1[i].y += e1.y; a1[i].z += e1.z; a1[i].w += e1.w;
                }
            }
            if (g >= 2) {   // reuse stage s: its last commit was step g-2 (index (g>>1)-1)
                MBARRIER_WAIT_PARITY(s ? MBAR1 : MBAR0, ((g >> 1) - 1) & 1);
            }
            char* sb = smem + 1024 + 131072 + s * 32768;
#pragma unroll
            for (int i = 0; i < 4; i++) {
                uint32_t ah[4], al[4];
                SPLIT8(a0[i], a1[i], ah, al);
                *(uint4*)(sb + swr + i * 4096)         = make_uint4(ah[0], ah[1], ah[2], ah[3]);
                *(uint4*)(sb + 16384 + swr + i * 4096) = make_uint4(al[0], al[1], al[2], al[3]);
            }
            FENCE_PROXY_ASYNC();
            __syncthreads();

            if (wid == 0) {
                if (elect_one_pred()) {
                    uint64_t dah = make_sw128_desc(AST + s * 32768);
                    uint64_t dal = make_sw128_desc(AST + s * 32768 + 16384);
                    uint64_t dbh = make_sw128_desc(BH_S + kt * 16384);
                    uint64_t dbl = make_sw128_desc(BL_S + kt * 16384);
#pragma unroll
                    for (int ks = 0; ks < 4; ks++) {
                        TCGEN05_MMA_F16_SS(tmem, dah + ks * 2, dbh + ks * 2,
                                           TCG_IDESC, (kt > 0) || (ks > 0));
                        TCGEN05_MMA_F16_SS(tmem, dah + ks * 2, dbl + ks * 2,
                                           TCG_IDESC, 1);
                        TCGEN05_MMA_F16_SS(tmem, dal + ks * 2, dbh + ks * 2,
                                           TCG_IDESC, 1);
                    }
                    TCGEN05_COMMIT(s ? MBAR1 : MBAR0);
                }
            }
        }

        // Epilogue for tile m: wait last commit (step g-1, index (g-1)>>1)
        {
            int gl = g - 1;
            MBARRIER_WAIT_PARITY((gl & 1) ? MBAR1 : MBAR0, (gl >> 1) & 1);
            TCGEN05_FENCE_AFTER();

            int colbase = (wid >> 2) * 64;
            uint32_t d0[32], d1[32];
            TCGEN05_LD32(d0, tmem + colbase);
            TCGEN05_LD32(d1, tmem + colbase + 32);
            TCGEN05_WAIT_LD();
            TCGEN05_FENCE_BEFORE();

            int r = brow + (wid & 3) * 32 + lane;
            float* Crow = C + (size_t)r * N + bcol + colbase;
            const float* bb = bias + bcol + colbase;
#pragma unroll
            for (int c = 0; c < 32; c += 4) {
                float4 o;
                o.x = __uint_as_float(d0[c + 0]) + bb[c + 0];
                o.y = __uint_as_float(d0[c + 1]) + bb[c + 1];
                o.z = __uint_as_float(d0[c + 2]) + bb[c + 2];
                o.w = __uint_as_float(d0[c + 3]) + bb[c + 3];
                if (RELU) {
                    o.x = fmaxf(o.x, 0.f); o.y = fmaxf(o.y, 0.f);
                    o.z = fmaxf(o.z, 0.f); o.w = fmaxf(o.w, 0.f);
                }
                *(float4*)(Crow + c) = o;
            }
#pragma unroll
            for (int c = 0; c < 32; c += 4) {
                float4 o;
                o.x = __uint_as_float(d1[c + 0]) + bb[32 + c + 0];
                o.y = __uint_as_float(d1[c + 1]) + bb[32 + c + 1];
                o.z = __uint_as_float(d1[c + 2]) + bb[32 + c + 2];
                o.w = __uint_as_float(d1[c + 3]) + bb[32 + c + 3];
                if (RELU) {
                    o.x = fmaxf(o.x, 0.f); o.y = fmaxf(o.y, 0.f);
                    o.z = fmaxf(o.z, 0.f); o.w = fmaxf(o.w, 0.f);
                }
                *(float4*)(Crow + 32 + c) = o;
            }
            __syncthreads();   // D buffer free before next tile's MMAs
        }
    }

    __syncthreads();
    if (tid == 0) { MBARRIER_INVAL(MBAR0); MBARRIER_INVAL(MBAR1); }
    __syncthreads();
    if (wid == 0) TCGEN05_DEALLOC(tmem, 128);

#else  // SIMT fallback: simple tiled GEMM over assigned m-tiles
    float (*As)[132] = (float(*)[132])(smem);
    float (*Bs)[132] = (float(*)[132])(smem + 64 * 132 * 4);
    int ty = (tid >> 4) * 8;
    int tx = (tid & 15) * 8;

    for (int m = cid; m < MT_TILES; m += CPC) {
        int brow = m * 128;
        float acc[8][8];
#pragma unroll
        for (int i = 0; i < 8; i++)
#pragma unroll
            for (int j = 0; j < 8; j++) acc[i][j] = 0.f;

        for (int kt = 0; kt < 4; kt++) {
            __syncthreads();
#pragma unroll
            for (int i = 0; i < 4; i++) {
                int row = i * 32 + lr;
                size_t aro = (size_t)(brow + row) * K + kt * 64 + c16 * 8;
                float4 x0 = *(const float4*)(A + aro);
                float4 x1 = *(const float4*)(A + aro + 4);
                if (A2) {
                    float4 e0 = *(const float4*)(A2 + aro);
                    float4 e1 = *(const float4*)(A2 + aro + 4);
                    x0.x += e0.x; x0.y += e0.y; x0.z += e0.z; x0.w += e0.w;
                    x1.x += e1.x; x1.y += e1.y; x1.z += e1.z; x1.w += e1.w;
                }
                float av[8] = {x0.x, x0.y, x0.z, x0.w, x1.x, x1.y, x1.z, x1.w};
                size_t bro = (size_t)(bcol + row) * K + kt * 64 + c16 * 8;
#pragma unroll
                for (int j = 0; j < 8; j++) {
                    As[c16 * 8 + j][row] = av[j];
                    Bs[c16 * 8 + j][row] = __half2float(WH[bro + j]) + __half2float(WL[bro + j]);
                }
            }
            __syncthreads();
#pragma unroll 16
            for (int k = 0; k < 64; k++) {
                float av[8], bv[8];
#pragma unroll
                for (int i = 0; i < 8; i++) { av[i] = As[k][ty + i]; bv[i] = Bs[k][tx + i]; }
#pragma unroll
                for (int i = 0; i < 8; i++)
#pragma unroll
                    for (int j = 0; j < 8; j++)
                        acc[i][j] += av[i] * bv[j];
            }
        }
        int row = brow + ty;
        int cc  = bcol + tx;
#pragma unroll
        for (int i = 0; i < 8; i++)
#pragma unroll
            for (int j = 0; j < 8; j++) {
                float v = acc[i][j] + bias[cc + j];
                if (RELU) v = fmaxf(v, 0.f);
                C[(size_t)(row + i) * N + cc + j] = v;
            }
        __syncthreads();
    }
#endif
}

// ---------------------------------------------------------------------------
// Fused weight transpose + fp16 split (all 6 types, 3 layers per launch)
// ---------------------------------------------------------------------------
__global__ void transplit_all(const float* __restrict__ Wval, const float* __restrict__ Woff,
                              const float* __restrict__ Wattn, const float* __restrict__ Wout,
                              const float* __restrict__ W1, const float* __restrict__ W2,
                              __half* __restrict__ wth, __half* __restrict__ wtl,
                              int layer0) {
    int type  = blockIdx.y;
    int layer = layer0 + blockIdx.z;
    const float* W; int K, N, off;
    switch (type) {
        case 0: W = Wval  + (size_t)layer * 65536;  K = 256;  N = 256;  off = WT_VAL;  break;
        case 1: W = Woff  + (size_t)layer * 65536;  K = 256;  N = 256;  off = WT_OFF;  break;
        case 2: W = Wattn + (size_t)layer * 32768;  K = 256;  N = 128;  off = WT_ATTN; break;
        case 3: W = Wout  + (size_t)layer * 65536;  K = 256;  N = 256;  off = WT_OUT;  break;
        case 4: W = W1    + (size_t)layer * 262144; K = 256;  N = 1024; off = WT_W1;   break;
        default: W = W2   + (size_t)layer * 262144; K = 1024; N = 256;  off = WT_W2;   break;
    }
    int tK = K >> 5, tN = N >> 5;
    int t = blockIdx.x;
    if (t >= tK * tN) return;
    int k0 = (t % tK) * 32, n0 = (t / tK) * 32;

    __shared__ float tile[32][33];
    tile[threadIdx.y][threadIdx.x] = W[(size_t)(k0 + threadIdx.y) * N + n0 + threadIdx.x];
    __syncthreads();
    float v = tile[threadIdx.x][threadIdx.y];
    __half h = __float2half_rn(v);
    size_t o = (size_t)layer * WT_LAYER + off + (size_t)(n0 + threadIdx.y) * K + k0 + threadIdx.x;
    wth[o] = h;
    wtl[o] = __float2half_rn(v - __half2float(h));
}

// ---------------------------------------------------------------------------
// Flatten pair of levels: src [B, D, h, w] -> out [B, S, D]; pos + level_embed
// ---------------------------------------------------------------------------
__global__ void flatten_pair(const float* __restrict__ sA, const float* __restrict__ pA,
                             int hwA, int stA, int lvA,
                             const float* __restrict__ sB, const float* __restrict__ pB,
                             int hwB, int stB, int lvB,
                             const float* __restrict__ lemb,
                             float* __restrict__ out, float* __restrict__ posout) {
    __shared__ float ts[32][33];
    __shared__ float tp[32][33];
    int px = blockIdx.x;
    const float *src, *pos; int hw, start, level, p0;
    int tA = hwA >> 5;
    if (px < tA) { src = sA; pos = pA; hw = hwA; start = stA; level = lvA; p0 = px * 32; }
    else         { src = sB; pos = pB; hw = hwB; start = stB; level = lvB; p0 = (px - tA) * 32; }

    int b  = blockIdx.z;
    int d0 = blockIdx.y * 32;
    int tx = threadIdx.x, ty = threadIdx.y;

    const float* sp = src + ((size_t)b * D_MODEL + d0 + ty) * hw + p0;
    const float* pp = pos + ((size_t)b * D_MODEL + d0 + ty) * hw + p0;
    ts[ty][tx] = sp[tx];
    tp[ty][tx] = pp[tx];
    __syncthreads();

    int d = d0 + tx;
    float le = lemb[level * D_MODEL + d];
    size_t srow = (size_t)b * S_TOTAL + start + p0 + ty;
    out[srow * D_MODEL + d]    = ts[tx][ty];
    posout[srow * D_MODEL + d] = tp[tx][ty] + le;
}

// ---------------------------------------------------------------------------
// Residual + LayerNorm: out = LN(x + r) * gamma + beta. One warp per row.
// ---------------------------------------------------------------------------
__global__ void resid_ln_kernel(const float* __restrict__ X, const float* __restrict__ R,
                                const float* __restrict__ g, const float* __restrict__ bt,
                                float* __restrict__ O, int rows) {
    int warp = (blockIdx.x * blockDim.x + threadIdx.x) >> 5;
    int lane = threadIdx.x & 31;
    if (warp >= rows) return;
    const float* xr = X + (size_t)warp * D_MODEL;
    const float* rr = R + (size_t)warp * D_MODEL;

    float v[8];
    float s = 0.f, s2 = 0.f;
#pragma unroll
    for (int u = 0; u < 2; u++) {
        float4 a = *(const float4*)(xr + lane * 4 + u * 128);
        float4 c = *(const float4*)(rr + lane * 4 + u * 128);
        float t0 = a.x + c.x, t1 = a.y + c.y, t2 = a.z + c.z, t3 = a.w + c.w;
        v[u * 4 + 0] = t0; v[u * 4 + 1] = t1; v[u * 4 + 2] = t2; v[u * 4 + 3] = t3;
        s += t0 + t1 + t2 + t3;
        s2 += t0 * t0 + t1 * t1 + t2 * t2 + t3 * t3;
    }
#pragma unroll
    for (int o = 16; o > 0; o >>= 1) {
        s  += __shfl_xor_sync(0xffffffffu, s, o);
        s2 += __shfl_xor_sync(0xffffffffu, s2, o);
    }
    float mean = s * (1.f / D_MODEL);
    float var  = s2 * (1.f / D_MODEL) - mean * mean;
    float inv  = rsqrtf(var + 1e-5f);
#pragma unroll
    for (int u = 0; u < 2; u++) {
        int d = lane * 4 + u * 128;
        float4 o4;
        o4.x = (v[u * 4 + 0] - mean) * inv * g[d + 0] + bt[d + 0];
        o4.y = (v[u * 4 + 1] - mean) * inv * g[d + 1] + bt[d + 1];
        o4.z = (v[u * 4 + 2] - mean) * inv * g[d + 2] + bt[d + 2];
        o4.w = (v[u * 4 + 3] - mean) * inv * g[d + 3] + bt[d + 3];
        *(float4*)(O + (size_t)warp * D_MODEL + d) = o4;
    }
}

// ---------------------------------------------------------------------------
// Deformable sampling (round-8 proven). One warp per (token, head).
// ---------------------------------------------------------------------------
__constant__ int c_lw[4]     = {128, 64, 32, 16};
__constant__ int c_lstart[4] = {0, 16384, 20480, 21504};

__global__ void sample_kernel(const float* __restrict__ Val, const float* __restrict__ Off,
                              const float* __restrict__ Awl, float* __restrict__ Samp) {
    __shared__ int2 tab[8][16][4];
    int gw   = (blockIdx.x * blockDim.x + threadIdx.x) >> 5;
    int lane = threadIdx.x & 31;
    int wpb  = threadIdx.x >> 5;
    if (gw >= M_TOT * NH) return;
    int h   = gw & 7;
    int tok = gw >> 3;
    int s   = tok % S_TOTAL;
    int b   = tok / S_TOTAL;

    int wt, st, sh;
    if (s < 16384)      { wt = 128; st = 0;     sh = 7; }
    else if (s < 20480) { wt = 64;  st = 16384; sh = 6; }
    else if (s < 21504) { wt = 32;  st = 20480; sh = 5; }
    else                { wt = 16;  st = 21504; sh = 4; }
    int sl = s - st;
    int iy = sl >> sh;
    int ix = sl - (iy << sh);
    float refx = (ix + 0.5f) / (float)wt;
    float refy = (iy + 0.5f) / (float)wt;

    size_t rb = (size_t)tok;

    float lv = (lane < 16) ? Awl[rb * 128 + h * 16 + lane] : -1e30f;
    float m = lv;
#pragma unroll
    for (int o = 8; o > 0; o >>= 1) m = fmaxf(m, __shfl_xor_sync(0xffffffffu, m, o));
    float e = (lane < 16) ? expf(lv - m) : 0.f;
    float ssum = e;
#pragma unroll
    for (int o = 8; o > 0; o >>= 1) ssum += __shfl_xor_sync(0xffffffffu, ssum, o);
    float aw = e / ssum;

    if (lane < 16) {
        int l   = lane >> 2;
        int wl  = c_lw[l];
        int stl = c_lstart[l];
        float ox = Off[rb * 256 + (size_t)(h * 16 + lane) * 2 + 0];
        float oy = Off[rb * 256 + (size_t)(h * 16 + lane) * 2 + 1];
        float x = refx * (float)wl + ox - 0.5f;
        float y = refy * (float)wl + oy - 0.5f;
        float xf = floorf(x), yf = floorf(y);
        float lx = x - xf, ly = y - yf;
        int x0 = (int)xf, y0 = (int)yf;
        int x1 = x0 + 1, y1 = y0 + 1;
        bool okx0 = (x0 >= 0) & (x0 < wl);
        bool okx1 = (x1 >= 0) & (x1 < wl);
        bool oky0 = (y0 >= 0) & (y0 < wl);
        bool oky1 = (y1 >= 0) & (y1 < wl);
        int cx0 = min(max(x0, 0), wl - 1), cx1 = min(max(x1, 0), wl - 1);
        int cy0 = min(max(y0, 0), wl - 1), cy1 = min(max(y1, 0), wl - 1);
        float w0 = (1.f - lx) * (1.f - ly) * aw * ((okx0 && oky0) ? 1.f : 0.f);
        float w1 = lx * (1.f - ly) * aw * ((okx1 && oky0) ? 1.f : 0.f);
        float w2 = (1.f - lx) * ly * aw * ((okx0 && oky1) ? 1.f : 0.f);
        float w3 = lx * ly * aw * ((okx1 && oky1) ? 1.f : 0.f);
        tab[wpb][lane][0] = make_int2(stl + cy0 * wl + cx0, __float_as_int(w0));
        tab[wpb][lane][1] = make_int2(stl + cy0 * wl + cx1, __float_as_int(w1));
        tab[wpb][lane][2] = make_int2(stl + cy1 * wl + cx0, __float_as_int(w2));
        tab[wpb][lane][3] = make_int2(stl + cy1 * wl + cx1, __float_as_int(w3));
    }
    __syncwarp();

    int t   = lane >> 3;
    int ch4 = lane & 7;
    const float4* base = (const float4*)Val + (size_t)b * S_TOTAL * 64 + h * 8 + ch4;
    float4 acc = make_float4(0.f, 0.f, 0.f, 0.f);
#pragma unroll
    for (int j = 0; j < 16; j++) {
        int2 ee = tab[wpb][j][t];
        float4 v = base[(size_t)ee.x * 64];
        float f = __int_as_float(ee.y);
        acc.x += f * v.x; acc.y += f * v.y; acc.z += f * v.z; acc.w += f * v.w;
    }
#pragma unroll
    for (int msk = 8; msk <= 16; msk <<= 1) {
        acc.x += __shfl_xor_sync(0xffffffffu, acc.x, msk);
        acc.y += __shfl_xor_sync(0xffffffffu, acc.y, msk);
        acc.z += __shfl_xor_sync(0xffffffffu, acc.z, msk);
        acc.w += __shfl_xor_sync(0xffffffffu, acc.w, msk);
    }
    if (lane < 8)
        ((float4*)(Samp + (size_t)tok * 256 + h * 32))[ch4] = acc;
}

// ---------------------------------------------------------------------------
// Host orchestration
// ---------------------------------------------------------------------------
extern "C" void kernel_launch(void* const* d_in, const int* in_sizes, int n_in,
                              void* d_out, int out_size) {
    const float* src[4];
    const float* posin[4];
    bool interleaved = (in_sizes[1] == in_sizes[0]);
    for (int l = 0; l < 4; l++) {
        if (interleaved) {
            src[l]   = (const float*)d_in[2 * l];
            posin[l] = (const float*)d_in[2 * l + 1];
        } else {
            src[l]   = (const float*)d_in[l];
            posin[l] = (const float*)d_in[4 + l];
        }
    }
    const float* lemb  = (const float*)d_in[8];
    const float* Woff  = (const float*)d_in[9];
    const float* boff  = (const float*)d_in[10];
    const float* Wattn = (const float*)d_in[11];
    const float* battn = (const float*)d_in[12];
    const float* Wval  = (const float*)d_in[13];
    const float* bval  = (const float*)d_in[14];
    const float* Wout  = (const float*)d_in[15];
    const float* bout  = (const float*)d_in[16];
    const float* ln1s  = (const float*)d_in[17];
    const float* ln1b  = (const float*)d_in[18];
    const float* W1    = (const float*)d_in[19];
    const float* b1    = (const float*)d_in[20];
    const float* W2    = (const float*)d_in[21];
    const float* b2    = (const float*)d_in[22];
    const float* ln2s  = (const float*)d_in[23];
    const float* ln2b  = (const float*)d_in[24];

    float* out = (float*)d_out;

    float *pos, *val, *off, *awl, *samp, *tmp, *ffh;
    __half *wth, *wtl;
    cudaGetSymbolAddress((void**)&pos,  g_pos);
    cudaGetSymbolAddress((void**)&val,  g_val);
    cudaGetSymbolAddress((void**)&off,  g_off);
    cudaGetSymbolAddress((void**)&awl,  g_awl);
    cudaGetSymbolAddress((void**)&samp, g_samp);
    cudaGetSymbolAddress((void**)&tmp,  g_tmp);
    cudaGetSymbolAddress((void**)&ffh,  g_ffh);
    cudaGetSymbolAddress((void**)&wth,  g_wth);
    cudaGetSymbolAddress((void**)&wtl,  g_wtl);

    cudaFuncSetAttribute(tc_gemm<0>,      cudaFuncAttributeMaxDynamicSharedMemorySize, TCG_SMEM);
    cudaFuncSetAttribute(tc_gemm_pers<0>, cudaFuncAttributeMaxDynamicSharedMemorySize, PERS_SMEM);
    cudaFuncSetAttribute(tc_gemm_pers<1>, cudaFuncAttributeMaxDynamicSharedMemorySize, PERS_SMEM);

    // Prologue: exactly 4 launches
    transplit_all<<<dim3(256, 6, 3), dim3(32, 32)>>>(Wval, Woff, Wattn, Wout, W1, W2,
                                                     wth, wtl, 0);
    transplit_all<<<dim3(256, 6, 3), dim3(32, 32)>>>(Wval, Woff, Wattn, Wout, W1, W2,
                                                     wth, wtl, 3);
    flatten_pair<<<dim3(16384/32 + 4096/32, 8, BATCH), dim3(32, 32)>>>(
        src[0], posin[0], 16384, 0, 0, src[1], posin[1], 4096, 16384, 1,
        lemb, out, pos);
    flatten_pair<<<dim3(1024/32 + 256/32, 8, BATCH), dim3(32, 32)>>>(
        src[2], posin[2], 1024, 20480, 2, src[3], posin[3], 256, 21504, 3,
        lemb, out, pos);

    for (int i = 0; i < NLAYERS; i++) {
        const __half* bh = wth + (size_t)i * WT_LAYER;
        const __half* bl = wtl + (size_t)i * WT_LAYER;
        // value = out @ Wval + bval            (N=256: 2 cols x 74 CTAs)
        tc_gemm_pers<0><<<148, 256, PERS_SMEM>>>(out, nullptr, bh + WT_VAL, bl + WT_VAL,
                                                 bval + i * 256, val, 256, 74);
        // off = (out + pos) @ Woff + boff
        tc_gemm_pers<0><<<148, 256, PERS_SMEM>>>(out, pos, bh + WT_OFF, bl + WT_OFF,
                                                 boff + i * 256, off, 256, 74);
        // attn logits = (out + pos) @ Wattn + battn   (N=128: 1 col x 148 CTAs)
        tc_gemm_pers<0><<<148, 256, PERS_SMEM>>>(out, pos, bh + WT_ATTN, bl + WT_ATTN,
                                                 battn + i * 128, awl, 128, 148);
        // deformable sampling
        sample_kernel<<<M_TOT * NH / 8, 256>>>(val, off, awl, samp);
        // attn out = samp @ Wout + bout
        tc_gemm_pers<0><<<148, 256, PERS_SMEM>>>(samp, nullptr, bh + WT_OUT, bl + WT_OUT,
                                                 bout + i * 256, tmp, 256, 74);
        // out = LN(out + attn)
        resid_ln_kernel<<<(M_TOT + 7) / 8, 256>>>(tmp, out, ln1s + i * 256,
                                                  ln1b + i * 256, out, M_TOT);
        // h = relu(out @ W1 + b1)              (N=1024: 8 cols x 18 CTAs)
        tc_gemm_pers<1><<<144, 256, PERS_SMEM>>>(out, nullptr, bh + WT_W1, bl + WT_W1,
                                                 b1 + i * 1024, ffh, 1024, 18);
        // ff = h @ W2 + b2                     (K=1024: streaming kernel)
        tc_gemm<0><<<dim3(M_TOT / 128, 2), 256, TCG_SMEM>>>(ffh, nullptr, bh + WT_W2, bl + WT_W2,
                                                            b2 + i * 256, tmp, M_TOT, 256, 1024);
        // out = LN(out + ff)
        resid_ln_kernel<<<(M_TOT + 7) / 8, 256>>>(tmp, out, ln2s + i * 256,
                                                  ln2b + i * 256, out, M_TOT);
    }
}

// round 10
// speedup vs baseline: 2.6669x; 1.0475x over previous
#include <cuda_runtime.h>
#include <cuda_fp16.h>
#include <math.h>
#include <stdint.h>

// ---------------------------------------------------------------------------
// MSDeformAttn transformer encoder (6 layers).
// K=256 GEMMs: persistent-B tcgen05 kind::f16 3-split (B resident in SMEM).
// val GEMM emits fp16 values; off+attn fused into one N=384 GEMM.
// W2 (K=1024): streaming kernel. sm_103a arch-feature guarded.
// D=256, NH=8, NL=4, NP=4, DH=32, DFF=1024, B=2, S=21760.
// ---------------------------------------------------------------------------

#define D_MODEL 256
#define NH 8
#define DFF 1024
#define NLAYERS 6
#define BATCH 2
#define S_TOTAL 21760
#define M_TOT (BATCH * S_TOTAL)   // 43520 rows; 340 M-tiles of 128

#if defined(__CUDA_ARCH_FEAT_SM103_ALL) || defined(__CUDA_ARCH_FEAT_SM100_ALL) || defined(__CUDA_ARCH_FEAT_SM101_ALL)
#define HAS_TCGEN05 1
#else
#define HAS_TCGEN05 0
#endif

// Scratch (allocation-free: __device__ globals)
__device__ float  g_pos[M_TOT * D_MODEL];
__device__ __half g_valh[M_TOT * D_MODEL];        // fp16 value tensor
__device__ float  g_offawl[M_TOT * 384];          // [off 256 | awl 128] per row
__device__ float  g_samp[M_TOT * D_MODEL];
__device__ float  g_tmp[M_TOT * D_MODEL];
__device__ float  g_ffh[M_TOT * DFF];
__device__ float  g_biasoa[NLAYERS * 384];        // [boff 256 | battn 128]

// Transposed + fp16-split weights: per layer 753664 elements
#define WT_LAYER 753664
__device__ __half g_wth[NLAYERS * WT_LAYER];
__device__ __half g_wtl[NLAYERS * WT_LAYER];
#define WT_VAL  0
#define WT_OFF  65536      // rows 0..255 of combined [384,256] (attn follows)
#define WT_ATTN 131072
#define WT_OUT  163840
#define WT_W1   229376
#define WT_W2   491520

// ---------------------------------------------------------------------------
// PTX helpers
// ---------------------------------------------------------------------------
__device__ __forceinline__ uint32_t elect_one_pred() {
    uint32_t pred;
    asm volatile(
        "{\n\t.reg .pred p;\n\telect.sync _|p, 0xFFFFFFFF;\n\t"
        "selp.b32 %0, 1, 0, p;\n\t}" : "=r"(pred));
    return pred;
}
__device__ __forceinline__ uint32_t smem_to_u32(const void* p) {
    uint32_t a;
    asm("{ .reg .u64 t; cvta.to.shared.u64 t, %1; cvt.u32.u64 %0, t; }"
        : "=r"(a) : "l"(p));
    return a;
}

#define TCGEN05_ALLOC(addr, n) \
    asm volatile("tcgen05.alloc.cta_group::1.sync.aligned.shared::cta.b32 [%0], %1;" \
                 :: "r"((uint32_t)(addr)), "r"((uint32_t)(n)) : "memory")
#define TCGEN05_DEALLOC(tmem, n) \
    asm volatile("tcgen05.dealloc.cta_group::1.sync.aligned.b32 %0, %1;" \
                 :: "r"(tmem), "r"((uint32_t)(n)))
#define TCGEN05_RELINQ() \
    asm volatile("tcgen05.relinquish_alloc_permit.cta_group::1.sync.aligned;")
#define TCGEN05_COMMIT(mbar) \
    asm volatile("tcgen05.commit.cta_group::1.mbarrier::arrive::one.shared::cluster.b64 [%0];" \
                 :: "r"((uint32_t)(mbar)) : "memory")
#define TCGEN05_FENCE_AFTER() \
    asm volatile("tcgen05.fence::after_thread_sync;" ::: "memory")
#define TCGEN05_FENCE_BEFORE() \
    asm volatile("tcgen05.fence::before_thread_sync;" ::: "memory")
#define TCGEN05_WAIT_LD() \
    asm volatile("tcgen05.wait::ld.sync.aligned;" ::: "memory")
#define FENCE_PROXY_ASYNC() \
    asm volatile("fence.proxy.async.shared::cta;" ::: "memory")
#define MBARRIER_INIT(mbar, cnt) \
    asm volatile("mbarrier.init.shared.b64 [%0], %1;" \
                 :: "r"((uint32_t)(mbar)), "r"((uint32_t)(cnt)) : "memory")
#define MBARRIER_INVAL(mbar) \
    asm volatile("mbarrier.inval.shared.b64 [%0];" :: "r"((uint32_t)(mbar)) : "memory")

#define MBARRIER_WAIT_PARITY(mbar, parity) do {                               \
    uint32_t _m = (uint32_t)(mbar);                                           \
    uint32_t _p = (uint32_t)(parity);                                         \
    asm volatile(                                                             \
        "{\n\t.reg .pred P1;\n\t"                                             \
        "WAIT_LOOP_%=:\n\t"                                                   \
        "mbarrier.try_wait.parity.acquire.cta.shared::cta.b64 P1, [%0], %1, 0x989680;\n\t" \
        "@P1 bra.uni WAIT_DONE_%=;\n\t"                                       \
        "bra.uni WAIT_LOOP_%=;\n\t"                                           \
        "WAIT_DONE_%=:\n\t}"                                                  \
        :: "r"(_m), "r"(_p) : "memory");                                      \
} while (0)

// fp16 SS MMA (fp32 accum), cta_group::1
#define TCGEN05_MMA_F16_SS(d, ad, bd, id, en) do {                            \
    uint32_t _e = (en) ? 1u : 0u; uint32_t _z = 0;                            \
    asm volatile(                                                             \
        "{\n\t.reg .pred p;\n\tsetp.ne.u32 p, %5, 0;\n\t"                     \
        "tcgen05.mma.cta_group::1.kind::f16 [%0], %1, %2, %3, {%4,%4,%4,%4}, p;\n\t}" \
        :: "r"(d), "l"(ad), "l"(bd), "r"(id), "r"(_z), "r"(_e) : "memory");   \
} while (0)

#define TCGEN05_LD32(r, addr)                                                 \
    asm volatile(                                                             \
        "tcgen05.ld.sync.aligned.32x32b.x32.b32 "                             \
        "{%0, %1, %2, %3, %4, %5, %6, %7, "                                   \
        " %8, %9, %10, %11, %12, %13, %14, %15, "                             \
        " %16, %17, %18, %19, %20, %21, %22, %23, "                           \
        " %24, %25, %26, %27, %28, %29, %30, %31}, [%32];"                    \
        : "=r"((r)[0]),  "=r"((r)[1]),  "=r"((r)[2]),  "=r"((r)[3]),          \
          "=r"((r)[4]),  "=r"((r)[5]),  "=r"((r)[6]),  "=r"((r)[7]),          \
          "=r"((r)[8]),  "=r"((r)[9]),  "=r"((r)[10]), "=r"((r)[11]),         \
          "=r"((r)[12]), "=r"((r)[13]), "=r"((r)[14]), "=r"((r)[15]),         \
          "=r"((r)[16]), "=r"((r)[17]), "=r"((r)[18]), "=r"((r)[19]),         \
          "=r"((r)[20]), "=r"((r)[21]), "=r"((r)[22]), "=r"((r)[23]),         \
          "=r"((r)[24]), "=r"((r)[25]), "=r"((r)[26]), "=r"((r)[27]),         \
          "=r"((r)[28]), "=r"((r)[29]), "=r"((r)[30]), "=r"((r)[31])          \
        : "r"(addr))

// SW128 K-major smem descriptor: layout=2, version=1, SBO=64, LBO=1
__device__ __forceinline__ uint64_t make_sw128_desc(uint32_t addr) {
    const uint64_t base = (uint64_t(2) << 61) | (uint64_t(1) << 46)
                        | (uint64_t(64) << 32) | (uint64_t(1) << 16);
    return base | ((uint64_t)(addr >> 4) & 0x3FFF);
}

#define SPLIT8(x0, x1, hi, lo) do {                                           \
    float _v[8] = {x0.x, x0.y, x0.z, x0.w, x1.x, x1.y, x1.z, x1.w};           \
    _Pragma("unroll")                                                         \
    for (int _j = 0; _j < 4; _j++) {                                          \
        __half hx = __float2half_rn(_v[2*_j]);                                \
        __half hy = __float2half_rn(_v[2*_j+1]);                              \
        __half lx = __float2half_rn(_v[2*_j]   - __half2float(hx));           \
        __half ly = __float2half_rn(_v[2*_j+1] - __half2float(hy));           \
        __half2 hp = __halves2half2(hx, hy);                                  \
        __half2 lp = __halves2half2(lx, ly);                                  \
        (hi)[_j] = *(uint32_t*)&hp;                                           \
        (lo)[_j] = *(uint32_t*)&lp;                                           \
    }                                                                         \
} while (0)

#define TCG_IDESC 0x8200010u

// Epilogue store of 4 consecutive cols (float or half)
template <int RELU, int OUTH>
__device__ __forceinline__ void epi_store4(float* Cf, size_t idx, float4 o) {
    if (RELU) {
        o.x = fmaxf(o.x, 0.f); o.y = fmaxf(o.y, 0.f);
        o.z = fmaxf(o.z, 0.f); o.w = fmaxf(o.w, 0.f);
    }
    if (OUTH) {
        __half2 h0 = __halves2half2(__float2half_rn(o.x), __float2half_rn(o.y));
        __half2 h1 = __halves2half2(__float2half_rn(o.z), __float2half_rn(o.w));
        uint2 u; u.x = *(uint32_t*)&h0; u.y = *(uint32_t*)&h1;
        *(uint2*)((__half*)Cf + idx) = u;
    } else {
        *(float4*)(Cf + idx) = o;
    }
}

// ---------------------------------------------------------------------------
// Streaming GEMM (proven): used for W2 (K=1024).
// ---------------------------------------------------------------------------
#define STAGE_BYTES 65536
#define OFF_AH 0
#define OFF_AL 16384
#define OFF_BH 32768
#define OFF_BL 49152
#define TCG_SMEM (1024 + 2 * STAGE_BYTES)   // 132096

template <int RELU>
__global__ __launch_bounds__(256, 1)
void tc_gemm(const float* __restrict__ A, const float* __restrict__ A2,
             const __half* __restrict__ WH, const __half* __restrict__ WL,
             const float* __restrict__ bias, float* __restrict__ C,
             int M, int N, int K) {
    extern __shared__ char smem[];
    const int tid  = threadIdx.x;
    const int brow = blockIdx.x * 128;
    const int bcol = blockIdx.y * 128;

    const int lr = tid >> 3;
    const int c8 = (tid & 7) * 8;
    const float*  Ab  = A  + (size_t)(brow + lr) * K + c8;
    const float*  A2b = A2 ? A2 + (size_t)(brow + lr) * K + c8 : (const float*)0;
    const __half* BHb = WH + (size_t)(bcol + lr) * K + c8;
    const __half* BLb = WL + (size_t)(bcol + lr) * K + c8;
    const int KT = K >> 6;

    float4 a0[4], a1[4];
    uint4  bh[4], bl[4];

#define LDG_TILE(kt) do {                                                     \
    int _k = (kt) * 64;                                                       \
    _Pragma("unroll")                                                         \
    for (int i = 0; i < 4; i++) {                                             \
        size_t ro = (size_t)(i * 32) * K + _k;                                \
        a0[i] = *(const float4*)(Ab + ro);                                    \
        a1[i] = *(const float4*)(Ab + ro + 4);                                \
        if (A2b) {                                                            \
            float4 e0 = *(const float4*)(A2b + ro);                           \
            float4 e1 = *(const float4*)(A2b + ro + 4);                       \
            a0[i].x += e0.x; a0[i].y += e0.y; a0[i].z += e0.z; a0[i].w += e0.w; \
            a1[i].x += e1.x; a1[i].y += e1.y; a1[i].z += e1.z; a1[i].w += e1.w; \
        }                                                                     \
        bh[i] = *(const uint4*)(BHb + ro);                                    \
        bl[i] = *(const uint4*)(BLb + ro);                                    \
    }                                                                         \
} while (0)

#if HAS_TCGEN05
    const uint32_t sbase = smem_to_u32(smem);
    const int wid  = tid >> 5;
    const int lane = tid & 31;

    const uint32_t TMEMP = sbase;
    const uint32_t MBAR0 = sbase + 8;
    const uint32_t MBAR1 = sbase + 16;
    const uint32_t STG0  = sbase + 1024;

    if (wid == 0) TCGEN05_ALLOC(TMEMP, 128);
    if (tid == 0) { MBARRIER_INIT(MBAR0, 1); MBARRIER_INIT(MBAR1, 1); }
    __syncthreads();
    uint32_t tmem;
    asm volatile("ld.shared.b32 %0, [%1];" : "=r"(tmem) : "r"(TMEMP));
    if (wid == 0) TCGEN05_RELINQ();

    uint32_t swoff[4];
#pragma unroll
    for (int i = 0; i < 4; i++) {
        uint32_t off = (uint32_t)(i * 32 + lr) * 128 + (tid & 7) * 16;
        swoff[i] = off ^ ((off >> 3) & 0x70);
    }

    int ph0 = 0, ph1 = 0;

#define STS_TILE(stoff) do {                                                  \
    char* _sb = smem + 1024 + (stoff);                                        \
    _Pragma("unroll")                                                         \
    for (int i = 0; i < 4; i++) {                                             \
        uint32_t ah[4], al[4];                                                \
        SPLIT8(a0[i], a1[i], ah, al);                                         \
        *(uint4*)(_sb + OFF_AH + swoff[i]) = make_uint4(ah[0], ah[1], ah[2], ah[3]); \
        *(uint4*)(_sb + OFF_AL + swoff[i]) = make_uint4(al[0], al[1], al[2], al[3]); \
        *(uint4*)(_sb + OFF_BH + swoff[i]) = bh[i];                           \
        *(uint4*)(_sb + OFF_BL + swoff[i]) = bl[i];                           \
    }                                                                         \
} while (0)

    LDG_TILE(0);
    STS_TILE(0);
    FENCE_PROXY_ASYNC();
    __syncthreads();

    for (int kt = 0; kt < KT; kt++) {
        int s = kt & 1;
        bool have_next = (kt + 1 < KT);
        if (have_next) LDG_TILE(kt + 1);

        if (wid == 0) {
            if (elect_one_pred()) {
                uint32_t sb = STG0 + s * STAGE_BYTES;
                uint64_t dah = make_sw128_desc(sb + OFF_AH);
                uint64_t dal = make_sw128_desc(sb + OFF_AL);
                uint64_t dbh = make_sw128_desc(sb + OFF_BH);
                uint64_t dbl = make_sw128_desc(sb + OFF_BL);
#pragma unroll
                for (int ks = 0; ks < 4; ks++) {
                    TCGEN05_MMA_F16_SS(tmem, dah + ks * 2, dbh + ks * 2,
                                       TCG_IDESC, (kt > 0) || (ks > 0));
                    TCGEN05_MMA_F16_SS(tmem, dah + ks * 2, dbl + ks * 2,
                                       TCG_IDESC, 1);
                    TCGEN05_MMA_F16_SS(tmem, dal + ks * 2, dbh + ks * 2,
                                       TCG_IDESC, 1);
                }
                TCGEN05_COMMIT(s == 0 ? MBAR0 : MBAR1);
            }
        }

        if (have_next) {
            int ns = s ^ 1;
            if (kt >= 1) {
                if (ns == 0) { MBARRIER_WAIT_PARITY(MBAR0, ph0); ph0 ^= 1; }
                else         { MBARRIER_WAIT_PARITY(MBAR1, ph1); ph1 ^= 1; }
            }
            STS_TILE(ns * STAGE_BYTES);
            FENCE_PROXY_ASYNC();
            __syncthreads();
        }
    }

    if (((KT - 1) & 1) == 0) { MBARRIER_WAIT_PARITY(MBAR0, ph0); }
    else                     { MBARRIER_WAIT_PARITY(MBAR1, ph1); }
    TCGEN05_FENCE_AFTER();

    {
        int colbase = (wid >> 2) * 64;
        uint32_t d0[32], d1[32];
        TCGEN05_LD32(d0, tmem + colbase);
        TCGEN05_LD32(d1, tmem + colbase + 32);
        TCGEN05_WAIT_LD();
        TCGEN05_FENCE_BEFORE();

        int r = brow + (wid & 3) * 32 + lane;
        size_t base = (size_t)r * N + bcol + colbase;
        const float* bb = bias + bcol + colbase;
#pragma unroll
        for (int c = 0; c < 32; c += 4) {
            float4 o;
            o.x = __uint_as_float(d0[c + 0]) + bb[c + 0];
            o.y = __uint_as_float(d0[c + 1]) + bb[c + 1];
            o.z = __uint_as_float(d0[c + 2]) + bb[c + 2];
            o.w = __uint_as_float(d0[c + 3]) + bb[c + 3];
            epi_store4<RELU, 0>(C, base + c, o);
        }
#pragma unroll
        for (int c = 0; c < 32; c += 4) {
            float4 o;
            o.x = __uint_as_float(d1[c + 0]) + bb[32 + c + 0];
            o.y = __uint_as_float(d1[c + 1]) + bb[32 + c + 1];
            o.z = __uint_as_float(d1[c + 2]) + bb[32 + c + 2];
            o.w = __uint_as_float(d1[c + 3]) + bb[32 + c + 3];
            epi_store4<RELU, 0>(C, base + 32 + c, o);
        }
    }

    __syncthreads();
    if (tid == 0) { MBARRIER_INVAL(MBAR0); MBARRIER_INVAL(MBAR1); }
    __syncthreads();
    if (wid == 0) TCGEN05_DEALLOC(tmem, 128);

#else  // SIMT fallback
    float (*As)[132] = (float(*)[132])(smem);
    float (*Bs)[132] = (float(*)[132])(smem + 64 * 132 * 4);

    int ty = (tid >> 4) * 8;
    int tx = (tid & 15) * 8;

    float acc[8][8];
#pragma unroll
    for (int i = 0; i < 8; i++)
#pragma unroll
        for (int j = 0; j < 8; j++) acc[i][j] = 0.f;

    for (int kt = 0; kt < KT; kt++) {
        LDG_TILE(kt);
        __syncthreads();
#pragma unroll
        for (int i = 0; i < 4; i++) {
            int r = i * 32 + lr;
            float av[8] = {a0[i].x, a0[i].y, a0[i].z, a0[i].w,
                           a1[i].x, a1[i].y, a1[i].z, a1[i].w};
            const __half* hh = (const __half*)&bh[i];
            const __half* ll = (const __half*)&bl[i];
#pragma unroll
            for (int j = 0; j < 8; j++) {
                As[c8 + j][r] = av[j];
                Bs[c8 + j][r] = __half2float(hh[j]) + __half2float(ll[j]);
            }
        }
        __syncthreads();
#pragma unroll 16
        for (int k = 0; k < 64; k++) {
            float av[8], bv[8];
#pragma unroll
            for (int i = 0; i < 8; i++) { av[i] = As[k][ty + i]; bv[i] = Bs[k][tx + i]; }
#pragma unroll
            for (int i = 0; i < 8; i++)
#pragma unroll
                for (int j = 0; j < 8; j++)
                    acc[i][j] += av[i] * bv[j];
        }
    }

    int row = brow + ty;
    int col = bcol + tx;
#pragma unroll
    for (int i = 0; i < 8; i++) {
#pragma unroll
        for (int j = 0; j < 8; j++) {
            float v = acc[i][j] + bias[col + j];
            if (RELU) v = fmaxf(v, 0.f);
            C[(size_t)(row + i) * N + col + j] = v;
        }
    }
#endif
}

// ---------------------------------------------------------------------------
// Persistent-B GEMM for K=256 (round-9 proven structure).
// OUTH=1 emits __half output (C reinterpreted as __half*).
// ---------------------------------------------------------------------------
#define PERS_SMEM 197632
#define MT_TILES (M_TOT / 128)   // 340

template <int RELU, int OUTH>
__global__ __launch_bounds__(256, 1)
void tc_gemm_pers(const float* __restrict__ A, const float* __restrict__ A2,
                  const __half* __restrict__ WH, const __half* __restrict__ WL,
                  const float* __restrict__ bias, float* __restrict__ C,
                  int N, int CPC) {
    extern __shared__ char smem[];
    const int tid = threadIdx.x;
    const int K = 256;
    const int col = blockIdx.x / CPC;
    const int cid = blockIdx.x % CPC;
    const int bcol = col * 128;

    const int lr  = tid >> 3;
    const int c16 = tid & 7;
    const uint32_t swr = (uint32_t)lr * 128 + (uint32_t)((c16 ^ (lr & 7)) * 16);

#if HAS_TCGEN05
    const uint32_t sbase = smem_to_u32(smem);
    const int wid = tid >> 5, lane = tid & 31;
    const uint32_t TMEMP = sbase;
    const uint32_t MBAR0 = sbase + 8;
    const uint32_t MBAR1 = sbase + 16;
    const uint32_t BH_S  = sbase + 1024;
    const uint32_t BL_S  = BH_S + 65536;
    const uint32_t AST   = BL_S + 65536;

    if (wid == 0) TCGEN05_ALLOC(TMEMP, 128);
    if (tid == 0) { MBARRIER_INIT(MBAR0, 1); MBARRIER_INIT(MBAR1, 1); }
    __syncthreads();
    uint32_t tmem;
    asm volatile("ld.shared.b32 %0, [%1];" : "=r"(tmem) : "r"(TMEMP));
    if (wid == 0) TCGEN05_RELINQ();

    // Load resident B hi/lo: 4 K64 sub-tiles of 16KB per plane
    {
        const __half* BHb = WH + (size_t)(bcol + lr) * K + c16 * 8;
        const __half* BLb = WL + (size_t)(bcol + lr) * K + c16 * 8;
#pragma unroll
        for (int kt = 0; kt < 4; kt++) {
#pragma unroll
            for (int i = 0; i < 4; i++) {
                size_t ro = (size_t)(i * 32) * K + kt * 64;
                uint32_t so = (uint32_t)kt * 16384 + swr + (uint32_t)i * 4096;
                *(uint4*)(smem + 1024 + so)         = *(const uint4*)(BHb + ro);
                *(uint4*)(smem + 1024 + 65536 + so) = *(const uint4*)(BLb + ro);
            }
        }
    }
    FENCE_PROXY_ASYNC();
    __syncthreads();

    int g = 0;
    for (int m = cid; m < MT_TILES; m += CPC) {
        const int brow = m * 128;
        const float* Ab  = A  + (size_t)(brow + lr) * K + c16 * 8;
        const float* A2b = A2 ? A2 + (size_t)(brow + lr) * K + c16 * 8 : (const float*)0;

#pragma unroll 1
        for (int kt = 0; kt < 4; kt++, g++) {
            const int s = g & 1;
            float4 a0[4], a1[4];
#pragma unroll
            for (int i = 0; i < 4; i++) {
                size_t ro = (size_t)(i * 32) * K + kt * 64;
                a0[i] = *(const float4*)(Ab + ro);
                a1[i] = *(const float4*)(Ab + ro + 4);
                if (A2b) {
                    float4 e0 = *(const float4*)(A2b + ro);
                    float4 e1 = *(const float4*)(A2b + ro + 4);
                    a0[i].x += e0.x; a0[i].y += e0.y; a0[i].z += e0.z; a0[i].w += e0.w;
                    a1[i].x += e1.x; a1[i].y += e1.y; a1[i].z += e1.z; a1[i].w += e1.w;
                }
            }
            if (g >= 2) {
                MBARRIER_WAIT_PARITY(s ? MBAR1 : MBAR0, ((g >> 1) - 1) & 1);
            }
            char* sb = smem + 1024 + 131072 + s * 32768;
#pragma unroll
            for (int i = 0; i < 4; i++) {
                uint32_t ah[4], al[4];
                SPLIT8(a0[i], a1[i], ah, al);
                *(uint4*)(sb + swr + i * 4096)         = make_uint4(ah[0], ah[1], ah[2], ah[3]);
                *(uint4*)(sb + 16384 + swr + i * 4096) = make_uint4(al[0], al[1], al[2], al[3]);
            }
            FENCE_PROXY_ASYNC();
            __syncthreads();

            if (wid == 0) {
                if (elect_one_pred()) {
                    uint64_t dah = make_sw128_desc(AST + s * 32768);
                    uint64_t dal = make_sw128_desc(AST + s * 32768 + 16384);
                    uint64_t dbh = make_sw128_desc(BH_S + kt * 16384);
                    uint64_t dbl = make_sw128_desc(BL_S + kt * 16384);
#pragma unroll
                    for (int ks = 0; ks < 4; ks++) {
                        TCGEN05_MMA_F16_SS(tmem, dah + ks * 2, dbh + ks * 2,
                                           TCG_IDESC, (kt > 0) || (ks > 0));
                        TCGEN05_MMA_F16_SS(tmem, dah + ks * 2, dbl + ks * 2,
                                           TCG_IDESC, 1);
                        TCGEN05_MMA_F16_SS(tmem, dal + ks * 2, dbh + ks * 2,
                                           TCG_IDESC, 1);
                    }
                    TCGEN05_COMMIT(s ? MBAR1 : MBAR0);
                }
            }
        }

        {
            int gl = g - 1;
            MBARRIER_WAIT_PARITY((gl & 1) ? MBAR1 : MBAR0, (gl >> 1) & 1);
            TCGEN05_FENCE_AFTER();

            int colbase = (wid >> 2) * 64;
            uint32_t d0[32], d1[32];
            TCGEN05_LD32(d0, tmem + colbase);
            TCGEN05_LD32(d1, tmem + colbase + 32);
            TCGEN05_WAIT_LD();
            TCGEN05_FENCE_BEFORE();

            int r = brow + (wid & 3) * 32 + lane;
            size_t cb = (size_t)r * N + bcol + colbase;
            const float* bb = bias + bcol + colbase;
#pragma unroll
            for (int c = 0; c < 32; c += 4) {
                float4 o;
                o.x = __uint_as_float(d0[c + 0]) + bb[c + 0];
                o.y = __uint_as_float(d0[c + 1]) + bb[c + 1];
                o.z = __uint_as_float(d0[c + 2]) + bb[c + 2];
                o.w = __uint_as_float(d0[c + 3]) + bb[c + 3];
                epi_store4<RELU, OUTH>(C, cb + c, o);
            }
#pragma unroll
            for (int c = 0; c < 32; c += 4) {
                float4 o;
                o.x = __uint_as_float(d1[c + 0]) + bb[32 + c + 0];
                o.y = __uint_as_float(d1[c + 1]) + bb[32 + c + 1];
                o.z = __uint_as_float(d1[c + 2]) + bb[32 + c + 2];
                o.w = __uint_as_float(d1[c + 3]) + bb[32 + c + 3];
                epi_store4<RELU, OUTH>(C, cb + 32 + c, o);
            }
            __syncthreads();
        }
    }

    __syncthreads();
    if (tid == 0) { MBARRIER_INVAL(MBAR0); MBARRIER_INVAL(MBAR1); }
    __syncthreads();
    if (wid == 0) TCGEN05_DEALLOC(tmem, 128);

#else  // SIMT fallback
    float (*As)[132] = (float(*)[132])(smem);
    float (*Bs)[132] = (float(*)[132])(smem + 64 * 132 * 4);
    int ty = (tid >> 4) * 8;
    int tx = (tid & 15) * 8;

    for (int m = cid; m < MT_TILES; m += CPC) {
        int brow = m * 128;
        float acc[8][8];
#pragma unroll
        for (int i = 0; i < 8; i++)
#pragma unroll
            for (int j = 0; j < 8; j++) acc[i][j] = 0.f;

        for (int kt = 0; kt < 4; kt++) {
            __syncthreads();
#pragma unroll
            for (int i = 0; i < 4; i++) {
                int row = i * 32 + lr;
                size_t aro = (size_t)(brow + row) * K + kt * 64 + c16 * 8;
                float4 x0 = *(const float4*)(A + aro);
                float4 x1 = *(const float4*)(A + aro + 4);
                if (A2) {
                    float4 e0 = *(const float4*)(A2 + aro);
                    float4 e1 = *(const float4*)(A2 + aro + 4);
                    x0.x += e0.x; x0.y += e0.y; x0.z += e0.z; x0.w += e0.w;
                    x1.x += e1.x; x1.y += e1.y; x1.z += e1.z; x1.w += e1.w;
                }
                float av[8] = {x0.x, x0.y, x0.z, x0.w, x1.x, x1.y, x1.z, x1.w};
                size_t bro = (size_t)(bcol + row) * K + kt * 64 + c16 * 8;
#pragma unroll
                for (int j = 0; j < 8; j++) {
                    As[c16 * 8 + j][row] = av[j];
                    Bs[c16 * 8 + j][row] = __half2float(WH[bro + j]) + __half2float(WL[bro + j]);
                }
            }
            __syncthreads();
#pragma unroll 16
            for (int k = 0; k < 64; k++) {
                float av[8], bv[8];
#pragma unroll
                for (int i = 0; i < 8; i++) { av[i] = As[k][ty + i]; bv[i] = Bs[k][tx + i]; }
#pragma unroll
                for (int i = 0; i < 8; i++)
#pragma unroll
                    for (int j = 0; j < 8; j++)
                        acc[i][j] += av[i] * bv[j];
            }
        }
        int row = brow + ty;
        int cc  = bcol + tx;
#pragma unroll
        for (int i = 0; i < 8; i++)
#pragma unroll
            for (int j = 0; j < 8; j++) {
                float v = acc[i][j] + bias[cc + j];
                if (RELU) v = fmaxf(v, 0.f);
                if (OUTH) ((__half*)C)[(size_t)(row + i) * N + cc + j] = __float2half_rn(v);
                else      C[(size_t)(row + i) * N + cc + j] = v;
            }
        __syncthreads();
    }
#endif
}

// ---------------------------------------------------------------------------
// Fused weight transpose + fp16 split (all 6 types, 3 layers per launch)
// ---------------------------------------------------------------------------
__global__ void transplit_all(const float* __restrict__ Wval, const float* __restrict__ Woff,
                              const float* __restrict__ Wattn, const float* __restrict__ Wout,
                              const float* __restrict__ W1, const float* __restrict__ W2,
                              __half* __restrict__ wth, __half* __restrict__ wtl,
                              int layer0) {
    int type  = blockIdx.y;
    int layer = layer0 + blockIdx.z;
    const float* W; int K, N, off;
    switch (type) {
        case 0: W = Wval  + (size_t)layer * 65536;  K = 256;  N = 256;  off = WT_VAL;  break;
        case 1: W = Woff  + (size_t)layer * 65536;  K = 256;  N = 256;  off = WT_OFF;  break;
        case 2: W = Wattn + (size_t)layer * 32768;  K = 256;  N = 128;  off = WT_ATTN; break;
        case 3: W = Wout  + (size_t)layer * 65536;  K = 256;  N = 256;  off = WT_OUT;  break;
        case 4: W = W1    + (size_t)layer * 262144; K = 256;  N = 1024; off = WT_W1;   break;
        default: W = W2   + (size_t)layer * 262144; K = 1024; N = 256;  off = WT_W2;   break;
    }
    int tK = K >> 5, tN = N >> 5;
    int t = blockIdx.x;
    if (t >= tK * tN) return;
    int k0 = (t % tK) * 32, n0 = (t / tK) * 32;

    __shared__ float tile[32][33];
    tile[threadIdx.y][threadIdx.x] = W[(size_t)(k0 + threadIdx.y) * N + n0 + threadIdx.x];
    __syncthreads();
    float v = tile[threadIdx.x][threadIdx.y];
    __half h = __float2half_rn(v);
    size_t o = (size_t)layer * WT_LAYER + off + (size_t)(n0 + threadIdx.y) * K + k0 + threadIdx.x;
    wth[o] = h;
    wtl[o] = __float2half_rn(v - __half2float(h));
}

// Bias concat: g_biasoa[l][0..255]=boff, [256..383]=battn
__global__ void biascat_kernel(const float* __restrict__ boff,
                               const float* __restrict__ battn,
                               float* __restrict__ dst) {
    int l = blockIdx.x, j = threadIdx.x;
    dst[l * 384 + j] = (j < 256) ? boff[l * 256 + j] : battn[l * 128 + j - 256];
}

// ---------------------------------------------------------------------------
// Flatten pair of levels: src [B, D, h, w] -> out [B, S, D]; pos + level_embed
// ---------------------------------------------------------------------------
__global__ void flatten_pair(const float* __restrict__ sA, const float* __restrict__ pA,
                             int hwA, int stA, int lvA,
                             const float* __restrict__ sB, const float* __restrict__ pB,
                             int hwB, int stB, int lvB,
                             const float* __restrict__ lemb,
                             float* __restrict__ out, float* __restrict__ posout) {
    __shared__ float ts[32][33];
    __shared__ float tp[32][33];
    int px = blockIdx.x;
    const float *src, *pos; int hw, start, level, p0;
    int tA = hwA >> 5;
    if (px < tA) { src = sA; pos = pA; hw = hwA; start = stA; level = lvA; p0 = px * 32; }
    else         { src = sB; pos = pB; hw = hwB; start = stB; level = lvB; p0 = (px - tA) * 32; }

    int b  = blockIdx.z;
    int d0 = blockIdx.y * 32;
    int tx = threadIdx.x, ty = threadIdx.y;

    const float* sp = src + ((size_t)b * D_MODEL + d0 + ty) * hw + p0;
    const float* pp = pos + ((size_t)b * D_MODEL + d0 + ty) * hw + p0;
    ts[ty][tx] = sp[tx];
    tp[ty][tx] = pp[tx];
    __syncthreads();

    int d = d0 + tx;
    float le = lemb[level * D_MODEL + d];
    size_t srow = (size_t)b * S_TOTAL + start + p0 + ty;
    out[srow * D_MODEL + d]    = ts[tx][ty];
    posout[srow * D_MODEL + d] = tp[tx][ty] + le;
}

// ---------------------------------------------------------------------------
// Residual + LayerNorm: out = LN(x + r) * gamma + beta. One warp per row.
// ---------------------------------------------------------------------------
__global__ void resid_ln_kernel(const float* __restrict__ X, const float* __restrict__ R,
                                const float* __restrict__ g, const float* __restrict__ bt,
                                float* __restrict__ O, int rows) {
    int warp = (blockIdx.x * blockDim.x + threadIdx.x) >> 5;
    int lane = threadIdx.x & 31;
    if (warp >= rows) return;
    const float* xr = X + (size_t)warp * D_MODEL;
    const float* rr = R + (size_t)warp * D_MODEL;

    float v[8];
    float s = 0.f, s2 = 0.f;
#pragma unroll
    for (int u = 0; u < 2; u++) {
        float4 a = *(const float4*)(xr + lane * 4 + u * 128);
        float4 c = *(const float4*)(rr + lane * 4 + u * 128);
        float t0 = a.x + c.x, t1 = a.y + c.y, t2 = a.z + c.z, t3 = a.w + c.w;
        v[u * 4 + 0] = t0; v[u * 4 + 1] = t1; v[u * 4 + 2] = t2; v[u * 4 + 3] = t3;
        s += t0 + t1 + t2 + t3;
        s2 += t0 * t0 + t1 * t1 + t2 * t2 + t3 * t3;
    }
#pragma unroll
    for (int o = 16; o > 0; o >>= 1) {
        s  += __shfl_xor_sync(0xffffffffu, s, o);
        s2 += __shfl_xor_sync(0xffffffffu, s2, o);
    }
    float mean = s * (1.f / D_MODEL);
    float var  = s2 * (1.f / D_MODEL) - mean * mean;
    float inv  = rsqrtf(var + 1e-5f);
#pragma unroll
    for (int u = 0; u < 2; u++) {
        int d = lane * 4 + u * 128;
        float4 o4;
        o4.x = (v[u * 4 + 0] - mean) * inv * g[d + 0] + bt[d + 0];
        o4.y = (v[u * 4 + 1] - mean) * inv * g[d + 1] + bt[d + 1];
        o4.z = (v[u * 4 + 2] - mean) * inv * g[d + 2] + bt[d + 2];
        o4.w = (v[u * 4 + 3] - mean) * inv * g[d + 3] + bt[d + 3];
        *(float4*)(O + (size_t)warp * D_MODEL + d) = o4;
    }
}

// ---------------------------------------------------------------------------
// Deformable sampling, fp16 values. One warp per (token, head).
// Lanes 0..15 compute the 16 samples' taps into a smem table; then lanes
// (tap = lane>>3, ch4 = lane&7) gather uint2 (4 halves) and accumulate;
// cross-tap reduction via shfl; lanes 0..7 store float4.
// ---------------------------------------------------------------------------
__constant__ int c_lw[4]     = {128, 64, 32, 16};
__constant__ int c_lstart[4] = {0, 16384, 20480, 21504};

__global__ void sample_kernel(const __half* __restrict__ Valh,
                              const float* __restrict__ OA,
                              float* __restrict__ Samp) {
    __shared__ int2 tab[8][16][4];
    int gw   = (blockIdx.x * blockDim.x + threadIdx.x) >> 5;
    int lane = threadIdx.x & 31;
    int wpb  = threadIdx.x >> 5;
    if (gw >= M_TOT * NH) return;
    int h   = gw & 7;
    int tok = gw >> 3;
    int s   = tok % S_TOTAL;
    int b   = tok / S_TOTAL;

    int wt, st, sh;
    if (s < 16384)      { wt = 128; st = 0;     sh = 7; }
    else if (s < 20480) { wt = 64;  st = 16384; sh = 6; }
    else if (s < 21504) { wt = 32;  st = 20480; sh = 5; }
    else                { wt = 16;  st = 21504; sh = 4; }
    int sl = s - st;
    int iy = sl >> sh;
    int ix = sl - (iy << sh);
    float refx = (ix + 0.5f) / (float)wt;
    float refy = (iy + 0.5f) / (float)wt;

    size_t rb = (size_t)tok;

    float lv = (lane < 16) ? OA[rb * 384 + 256 + h * 16 + lane] : -1e30f;
    float m = lv;
#pragma unroll
    for (int o = 8; o > 0; o >>= 1) m = fmaxf(m, __shfl_xor_sync(0xffffffffu, m, o));
    float e = (lane < 16) ? expf(lv - m) : 0.f;
    float ssum = e;
#pragma unroll
    for (int o = 8; o > 0; o >>= 1) ssum += __shfl_xor_sync(0xffffffffu, ssum, o);
    float aw = e / ssum;

    if (lane < 16) {
        int l   = lane >> 2;
        int wl  = c_lw[l];
        int stl = c_lstart[l];
        float ox = OA[rb * 384 + (size_t)(h * 16 + lane) * 2 + 0];
        float oy = OA[rb * 384 + (size_t)(h * 16 + lane) * 2 + 1];
        float x = refx * (float)wl + ox - 0.5f;
        float y = refy * (float)wl + oy - 0.5f;
        float xf = floorf(x), yf = floorf(y);
        float lx = x - xf, ly = y - yf;
        int x0 = (int)xf, y0 = (int)yf;
        int x1 = x0 + 1, y1 = y0 + 1;
        bool okx0 = (x0 >= 0) & (x0 < wl);
        bool okx1 = (x1 >= 0) & (x1 < wl);
        bool oky0 = (y0 >= 0) & (y0 < wl);
        bool oky1 = (y1 >= 0) & (y1 < wl);
        int cx0 = min(max(x0, 0), wl - 1), cx1 = min(max(x1, 0), wl - 1);
        int cy0 = min(max(y0, 0), wl - 1), cy1 = min(max(y1, 0), wl - 1);
        float w0 = (1.f - lx) * (1.f - ly) * aw * ((okx0 && oky0) ? 1.f : 0.f);
        float w1 = lx * (1.f - ly) * aw * ((okx1 && oky0) ? 1.f : 0.f);
        float w2 = (1.f - lx) * ly * aw * ((okx0 && oky1) ? 1.f : 0.f);
        float w3 = lx * ly * aw * ((okx1 && oky1) ? 1.f : 0.f);
        tab[wpb][lane][0] = make_int2(stl + cy0 * wl + cx0, __float_as_int(w0));
        tab[wpb][lane][1] = make_int2(stl + cy0 * wl + cx1, __float_as_int(w1));
        tab[wpb][lane][2] = make_int2(stl + cy1 * wl + cx0, __float_as_int(w2));
        tab[wpb][lane][3] = make_int2(stl + cy1 * wl + cx1, __float_as_int(w3));
    }
    __syncwarp();

    int t   = lane >> 3;
    int ch4 = lane & 7;
    const __half* vb = Valh + (size_t)b * S_TOTAL * 256 + h * 32 + ch4 * 4;
    float4 acc = make_float4(0.f, 0.f, 0.f, 0.f);
#pragma unroll
    for (int j = 0; j < 16; j++) {
        int2 ee = tab[wpb][j][t];
        uint2 u = *(const uint2*)(vb + (size_t)ee.x * 256);
        __half2 p0 = *(__half2*)&u.x;
        __half2 p1 = *(__half2*)&u.y;
        float2 f0 = __half22float2(p0);
        float2 f1 = __half22float2(p1);
        float f = __int_as_float(ee.y);
        acc.x += f * f0.x; acc.y += f * f0.y;
        acc.z += f * f1.x; acc.w += f * f1.y;
    }
#pragma unroll
    for (int msk = 8; msk <= 16; msk <<= 1) {
        acc.x += __shfl_xor_sync(0xffffffffu, acc.x, msk);
        acc.y += __shfl_xor_sync(0xffffffffu, acc.y, msk);
        acc.z += __shfl_xor_sync(0xffffffffu, acc.z, msk);
        acc.w += __shfl_xor_sync(0xffffffffu, acc.w, msk);
    }
    if (lane < 8)
        ((float4*)(Samp + (size_t)tok * 256 + h * 32))[ch4] = acc;
}

// ---------------------------------------------------------------------------
// Host orchestration
// ---------------------------------------------------------------------------
extern "C" void kernel_launch(void* const* d_in, const int* in_sizes, int n_in,
                              void* d_out, int out_size) {
    const float* src[4];
    const float* posin[4];
    bool interleaved = (in_sizes[1] == in_sizes[0]);
    for (int l = 0; l < 4; l++) {
        if (interleaved) {
            src[l]   = (const float*)d_in[2 * l];
            posin[l] = (const float*)d_in[2 * l + 1];
        } else {
            src[l]   = (const float*)d_in[l];
            posin[l] = (const float*)d_in[4 + l];
        }
    }
    const float* lemb  = (const float*)d_in[8];
    const float* Woff  = (const float*)d_in[9];
    const float* boff  = (const float*)d_in[10];
    const float* Wattn = (const float*)d_in[11];
    const float* battn = (const float*)d_in[12];
    const float* Wval  = (const float*)d_in[13];
    const float* bval  = (const float*)d_in[14];
    const float* Wout  = (const float*)d_in[15];
    const float* bout  = (const float*)d_in[16];
    const float* ln1s  = (const float*)d_in[17];
    const float* ln1b  = (const float*)d_in[18];
    const float* W1    = (const float*)d_in[19];
    const float* b1    = (const float*)d_in[20];
    const float* W2    = (const float*)d_in[21];
    const float* b2    = (const float*)d_in[22];
    const float* ln2s  = (const float*)d_in[23];
    const float* ln2b  = (const float*)d_in[24];

    float* out = (float*)d_out;

    float *pos, *offawl, *samp, *tmp, *ffh, *biasoa;
    __half *valh, *wth, *wtl;
    cudaGetSymbolAddress((void**)&pos,    g_pos);
    cudaGetSymbolAddress((void**)&valh,   g_valh);
    cudaGetSymbolAddress((void**)&offawl, g_offawl);
    cudaGetSymbolAddress((void**)&samp,   g_samp);
    cudaGetSymbolAddress((void**)&tmp,    g_tmp);
    cudaGetSymbolAddress((void**)&ffh,    g_ffh);
    cudaGetSymbolAddress((void**)&biasoa, g_biasoa);
    cudaGetSymbolAddress((void**)&wth,    g_wth);
    cudaGetSymbolAddress((void**)&wtl,    g_wtl);

    cudaFuncSetAttribute(tc_gemm<0>,           cudaFuncAttributeMaxDynamicSharedMemorySize, TCG_SMEM);
    cudaFuncSetAttribute((tc_gemm_pers<0,0>),  cudaFuncAttributeMaxDynamicSharedMemorySize, PERS_SMEM);
    cudaFuncSetAttribute((tc_gemm_pers<0,1>),  cudaFuncAttributeMaxDynamicSharedMemorySize, PERS_SMEM);
    cudaFuncSetAttribute((tc_gemm_pers<1,0>),  cudaFuncAttributeMaxDynamicSharedMemorySize, PERS_SMEM);

    // Prologue: 5 launches
    transplit_all<<<dim3(256, 6, 3), dim3(32, 32)>>>(Wval, Woff, Wattn, Wout, W1, W2,
                                                     wth, wtl, 0);
    transplit_all<<<dim3(256, 6, 3), dim3(32, 32)>>>(Wval, Woff, Wattn, Wout, W1, W2,
                                                     wth, wtl, 3);
    biascat_kernel<<<NLAYERS, 384>>>(boff, battn, biasoa);
    flatten_pair<<<dim3(16384/32 + 4096/32, 8, BATCH), dim3(32, 32)>>>(
        src[0], posin[0], 16384, 0, 0, src[1], posin[1], 4096, 16384, 1,
        lemb, out, pos);
    flatten_pair<<<dim3(1024/32 + 256/32, 8, BATCH), dim3(32, 32)>>>(
        src[2], posin[2], 1024, 20480, 2, src[3], posin[3], 256, 21504, 3,
        lemb, out, pos);

    for (int i = 0; i < NLAYERS; i++) {
        const __half* bh = wth + (size_t)i * WT_LAYER;
        const __half* bl = wtl + (size_t)i * WT_LAYER;
        // value (fp16 out) = out @ Wval + bval       (N=256: 2 cols x 74 CTAs)
        tc_gemm_pers<0,1><<<148, 256, PERS_SMEM>>>(out, nullptr, bh + WT_VAL, bl + WT_VAL,
                                                   bval + i * 256, (float*)valh, 256, 74);
        // [off|awl] = (out + pos) @ [Woff|Wattn] + [boff|battn]  (N=384: 3 cols x 49)
        tc_gemm_pers<0,0><<<147, 256, PERS_SMEM>>>(out, pos, bh + WT_OFF, bl + WT_OFF,
                                                   biasoa + i * 384, offawl, 384, 49);
        // deformable sampling (fp16 values)
        sample_kernel<<<M_TOT * NH / 8, 256>>>(valh, offawl, samp);
        // attn out = samp @ Wout + bout
        tc_gemm_pers<0,0><<<148, 256, PERS_SMEM>>>(samp, nullptr, bh + WT_OUT, bl + WT_OUT,
                                                   bout + i * 256, tmp, 256, 74);
        // out = LN(out + attn)
        resid_ln_kernel<<<(M_TOT + 7) / 8, 256>>>(tmp, out, ln1s + i * 256,
                                                  ln1b + i * 256, out, M_TOT);
        // h = relu(out @ W1 + b1)                    (N=1024: 8 cols x 18 CTAs)
        tc_gemm_pers<1,0><<<144, 256, PERS_SMEM>>>(out, nullptr, bh + WT_W1, bl + WT_W1,
                                                   b1 + i * 1024, ffh, 1024, 18);
        // ff = h @ W2 + b2                           (K=1024: streaming kernel)
        tc_gemm<0><<<dim3(M_TOT / 128, 2), 256, TCG_SMEM>>>(ffh, nullptr, bh + WT_W2, bl + WT_W2,
                                                            b2 + i * 256, tmp, M_TOT, 256, 1024);
        // out = LN(out + ff)
        resid_ln_kernel<<<(M_TOT + 7) / 8, 256>>>(tmp, out, ln2s + i * 256,
                                                  ln2b + i * 256, out, M_TOT);
    }
}

// round 12
// speedup vs baseline: 2.9053x; 1.0894x over previous
#include <cuda_runtime.h>
#include <cuda_fp16.h>
#include <math.h>
#include <stdint.h>

// ---------------------------------------------------------------------------
// MSDeformAttn transformer encoder (6 layers).
// K=256 GEMMs: persistent-B tcgen05 kind::f16 3-split (B resident in SMEM).
// fp16 activations for val / samp / ffh (A-side exact -> 2-MMA chunks).
// W2 (K=1024): streaming fp16-A kernel. sm_103a arch-feature guarded.
// D=256, NH=8, NL=4, NP=4, DH=32, DFF=1024, B=2, S=21760.
// ---------------------------------------------------------------------------

#define D_MODEL 256
#define NH 8
#define DFF 1024
#define NLAYERS 6
#define BATCH 2
#define S_TOTAL 21760
#define M_TOT (BATCH * S_TOTAL)   // 43520 rows; 340 M-tiles of 128

#if defined(__CUDA_ARCH_FEAT_SM103_ALL) || defined(__CUDA_ARCH_FEAT_SM100_ALL) || defined(__CUDA_ARCH_FEAT_SM101_ALL)
#define HAS_TCGEN05 1
#else
#define HAS_TCGEN05 0
#endif

// Scratch (allocation-free: __device__ globals)
__device__ float  g_pos[M_TOT * D_MODEL];
__device__ __half g_valh[M_TOT * D_MODEL];        // fp16 value tensor
__device__ float  g_offawl[M_TOT * 384];          // [off 256 | awl 128] per row
__device__ __half g_samph[M_TOT * D_MODEL];       // fp16 sampled tensor
__device__ float  g_tmp[M_TOT * D_MODEL];
__device__ __half g_ffh[M_TOT * DFF];             // fp16 FF hidden
__device__ float  g_biasoa[NLAYERS * 384];        // [boff 256 | battn 128]

// Transposed + fp16-split weights: per layer 753664 elements
#define WT_LAYER 753664
__device__ __half g_wth[NLAYERS * WT_LAYER];
__device__ __half g_wtl[NLAYERS * WT_LAYER];
#define WT_VAL  0
#define WT_OFF  65536      // rows 0..255 of combined [384,256] (attn follows)
#define WT_ATTN 131072
#define WT_OUT  163840
#define WT_W1   229376
#define WT_W2   491520

// ---------------------------------------------------------------------------
// PTX helpers
// ---------------------------------------------------------------------------
__device__ __forceinline__ uint32_t elect_one_pred() {
    uint32_t pred;
    asm volatile(
        "{\n\t.reg .pred p;\n\telect.sync _|p, 0xFFFFFFFF;\n\t"
        "selp.b32 %0, 1, 0, p;\n\t}" : "=r"(pred));
    return pred;
}
__device__ __forceinline__ uint32_t smem_to_u32(const void* p) {
    uint32_t a;
    asm("{ .reg .u64 t; cvta.to.shared.u64 t, %1; cvt.u32.u64 %0, t; }"
        : "=r"(a) : "l"(p));
    return a;
}

#define TCGEN05_ALLOC(addr, n) \
    asm volatile("tcgen05.alloc.cta_group::1.sync.aligned.shared::cta.b32 [%0], %1;" \
                 :: "r"((uint32_t)(addr)), "r"((uint32_t)(n)) : "memory")
#define TCGEN05_DEALLOC(tmem, n) \
    asm volatile("tcgen05.dealloc.cta_group::1.sync.aligned.b32 %0, %1;" \
                 :: "r"(tmem), "r"((uint32_t)(n)))
#define TCGEN05_RELINQ() \
    asm volatile("tcgen05.relinquish_alloc_permit.cta_group::1.sync.aligned;")
#define TCGEN05_COMMIT(mbar) \
    asm volatile("tcgen05.commit.cta_group::1.mbarrier::arrive::one.shared::cluster.b64 [%0];" \
                 :: "r"((uint32_t)(mbar)) : "memory")
#define TCGEN05_FENCE_AFTER() \
    asm volatile("tcgen05.fence::after_thread_sync;" ::: "memory")
#define TCGEN05_FENCE_BEFORE() \
    asm volatile("tcgen05.fence::before_thread_sync;" ::: "memory")
#define TCGEN05_WAIT_LD() \
    asm volatile("tcgen05.wait::ld.sync.aligned;" ::: "memory")
#define FENCE_PROXY_ASYNC() \
    asm volatile("fence.proxy.async.shared::cta;" ::: "memory")
#define MBARRIER_INIT(mbar, cnt) \
    asm volatile("mbarrier.init.shared.b64 [%0], %1;" \
                 :: "r"((uint32_t)(mbar)), "r"((uint32_t)(cnt)) : "memory")
#define MBARRIER_INVAL(mbar) \
    asm volatile("mbarrier.inval.shared.b64 [%0];" :: "r"((uint32_t)(mbar)) : "memory")

#define MBARRIER_WAIT_PARITY(mbar, parity) do {                               \
    uint32_t _m = (uint32_t)(mbar);                                           \
    uint32_t _p = (uint32_t)(parity);                                         \
    asm volatile(                                                             \
        "{\n\t.reg .pred P1;\n\t"                                             \
        "WAIT_LOOP_%=:\n\t"                                                   \
        "mbarrier.try_wait.parity.acquire.cta.shared::cta.b64 P1, [%0], %1, 0x989680;\n\t" \
        "@P1 bra.uni WAIT_DONE_%=;\n\t"                                       \
        "bra.uni WAIT_LOOP_%=;\n\t"                                           \
        "WAIT_DONE_%=:\n\t}"                                                  \
        :: "r"(_m), "r"(_p) : "memory");                                      \
} while (0)

// fp16 SS MMA (fp32 accum), cta_group::1
#define TCGEN05_MMA_F16_SS(d, ad, bd, id, en) do {                            \
    uint32_t _e = (en) ? 1u : 0u; uint32_t _z = 0;                            \
    asm volatile(                                                             \
        "{\n\t.reg .pred p;\n\tsetp.ne.u32 p, %5, 0;\n\t"                     \
        "tcgen05.mma.cta_group::1.kind::f16 [%0], %1, %2, %3, {%4,%4,%4,%4}, p;\n\t}" \
        :: "r"(d), "l"(ad), "l"(bd), "r"(id), "r"(_z), "r"(_e) : "memory");   \
} while (0)

#define TCGEN05_LD32(r, addr)                                                 \
    asm volatile(                                                             \
        "tcgen05.ld.sync.aligned.32x32b.x32.b32 "                             \
        "{%0, %1, %2, %3, %4, %5, %6, %7, "                                   \
        " %8, %9, %10, %11, %12, %13, %14, %15, "                             \
        " %16, %17, %18, %19, %20, %21, %22, %23, "                           \
        " %24, %25, %26, %27, %28, %29, %30, %31}, [%32];"                    \
        : "=r"((r)[0]),  "=r"((r)[1]),  "=r"((r)[2]),  "=r"((r)[3]),          \
          "=r"((r)[4]),  "=r"((r)[5]),  "=r"((r)[6]),  "=r"((r)[7]),          \
          "=r"((r)[8]),  "=r"((r)[9]),  "=r"((r)[10]), "=r"((r)[11]),         \
          "=r"((r)[12]), "=r"((r)[13]), "=r"((r)[14]), "=r"((r)[15]),         \
          "=r"((r)[16]), "=r"((r)[17]), "=r"((r)[18]), "=r"((r)[19]),         \
          "=r"((r)[20]), "=r"((r)[21]), "=r"((r)[22]), "=r"((r)[23]),         \
          "=r"((r)[24]), "=r"((r)[25]), "=r"((r)[26]), "=r"((r)[27]),         \
          "=r"((r)[28]), "=r"((r)[29]), "=r"((r)[30]), "=r"((r)[31])          \
        : "r"(addr))

// SW128 K-major smem descriptor: layout=2, version=1, SBO=64, LBO=1
__device__ __forceinline__ uint64_t make_sw128_desc(uint32_t addr) {
    const uint64_t base = (uint64_t(2) << 61) | (uint64_t(1) << 46)
                        | (uint64_t(64) << 32) | (uint64_t(1) << 16);
    return base | ((uint64_t)(addr >> 4) & 0x3FFF);
}

#define SPLIT8(x0, x1, hi, lo) do {                                           \
    float _v[8] = {x0.x, x0.y, x0.z, x0.w, x1.x, x1.y, x1.z, x1.w};           \
    _Pragma("unroll")                                                         \
    for (int _j = 0; _j < 4; _j++) {                                          \
        __half hx = __float2half_rn(_v[2*_j]);                                \
        __half hy = __float2half_rn(_v[2*_j+1]);                              \
        __half lx = __float2half_rn(_v[2*_j]   - __half2float(hx));           \
        __half ly = __float2half_rn(_v[2*_j+1] - __half2float(hy));           \
        __half2 hp = __halves2half2(hx, hy);                                  \
        __half2 lp = __halves2half2(lx, ly);                                  \
        (hi)[_j] = *(uint32_t*)&hp;                                           \
        (lo)[_j] = *(uint32_t*)&lp;                                           \
    }                                                                         \
} while (0)

#define TCG_IDESC 0x8200010u

// Epilogue store of 4 consecutive cols (float or half)
template <int RELU, int OUTH>
__device__ __forceinline__ void epi_store4(float* Cf, size_t idx, float4 o) {
    if (RELU) {
        o.x = fmaxf(o.x, 0.f); o.y = fmaxf(o.y, 0.f);
        o.z = fmaxf(o.z, 0.f); o.w = fmaxf(o.w, 0.f);
    }
    if (OUTH) {
        __half2 h0 = __halves2half2(__float2half_rn(o.x), __float2half_rn(o.y));
        __half2 h1 = __halves2half2(__float2half_rn(o.z), __float2half_rn(o.w));
        uint2 u; u.x = *(uint32_t*)&h0; u.y = *(uint32_t*)&h1;
        *(uint2*)((__half*)Cf + idx) = u;
    } else {
        *(float4*)(Cf + idx) = o;
    }
}

// ---------------------------------------------------------------------------
// Streaming GEMM, fp16 A (exact): used for W2 (K=1024, A = ffh half).
// Per K64 chunk: 2 MMAs (A*BH + A*BL). Stage = AH 16K + BH 16K + BL 16K.
// ---------------------------------------------------------------------------
#define HOFF_AH 0
#define HOFF_BH 16384
#define HOFF_BL 32768
#define HSTAGE  49152
#define TCGH_SMEM (1024 + 2 * HSTAGE)   // 99328

template <int RELU>
__global__ __launch_bounds__(256, 1)
void tc_gemm_h(const __half* __restrict__ A,
               const __half* __restrict__ WH, const __half* __restrict__ WL,
               const float* __restrict__ bias, float* __restrict__ C,
               int M, int N, int K) {
    extern __shared__ char smem[];
    const int tid  = threadIdx.x;
    const int brow = blockIdx.x * 128;
    const int bcol = blockIdx.y * 128;

    const int lr = tid >> 3;
    const int c8 = (tid & 7) * 8;
    const __half* Ab  = A  + (size_t)(brow + lr) * K + c8;
    const __half* BHb = WH + (size_t)(bcol + lr) * K + c8;
    const __half* BLb = WL + (size_t)(bcol + lr) * K + c8;
    const int KT = K >> 6;

    uint4 ua[4], bh[4], bl[4];

#define HLDG_TILE(kt) do {                                                    \
    int _k = (kt) * 64;                                                       \
    _Pragma("unroll")                                                         \
    for (int i = 0; i < 4; i++) {                                             \
        size_t ro = (size_t)(i * 32) * K + _k;                                \
        ua[i] = *(const uint4*)(Ab + ro);                                     \
        bh[i] = *(const uint4*)(BHb + ro);                                    \
        bl[i] = *(const uint4*)(BLb + ro);                                    \
    }                                                                         \
} while (0)

#if HAS_TCGEN05
    const uint32_t sbase = smem_to_u32(smem);
    const int wid  = tid >> 5;
    const int lane = tid & 31;

    const uint32_t TMEMP = sbase;
    const uint32_t MBAR0 = sbase + 8;
    const uint32_t MBAR1 = sbase + 16;
    const uint32_t STG0  = sbase + 1024;

    if (wid == 0) TCGEN05_ALLOC(TMEMP, 128);
    if (tid == 0) { MBARRIER_INIT(MBAR0, 1); MBARRIER_INIT(MBAR1, 1); }
    __syncthreads();
    uint32_t tmem;
    asm volatile("ld.shared.b32 %0, [%1];" : "=r"(tmem) : "r"(TMEMP));
    if (wid == 0) TCGEN05_RELINQ();

    uint32_t swoff[4];
#pragma unroll
    for (int i = 0; i < 4; i++) {
        uint32_t off = (uint32_t)(i * 32 + lr) * 128 + (tid & 7) * 16;
        swoff[i] = off ^ ((off >> 3) & 0x70);
    }

    int ph0 = 0, ph1 = 0;

#define HSTS_TILE(stoff) do {                                                 \
    char* _sb = smem + 1024 + (stoff);                                        \
    _Pragma("unroll")                                                         \
    for (int i = 0; i < 4; i++) {                                             \
        *(uint4*)(_sb + HOFF_AH + swoff[i]) = ua[i];                          \
        *(uint4*)(_sb + HOFF_BH + swoff[i]) = bh[i];                          \
        *(uint4*)(_sb + HOFF_BL + swoff[i]) = bl[i];                          \
    }                                                                         \
} while (0)

    HLDG_TILE(0);
    HSTS_TILE(0);
    FENCE_PROXY_ASYNC();
    __syncthreads();

    for (int kt = 0; kt < KT; kt++) {
        int s = kt & 1;
        bool have_next = (kt + 1 < KT);
        if (have_next) HLDG_TILE(kt + 1);

        if (wid == 0) {
            if (elect_one_pred()) {
                uint32_t sb = STG0 + s * HSTAGE;
                uint64_t dah = make_sw128_desc(sb + HOFF_AH);
                uint64_t dbh = make_sw128_desc(sb + HOFF_BH);
                uint64_t dbl = make_sw128_desc(sb + HOFF_BL);
#pragma unroll
                for (int ks = 0; ks < 4; ks++) {
                    TCGEN05_MMA_F16_SS(tmem, dah + ks * 2, dbh + ks * 2,
                                       TCG_IDESC, (kt > 0) || (ks > 0));
                    TCGEN05_MMA_F16_SS(tmem, dah + ks * 2, dbl + ks * 2,
                                       TCG_IDESC, 1);
                }
                TCGEN05_COMMIT(s == 0 ? MBAR0 : MBAR1);
            }
        }

        if (have_next) {
            int ns = s ^ 1;
            if (kt >= 1) {
                if (ns == 0) { MBARRIER_WAIT_PARITY(MBAR0, ph0); ph0 ^= 1; }
                else         { MBARRIER_WAIT_PARITY(MBAR1, ph1); ph1 ^= 1; }
            }
            HSTS_TILE(ns * HSTAGE);
            FENCE_PROXY_ASYNC();
            __syncthreads();
        }
    }

    if (((KT - 1) & 1) == 0) { MBARRIER_WAIT_PARITY(MBAR0, ph0); }
    else                     { MBARRIER_WAIT_PARITY(MBAR1, ph1); }
    TCGEN05_FENCE_AFTER();

    {
        int colbase = (wid >> 2) * 64;
        uint32_t d0[32], d1[32];
        TCGEN05_LD32(d0, tmem + colbase);
        TCGEN05_LD32(d1, tmem + colbase + 32);
        TCGEN05_WAIT_LD();
        TCGEN05_FENCE_BEFORE();

        int r = brow + (wid & 3) * 32 + lane;
        size_t base = (size_t)r * N + bcol + colbase;
        const float* bb = bias + bcol + colbase;
#pragma unroll
        for (int c = 0; c < 32; c += 4) {
            float4 o;
            o.x = __uint_as_float(d0[c + 0]) + bb[c + 0];
            o.y = __uint_as_float(d0[c + 1]) + bb[c + 1];
            o.z = __uint_as_float(d0[c + 2]) + bb[c + 2];
            o.w = __uint_as_float(d0[c + 3]) + bb[c + 3];
            epi_store4<RELU, 0>(C, base + c, o);
        }
#pragma unroll
        for (int c = 0; c < 32; c += 4) {
            float4 o;
            o.x = __uint_as_float(d1[c + 0]) + bb[32 + c + 0];
            o.y = __uint_as_float(d1[c + 1]) + bb[32 + c + 1];
            o.z = __uint_as_float(d1[c + 2]) + bb[32 + c + 2];
            o.w = __uint_as_float(d1[c + 3]) + bb[32 + c + 3];
            epi_store4<RELU, 0>(C, base + 32 + c, o);
        }
    }

    __syncthreads();
    if (tid == 0) { MBARRIER_INVAL(MBAR0); MBARRIER_INVAL(MBAR1); }
    __syncthreads();
    if (wid == 0) TCGEN05_DEALLOC(tmem, 128);

#else  // SIMT fallback
    float (*As)[132] = (float(*)[132])(smem);
    float (*Bs)[132] = (float(*)[132])(smem + 64 * 132 * 4);

    int ty = (tid >> 4) * 8;
    int tx = (tid & 15) * 8;

    float acc[8][8];
#pragma unroll
    for (int i = 0; i < 8; i++)
#pragma unroll
        for (int j = 0; j < 8; j++) acc[i][j] = 0.f;

    for (int kt = 0; kt < KT; kt++) {
        HLDG_TILE(kt);
        __syncthreads();
#pragma unroll
        for (int i = 0; i < 4; i++) {
            int r = i * 32 + lr;
            const __half* ha = (const __half*)&ua[i];
            const __half* hh = (const __half*)&bh[i];
            const __half* ll = (const __half*)&bl[i];
#pragma unroll
            for (int j = 0; j < 8; j++) {
                As[c8 + j][r] = __half2float(ha[j]);
                Bs[c8 + j][r] = __half2float(hh[j]) + __half2float(ll[j]);
            }
        }
        __syncthreads();
#pragma unroll 16
        for (int k = 0; k < 64; k++) {
            float av[8], bv[8];
#pragma unroll
            for (int i = 0; i < 8; i++) { av[i] = As[k][ty + i]; bv[i] = Bs[k][tx + i]; }
#pragma unroll
            for (int i = 0; i < 8; i++)
#pragma unroll
                for (int j = 0; j < 8; j++)
                    acc[i][j] += av[i] * bv[j];
        }
    }

    int row = brow + ty;
    int col = bcol + tx;
#pragma unroll
    for (int i = 0; i < 8; i++) {
#pragma unroll
        for (int j = 0; j < 8; j++) {
            float v = acc[i][j] + bias[col + j];
            if (RELU) v = fmaxf(v, 0.f);
            C[(size_t)(row + i) * N + col + j] = v;
        }
    }
#endif
}

// ---------------------------------------------------------------------------
// Persistent-B GEMM for K=256 (proven structure).
// OUTH=1 emits __half output. AF16=1: A is __half (exact, 2-MMA chunks).
// ---------------------------------------------------------------------------
#define PERS_SMEM   197632   // AF16=0: 1024 hdr + 131072 B + 2x32768 A
#define PERS_SMEM_H 164864   // AF16=1: 1024 hdr + 131072 B + 2x16384 A
#define MT_TILES (M_TOT / 128)   // 340

template <int RELU, int OUTH, int AF16>
__global__ __launch_bounds__(256, 1)
void tc_gemm_pers(const void* __restrict__ Av, const float* __restrict__ A2,
                  const __half* __restrict__ WH, const __half* __restrict__ WL,
                  const float* __restrict__ bias, float* __restrict__ C,
                  int N, int CPC) {
    extern __shared__ char smem[];
    const int tid = threadIdx.x;
    const int K = 256;
    const int col = blockIdx.x / CPC;
    const int cid = blockIdx.x % CPC;
    const int bcol = col * 128;
    constexpr int ASTAGE = AF16 ? 16384 : 32768;

    const int lr  = tid >> 3;
    const int c16 = tid & 7;
    const uint32_t swr = (uint32_t)lr * 128 + (uint32_t)((c16 ^ (lr & 7)) * 16);

#if HAS_TCGEN05
    const uint32_t sbase = smem_to_u32(smem);
    const int wid = tid >> 5, lane = tid & 31;
    const uint32_t TMEMP = sbase;
    const uint32_t MBAR0 = sbase + 8;
    const uint32_t MBAR1 = sbase + 16;
    const uint32_t BH_S  = sbase + 1024;
    const uint32_t BL_S  = BH_S + 65536;
    const uint32_t AST   = BL_S + 65536;

    if (wid == 0) TCGEN05_ALLOC(TMEMP, 128);
    if (tid == 0) { MBARRIER_INIT(MBAR0, 1); MBARRIER_INIT(MBAR1, 1); }
    __syncthreads();
    uint32_t tmem;
    asm volatile("ld.shared.b32 %0, [%1];" : "=r"(tmem) : "r"(TMEMP));
    if (wid == 0) TCGEN05_RELINQ();

    // Load resident B hi/lo: 4 K64 sub-tiles of 16KB per plane
    {
        const __half* BHb = WH + (size_t)(bcol + lr) * K + c16 * 8;
        const __half* BLb = WL + (size_t)(bcol + lr) * K + c16 * 8;
#pragma unroll
        for (int kt = 0; kt < 4; kt++) {
#pragma unroll
            for (int i = 0; i < 4; i++) {
                size_t ro = (size_t)(i * 32) * K + kt * 64;
                uint32_t so = (uint32_t)kt * 16384 + swr + (uint32_t)i * 4096;
                *(uint4*)(smem + 1024 + so)         = *(const uint4*)(BHb + ro);
                *(uint4*)(smem + 1024 + 65536 + so) = *(const uint4*)(BLb + ro);
            }
        }
    }
    FENCE_PROXY_ASYNC();
    __syncthreads();

    int g = 0;
    for (int m = cid; m < MT_TILES; m += CPC) {
        const int brow = m * 128;
        const float*  Ab  = AF16 ? (const float*)0
                                 : (const float*)Av + (size_t)(brow + lr) * K + c16 * 8;
        const __half* Ahb = AF16 ? (const __half*)Av + (size_t)(brow + lr) * K + c16 * 8
                                 : (const __half*)0;
        const float*  A2b = (!AF16 && A2) ? A2 + (size_t)(brow + lr) * K + c16 * 8
                                          : (const float*)0;

#pragma unroll 1
        for (int kt = 0; kt < 4; kt++, g++) {
            const int s = g & 1;
            float4 a0[4], a1[4];
            uint4  ua[4];
            if (AF16) {
#pragma unroll
                for (int i = 0; i < 4; i++)
                    ua[i] = *(const uint4*)(Ahb + (size_t)(i * 32) * K + kt * 64);
            } else {
#pragma unroll
                for (int i = 0; i < 4; i++) {
                    size_t ro = (size_t)(i * 32) * K + kt * 64;
                    a0[i] = *(const float4*)(Ab + ro);
                    a1[i] = *(const float4*)(Ab + ro + 4);
                    if (A2b) {
                        float4 e0 = *(const float4*)(A2b + ro);
                        float4 e1 = *(const float4*)(A2b + ro + 4);
                        a0[i].x += e0.x; a0[i].y += e0.y; a0[i].z += e0.z; a0[i].w += e0.w;
                        a1[i].x += e1.x; a1[i].y += e1.y; a1[i].z += e1.z; a1[i].w += e1.w;
                    }
                }
            }
            if (g >= 2) {
                MBARRIER_WAIT_PARITY(s ? MBAR1 : MBAR0, ((g >> 1) - 1) & 1);
            }
            char* sb = smem + 1024 + 131072 + s * ASTAGE;
            if (AF16) {
#pragma unroll
                for (int i = 0; i < 4; i++)
                    *(uint4*)(sb + swr + i * 4096) = ua[i];
            } else {
#pragma unroll
                for (int i = 0; i < 4; i++) {
                    uint32_t ah[4], al[4];
                    SPLIT8(a0[i], a1[i], ah, al);
                    *(uint4*)(sb + swr + i * 4096)         = make_uint4(ah[0], ah[1], ah[2], ah[3]);
                    *(uint4*)(sb + 16384 + swr + i * 4096) = make_uint4(al[0], al[1], al[2], al[3]);
                }
            }
            FENCE_PROXY_ASYNC();
            __syncthreads();

            if (wid == 0) {
                if (elect_one_pred()) {
                    uint64_t dah = make_sw128_desc(AST + s * ASTAGE);
                    uint64_t dbh = make_sw128_desc(BH_S + kt * 16384);
                    uint64_t dbl = make_sw128_desc(BL_S + kt * 16384);
#pragma unroll
                    for (int ks = 0; ks < 4; ks++) {
                        TCGEN05_MMA_F16_SS(tmem, dah + ks * 2, dbh + ks * 2,
                                           TCG_IDESC, (kt > 0) || (ks > 0));
                        TCGEN05_MMA_F16_SS(tmem, dah + ks * 2, dbl + ks * 2,
                                           TCG_IDESC, 1);
                        if (!AF16) {
                            uint64_t dal = make_sw128_desc(AST + s * ASTAGE + 16384);
                            TCGEN05_MMA_F16_SS(tmem, dal + ks * 2, dbh + ks * 2,
                                               TCG_IDESC, 1);
                        }
                    }
                    TCGEN05_COMMIT(s ? MBAR1 : MBAR0);
                }
            }
        }

        {
            int gl = g - 1;
            MBARRIER_WAIT_PARITY((gl & 1) ? MBAR1 : MBAR0, (gl >> 1) & 1);
            TCGEN05_FENCE_AFTER();

            int colbase = (wid >> 2) * 64;
            uint32_t d0[32], d1[32];
            TCGEN05_LD32(d0, tmem + colbase);
            TCGEN05_LD32(d1, tmem + colbase + 32);
            TCGEN05_WAIT_LD();
            TCGEN05_FENCE_BEFORE();

            int r = brow + (wid & 3) * 32 + lane;
            size_t cb = (size_t)r * N + bcol + colbase;
            const float* bb = bias + bcol + colbase;
#pragma unroll
            for (int c = 0; c < 32; c += 4) {
                float4 o;
                o.x = __uint_as_float(d0[c + 0]) + bb[c + 0];
                o.y = __uint_as_float(d0[c + 1]) + bb[c + 1];
                o.z = __uint_as_float(d0[c + 2]) + bb[c + 2];
                o.w = __uint_as_float(d0[c + 3]) + bb[c + 3];
                epi_store4<RELU, OUTH>(C, cb + c, o);
            }
#pragma unroll
            for (int c = 0; c < 32; c += 4) {
                float4 o;
                o.x = __uint_as_float(d1[c + 0]) + bb[32 + c + 0];
                o.y = __uint_as_float(d1[c + 1]) + bb[32 + c + 1];
                o.z = __uint_as_float(d1[c + 2]) + bb[32 + c + 2];
                o.w = __uint_as_float(d1[c + 3]) + bb[32 + c + 3];
                epi_store4<RELU, OUTH>(C, cb + 32 + c, o);
            }
            __syncthreads();
        }
    }

    __syncthreads();
    if (tid == 0) { MBARRIER_INVAL(MBAR0); MBARRIER_INVAL(MBAR1); }
    __syncthreads();
    if (wid == 0) TCGEN05_DEALLOC(tmem, 128);

#else  // SIMT fallback
    float (*As)[132] = (float(*)[132])(smem);
    float (*Bs)[132] = (float(*)[132])(smem + 64 * 132 * 4);
    int ty = (tid >> 4) * 8;
    int tx = (tid & 15) * 8;

    for (int m = cid; m < MT_TILES; m += CPC) {
        int brow = m * 128;
        float acc[8][8];
#pragma unroll
        for (int i = 0; i < 8; i++)
#pragma unroll
            for (int j = 0; j < 8; j++) acc[i][j] = 0.f;

        for (int kt = 0; kt < 4; kt++) {
            __syncthreads();
#pragma unroll
            for (int i = 0; i < 4; i++) {
                int row = i * 32 + lr;
                size_t aro = (size_t)(brow + row) * K + kt * 64 + c16 * 8;
                float av[8];
                if (AF16) {
                    const __half* Ah = (const __half*)Av;
#pragma unroll
                    for (int j = 0; j < 8; j++) av[j] = __half2float(Ah[aro + j]);
                } else {
                    const float* Af = (const float*)Av;
                    float4 x0 = *(const float4*)(Af + aro);
                    float4 x1 = *(const float4*)(Af + aro + 4);
                    if (A2) {
                        float4 e0 = *(const float4*)(A2 + aro);
                        float4 e1 = *(const float4*)(A2 + aro + 4);
                        x0.x += e0.x; x0.y += e0.y; x0.z += e0.z; x0.w += e0.w;
                        x1.x += e1.x; x1.y += e1.y; x1.z += e1.z; x1.w += e1.w;
                    }
                    av[0] = x0.x; av[1] = x0.y; av[2] = x0.z; av[3] = x0.w;
                    av[4] = x1.x; av[5] = x1.y; av[6] = x1.z; av[7] = x1.w;
                }
                size_t bro = (size_t)(bcol + row) * K + kt * 64 + c16 * 8;
#pragma unroll
                for (int j = 0; j < 8; j++) {
                    As[c16 * 8 + j][row] = av[j];
                    Bs[c16 * 8 + j][row] = __half2float(WH[bro + j]) + __half2float(WL[bro + j]);
                }
            }
            __syncthreads();
#pragma unroll 16
            for (int k = 0; k < 64; k++) {
                float av[8], bv[8];
#pragma unroll
                for (int i = 0; i < 8; i++) { av[i] = As[k][ty + i]; bv[i] = Bs[k][tx + i]; }
#pragma unroll
                for (int i = 0; i < 8; i++)
#pragma unroll
                    for (int j = 0; j < 8; j++)
                        acc[i][j] += av[i] * bv[j];
            }
        }
        int row = brow + ty;
        int cc  = bcol + tx;
#pragma unroll
        for (int i = 0; i < 8; i++)
#pragma unroll
            for (int j = 0; j < 8; j++) {
                float v = acc[i][j] + bias[cc + j];
                if (RELU) v = fmaxf(v, 0.f);
                if (OUTH) ((__half*)C)[(size_t)(row + i) * N + cc + j] = __float2half_rn(v);
                else      C[(size_t)(row + i) * N + cc + j] = v;
            }
        __syncthreads();
    }
#endif
}

// ---------------------------------------------------------------------------
// Fused weight transpose + fp16 split (all 6 types, 3 layers per launch)
// ---------------------------------------------------------------------------
__global__ void transplit_all(const float* __restrict__ Wval, const float* __restrict__ Woff,
                              const float* __restrict__ Wattn, const float* __restrict__ Wout,
                              const float* __restrict__ W1, const float* __restrict__ W2,
                              __half* __restrict__ wth, __half* __restrict__ wtl,
                              int layer0) {
    int type  = blockIdx.y;
    int layer = layer0 + blockIdx.z;
    const float* W; int K, N, off;
    switch (type) {
        case 0: W = Wval  + (size_t)layer * 65536;  K = 256;  N = 256;  off = WT_VAL;  break;
        case 1: W = Woff  + (size_t)layer * 65536;  K = 256;  N = 256;  off = WT_OFF;  break;
        case 2: W = Wattn + (size_t)layer * 32768;  K = 256;  N = 128;  off = WT_ATTN; break;
        case 3: W = Wout  + (size_t)layer * 65536;  K = 256;  N = 256;  off = WT_OUT;  break;
        case 4: W = W1    + (size_t)layer * 262144; K = 256;  N = 1024; off = WT_W1;   break;
        default: W = W2   + (size_t)layer * 262144; K = 1024; N = 256;  off = WT_W2;   break;
    }
    int tK = K >> 5, tN = N >> 5;
    int t = blockIdx.x;
    if (t >= tK * tN) return;
    int k0 = (t % tK) * 32, n0 = (t / tK) * 32;

    __shared__ float tile[32][33];
    tile[threadIdx.y][threadIdx.x] = W[(size_t)(k0 + threadIdx.y) * N + n0 + threadIdx.x];
    __syncthreads();
    float v = tile[threadIdx.x][threadIdx.y];
    __half h = __float2half_rn(v);
    size_t o = (size_t)layer * WT_LAYER + off + (size_t)(n0 + threadIdx.y) * K + k0 + threadIdx.x;
    wth[o] = h;
    wtl[o] = __float2half_rn(v - __half2float(h));
}

// Bias concat: g_biasoa[l][0..255]=boff, [256..383]=battn
__global__ void biascat_kernel(const float* __restrict__ boff,
                               const float* __restrict__ battn,
                               float* __restrict__ dst) {
    int l = blockIdx.x, j = threadIdx.x;
    dst[l * 384 + j] = (j < 256) ? boff[l * 256 + j] : battn[l * 128 + j - 256];
}

// ---------------------------------------------------------------------------
// Flatten pair of levels: src [B, D, h, w] -> out [B, S, D]; pos + level_embed
// ---------------------------------------------------------------------------
__global__ void flatten_pair(const float* __restrict__ sA, const float* __restrict__ pA,
                             int hwA, int stA, int lvA,
                             const float* __restrict__ sB, const float* __restrict__ pB,
                             int hwB, int stB, int lvB,
                             const float* __restrict__ lemb,
                             float* __restrict__ out, float* __restrict__ posout) {
    __shared__ float ts[32][33];
    __shared__ float tp[32][33];
    int px = blockIdx.x;
    const float *src, *pos; int hw, start, level, p0;
    int tA = hwA >> 5;
    if (px < tA) { src = sA; pos = pA; hw = hwA; start = stA; level = lvA; p0 = px * 32; }
    else         { src = sB; pos = pB; hw = hwB; start = stB; level = lvB; p0 = (px - tA) * 32; }

    int b  = blockIdx.z;
    int d0 = blockIdx.y * 32;
    int tx = threadIdx.x, ty = threadIdx.y;

    const float* sp = src + ((size_t)b * D_MODEL + d0 + ty) * hw + p0;
    const float* pp = pos + ((size_t)b * D_MODEL + d0 + ty) * hw + p0;
    ts[ty][tx] = sp[tx];
    tp[ty][tx] = pp[tx];
    __syncthreads();

    int d = d0 + tx;
    float le = lemb[level * D_MODEL + d];
    size_t srow = (size_t)b * S_TOTAL + start + p0 + ty;
    out[srow * D_MODEL + d]    = ts[tx][ty];
    posout[srow * D_MODEL + d] = tp[tx][ty] + le;
}

// ---------------------------------------------------------------------------
// Residual + LayerNorm: out = LN(x + r) * gamma + beta. One warp per row.
// ---------------------------------------------------------------------------
__global__ void resid_ln_kernel(const float* __restrict__ X, const float* __restrict__ R,
                                const float* __restrict__ g, const float* __restrict__ bt,
                                float* __restrict__ O, int rows) {
    int warp = (blockIdx.x * blockDim.x + threadIdx.x) >> 5;
    int lane = threadIdx.x & 31;
    if (warp >= rows) return;
    const float* xr = X + (size_t)warp * D_MODEL;
    const float* rr = R + (size_t)warp * D_MODEL;

    float v[8];
    float s = 0.f, s2 = 0.f;
#pragma unroll
    for (int u = 0; u < 2; u++) {
        float4 a = *(const float4*)(xr + lane * 4 + u * 128);
        float4 c = *(const float4*)(rr + lane * 4 + u * 128);
        float t0 = a.x + c.x, t1 = a.y + c.y, t2 = a.z + c.z, t3 = a.w + c.w;
        v[u * 4 + 0] = t0; v[u * 4 + 1] = t1; v[u * 4 + 2] = t2; v[u * 4 + 3] = t3;
        s += t0 + t1 + t2 + t3;
        s2 += t0 * t0 + t1 * t1 + t2 * t2 + t3 * t3;
    }
#pragma unroll
    for (int o = 16; o > 0; o >>= 1) {
        s  += __shfl_xor_sync(0xffffffffu, s, o);
        s2 += __shfl_xor_sync(0xffffffffu, s2, o);
    }
    float mean = s * (1.f / D_MODEL);
    float var  = s2 * (1.f / D_MODEL) - mean * mean;
    float inv  = rsqrtf(var + 1e-5f);
#pragma unroll
    for (int u = 0; u < 2; u++) {
        int d = lane * 4 + u * 128;
        float4 o4;
        o4.x = (v[u * 4 + 0] - mean) * inv * g[d + 0] + bt[d + 0];
        o4.y = (v[u * 4 + 1] - mean) * inv * g[d + 1] + bt[d + 1];
        o4.z = (v[u * 4 + 2] - mean) * inv * g[d + 2] + bt[d + 2];
        o4.w = (v[u * 4 + 3] - mean) * inv * g[d + 3] + bt[d + 3];
        *(float4*)(O + (size_t)warp * D_MODEL + d) = o4;
    }
}

// ---------------------------------------------------------------------------
// Deformable sampling, fp16 values in, fp16 samp out. One warp per (token, head).
// ---------------------------------------------------------------------------
__constant__ int c_lw[4]     = {128, 64, 32, 16};
__constant__ int c_lstart[4] = {0, 16384, 20480, 21504};

__global__ void sample_kernel(const __half* __restrict__ Valh,
                              const float* __restrict__ OA,
                              __half* __restrict__ Samph) {
    __shared__ int2 tab[8][16][4];
    int gw   = (blockIdx.x * blockDim.x + threadIdx.x) >> 5;
    int lane = threadIdx.x & 31;
    int wpb  = threadIdx.x >> 5;
    if (gw >= M_TOT * NH) return;
    int h   = gw & 7;
    int tok = gw >> 3;
    int s   = tok % S_TOTAL;
    int b   = tok / S_TOTAL;

    int wt, st, sh;
    if (s < 16384)      { wt = 128; st = 0;     sh = 7; }
    else if (s < 20480) { wt = 64;  st = 16384; sh = 6; }
    else if (s < 21504) { wt = 32;  st = 20480; sh = 5; }
    else                { wt = 16;  st = 21504; sh = 4; }
    int sl = s - st;
    int iy = sl >> sh;
    int ix = sl - (iy << sh);
    float refx = (ix + 0.5f) / (float)wt;
    float refy = (iy + 0.5f) / (float)wt;

    size_t rb = (size_t)tok;

    float lv = (lane < 16) ? OA[rb * 384 + 256 + h * 16 + lane] : -1e30f;
    float m = lv;
#pragma unroll
    for (int o = 8; o > 0; o >>= 1) m = fmaxf(m, __shfl_xor_sync(0xffffffffu, m, o));
    float e = (lane < 16) ? expf(lv - m) : 0.f;
    float ssum = e;
#pragma unroll
    for (int o = 8; o > 0; o >>= 1) ssum += __shfl_xor_sync(0xffffffffu, ssum, o);
    float aw = e / ssum;

    if (lane < 16) {
        int l   = lane >> 2;
        int wl  = c_lw[l];
        int stl = c_lstart[l];
        float ox = OA[rb * 384 + (size_t)(h * 16 + lane) * 2 + 0];
        float oy = OA[rb * 384 + (size_t)(h * 16 + lane) * 2 + 1];
        float x = refx * (float)wl + ox - 0.5f;
        float y = refy * (float)wl + oy - 0.5f;
        float xf = floorf(x), yf = floorf(y);
        float lx = x - xf, ly = y - yf;
        int x0 = (int)xf, y0 = (int)yf;
        int x1 = x0 + 1, y1 = y0 + 1;
        bool okx0 = (x0 >= 0) & (x0 < wl);
        bool okx1 = (x1 >= 0) & (x1 < wl);
        bool oky0 = (y0 >= 0) & (y0 < wl);
        bool oky1 = (y1 >= 0) & (y1 < wl);
        int cx0 = min(max(x0, 0), wl - 1), cx1 = min(max(x1, 0), wl - 1);
        int cy0 = min(max(y0, 0), wl - 1), cy1 = min(max(y1, 0), wl - 1);
        float w0 = (1.f - lx) * (1.f - ly) * aw * ((okx0 && oky0) ? 1.f : 0.f);
        float w1 = lx * (1.f - ly) * aw * ((okx1 && oky0) ? 1.f : 0.f);
        float w2 = (1.f - lx) * ly * aw * ((okx0 && oky1) ? 1.f : 0.f);
        float w3 = lx * ly * aw * ((okx1 && oky1) ? 1.f : 0.f);
        tab[wpb][lane][0] = make_int2(stl + cy0 * wl + cx0, __float_as_int(w0));
        tab[wpb][lane][1] = make_int2(stl + cy0 * wl + cx1, __float_as_int(w1));
        tab[wpb][lane][2] = make_int2(stl + cy1 * wl + cx0, __float_as_int(w2));
        tab[wpb][lane][3] = make_int2(stl + cy1 * wl + cx1, __float_as_int(w3));
    }
    __syncwarp();

    int t   = lane >> 3;
    int ch4 = lane & 7;
    const __half* vb = Valh + (size_t)b * S_TOTAL * 256 + h * 32 + ch4 * 4;
    float4 acc = make_float4(0.f, 0.f, 0.f, 0.f);
#pragma unroll
    for (int j = 0; j < 16; j++) {
        int2 ee = tab[wpb][j][t];
        uint2 u = *(const uint2*)(vb + (size_t)ee.x * 256);
        __half2 p0 = *(__half2*)&u.x;
        __half2 p1 = *(__half2*)&u.y;
        float2 f0 = __half22float2(p0);
        float2 f1 = __half22float2(p1);
        float f = __int_as_float(ee.y);
        acc.x += f * f0.x; acc.y += f * f0.y;
        acc.z += f * f1.x; acc.w += f * f1.y;
    }
#pragma unroll
    for (int msk = 8; msk <= 16; msk <<= 1) {
        acc.x += __shfl_xor_sync(0xffffffffu, acc.x, msk);
        acc.y += __shfl_xor_sync(0xffffffffu, acc.y, msk);
        acc.z += __shfl_xor_sync(0xffffffffu, acc.z, msk);
        acc.w += __shfl_xor_sync(0xffffffffu, acc.w, msk);
    }
    if (lane < 8) {
        __half2 h0 = __halves2half2(__float2half_rn(acc.x), __float2half_rn(acc.y));
        __half2 h1 = __halves2half2(__float2half_rn(acc.z), __float2half_rn(acc.w));
        uint2 u; u.x = *(uint32_t*)&h0; u.y = *(uint32_t*)&h1;
        ((uint2*)(Samph + (size_t)tok * 256 + h * 32))[ch4] = u;
    }
}

// ---------------------------------------------------------------------------
// Host orchestration
// ---------------------------------------------------------------------------
extern "C" void kernel_launch(void* const* d_in, const int* in_sizes, int n_in,
                              void* d_out, int out_size) {
    const float* src[4];
    const float* posin[4];
    bool interleaved = (in_sizes[1] == in_sizes[0]);
    for (int l = 0; l < 4; l++) {
        if (interleaved) {
            src[l]   = (const float*)d_in[2 * l];
            posin[l] = (const float*)d_in[2 * l + 1];
        } else {
            src[l]   = (const float*)d_in[l];
            posin[l] = (const float*)d_in[4 + l];
        }
    }
    const float* lemb  = (const float*)d_in[8];
    const float* Woff  = (const float*)d_in[9];
    const float* boff  = (const float*)d_in[10];
    const float* Wattn = (const float*)d_in[11];
    const float* battn = (const float*)d_in[12];
    const float* Wval  = (const float*)d_in[13];
    const float* bval  = (const float*)d_in[14];
    const float* Wout  = (const float*)d_in[15];
    const float* bout  = (const float*)d_in[16];
    const float* ln1s  = (const float*)d_in[17];
    const float* ln1b  = (const float*)d_in[18];
    const float* W1    = (const float*)d_in[19];
    const float* b1    = (const float*)d_in[20];
    const float* W2    = (const float*)d_in[21];
    const float* b2    = (const float*)d_in[22];
    const float* ln2s  = (const float*)d_in[23];
    const float* ln2b  = (const float*)d_in[24];

    float* out = (float*)d_out;

    float *pos, *offawl, *tmp, *biasoa;
    __half *valh, *samph, *ffh, *wth, *wtl;
    cudaGetSymbolAddress((void**)&pos,    g_pos);
    cudaGetSymbolAddress((void**)&valh,   g_valh);
    cudaGetSymbolAddress((void**)&offawl, g_offawl);
    cudaGetSymbolAddress((void**)&samph,  g_samph);
    cudaGetSymbolAddress((void**)&tmp,    g_tmp);
    cudaGetSymbolAddress((void**)&ffh,    g_ffh);
    cudaGetSymbolAddress((void**)&biasoa, g_biasoa);
    cudaGetSymbolAddress((void**)&wth,    g_wth);
    cudaGetSymbolAddress((void**)&wtl,    g_wtl);

    cudaFuncSetAttribute((tc_gemm_h<0>),        cudaFuncAttributeMaxDynamicSharedMemorySize, TCGH_SMEM);
    cudaFuncSetAttribute((tc_gemm_pers<0,0,0>), cudaFuncAttributeMaxDynamicSharedMemorySize, PERS_SMEM);
    cudaFuncSetAttribute((tc_gemm_pers<0,1,0>), cudaFuncAttributeMaxDynamicSharedMemorySize, PERS_SMEM);
    cudaFuncSetAttribute((tc_gemm_pers<1,1,0>), cudaFuncAttributeMaxDynamicSharedMemorySize, PERS_SMEM);
    cudaFuncSetAttribute((tc_gemm_pers<0,0,1>), cudaFuncAttributeMaxDynamicSharedMemorySize, PERS_SMEM_H);

    // Prologue: 5 launches
    transplit_all<<<dim3(256, 6, 3), dim3(32, 32)>>>(Wval, Woff, Wattn, Wout, W1, W2,
                                                     wth, wtl, 0);
    transplit_all<<<dim3(256, 6, 3), dim3(32, 32)>>>(Wval, Woff, Wattn, Wout, W1, W2,
                                                     wth, wtl, 3);
    biascat_kernel<<<NLAYERS, 384>>>(boff, battn, biasoa);
    flatten_pair<<<dim3(16384/32 + 4096/32, 8, BATCH), dim3(32, 32)>>>(
        src[0], posin[0], 16384, 0, 0, src[1], posin[1], 4096, 16384, 1,
        lemb, out, pos);
    flatten_pair<<<dim3(1024/32 + 256/32, 8, BATCH), dim3(32, 32)>>>(
        src[2], posin[2], 1024, 20480, 2, src[3], posin[3], 256, 21504, 3,
        lemb, out, pos);

    for (int i = 0; i < NLAYERS; i++) {
        const __half* bh = wth + (size_t)i * WT_LAYER;
        const __half* bl = wtl + (size_t)i * WT_LAYER;
        // value (fp16 out) = out @ Wval + bval       (N=256: 2 cols x 74 CTAs)
        tc_gemm_pers<0,1,0><<<148, 256, PERS_SMEM>>>(out, nullptr, bh + WT_VAL, bl + WT_VAL,
                                                     bval + i * 256, (float*)valh, 256, 74);
        // [off|awl] = (out + pos) @ [Woff|Wattn] + [boff|battn]  (N=384: 3 cols x 49)
        tc_gemm_pers<0,0,0><<<147, 256, PERS_SMEM>>>(out, pos, bh + WT_OFF, bl + WT_OFF,
                                                     biasoa + i * 384, offawl, 384, 49);
        // deformable sampling (fp16 values in, fp16 samp out)
        sample_kernel<<<M_TOT * NH / 8, 256>>>(valh, offawl, samph);
        // attn out = samp(fp16) @ Wout + bout        (AF16 pers, 2-MMA chunks)
        tc_gemm_pers<0,0,1><<<148, 256, PERS_SMEM_H>>>(samph, nullptr, bh + WT_OUT, bl + WT_OUT,
                                                       bout + i * 256, tmp, 256, 74);
        // out = LN(out + attn)
        resid_ln_kernel<<<(M_TOT + 7) / 8, 256>>>(tmp, out, ln1s + i * 256,
                                                  ln1b + i * 256, out, M_TOT);
        // h(fp16) = relu(out @ W1 + b1)              (N=1024: 8 cols x 18 CTAs)
        tc_gemm_pers<1,1,0><<<144, 256, PERS_SMEM>>>(out, nullptr, bh + WT_W1, bl + WT_W1,
                                                     b1 + i * 1024, (float*)ffh, 1024, 18);
        // ff = h(fp16) @ W2 + b2                     (K=1024: streaming fp16-A)
        tc_gemm_h<0><<<dim3(M_TOT / 128, 2), 256, TCGH_SMEM>>>(ffh, bh + WT_W2, bl + WT_W2,
                                                               b2 + i * 256, tmp, M_TOT, 256, 1024);
        // out = LN(out + ff)
        resid_ln_kernel<<<(M_TOT + 7) / 8, 256>>>(tmp, out, ln2s + i * 256,
                                                  ln2b + i * 256, out, M_TOT);
    }
}

// round 13
// speedup vs baseline: 3.1456x; 1.0827x over previous
#include <cuda_runtime.h>
#include <cuda_fp16.h>
#include <math.h>
#include <stdint.h>

// ---------------------------------------------------------------------------
// MSDeformAttn transformer encoder (6 layers).
// All K=256 GEMMs: persistent-B tcgen05 kind::f16, fp16-A (exact, 2 MMAs per
// K64 chunk), B hi/lo resident in SMEM. Residual stream mirrored in fp16
// (outh / qh) by LN. W2 (K=1024): streaming fp16-A kernel.
// sm_103a arch-feature guarded; SIMT fallback otherwise.
// D=256, NH=8, NL=4, NP=4, DH=32, DFF=1024, B=2, S=21760.
// ---------------------------------------------------------------------------

#define D_MODEL 256
#define NH 8
#define DFF 1024
#define NLAYERS 6
#define BATCH 2
#define S_TOTAL 21760
#define M_TOT (BATCH * S_TOTAL)   // 43520 rows; 340 M-tiles of 128

#if defined(__CUDA_ARCH_FEAT_SM103_ALL) || defined(__CUDA_ARCH_FEAT_SM100_ALL) || defined(__CUDA_ARCH_FEAT_SM101_ALL)
#define HAS_TCGEN05 1
#else
#define HAS_TCGEN05 0
#endif

// Scratch (allocation-free: __device__ globals)
__device__ float  g_pos[M_TOT * D_MODEL];
__device__ __half g_outh[M_TOT * D_MODEL];        // fp16 residual stream
__device__ __half g_qh[M_TOT * D_MODEL];          // fp16 (out + pos)
__device__ __half g_valh[M_TOT * D_MODEL];        // fp16 value tensor
__device__ float  g_offawl[M_TOT * 384];          // [off 256 | awl 128] per row
__device__ __half g_samph[M_TOT * D_MODEL];       // fp16 sampled tensor
__device__ float  g_tmp[M_TOT * D_MODEL];
__device__ __half g_ffh[M_TOT * DFF];             // fp16 FF hidden
__device__ float  g_biasoa[NLAYERS * 384];        // [boff 256 | battn 128]

// Transposed + fp16-split weights: per layer 753664 elements
#define WT_LAYER 753664
__device__ __half g_wth[NLAYERS * WT_LAYER];
__device__ __half g_wtl[NLAYERS * WT_LAYER];
#define WT_VAL  0
#define WT_OFF  65536      // rows 0..255 of combined [384,256] (attn follows)
#define WT_ATTN 131072
#define WT_OUT  163840
#define WT_W1   229376
#define WT_W2   491520

// ---------------------------------------------------------------------------
// PTX helpers
// ---------------------------------------------------------------------------
__device__ __forceinline__ uint32_t elect_one_pred() {
    uint32_t pred;
    asm volatile(
        "{\n\t.reg .pred p;\n\telect.sync _|p, 0xFFFFFFFF;\n\t"
        "selp.b32 %0, 1, 0, p;\n\t}" : "=r"(pred));
    return pred;
}
__device__ __forceinline__ uint32_t smem_to_u32(const void* p) {
    uint32_t a;
    asm("{ .reg .u64 t; cvta.to.shared.u64 t, %1; cvt.u32.u64 %0, t; }"
        : "=r"(a) : "l"(p));
    return a;
}

#define TCGEN05_ALLOC(addr, n) \
    asm volatile("tcgen05.alloc.cta_group::1.sync.aligned.shared::cta.b32 [%0], %1;" \
                 :: "r"((uint32_t)(addr)), "r"((uint32_t)(n)) : "memory")
#define TCGEN05_DEALLOC(tmem, n) \
    asm volatile("tcgen05.dealloc.cta_group::1.sync.aligned.b32 %0, %1;" \
                 :: "r"(tmem), "r"((uint32_t)(n)))
#define TCGEN05_RELINQ() \
    asm volatile("tcgen05.relinquish_alloc_permit.cta_group::1.sync.aligned;")
#define TCGEN05_COMMIT(mbar) \
    asm volatile("tcgen05.commit.cta_group::1.mbarrier::arrive::one.shared::cluster.b64 [%0];" \
                 :: "r"((uint32_t)(mbar)) : "memory")
#define TCGEN05_FENCE_AFTER() \
    asm volatile("tcgen05.fence::after_thread_sync;" ::: "memory")
#define TCGEN05_FENCE_BEFORE() \
    asm volatile("tcgen05.fence::before_thread_sync;" ::: "memory")
#define TCGEN05_WAIT_LD() \
    asm volatile("tcgen05.wait::ld.sync.aligned;" ::: "memory")
#define FENCE_PROXY_ASYNC() \
    asm volatile("fence.proxy.async.shared::cta;" ::: "memory")
#define MBARRIER_INIT(mbar, cnt) \
    asm volatile("mbarrier.init.shared.b64 [%0], %1;" \
                 :: "r"((uint32_t)(mbar)), "r"((uint32_t)(cnt)) : "memory")
#define MBARRIER_INVAL(mbar) \
    asm volatile("mbarrier.inval.shared.b64 [%0];" :: "r"((uint32_t)(mbar)) : "memory")

#define MBARRIER_WAIT_PARITY(mbar, parity) do {                               \
    uint32_t _m = (uint32_t)(mbar);                                           \
    uint32_t _p = (uint32_t)(parity);                                         \
    asm volatile(                                                             \
        "{\n\t.reg .pred P1;\n\t"                                             \
        "WAIT_LOOP_%=:\n\t"                                                   \
        "mbarrier.try_wait.parity.acquire.cta.shared::cta.b64 P1, [%0], %1, 0x989680;\n\t" \
        "@P1 bra.uni WAIT_DONE_%=;\n\t"                                       \
        "bra.uni WAIT_LOOP_%=;\n\t"                                           \
        "WAIT_DONE_%=:\n\t}"                                                  \
        :: "r"(_m), "r"(_p) : "memory");                                      \
} while (0)

// fp16 SS MMA (fp32 accum), cta_group::1
#define TCGEN05_MMA_F16_SS(d, ad, bd, id, en) do {                            \
    uint32_t _e = (en) ? 1u : 0u; uint32_t _z = 0;                            \
    asm volatile(                                                             \
        "{\n\t.reg .pred p;\n\tsetp.ne.u32 p, %5, 0;\n\t"                     \
        "tcgen05.mma.cta_group::1.kind::f16 [%0], %1, %2, %3, {%4,%4,%4,%4}, p;\n\t}" \
        :: "r"(d), "l"(ad), "l"(bd), "r"(id), "r"(_z), "r"(_e) : "memory");   \
} while (0)

#define TCGEN05_LD32(r, addr)                                                 \
    asm volatile(                                                             \
        "tcgen05.ld.sync.aligned.32x32b.x32.b32 "                             \
        "{%0, %1, %2, %3, %4, %5, %6, %7, "                                   \
        " %8, %9, %10, %11, %12, %13, %14, %15, "                             \
        " %16, %17, %18, %19, %20, %21, %22, %23, "                           \
        " %24, %25, %26, %27, %28, %29, %30, %31}, [%32];"                    \
        : "=r"((r)[0]),  "=r"((r)[1]),  "=r"((r)[2]),  "=r"((r)[3]),          \
          "=r"((r)[4]),  "=r"((r)[5]),  "=r"((r)[6]),  "=r"((r)[7]),          \
          "=r"((r)[8]),  "=r"((r)[9]),  "=r"((r)[10]), "=r"((r)[11]),         \
          "=r"((r)[12]), "=r"((r)[13]), "=r"((r)[14]), "=r"((r)[15]),         \
          "=r"((r)[16]), "=r"((r)[17]), "=r"((r)[18]), "=r"((r)[19]),         \
          "=r"((r)[20]), "=r"((r)[21]), "=r"((r)[22]), "=r"((r)[23]),         \
          "=r"((r)[24]), "=r"((r)[25]), "=r"((r)[26]), "=r"((r)[27]),         \
          "=r"((r)[28]), "=r"((r)[29]), "=r"((r)[30]), "=r"((r)[31])          \
        : "r"(addr))

// SW128 K-major smem descriptor: layout=2, version=1, SBO=64, LBO=1
__device__ __forceinline__ uint64_t make_sw128_desc(uint32_t addr) {
    const uint64_t base = (uint64_t(2) << 61) | (uint64_t(1) << 46)
                        | (uint64_t(64) << 32) | (uint64_t(1) << 16);
    return base | ((uint64_t)(addr >> 4) & 0x3FFF);
}

#define TCG_IDESC 0x8200010u

// Epilogue store of 4 consecutive cols (float or half)
template <int RELU, int OUTH>
__device__ __forceinline__ void epi_store4(float* Cf, size_t idx, float4 o) {
    if (RELU) {
        o.x = fmaxf(o.x, 0.f); o.y = fmaxf(o.y, 0.f);
        o.z = fmaxf(o.z, 0.f); o.w = fmaxf(o.w, 0.f);
    }
    if (OUTH) {
        __half2 h0 = __halves2half2(__float2half_rn(o.x), __float2half_rn(o.y));
        __half2 h1 = __halves2half2(__float2half_rn(o.z), __float2half_rn(o.w));
        uint2 u; u.x = *(uint32_t*)&h0; u.y = *(uint32_t*)&h1;
        *(uint2*)((__half*)Cf + idx) = u;
    } else {
        *(float4*)(Cf + idx) = o;
    }
}

// ---------------------------------------------------------------------------
// Streaming GEMM, fp16 A (exact): used for W2 (K=1024, A = ffh half).
// Per K64 chunk: 2 MMAs (A*BH + A*BL). Stage = AH 16K + BH 16K + BL 16K.
// ---------------------------------------------------------------------------
#define HOFF_AH 0
#define HOFF_BH 16384
#define HOFF_BL 32768
#define HSTAGE  49152
#define TCGH_SMEM (1024 + 2 * HSTAGE)   // 99328

template <int RELU>
__global__ __launch_bounds__(256, 1)
void tc_gemm_h(const __half* __restrict__ A,
               const __half* __restrict__ WH, const __half* __restrict__ WL,
               const float* __restrict__ bias, float* __restrict__ C,
               int M, int N, int K) {
    extern __shared__ char smem[];
    const int tid  = threadIdx.x;
    const int brow = blockIdx.x * 128;
    const int bcol = blockIdx.y * 128;

    const int lr = tid >> 3;
    const int c8 = (tid & 7) * 8;
    const __half* Ab  = A  + (size_t)(brow + lr) * K + c8;
    const __half* BHb = WH + (size_t)(bcol + lr) * K + c8;
    const __half* BLb = WL + (size_t)(bcol + lr) * K + c8;
    const int KT = K >> 6;

    uint4 ua[4], bh[4], bl[4];

#define HLDG_TILE(kt) do {                                                    \
    int _k = (kt) * 64;                                                       \
    _Pragma("unroll")                                                         \
    for (int i = 0; i < 4; i++) {                                             \
        size_t ro = (size_t)(i * 32) * K + _k;                                \
        ua[i] = *(const uint4*)(Ab + ro);                                     \
        bh[i] = *(const uint4*)(BHb + ro);                                    \
        bl[i] = *(const uint4*)(BLb + ro);                                    \
    }                                                                         \
} while (0)

#if HAS_TCGEN05
    const uint32_t sbase = smem_to_u32(smem);
    const int wid  = tid >> 5;
    const int lane = tid & 31;

    const uint32_t TMEMP = sbase;
    const uint32_t MBAR0 = sbase + 8;
    const uint32_t MBAR1 = sbase + 16;
    const uint32_t STG0  = sbase + 1024;

    if (wid == 0) TCGEN05_ALLOC(TMEMP, 128);
    if (tid == 0) { MBARRIER_INIT(MBAR0, 1); MBARRIER_INIT(MBAR1, 1); }
    __syncthreads();
    uint32_t tmem;
    asm volatile("ld.shared.b32 %0, [%1];" : "=r"(tmem) : "r"(TMEMP));
    if (wid == 0) TCGEN05_RELINQ();

    uint32_t swoff[4];
#pragma unroll
    for (int i = 0; i < 4; i++) {
        uint32_t off = (uint32_t)(i * 32 + lr) * 128 + (tid & 7) * 16;
        swoff[i] = off ^ ((off >> 3) & 0x70);
    }

    int ph0 = 0, ph1 = 0;

#define HSTS_TILE(stoff) do {                                                 \
    char* _sb = smem + 1024 + (stoff);                                        \
    _Pragma("unroll")                                                         \
    for (int i = 0; i < 4; i++) {                                             \
        *(uint4*)(_sb + HOFF_AH + swoff[i]) = ua[i];                          \
        *(uint4*)(_sb + HOFF_BH + swoff[i]) = bh[i];                          \
        *(uint4*)(_sb + HOFF_BL + swoff[i]) = bl[i];                          \
    }                                                                         \
} while (0)

    HLDG_TILE(0);
    HSTS_TILE(0);
    FENCE_PROXY_ASYNC();
    __syncthreads();

    for (int kt = 0; kt < KT; kt++) {
        int s = kt & 1;
        bool have_next = (kt + 1 < KT);
        if (have_next) HLDG_TILE(kt + 1);

        if (wid == 0) {
            if (elect_one_pred()) {
                uint32_t sb = STG0 + s * HSTAGE;
                uint64_t dah = make_sw128_desc(sb + HOFF_AH);
                uint64_t dbh = make_sw128_desc(sb + HOFF_BH);
                uint64_t dbl = make_sw128_desc(sb + HOFF_BL);
#pragma unroll
                for (int ks = 0; ks < 4; ks++) {
                    TCGEN05_MMA_F16_SS(tmem, dah + ks * 2, dbh + ks * 2,
                                       TCG_IDESC, (kt > 0) || (ks > 0));
                    TCGEN05_MMA_F16_SS(tmem, dah + ks * 2, dbl + ks * 2,
                                       TCG_IDESC, 1);
                }
                TCGEN05_COMMIT(s == 0 ? MBAR0 : MBAR1);
            }
        }

        if (have_next) {
            int ns = s ^ 1;
            if (kt >= 1) {
                if (ns == 0) { MBARRIER_WAIT_PARITY(MBAR0, ph0); ph0 ^= 1; }
                else         { MBARRIER_WAIT_PARITY(MBAR1, ph1); ph1 ^= 1; }
            }
            HSTS_TILE(ns * HSTAGE);
            FENCE_PROXY_ASYNC();
            __syncthreads();
        }
    }

    if (((KT - 1) & 1) == 0) { MBARRIER_WAIT_PARITY(MBAR0, ph0); }
    else                     { MBARRIER_WAIT_PARITY(MBAR1, ph1); }
    TCGEN05_FENCE_AFTER();

    {
        int colbase = (wid >> 2) * 64;
        uint32_t d0[32], d1[32];
        TCGEN05_LD32(d0, tmem + colbase);
        TCGEN05_LD32(d1, tmem + colbase + 32);
        TCGEN05_WAIT_LD();
        TCGEN05_FENCE_BEFORE();

        int r = brow + (wid & 3) * 32 + lane;
        size_t base = (size_t)r * N + bcol + colbase;
        const float* bb = bias + bcol + colbase;
#pragma unroll
        for (int c = 0; c < 32; c += 4) {
            float4 o;
            o.x = __uint_as_float(d0[c + 0]) + bb[c + 0];
            o.y = __uint_as_float(d0[c + 1]) + bb[c + 1];
            o.z = __uint_as_float(d0[c + 2]) + bb[c + 2];
            o.w = __uint_as_float(d0[c + 3]) + bb[c + 3];
            epi_store4<RELU, 0>(C, base + c, o);
        }
#pragma unroll
        for (int c = 0; c < 32; c += 4) {
            float4 o;
            o.x = __uint_as_float(d1[c + 0]) + bb[32 + c + 0];
            o.y = __uint_as_float(d1[c + 1]) + bb[32 + c + 1];
            o.z = __uint_as_float(d1[c + 2]) + bb[32 + c + 2];
            o.w = __uint_as_float(d1[c + 3]) + bb[32 + c + 3];
            epi_store4<RELU, 0>(C, base + 32 + c, o);
        }
    }

    __syncthreads();
    if (tid == 0) { MBARRIER_INVAL(MBAR0); MBARRIER_INVAL(MBAR1); }
    __syncthreads();
    if (wid == 0) TCGEN05_DEALLOC(tmem, 128);

#else  // SIMT fallback
    float (*As)[132] = (float(*)[132])(smem);
    float (*Bs)[132] = (float(*)[132])(smem + 64 * 132 * 4);

    int ty = (tid >> 4) * 8;
    int tx = (tid & 15) * 8;

    float acc[8][8];
#pragma unroll
    for (int i = 0; i < 8; i++)
#pragma unroll
        for (int j = 0; j < 8; j++) acc[i][j] = 0.f;

    for (int kt = 0; kt < KT; kt++) {
        HLDG_TILE(kt);
        __syncthreads();
#pragma unroll
        for (int i = 0; i < 4; i++) {
            int r = i * 32 + lr;
            const __half* ha = (const __half*)&ua[i];
            const __half* hh = (const __half*)&bh[i];
            const __half* ll = (const __half*)&bl[i];
#pragma unroll
            for (int j = 0; j < 8; j++) {
                As[c8 + j][r] = __half2float(ha[j]);
                Bs[c8 + j][r] = __half2float(hh[j]) + __half2float(ll[j]);
            }
        }
        __syncthreads();
#pragma unroll 16
        for (int k = 0; k < 64; k++) {
            float av[8], bv[8];
#pragma unroll
            for (int i = 0; i < 8; i++) { av[i] = As[k][ty + i]; bv[i] = Bs[k][tx + i]; }
#pragma unroll
            for (int i = 0; i < 8; i++)
#pragma unroll
                for (int j = 0; j < 8; j++)
                    acc[i][j] += av[i] * bv[j];
        }
    }

    int row = brow + ty;
    int col = bcol + tx;
#pragma unroll
    for (int i = 0; i < 8; i++) {
#pragma unroll
        for (int j = 0; j < 8; j++) {
            float v = acc[i][j] + bias[col + j];
            if (RELU) v = fmaxf(v, 0.f);
            C[(size_t)(row + i) * N + col + j] = v;
        }
    }
#endif
}

// ---------------------------------------------------------------------------
// Persistent-B GEMM, fp16 A (exact, 2-MMA chunks). K=256.
// OUTH=1 emits __half output.
// SMEM: 1024 hdr + 131072 B + 2x16384 A = 164864 (validated).
// ---------------------------------------------------------------------------
#define PERS_SMEM_H 164864
#define MT_TILES (M_TOT / 128)   // 340

template <int RELU, int OUTH>
__global__ __launch_bounds__(256, 1)
void tc_gemm_pers(const __half* __restrict__ A,
                  const __half* __restrict__ WH, const __half* __restrict__ WL,
                  const float* __restrict__ bias, float* __restrict__ C,
                  int N, int CPC) {
    extern __shared__ char smem[];
    const int tid = threadIdx.x;
    const int K = 256;
    const int col = blockIdx.x / CPC;
    const int cid = blockIdx.x % CPC;
    const int bcol = col * 128;
    constexpr int ASTAGE = 16384;

    const int lr  = tid >> 3;
    const int c16 = tid & 7;
    const uint32_t swr = (uint32_t)lr * 128 + (uint32_t)((c16 ^ (lr & 7)) * 16);

#if HAS_TCGEN05
    const uint32_t sbase = smem_to_u32(smem);
    const int wid = tid >> 5, lane = tid & 31;
    const uint32_t TMEMP = sbase;
    const uint32_t MBAR0 = sbase + 8;
    const uint32_t MBAR1 = sbase + 16;
    const uint32_t BH_S  = sbase + 1024;
    const uint32_t BL_S  = BH_S + 65536;
    const uint32_t AST   = BL_S + 65536;

    if (wid == 0) TCGEN05_ALLOC(TMEMP, 128);
    if (tid == 0) { MBARRIER_INIT(MBAR0, 1); MBARRIER_INIT(MBAR1, 1); }
    __syncthreads();
    uint32_t tmem;
    asm volatile("ld.shared.b32 %0, [%1];" : "=r"(tmem) : "r"(TMEMP));
    if (wid == 0) TCGEN05_RELINQ();

    // Load resident B hi/lo: 4 K64 sub-tiles of 16KB per plane
    {
        const __half* BHb = WH + (size_t)(bcol + lr) * K + c16 * 8;
        const __half* BLb = WL + (size_t)(bcol + lr) * K + c16 * 8;
#pragma unroll
        for (int kt = 0; kt < 4; kt++) {
#pragma unroll
            for (int i = 0; i < 4; i++) {
                size_t ro = (size_t)(i * 32) * K + kt * 64;
                uint32_t so = (uint32_t)kt * 16384 + swr + (uint32_t)i * 4096;
                *(uint4*)(smem + 1024 + so)         = *(const uint4*)(BHb + ro);
                *(uint4*)(smem + 1024 + 65536 + so) = *(const uint4*)(BLb + ro);
            }
        }
    }
    FENCE_PROXY_ASYNC();
    __syncthreads();

    int g = 0;
    for (int m = cid; m < MT_TILES; m += CPC) {
        const int brow = m * 128;
        const __half* Ahb = A + (size_t)(brow + lr) * K + c16 * 8;

#pragma unroll 1
        for (int kt = 0; kt < 4; kt++, g++) {
            const int s = g & 1;
            uint4 ua[4];
#pragma unroll
            for (int i = 0; i < 4; i++)
                ua[i] = *(const uint4*)(Ahb + (size_t)(i * 32) * K + kt * 64);

            if (g >= 2) {
                MBARRIER_WAIT_PARITY(s ? MBAR1 : MBAR0, ((g >> 1) - 1) & 1);
            }
            char* sb = smem + 1024 + 131072 + s * ASTAGE;
#pragma unroll
            for (int i = 0; i < 4; i++)
                *(uint4*)(sb + swr + i * 4096) = ua[i];
            FENCE_PROXY_ASYNC();
            __syncthreads();

            if (wid == 0) {
                if (elect_one_pred()) {
                    uint64_t dah = make_sw128_desc(AST + s * ASTAGE);
                    uint64_t dbh = make_sw128_desc(BH_S + kt * 16384);
                    uint64_t dbl = make_sw128_desc(BL_S + kt * 16384);
#pragma unroll
                    for (int ks = 0; ks < 4; ks++) {
                        TCGEN05_MMA_F16_SS(tmem, dah + ks * 2, dbh + ks * 2,
                                           TCG_IDESC, (kt > 0) || (ks > 0));
                        TCGEN05_MMA_F16_SS(tmem, dah + ks * 2, dbl + ks * 2,
                                           TCG_IDESC, 1);
                    }
                    TCGEN05_COMMIT(s ? MBAR1 : MBAR0);
                }
            }
        }

        {
            int gl = g - 1;
            MBARRIER_WAIT_PARITY((gl & 1) ? MBAR1 : MBAR0, (gl >> 1) & 1);
            TCGEN05_FENCE_AFTER();

            int colbase = (wid >> 2) * 64;
            uint32_t d0[32], d1[32];
            TCGEN05_LD32(d0, tmem + colbase);
            TCGEN05_LD32(d1, tmem + colbase + 32);
            TCGEN05_WAIT_LD();
            TCGEN05_FENCE_BEFORE();

            int r = brow + (wid & 3) * 32 + lane;
            size_t cb = (size_t)r * N + bcol + colbase;
            const float* bb = bias + bcol + colbase;
#pragma unroll
            for (int c = 0; c < 32; c += 4) {
                float4 o;
                o.x = __uint_as_float(d0[c + 0]) + bb[c + 0];
                o.y = __uint_as_float(d0[c + 1]) + bb[c + 1];
                o.z = __uint_as_float(d0[c + 2]) + bb[c + 2];
                o.w = __uint_as_float(d0[c + 3]) + bb[c + 3];
                epi_store4<RELU, OUTH>(C, cb + c, o);
            }
#pragma unroll
            for (int c = 0; c < 32; c += 4) {
                float4 o;
                o.x = __uint_as_float(d1[c + 0]) + bb[32 + c + 0];
                o.y = __uint_as_float(d1[c + 1]) + bb[32 + c + 1];
                o.z = __uint_as_float(d1[c + 2]) + bb[32 + c + 2];
                o.w = __uint_as_float(d1[c + 3]) + bb[32 + c + 3];
                epi_store4<RELU, OUTH>(C, cb + 32 + c, o);
            }
            __syncthreads();
        }
    }

    __syncthreads();
    if (tid == 0) { MBARRIER_INVAL(MBAR0); MBARRIER_INVAL(MBAR1); }
    __syncthreads();
    if (wid == 0) TCGEN05_DEALLOC(tmem, 128);

#else  // SIMT fallback
    float (*As)[132] = (float(*)[132])(smem);
    float (*Bs)[132] = (float(*)[132])(smem + 64 * 132 * 4);
    int ty = (tid >> 4) * 8;
    int tx = (tid & 15) * 8;

    for (int m = cid; m < MT_TILES; m += CPC) {
        int brow = m * 128;
        float acc[8][8];
#pragma unroll
        for (int i = 0; i < 8; i++)
#pragma unroll
            for (int j = 0; j < 8; j++) acc[i][j] = 0.f;

        for (int kt = 0; kt < 4; kt++) {
            __syncthreads();
#pragma unroll
            for (int i = 0; i < 4; i++) {
                int row = i * 32 + lr;
                size_t aro = (size_t)(brow + row) * K + kt * 64 + c16 * 8;
                size_t bro = (size_t)(bcol + row) * K + kt * 64 + c16 * 8;
#pragma unroll
                for (int j = 0; j < 8; j++) {
                    As[c16 * 8 + j][row] = __half2float(A[aro + j]);
                    Bs[c16 * 8 + j][row] = __half2float(WH[bro + j]) + __half2float(WL[bro + j]);
                }
            }
            __syncthreads();
#pragma unroll 16
            for (int k = 0; k < 64; k++) {
                float av[8], bv[8];
#pragma unroll
                for (int i = 0; i < 8; i++) { av[i] = As[k][ty + i]; bv[i] = Bs[k][tx + i]; }
#pragma unroll
                for (int i = 0; i < 8; i++)
#pragma unroll
                    for (int j = 0; j < 8; j++)
                        acc[i][j] += av[i] * bv[j];
            }
        }
        int row = brow + ty;
        int cc  = bcol + tx;
#pragma unroll
        for (int i = 0; i < 8; i++)
#pragma unroll
            for (int j = 0; j < 8; j++) {
                float v = acc[i][j] + bias[cc + j];
                if (RELU) v = fmaxf(v, 0.f);
                if (OUTH) ((__half*)C)[(size_t)(row + i) * N + cc + j] = __float2half_rn(v);
                else      C[(size_t)(row + i) * N + cc + j] = v;
            }
        __syncthreads();
    }
#endif
}

// ---------------------------------------------------------------------------
// Fused weight transpose + fp16 split (all 6 types, 3 layers per launch)
// ---------------------------------------------------------------------------
__global__ void transplit_all(const float* __restrict__ Wval, const float* __restrict__ Woff,
                              const float* __restrict__ Wattn, const float* __restrict__ Wout,
                              const float* __restrict__ W1, const float* __restrict__ W2,
                              __half* __restrict__ wth, __half* __restrict__ wtl,
                              int layer0) {
    int type  = blockIdx.y;
    int layer = layer0 + blockIdx.z;
    const float* W; int K, N, off;
    switch (type) {
        case 0: W = Wval  + (size_t)layer * 65536;  K = 256;  N = 256;  off = WT_VAL;  break;
        case 1: W = Woff  + (size_t)layer * 65536;  K = 256;  N = 256;  off = WT_OFF;  break;
        case 2: W = Wattn + (size_t)layer * 32768;  K = 256;  N = 128;  off = WT_ATTN; break;
        case 3: W = Wout  + (size_t)layer * 65536;  K = 256;  N = 256;  off = WT_OUT;  break;
        case 4: W = W1    + (size_t)layer * 262144; K = 256;  N = 1024; off = WT_W1;   break;
        default: W = W2   + (size_t)layer * 262144; K = 1024; N = 256;  off = WT_W2;   break;
    }
    int tK = K >> 5, tN = N >> 5;
    int t = blockIdx.x;
    if (t >= tK * tN) return;
    int k0 = (t % tK) * 32, n0 = (t / tK) * 32;

    __shared__ float tile[32][33];
    tile[threadIdx.y][threadIdx.x] = W[(size_t)(k0 + threadIdx.y) * N + n0 + threadIdx.x];
    __syncthreads();
    float v = tile[threadIdx.x][threadIdx.y];
    __half h = __float2half_rn(v);
    size_t o = (size_t)layer * WT_LAYER + off + (size_t)(n0 + threadIdx.y) * K + k0 + threadIdx.x;
    wth[o] = h;
    wtl[o] = __float2half_rn(v - __half2float(h));
}

// Bias concat: g_biasoa[l][0..255]=boff, [256..383]=battn
__global__ void biascat_kernel(const float* __restrict__ boff,
                               const float* __restrict__ battn,
                               float* __restrict__ dst) {
    int l = blockIdx.x, j = threadIdx.x;
    dst[l * 384 + j] = (j < 256) ? boff[l * 256 + j] : battn[l * 128 + j - 256];
}

// ---------------------------------------------------------------------------
// Flatten pair of levels: src [B, D, h, w] -> out [B, S, D]; pos + level_embed.
// Also seeds the fp16 residual mirrors: outh = fp16(out), qh = fp16(out+pos).
// ---------------------------------------------------------------------------
__global__ void flatten_pair(const float* __restrict__ sA, const float* __restrict__ pA,
                             int hwA, int stA, int lvA,
                             const float* __restrict__ sB, const float* __restrict__ pB,
                             int hwB, int stB, int lvB,
                             const float* __restrict__ lemb,
                             float* __restrict__ out, float* __restrict__ posout,
                             __half* __restrict__ outh, __half* __restrict__ qh) {
    __shared__ float ts[32][33];
    __shared__ float tp[32][33];
    int px = blockIdx.x;
    const float *src, *pos; int hw, start, level, p0;
    int tA = hwA >> 5;
    if (px < tA) { src = sA; pos = pA; hw = hwA; start = stA; level = lvA; p0 = px * 32; }
    else         { src = sB; pos = pB; hw = hwB; start = stB; level = lvB; p0 = (px - tA) * 32; }

    int b  = blockIdx.z;
    int d0 = blockIdx.y * 32;
    int tx = threadIdx.x, ty = threadIdx.y;

    const float* sp = src + ((size_t)b * D_MODEL + d0 + ty) * hw + p0;
    const float* pp = pos + ((size_t)b * D_MODEL + d0 + ty) * hw + p0;
    ts[ty][tx] = sp[tx];
    tp[ty][tx] = pp[tx];
    __syncthreads();

    int d = d0 + tx;
    float le = lemb[level * D_MODEL + d];
    size_t srow = (size_t)b * S_TOTAL + start + p0 + ty;
    float v = ts[tx][ty];
    float p = tp[tx][ty] + le;
    out[srow * D_MODEL + d]    = v;
    posout[srow * D_MODEL + d] = p;
    outh[srow * D_MODEL + d]   = __float2half_rn(v);
    qh[srow * D_MODEL + d]     = __float2half_rn(v + p);
}

// ---------------------------------------------------------------------------
// Residual + LayerNorm: out = LN(x + r) * gamma + beta. One warp per row.
// Also emits outh = fp16(out); if Qh != null, qh = fp16(out + pos).
// ---------------------------------------------------------------------------
__global__ void resid_ln_kernel(const float* __restrict__ X, const float* __restrict__ R,
                                const float* __restrict__ g, const float* __restrict__ bt,
                                float* __restrict__ O, __half* __restrict__ Oh,
                                const float* __restrict__ P, __half* __restrict__ Qh,
                                int rows) {
    int warp = (blockIdx.x * blockDim.x + threadIdx.x) >> 5;
    int lane = threadIdx.x & 31;
    if (warp >= rows) return;
    const float* xr = X + (size_t)warp * D_MODEL;
    const float* rr = R + (size_t)warp * D_MODEL;

    float v[8];
    float s = 0.f, s2 = 0.f;
#pragma unroll
    for (int u = 0; u < 2; u++) {
        float4 a = *(const float4*)(xr + lane * 4 + u * 128);
        float4 c = *(const float4*)(rr + lane * 4 + u * 128);
        float t0 = a.x + c.x, t1 = a.y + c.y, t2 = a.z + c.z, t3 = a.w + c.w;
        v[u * 4 + 0] = t0; v[u * 4 + 1] = t1; v[u * 4 + 2] = t2; v[u * 4 + 3] = t3;
        s += t0 + t1 + t2 + t3;
        s2 += t0 * t0 + t1 * t1 + t2 * t2 + t3 * t3;
    }
#pragma unroll
    for (int o = 16; o > 0; o >>= 1) {
        s  += __shfl_xor_sync(0xffffffffu, s, o);
        s2 += __shfl_xor_sync(0xffffffffu, s2, o);
    }
    float mean = s * (1.f / D_MODEL);
    float var  = s2 * (1.f / D_MODEL) - mean * mean;
    float inv  = rsqrtf(var + 1e-5f);
#pragma unroll
    for (int u = 0; u < 2; u++) {
        int d = lane * 4 + u * 128;
        float4 o4;
        o4.x = (v[u * 4 + 0] - mean) * inv * g[d + 0] + bt[d + 0];
        o4.y = (v[u * 4 + 1] - mean) * inv * g[d + 1] + bt[d + 1];
        o4.z = (v[u * 4 + 2] - mean) * inv * g[d + 2] + bt[d + 2];
        o4.w = (v[u * 4 + 3] - mean) * inv * g[d + 3] + bt[d + 3];
        *(float4*)(O + (size_t)warp * D_MODEL + d) = o4;

        __half2 h0 = __halves2half2(__float2half_rn(o4.x), __float2half_rn(o4.y));
        __half2 h1 = __halves2half2(__float2half_rn(o4.z), __float2half_rn(o4.w));
        uint2 uo; uo.x = *(uint32_t*)&h0; uo.y = *(uint32_t*)&h1;
        *(uint2*)(Oh + (size_t)warp * D_MODEL + d) = uo;

        if (Qh) {
            float4 p4 = *(const float4*)(P + (size_t)warp * D_MODEL + d);
            __half2 q0 = __halves2half2(__float2half_rn(o4.x + p4.x),
                                        __float2half_rn(o4.y + p4.y));
            __half2 q1 = __halves2half2(__float2half_rn(o4.z + p4.z),
                                        __float2half_rn(o4.w + p4.w));
            uint2 uq; uq.x = *(uint32_t*)&q0; uq.y = *(uint32_t*)&q1;
            *(uint2*)(Qh + (size_t)warp * D_MODEL + d) = uq;
        }
    }
}

// ---------------------------------------------------------------------------
// Deformable sampling, fp16 values in, fp16 samp out. One warp per (token, head).
// ---------------------------------------------------------------------------
__constant__ int c_lw[4]     = {128, 64, 32, 16};
__constant__ int c_lstart[4] = {0, 16384, 20480, 21504};

__global__ void sample_kernel(const __half* __restrict__ Valh,
                              const float* __restrict__ OA,
                              __half* __restrict__ Samph) {
    __shared__ int2 tab[8][16][4];
    int gw   = (blockIdx.x * blockDim.x + threadIdx.x) >> 5;
    int lane = threadIdx.x & 31;
    int wpb  = threadIdx.x >> 5;
    if (gw >= M_TOT * NH) return;
    int h   = gw & 7;
    int tok = gw >> 3;
    int s   = tok % S_TOTAL;
    int b   = tok / S_TOTAL;

    int wt, st, sh;
    if (s < 16384)      { wt = 128; st = 0;     sh = 7; }
    else if (s < 20480) { wt = 64;  st = 16384; sh = 6; }
    else if (s < 21504) { wt = 32;  st = 20480; sh = 5; }
    else                { wt = 16;  st = 21504; sh = 4; }
    int sl = s - st;
    int iy = sl >> sh;
    int ix = sl - (iy << sh);
    float refx = (ix + 0.5f) / (float)wt;
    float refy = (iy + 0.5f) / (float)wt;

    size_t rb = (size_t)tok;

    float lv = (lane < 16) ? OA[rb * 384 + 256 + h * 16 + lane] : -1e30f;
    float m = lv;
#pragma unroll
    for (int o = 8; o > 0; o >>= 1) m = fmaxf(m, __shfl_xor_sync(0xffffffffu, m, o));
    float e = (lane < 16) ? expf(lv - m) : 0.f;
    float ssum = e;
#pragma unroll
    for (int o = 8; o > 0; o >>= 1) ssum += __shfl_xor_sync(0xffffffffu, ssum, o);
    float aw = e / ssum;

    if (lane < 16) {
        int l   = lane >> 2;
        int wl  = c_lw[l];
        int stl = c_lstart[l];
        float ox = OA[rb * 384 + (size_t)(h * 16 + lane) * 2 + 0];
        float oy = OA[rb * 384 + (size_t)(h * 16 + lane) * 2 + 1];
        float x = refx * (float)wl + ox - 0.5f;
        float y = refy * (float)wl + oy - 0.5f;
        float xf = floorf(x), yf = floorf(y);
        float lx = x - xf, ly = y - yf;
        int x0 = (int)xf, y0 = (int)yf;
        int x1 = x0 + 1, y1 = y0 + 1;
        bool okx0 = (x0 >= 0) & (x0 < wl);
        bool okx1 = (x1 >= 0) & (x1 < wl);
        bool oky0 = (y0 >= 0) & (y0 < wl);
        bool oky1 = (y1 >= 0) & (y1 < wl);
        int cx0 = min(max(x0, 0), wl - 1), cx1 = min(max(x1, 0), wl - 1);
        int cy0 = min(max(y0, 0), wl - 1), cy1 = min(max(y1, 0), wl - 1);
        float w0 = (1.f - lx) * (1.f - ly) * aw * ((okx0 && oky0) ? 1.f : 0.f);
        float w1 = lx * (1.f - ly) * aw * ((okx1 && oky0) ? 1.f : 0.f);
        float w2 = (1.f - lx) * ly * aw * ((okx0 && oky1) ? 1.f : 0.f);
        float w3 = lx * ly * aw * ((okx1 && oky1) ? 1.f : 0.f);
        tab[wpb][lane][0] = make_int2(stl + cy0 * wl + cx0, __float_as_int(w0));
        tab[wpb][lane][1] = make_int2(stl + cy0 * wl + cx1, __float_as_int(w1));
        tab[wpb][lane][2] = make_int2(stl + cy1 * wl + cx0, __float_as_int(w2));
        tab[wpb][lane][3] = make_int2(stl + cy1 * wl + cx1, __float_as_int(w3));
    }
    __syncwarp();

    int t   = lane >> 3;
    int ch4 = lane & 7;
    const __half* vb = Valh + (size_t)b * S_TOTAL * 256 + h * 32 + ch4 * 4;
    float4 acc = make_float4(0.f, 0.f, 0.f, 0.f);
#pragma unroll
    for (int j = 0; j < 16; j++) {
        int2 ee = tab[wpb][j][t];
        uint2 u = *(const uint2*)(vb + (size_t)ee.x * 256);
        __half2 p0 = *(__half2*)&u.x;
        __half2 p1 = *(__half2*)&u.y;
        float2 f0 = __half22float2(p0);
        float2 f1 = __half22float2(p1);
        float f = __int_as_float(ee.y);
        acc.x += f * f0.x; acc.y += f * f0.y;
        acc.z += f * f1.x; acc.w += f * f1.y;
    }
#pragma unroll
    for (int msk = 8; msk <= 16; msk <<= 1) {
        acc.x += __shfl_xor_sync(0xffffffffu, acc.x, msk);
        acc.y += __shfl_xor_sync(0xffffffffu, acc.y, msk);
        acc.z += __shfl_xor_sync(0xffffffffu, acc.z, msk);
        acc.w += __shfl_xor_sync(0xffffffffu, acc.w, msk);
    }
    if (lane < 8) {
        __half2 h0 = __halves2half2(__float2half_rn(acc.x), __float2half_rn(acc.y));
        __half2 h1 = __halves2half2(__float2half_rn(acc.z), __float2half_rn(acc.w));
        uint2 u; u.x = *(uint32_t*)&h0; u.y = *(uint32_t*)&h1;
        ((uint2*)(Samph + (size_t)tok * 256 + h * 32))[ch4] = u;
    }
}

// ---------------------------------------------------------------------------
// Host orchestration
// ---------------------------------------------------------------------------
extern "C" void kernel_launch(void* const* d_in, const int* in_sizes, int n_in,
                              void* d_out, int out_size) {
    const float* src[4];
    const float* posin[4];
    bool interleaved = (in_sizes[1] == in_sizes[0]);
    for (int l = 0; l < 4; l++) {
        if (interleaved) {
            src[l]   = (const float*)d_in[2 * l];
            posin[l] = (const float*)d_in[2 * l + 1];
        } else {
            src[l]   = (const float*)d_in[l];
            posin[l] = (const float*)d_in[4 + l];
        }
    }
    const float* lemb  = (const float*)d_in[8];
    const float* Woff  = (const float*)d_in[9];
    const float* boff  = (const float*)d_in[10];
    const float* Wattn = (const float*)d_in[11];
    const float* battn = (const float*)d_in[12];
    const float* Wval  = (const float*)d_in[13];
    const float* bval  = (const float*)d_in[14];
    const float* Wout  = (const float*)d_in[15];
    const float* bout  = (const float*)d_in[16];
    const float* ln1s  = (const float*)d_in[17];
    const float* ln1b  = (const float*)d_in[18];
    const float* W1    = (const float*)d_in[19];
    const float* b1    = (const float*)d_in[20];
    const float* W2    = (const float*)d_in[21];
    const float* b2    = (const float*)d_in[22];
    const float* ln2s  = (const float*)d_in[23];
    const float* ln2b  = (const float*)d_in[24];

    float* out = (float*)d_out;

    float *pos, *offawl, *tmp, *biasoa;
    __half *outh, *qh, *valh, *samph, *ffh, *wth, *wtl;
    cudaGetSymbolAddress((void**)&pos,    g_pos);
    cudaGetSymbolAddress((void**)&outh,   g_outh);
    cudaGetSymbolAddress((void**)&qh,     g_qh);
    cudaGetSymbolAddress((void**)&valh,   g_valh);
    cudaGetSymbolAddress((void**)&offawl, g_offawl);
    cudaGetSymbolAddress((void**)&samph,  g_samph);
    cudaGetSymbolAddress((void**)&tmp,    g_tmp);
    cudaGetSymbolAddress((void**)&ffh,    g_ffh);
    cudaGetSymbolAddress((void**)&biasoa, g_biasoa);
    cudaGetSymbolAddress((void**)&wth,    g_wth);
    cudaGetSymbolAddress((void**)&wtl,    g_wtl);

    cudaFuncSetAttribute((tc_gemm_h<0>),      cudaFuncAttributeMaxDynamicSharedMemorySize, TCGH_SMEM);
    cudaFuncSetAttribute((tc_gemm_pers<0,0>), cudaFuncAttributeMaxDynamicSharedMemorySize, PERS_SMEM_H);
    cudaFuncSetAttribute((tc_gemm_pers<0,1>), cudaFuncAttributeMaxDynamicSharedMemorySize, PERS_SMEM_H);
    cudaFuncSetAttribute((tc_gemm_pers<1,1>), cudaFuncAttributeMaxDynamicSharedMemorySize, PERS_SMEM_H);

    // Prologue: 5 launches
    transplit_all<<<dim3(256, 6, 3), dim3(32, 32)>>>(Wval, Woff, Wattn, Wout, W1, W2,
                                                     wth, wtl, 0);
    transplit_all<<<dim3(256, 6, 3), dim3(32, 32)>>>(Wval, Woff, Wattn, Wout, W1, W2,
                                                     wth, wtl, 3);
    biascat_kernel<<<NLAYERS, 384>>>(boff, battn, biasoa);
    flatten_pair<<<dim3(16384/32 + 4096/32, 8, BATCH), dim3(32, 32)>>>(
        src[0], posin[0], 16384, 0, 0, src[1], posin[1], 4096, 16384, 1,
        lemb, out, pos, outh, qh);
    flatten_pair<<<dim3(1024/32 + 256/32, 8, BATCH), dim3(32, 32)>>>(
        src[2], posin[2], 1024, 20480, 2, src[3], posin[3], 256, 21504, 3,
        lemb, out, pos, outh, qh);

    for (int i = 0; i < NLAYERS; i++) {
        const __half* bh = wth + (size_t)i * WT_LAYER;
        const __half* bl = wtl + (size_t)i * WT_LAYER;
        // value (fp16 out) = outh @ Wval + bval      (N=256: 2 cols x 74 CTAs)
        tc_gemm_pers<0,1><<<148, 256, PERS_SMEM_H>>>(outh, bh + WT_VAL, bl + WT_VAL,
                                                     bval + i * 256, (float*)valh, 256, 74);
        // [off|awl] = qh @ [Woff|Wattn] + [boff|battn]  (N=384: 3 cols x 49)
        tc_gemm_pers<0,0><<<147, 256, PERS_SMEM_H>>>(qh, bh + WT_OFF, bl + WT_OFF,
                                                     biasoa + i * 384, offawl, 384, 49);
        // deformable sampling (fp16 values in, fp16 samp out)
        sample_kernel<<<M_TOT * NH / 8, 256>>>(valh, offawl, samph);
        // attn out = samph @ Wout + bout
        tc_gemm_pers<0,0><<<148, 256, PERS_SMEM_H>>>(samph, bh + WT_OUT, bl + WT_OUT,
                                                     bout + i * 256, tmp, 256, 74);
        // out = LN(out + attn); emit outh (no qh needed before W1)
        resid_ln_kernel<<<(M_TOT + 7) / 8, 256>>>(tmp, out, ln1s + i * 256,
                                                  ln1b + i * 256, out, outh,
                                                  nullptr, nullptr, M_TOT);
        // h(fp16) = relu(outh @ W1 + b1)             (N=1024: 8 cols x 18 CTAs)
        tc_gemm_pers<1,1><<<144, 256, PERS_SMEM_H>>>(outh, bh + WT_W1, bl + WT_W1,
                                                     b1 + i * 1024, (float*)ffh, 1024, 18);
        // ff = h(fp16) @ W2 + b2                     (K=1024: streaming fp16-A)
        tc_gemm_h<0><<<dim3(M_TOT / 128, 2), 256, TCGH_SMEM>>>(ffh, bh + WT_W2, bl + WT_W2,
                                                               b2 + i * 256, tmp, M_TOT, 256, 1024);
        // out = LN(out + ff); emit outh + qh for next layer
        resid_ln_kernel<<<(M_TOT + 7) / 8, 256>>>(tmp, out, ln2s + i * 256,
                                                  ln2b + i * 256, out, outh,
                                                  pos, qh, M_TOT);
    }
}

// round 14
// speedup vs baseline: 3.4891x; 1.1092x over previous
#include <cuda_runtime.h>
#include <cuda_fp16.h>
#include <math.h>
#include <stdint.h>

// ---------------------------------------------------------------------------
// MSDeformAttn transformer encoder (6 layers).
// All GEMMs full-fp16 tcgen05 kind::f16 (fp32 accum), 1 MMA per K64 chunk.
// K=256: persistent-B (B hi resident 64KB, 2 CTAs/SM). W2: streaming.
// Residual stream mirrored in fp16 (outh/qh) by LN.
// sm_103a arch-feature guarded; SIMT fallback otherwise.
// D=256, NH=8, NL=4, NP=4, DH=32, DFF=1024, B=2, S=21760.
// ---------------------------------------------------------------------------

#define D_MODEL 256
#define NH 8
#define DFF 1024
#define NLAYERS 6
#define BATCH 2
#define S_TOTAL 21760
#define M_TOT (BATCH * S_TOTAL)   // 43520 rows; 340 M-tiles of 128

#if defined(__CUDA_ARCH_FEAT_SM103_ALL) || defined(__CUDA_ARCH_FEAT_SM100_ALL) || defined(__CUDA_ARCH_FEAT_SM101_ALL)
#define HAS_TCGEN05 1
#else
#define HAS_TCGEN05 0
#endif

// Scratch (allocation-free: __device__ globals)
__device__ float  g_pos[M_TOT * D_MODEL];
__device__ __half g_outh[M_TOT * D_MODEL];        // fp16 residual stream
__device__ __half g_qh[M_TOT * D_MODEL];          // fp16 (out + pos)
__device__ __half g_valh[M_TOT * D_MODEL];        // fp16 value tensor
__device__ float  g_offawl[M_TOT * 384];          // [off 256 | awl 128] per row
__device__ __half g_samph[M_TOT * D_MODEL];       // fp16 sampled tensor
__device__ float  g_tmp[M_TOT * D_MODEL];
__device__ __half g_ffh[M_TOT * DFF];             // fp16 FF hidden
__device__ float  g_biasoa[NLAYERS * 384];        // [boff 256 | battn 128]

// Transposed fp16 weights: per layer 753664 elements
#define WT_LAYER 753664
__device__ __half g_wth[NLAYERS * WT_LAYER];
#define WT_VAL  0
#define WT_OFF  65536      // rows 0..255 of combined [384,256] (attn follows)
#define WT_ATTN 131072
#define WT_OUT  163840
#define WT_W1   229376
#define WT_W2   491520

// ---------------------------------------------------------------------------
// PTX helpers
// ---------------------------------------------------------------------------
__device__ __forceinline__ uint32_t elect_one_pred() {
    uint32_t pred;
    asm volatile(
        "{\n\t.reg .pred p;\n\telect.sync _|p, 0xFFFFFFFF;\n\t"
        "selp.b32 %0, 1, 0, p;\n\t}" : "=r"(pred));
    return pred;
}
__device__ __forceinline__ uint32_t smem_to_u32(const void* p) {
    uint32_t a;
    asm("{ .reg .u64 t; cvta.to.shared.u64 t, %1; cvt.u32.u64 %0, t; }"
        : "=r"(a) : "l"(p));
    return a;
}

#define TCGEN05_ALLOC(addr, n) \
    asm volatile("tcgen05.alloc.cta_group::1.sync.aligned.shared::cta.b32 [%0], %1;" \
                 :: "r"((uint32_t)(addr)), "r"((uint32_t)(n)) : "memory")
#define TCGEN05_DEALLOC(tmem, n) \
    asm volatile("tcgen05.dealloc.cta_group::1.sync.aligned.b32 %0, %1;" \
                 :: "r"(tmem), "r"((uint32_t)(n)))
#define TCGEN05_RELINQ() \
    asm volatile("tcgen05.relinquish_alloc_permit.cta_group::1.sync.aligned;")
#define TCGEN05_COMMIT(mbar) \
    asm volatile("tcgen05.commit.cta_group::1.mbarrier::arrive::one.shared::cluster.b64 [%0];" \
                 :: "r"((uint32_t)(mbar)) : "memory")
#define TCGEN05_FENCE_AFTER() \
    asm volatile("tcgen05.fence::after_thread_sync;" ::: "memory")
#define TCGEN05_FENCE_BEFORE() \
    asm volatile("tcgen05.fence::before_thread_sync;" ::: "memory")
#define TCGEN05_WAIT_LD() \
    asm volatile("tcgen05.wait::ld.sync.aligned;" ::: "memory")
#define FENCE_PROXY_ASYNC() \
    asm volatile("fence.proxy.async.shared::cta;" ::: "memory")
#define MBARRIER_INIT(mbar, cnt) \
    asm volatile("mbarrier.init.shared.b64 [%0], %1;" \
                 :: "r"((uint32_t)(mbar)), "r"((uint32_t)(cnt)) : "memory")
#define MBARRIER_INVAL(mbar) \
    asm volatile("mbarrier.inval.shared.b64 [%0];" :: "r"((uint32_t)(mbar)) : "memory")

#define MBARRIER_WAIT_PARITY(mbar, parity) do {                               \
    uint32_t _m = (uint32_t)(mbar);                                           \
    uint32_t _p = (uint32_t)(parity);                                         \
    asm volatile(                                                             \
        "{\n\t.reg .pred P1;\n\t"                                             \
        "WAIT_LOOP_%=:\n\t"                                                   \
        "mbarrier.try_wait.parity.acquire.cta.shared::cta.b64 P1, [%0], %1, 0x989680;\n\t" \
        "@P1 bra.uni WAIT_DONE_%=;\n\t"                                       \
        "bra.uni WAIT_LOOP_%=;\n\t"                                           \
        "WAIT_DONE_%=:\n\t}"                                                  \
        :: "r"(_m), "r"(_p) : "memory");                                      \
} while (0)

// fp16 SS MMA (fp32 accum), cta_group::1
#define TCGEN05_MMA_F16_SS(d, ad, bd, id, en) do {                            \
    uint32_t _e = (en) ? 1u : 0u; uint32_t _z = 0;                            \
    asm volatile(                                                             \
        "{\n\t.reg .pred p;\n\tsetp.ne.u32 p, %5, 0;\n\t"                     \
        "tcgen05.mma.cta_group::1.kind::f16 [%0], %1, %2, %3, {%4,%4,%4,%4}, p;\n\t}" \
        :: "r"(d), "l"(ad), "l"(bd), "r"(id), "r"(_z), "r"(_e) : "memory");   \
} while (0)

#define TCGEN05_LD32(r, addr)                                                 \
    asm volatile(                                                             \
        "tcgen05.ld.sync.aligned.32x32b.x32.b32 "                             \
        "{%0, %1, %2, %3, %4, %5, %6, %7, "                                   \
        " %8, %9, %10, %11, %12, %13, %14, %15, "                             \
        " %16, %17, %18, %19, %20, %21, %22, %23, "                           \
        " %24, %25, %26, %27, %28, %29, %30, %31}, [%32];"                    \
        : "=r"((r)[0]),  "=r"((r)[1]),  "=r"((r)[2]),  "=r"((r)[3]),          \
          "=r"((r)[4]),  "=r"((r)[5]),  "=r"((r)[6]),  "=r"((r)[7]),          \
          "=r"((r)[8]),  "=r"((r)[9]),  "=r"((r)[10]), "=r"((r)[11]),         \
          "=r"((r)[12]), "=r"((r)[13]), "=r"((r)[14]), "=r"((r)[15]),         \
          "=r"((r)[16]), "=r"((r)[17]), "=r"((r)[18]), "=r"((r)[19]),         \
          "=r"((r)[20]), "=r"((r)[21]), "=r"((r)[22]), "=r"((r)[23]),         \
          "=r"((r)[24]), "=r"((r)[25]), "=r"((r)[26]), "=r"((r)[27]),         \
          "=r"((r)[28]), "=r"((r)[29]), "=r"((r)[30]), "=r"((r)[31])          \
        : "r"(addr))

// SW128 K-major smem descriptor: layout=2, version=1, SBO=64, LBO=1
__device__ __forceinline__ uint64_t make_sw128_desc(uint32_t addr) {
    const uint64_t base = (uint64_t(2) << 61) | (uint64_t(1) << 46)
                        | (uint64_t(64) << 32) | (uint64_t(1) << 16);
    return base | ((uint64_t)(addr >> 4) & 0x3FFF);
}

#define TCG_IDESC 0x8200010u

// Epilogue store of 4 consecutive cols (float or half)
template <int RELU, int OUTH>
__device__ __forceinline__ void epi_store4(float* Cf, size_t idx, float4 o) {
    if (RELU) {
        o.x = fmaxf(o.x, 0.f); o.y = fmaxf(o.y, 0.f);
        o.z = fmaxf(o.z, 0.f); o.w = fmaxf(o.w, 0.f);
    }
    if (OUTH) {
        __half2 h0 = __halves2half2(__float2half_rn(o.x), __float2half_rn(o.y));
        __half2 h1 = __halves2half2(__float2half_rn(o.z), __float2half_rn(o.w));
        uint2 u; u.x = *(uint32_t*)&h0; u.y = *(uint32_t*)&h1;
        *(uint2*)((__half*)Cf + idx) = u;
    } else {
        *(float4*)(Cf + idx) = o;
    }
}

// ---------------------------------------------------------------------------
// Streaming GEMM, full fp16: used for W2 (K=1024, A = ffh half).
// Per K64 chunk: 1 MMA. Stage = AH 16K + BH 16K = 32K.
// ---------------------------------------------------------------------------
#define HOFF_AH 0
#define HOFF_BH 16384
#define HSTAGE  32768
#define TCGH_SMEM (1024 + 2 * HSTAGE)   // 66560

template <int RELU>
__global__ __launch_bounds__(256, 1)
void tc_gemm_h(const __half* __restrict__ A,
               const __half* __restrict__ WH,
               const float* __restrict__ bias, float* __restrict__ C,
               int M, int N, int K) {
    extern __shared__ char smem[];
    const int tid  = threadIdx.x;
    const int brow = blockIdx.x * 128;
    const int bcol = blockIdx.y * 128;

    const int lr = tid >> 3;
    const int c8 = (tid & 7) * 8;
    const __half* Ab  = A  + (size_t)(brow + lr) * K + c8;
    const __half* BHb = WH + (size_t)(bcol + lr) * K + c8;
    const int KT = K >> 6;

    uint4 ua[4], bh[4];

#define HLDG_TILE(kt) do {                                                    \
    int _k = (kt) * 64;                                                       \
    _Pragma("unroll")                                                         \
    for (int i = 0; i < 4; i++) {                                             \
        size_t ro = (size_t)(i * 32) * K + _k;                                \
        ua[i] = *(const uint4*)(Ab + ro);                                     \
        bh[i] = *(const uint4*)(BHb + ro);                                    \
    }                                                                         \
} while (0)

#if HAS_TCGEN05
    const uint32_t sbase = smem_to_u32(smem);
    const int wid  = tid >> 5;
    const int lane = tid & 31;

    const uint32_t TMEMP = sbase;
    const uint32_t MBAR0 = sbase + 8;
    const uint32_t MBAR1 = sbase + 16;
    const uint32_t STG0  = sbase + 1024;

    if (wid == 0) TCGEN05_ALLOC(TMEMP, 128);
    if (tid == 0) { MBARRIER_INIT(MBAR0, 1); MBARRIER_INIT(MBAR1, 1); }
    __syncthreads();
    uint32_t tmem;
    asm volatile("ld.shared.b32 %0, [%1];" : "=r"(tmem) : "r"(TMEMP));
    if (wid == 0) TCGEN05_RELINQ();

    uint32_t swoff[4];
#pragma unroll
    for (int i = 0; i < 4; i++) {
        uint32_t off = (uint32_t)(i * 32 + lr) * 128 + (tid & 7) * 16;
        swoff[i] = off ^ ((off >> 3) & 0x70);
    }

    int ph0 = 0, ph1 = 0;

#define HSTS_TILE(stoff) do {                                                 \
    char* _sb = smem + 1024 + (stoff);                                        \
    _Pragma("unroll")                                                         \
    for (int i = 0; i < 4; i++) {                                             \
        *(uint4*)(_sb + HOFF_AH + swoff[i]) = ua[i];                          \
        *(uint4*)(_sb + HOFF_BH + swoff[i]) = bh[i];                          \
    }                                                                         \
} while (0)

    HLDG_TILE(0);
    HSTS_TILE(0);
    FENCE_PROXY_ASYNC();
    __syncthreads();

    for (int kt = 0; kt < KT; kt++) {
        int s = kt & 1;
        bool have_next = (kt + 1 < KT);
        if (have_next) HLDG_TILE(kt + 1);

        if (wid == 0) {
            if (elect_one_pred()) {
                uint32_t sb = STG0 + s * HSTAGE;
                uint64_t dah = make_sw128_desc(sb + HOFF_AH);
                uint64_t dbh = make_sw128_desc(sb + HOFF_BH);
#pragma unroll
                for (int ks = 0; ks < 4; ks++) {
                    TCGEN05_MMA_F16_SS(tmem, dah + ks * 2, dbh + ks * 2,
                                       TCG_IDESC, (kt > 0) || (ks > 0));
                }
                TCGEN05_COMMIT(s == 0 ? MBAR0 : MBAR1);
            }
        }

        if (have_next) {
            int ns = s ^ 1;
            if (kt >= 1) {
                if (ns == 0) { MBARRIER_WAIT_PARITY(MBAR0, ph0); ph0 ^= 1; }
                else         { MBARRIER_WAIT_PARITY(MBAR1, ph1); ph1 ^= 1; }
            }
            HSTS_TILE(ns * HSTAGE);
            FENCE_PROXY_ASYNC();
            __syncthreads();
        }
    }

    if (((KT - 1) & 1) == 0) { MBARRIER_WAIT_PARITY(MBAR0, ph0); }
    else                     { MBARRIER_WAIT_PARITY(MBAR1, ph1); }
    TCGEN05_FENCE_AFTER();

    {
        int colbase = (wid >> 2) * 64;
        uint32_t d0[32], d1[32];
        TCGEN05_LD32(d0, tmem + colbase);
        TCGEN05_LD32(d1, tmem + colbase + 32);
        TCGEN05_WAIT_LD();
        TCGEN05_FENCE_BEFORE();

        int r = brow + (wid & 3) * 32 + lane;
        size_t base = (size_t)r * N + bcol + colbase;
        const float* bb = bias + bcol + colbase;
#pragma unroll
        for (int c = 0; c < 32; c += 4) {
            float4 o;
            o.x = __uint_as_float(d0[c + 0]) + bb[c + 0];
            o.y = __uint_as_float(d0[c + 1]) + bb[c + 1];
            o.z = __uint_as_float(d0[c + 2]) + bb[c + 2];
            o.w = __uint_as_float(d0[c + 3]) + bb[c + 3];
            epi_store4<RELU, 0>(C, base + c, o);
        }
#pragma unroll
        for (int c = 0; c < 32; c += 4) {
            float4 o;
            o.x = __uint_as_float(d1[c + 0]) + bb[32 + c + 0];
            o.y = __uint_as_float(d1[c + 1]) + bb[32 + c + 1];
            o.z = __uint_as_float(d1[c + 2]) + bb[32 + c + 2];
            o.w = __uint_as_float(d1[c + 3]) + bb[32 + c + 3];
            epi_store4<RELU, 0>(C, base + 32 + c, o);
        }
    }

    __syncthreads();
    if (tid == 0) { MBARRIER_INVAL(MBAR0); MBARRIER_INVAL(MBAR1); }
    __syncthreads();
    if (wid == 0) TCGEN05_DEALLOC(tmem, 128);

#else  // SIMT fallback
    float (*As)[132] = (float(*)[132])(smem);
    float (*Bs)[132] = (float(*)[132])(smem + 64 * 132 * 4);

    int ty = (tid >> 4) * 8;
    int tx = (tid & 15) * 8;

    float acc[8][8];
#pragma unroll
    for (int i = 0; i < 8; i++)
#pragma unroll
        for (int j = 0; j < 8; j++) acc[i][j] = 0.f;

    for (int kt = 0; kt < KT; kt++) {
        HLDG_TILE(kt);
        __syncthreads();
#pragma unroll
        for (int i = 0; i < 4; i++) {
            int r = i * 32 + lr;
            const __half* ha = (const __half*)&ua[i];
            const __half* hh = (const __half*)&bh[i];
#pragma unroll
            for (int j = 0; j < 8; j++) {
                As[c8 + j][r] = __half2float(ha[j]);
                Bs[c8 + j][r] = __half2float(hh[j]);
            }
        }
        __syncthreads();
#pragma unroll 16
        for (int k = 0; k < 64; k++) {
            float av[8], bv[8];
#pragma unroll
            for (int i = 0; i < 8; i++) { av[i] = As[k][ty + i]; bv[i] = Bs[k][tx + i]; }
#pragma unroll
            for (int i = 0; i < 8; i++)
#pragma unroll
                for (int j = 0; j < 8; j++)
                    acc[i][j] += av[i] * bv[j];
        }
    }

    int row = brow + ty;
    int col = bcol + tx;
#pragma unroll
    for (int i = 0; i < 8; i++) {
#pragma unroll
        for (int j = 0; j < 8; j++) {
            float v = acc[i][j] + bias[col + j];
            if (RELU) v = fmaxf(v, 0.f);
            C[(size_t)(row + i) * N + col + j] = v;
        }
    }
#endif
}

// ---------------------------------------------------------------------------
// Persistent-B GEMM, full fp16, 1 MMA per K64 chunk. K=256.
// OUTH=1 emits __half output.
// SMEM: 1024 hdr + 65536 B + 2x16384 A = 99328 -> 2 CTAs/SM.
// ---------------------------------------------------------------------------
#define PERS_SMEM_H 99328
#define MT_TILES (M_TOT / 128)   // 340

template <int RELU, int OUTH>
__global__ __launch_bounds__(256)
void tc_gemm_pers(const __half* __restrict__ A,
                  const __half* __restrict__ WH,
                  const float* __restrict__ bias, float* __restrict__ C,
                  int N, int CPC) {
    extern __shared__ char smem[];
    const int tid = threadIdx.x;
    const int K = 256;
    const int col = blockIdx.x / CPC;
    const int cid = blockIdx.x % CPC;
    const int bcol = col * 128;
    constexpr int ASTAGE = 16384;

    const int lr  = tid >> 3;
    const int c16 = tid & 7;
    const uint32_t swr = (uint32_t)lr * 128 + (uint32_t)((c16 ^ (lr & 7)) * 16);

#if HAS_TCGEN05
    const uint32_t sbase = smem_to_u32(smem);
    const int wid = tid >> 5, lane = tid & 31;
    const uint32_t TMEMP = sbase;
    const uint32_t MBAR0 = sbase + 8;
    const uint32_t MBAR1 = sbase + 16;
    const uint32_t BH_S  = sbase + 1024;
    const uint32_t AST   = BH_S + 65536;

    if (wid == 0) TCGEN05_ALLOC(TMEMP, 128);
    if (tid == 0) { MBARRIER_INIT(MBAR0, 1); MBARRIER_INIT(MBAR1, 1); }
    __syncthreads();
    uint32_t tmem;
    asm volatile("ld.shared.b32 %0, [%1];" : "=r"(tmem) : "r"(TMEMP));
    if (wid == 0) TCGEN05_RELINQ();

    // Load resident B hi: 4 K64 sub-tiles of 16KB
    {
        const __half* BHb = WH + (size_t)(bcol + lr) * K + c16 * 8;
#pragma unroll
        for (int kt = 0; kt < 4; kt++) {
#pragma unroll
            for (int i = 0; i < 4; i++) {
                size_t ro = (size_t)(i * 32) * K + kt * 64;
                uint32_t so = (uint32_t)kt * 16384 + swr + (uint32_t)i * 4096;
                *(uint4*)(smem + 1024 + so) = *(const uint4*)(BHb + ro);
            }
        }
    }
    FENCE_PROXY_ASYNC();
    __syncthreads();

    int g = 0;
    for (int m = cid; m < MT_TILES; m += CPC) {
        const int brow = m * 128;
        const __half* Ahb = A + (size_t)(brow + lr) * K + c16 * 8;

#pragma unroll 1
        for (int kt = 0; kt < 4; kt++, g++) {
            const int s = g & 1;
            uint4 ua[4];
#pragma unroll
            for (int i = 0; i < 4; i++)
                ua[i] = *(const uint4*)(Ahb + (size_t)(i * 32) * K + kt * 64);

            if (g >= 2) {
                MBARRIER_WAIT_PARITY(s ? MBAR1 : MBAR0, ((g >> 1) - 1) & 1);
            }
            char* sb = smem + 1024 + 65536 + s * ASTAGE;
#pragma unroll
            for (int i = 0; i < 4; i++)
                *(uint4*)(sb + swr + i * 4096) = ua[i];
            FENCE_PROXY_ASYNC();
            __syncthreads();

            if (wid == 0) {
                if (elect_one_pred()) {
                    uint64_t dah = make_sw128_desc(AST + s * ASTAGE);
                    uint64_t dbh = make_sw128_desc(BH_S + kt * 16384);
#pragma unroll
                    for (int ks = 0; ks < 4; ks++) {
                        TCGEN05_MMA_F16_SS(tmem, dah + ks * 2, dbh + ks * 2,
                                           TCG_IDESC, (kt > 0) || (ks > 0));
                    }
                    TCGEN05_COMMIT(s ? MBAR1 : MBAR0);
                }
            }
        }

        {
            int gl = g - 1;
            MBARRIER_WAIT_PARITY((gl & 1) ? MBAR1 : MBAR0, (gl >> 1) & 1);
            TCGEN05_FENCE_AFTER();

            int colbase = (wid >> 2) * 64;
            uint32_t d0[32], d1[32];
            TCGEN05_LD32(d0, tmem + colbase);
            TCGEN05_LD32(d1, tmem + colbase + 32);
            TCGEN05_WAIT_LD();
            TCGEN05_FENCE_BEFORE();

            int r = brow + (wid & 3) * 32 + lane;
            size_t cb = (size_t)r * N + bcol + colbase;
            const float* bb = bias + bcol + colbase;
#pragma unroll
            for (int c = 0; c < 32; c += 4) {
                float4 o;
                o.x = __uint_as_float(d0[c + 0]) + bb[c + 0];
                o.y = __uint_as_float(d0[c + 1]) + bb[c + 1];
                o.z = __uint_as_float(d0[c + 2]) + bb[c + 2];
                o.w = __uint_as_float(d0[c + 3]) + bb[c + 3];
                epi_store4<RELU, OUTH>(C, cb + c, o);
            }
#pragma unroll
            for (int c = 0; c < 32; c += 4) {
                float4 o;
                o.x = __uint_as_float(d1[c + 0]) + bb[32 + c + 0];
                o.y = __uint_as_float(d1[c + 1]) + bb[32 + c + 1];
                o.z = __uint_as_float(d1[c + 2]) + bb[32 + c + 2];
                o.w = __uint_as_float(d1[c + 3]) + bb[32 + c + 3];
                epi_store4<RELU, OUTH>(C, cb + 32 + c, o);
            }
            __syncthreads();
        }
    }

    __syncthreads();
    if (tid == 0) { MBARRIER_INVAL(MBAR0); MBARRIER_INVAL(MBAR1); }
    __syncthreads();
    if (wid == 0) TCGEN05_DEALLOC(tmem, 128);

#else  // SIMT fallback
    float (*As)[132] = (float(*)[132])(smem);
    float (*Bs)[132] = (float(*)[132])(smem + 64 * 132 * 4);
    int ty = (tid >> 4) * 8;
    int tx = (tid & 15) * 8;

    for (int m = cid; m < MT_TILES; m += CPC) {
        int brow = m * 128;
        float acc[8][8];
#pragma unroll
        for (int i = 0; i < 8; i++)
#pragma unroll
            for (int j = 0; j < 8; j++) acc[i][j] = 0.f;

        for (int kt = 0; kt < 4; kt++) {
            __syncthreads();
#pragma unroll
            for (int i = 0; i < 4; i++) {
                int row = i * 32 + lr;
                size_t aro = (size_t)(brow + row) * K + kt * 64 + c16 * 8;
                size_t bro = (size_t)(bcol + row) * K + kt * 64 + c16 * 8;
#pragma unroll
                for (int j = 0; j < 8; j++) {
                    As[c16 * 8 + j][row] = __half2float(A[aro + j]);
                    Bs[c16 * 8 + j][row] = __half2float(WH[bro + j]);
                }
            }
            __syncthreads();
#pragma unroll 16
            for (int k = 0; k < 64; k++) {
                float av[8], bv[8];
#pragma unroll
                for (int i = 0; i < 8; i++) { av[i] = As[k][ty + i]; bv[i] = Bs[k][tx + i]; }
#pragma unroll
                for (int i = 0; i < 8; i++)
#pragma unroll
                    for (int j = 0; j < 8; j++)
                        acc[i][j] += av[i] * bv[j];
            }
        }
        int row = brow + ty;
        int cc  = bcol + tx;
#pragma unroll
        for (int i = 0; i < 8; i++)
#pragma unroll
            for (int j = 0; j < 8; j++) {
                float v = acc[i][j] + bias[cc + j];
                if (RELU) v = fmaxf(v, 0.f);
                if (OUTH) ((__half*)C)[(size_t)(row + i) * N + cc + j] = __float2half_rn(v);
                else      C[(size_t)(row + i) * N + cc + j] = v;
            }
        __syncthreads();
    }
#endif
}

// ---------------------------------------------------------------------------
// Fused weight transpose + fp16 convert (all 6 types, 3 layers per launch)
// ---------------------------------------------------------------------------
__global__ void transplit_all(const float* __restrict__ Wval, const float* __restrict__ Woff,
                              const float* __restrict__ Wattn, const float* __restrict__ Wout,
                              const float* __restrict__ W1, const float* __restrict__ W2,
                              __half* __restrict__ wth, int layer0) {
    int type  = blockIdx.y;
    int layer = layer0 + blockIdx.z;
    const float* W; int K, N, off;
    switch (type) {
        case 0: W = Wval  + (size_t)layer * 65536;  K = 256;  N = 256;  off = WT_VAL;  break;
        case 1: W = Woff  + (size_t)layer * 65536;  K = 256;  N = 256;  off = WT_OFF;  break;
        case 2: W = Wattn + (size_t)layer * 32768;  K = 256;  N = 128;  off = WT_ATTN; break;
        case 3: W = Wout  + (size_t)layer * 65536;  K = 256;  N = 256;  off = WT_OUT;  break;
        case 4: W = W1    + (size_t)layer * 262144; K = 256;  N = 1024; off = WT_W1;   break;
        default: W = W2   + (size_t)layer * 262144; K = 1024; N = 256;  off = WT_W2;   break;
    }
    int tK = K >> 5, tN = N >> 5;
    int t = blockIdx.x;
    if (t >= tK * tN) return;
    int k0 = (t % tK) * 32, n0 = (t / tK) * 32;

    __shared__ float tile[32][33];
    tile[threadIdx.y][threadIdx.x] = W[(size_t)(k0 + threadIdx.y) * N + n0 + threadIdx.x];
    __syncthreads();
    float v = tile[threadIdx.x][threadIdx.y];
    size_t o = (size_t)layer * WT_LAYER + off + (size_t)(n0 + threadIdx.y) * K + k0 + threadIdx.x;
    wth[o] = __float2half_rn(v);
}

// Bias concat: g_biasoa[l][0..255]=boff, [256..383]=battn
__global__ void biascat_kernel(const float* __restrict__ boff,
                               const float* __restrict__ battn,
                               float* __restrict__ dst) {
    int l = blockIdx.x, j = threadIdx.x;
    dst[l * 384 + j] = (j < 256) ? boff[l * 256 + j] : battn[l * 128 + j - 256];
}

// ---------------------------------------------------------------------------
// Flatten pair of levels: src [B, D, h, w] -> out [B, S, D]; pos + level_embed.
// Also seeds the fp16 residual mirrors: outh = fp16(out), qh = fp16(out+pos).
// ---------------------------------------------------------------------------
__global__ void flatten_pair(const float* __restrict__ sA, const float* __restrict__ pA,
                             int hwA, int stA, int lvA,
                             const float* __restrict__ sB, const float* __restrict__ pB,
                             int hwB, int stB, int lvB,
                             const float* __restrict__ lemb,
                             float* __restrict__ out, float* __restrict__ posout,
                             __half* __restrict__ outh, __half* __restrict__ qh) {
    __shared__ float ts[32][33];
    __shared__ float tp[32][33];
    int px = blockIdx.x;
    const float *src, *pos; int hw, start, level, p0;
    int tA = hwA >> 5;
    if (px < tA) { src = sA; pos = pA; hw = hwA; start = stA; level = lvA; p0 = px * 32; }
    else         { src = sB; pos = pB; hw = hwB; start = stB; level = lvB; p0 = (px - tA) * 32; }

    int b  = blockIdx.z;
    int d0 = blockIdx.y * 32;
    int tx = threadIdx.x, ty = threadIdx.y;

    const float* sp = src + ((size_t)b * D_MODEL + d0 + ty) * hw + p0;
    const float* pp = pos + ((size_t)b * D_MODEL + d0 + ty) * hw + p0;
    ts[ty][tx] = sp[tx];
    tp[ty][tx] = pp[tx];
    __syncthreads();

    int d = d0 + tx;
    float le = lemb[level * D_MODEL + d];
    size_t srow = (size_t)b * S_TOTAL + start + p0 + ty;
    float v = ts[tx][ty];
    float p = tp[tx][ty] + le;
    out[srow * D_MODEL + d]    = v;
    posout[srow * D_MODEL + d] = p;
    outh[srow * D_MODEL + d]   = __float2half_rn(v);
    qh[srow * D_MODEL + d]     = __float2half_rn(v + p);
}

// ---------------------------------------------------------------------------
// Residual + LayerNorm: out = LN(x + r) * gamma + beta. One warp per row.
// Also emits outh = fp16(out); if Qh != null, qh = fp16(out + pos).
// ---------------------------------------------------------------------------
__global__ void resid_ln_kernel(const float* __restrict__ X, const float* __restrict__ R,
                                const float* __restrict__ g, const float* __restrict__ bt,
                                float* __restrict__ O, __half* __restrict__ Oh,
                                const float* __restrict__ P, __half* __restrict__ Qh,
                                int rows) {
    int warp = (blockIdx.x * blockDim.x + threadIdx.x) >> 5;
    int lane = threadIdx.x & 31;
    if (warp >= rows) return;
    const float* xr = X + (size_t)warp * D_MODEL;
    const float* rr = R + (size_t)warp * D_MODEL;

    float v[8];
    float s = 0.f, s2 = 0.f;
#pragma unroll
    for (int u = 0; u < 2; u++) {
        float4 a = *(const float4*)(xr + lane * 4 + u * 128);
        float4 c = *(const float4*)(rr + lane * 4 + u * 128);
        float t0 = a.x + c.x, t1 = a.y + c.y, t2 = a.z + c.z, t3 = a.w + c.w;
        v[u * 4 + 0] = t0; v[u * 4 + 1] = t1; v[u * 4 + 2] = t2; v[u * 4 + 3] = t3;
        s += t0 + t1 + t2 + t3;
        s2 += t0 * t0 + t1 * t1 + t2 * t2 + t3 * t3;
    }
#pragma unroll
    for (int o = 16; o > 0; o >>= 1) {
        s  += __shfl_xor_sync(0xffffffffu, s, o);
        s2 += __shfl_xor_sync(0xffffffffu, s2, o);
    }
    float mean = s * (1.f / D_MODEL);
    float var  = s2 * (1.f / D_MODEL) - mean * mean;
    float inv  = rsqrtf(var + 1e-5f);
#pragma unroll
    for (int u = 0; u < 2; u++) {
        int d = lane * 4 + u * 128;
        float4 o4;
        o4.x = (v[u * 4 + 0] - mean) * inv * g[d + 0] + bt[d + 0];
        o4.y = (v[u * 4 + 1] - mean) * inv * g[d + 1] + bt[d + 1];
        o4.z = (v[u * 4 + 2] - mean) * inv * g[d + 2] + bt[d + 2];
        o4.w = (v[u * 4 + 3] - mean) * inv * g[d + 3] + bt[d + 3];
        *(float4*)(O + (size_t)warp * D_MODEL + d) = o4;

        __half2 h0 = __halves2half2(__float2half_rn(o4.x), __float2half_rn(o4.y));
        __half2 h1 = __halves2half2(__float2half_rn(o4.z), __float2half_rn(o4.w));
        uint2 uo; uo.x = *(uint32_t*)&h0; uo.y = *(uint32_t*)&h1;
        *(uint2*)(Oh + (size_t)warp * D_MODEL + d) = uo;

        if (Qh) {
            float4 p4 = *(const float4*)(P + (size_t)warp * D_MODEL + d);
            __half2 q0 = __halves2half2(__float2half_rn(o4.x + p4.x),
                                        __float2half_rn(o4.y + p4.y));
            __half2 q1 = __halves2half2(__float2half_rn(o4.z + p4.z),
                                        __float2half_rn(o4.w + p4.w));
            uint2 uq; uq.x = *(uint32_t*)&q0; uq.y = *(uint32_t*)&q1;
            *(uint2*)(Qh + (size_t)warp * D_MODEL + d) = uq;
        }
    }
}

// ---------------------------------------------------------------------------
// Deformable sampling, fp16 values in, fp16 samp out. One warp per (token, head).
// ---------------------------------------------------------------------------
__constant__ int c_lw[4]     = {128, 64, 32, 16};
__constant__ int c_lstart[4] = {0, 16384, 20480, 21504};

__global__ void sample_kernel(const __half* __restrict__ Valh,
                              const float* __restrict__ OA,
                              __half* __restrict__ Samph) {
    __shared__ int2 tab[8][16][4];
    int gw   = (blockIdx.x * blockDim.x + threadIdx.x) >> 5;
    int lane = threadIdx.x & 31;
    int wpb  = threadIdx.x >> 5;
    if (gw >= M_TOT * NH) return;
    int h   = gw & 7;
    int tok = gw >> 3;
    int s   = tok % S_TOTAL;
    int b   = tok / S_TOTAL;

    int wt, st, sh;
    if (s < 16384)      { wt = 128; st = 0;     sh = 7; }
    else if (s < 20480) { wt = 64;  st = 16384; sh = 6; }
    else if (s < 21504) { wt = 32;  st = 20480; sh = 5; }
    else                { wt = 16;  st = 21504; sh = 4; }
    int sl = s - st;
    int iy = sl >> sh;
    int ix = sl - (iy << sh);
    float refx = (ix + 0.5f) / (float)wt;
    float refy = (iy + 0.5f) / (float)wt;

    size_t rb = (size_t)tok;

    float lv = (lane < 16) ? OA[rb * 384 + 256 + h * 16 + lane] : -1e30f;
    float m = lv;
#pragma unroll
    for (int o = 8; o > 0; o >>= 1) m = fmaxf(m, __shfl_xor_sync(0xffffffffu, m, o));
    float e = (lane < 16) ? expf(lv - m) : 0.f;
    float ssum = e;
#pragma unroll
    for (int o = 8; o > 0; o >>= 1) ssum += __shfl_xor_sync(0xffffffffu, ssum, o);
    float aw = e / ssum;

    if (lane < 16) {
        int l   = lane >> 2;
        int wl  = c_lw[l];
        int stl = c_lstart[l];
        float ox = OA[rb * 384 + (size_t)(h * 16 + lane) * 2 + 0];
        float oy = OA[rb * 384 + (size_t)(h * 16 + lane) * 2 + 1];
        float x = refx * (float)wl + ox - 0.5f;
        float y = refy * (float)wl + oy - 0.5f;
        float xf = floorf(x), yf = floorf(y);
        float lx = x - xf, ly = y - yf;
        int x0 = (int)xf, y0 = (int)yf;
        int x1 = x0 + 1, y1 = y0 + 1;
        bool okx0 = (x0 >= 0) & (x0 < wl);
        bool okx1 = (x1 >= 0) & (x1 < wl);
        bool oky0 = (y0 >= 0) & (y0 < wl);
        bool oky1 = (y1 >= 0) & (y1 < wl);
        int cx0 = min(max(x0, 0), wl - 1), cx1 = min(max(x1, 0), wl - 1);
        int cy0 = min(max(y0, 0), wl - 1), cy1 = min(max(y1, 0), wl - 1);
        float w0 = (1.f - lx) * (1.f - ly) * aw * ((okx0 && oky0) ? 1.f : 0.f);
        float w1 = lx * (1.f - ly) * aw * ((okx1 && oky0) ? 1.f : 0.f);
        float w2 = (1.f - lx) * ly * aw * ((okx0 && oky1) ? 1.f : 0.f);
        float w3 = lx * ly * aw * ((okx1 && oky1) ? 1.f : 0.f);
        tab[wpb][lane][0] = make_int2(stl + cy0 * wl + cx0, __float_as_int(w0));
        tab[wpb][lane][1] = make_int2(stl + cy0 * wl + cx1, __float_as_int(w1));
        tab[wpb][lane][2] = make_int2(stl + cy1 * wl + cx0, __float_as_int(w2));
        tab[wpb][lane][3] = make_int2(stl + cy1 * wl + cx1, __float_as_int(w3));
    }
    __syncwarp();

    int t   = lane >> 3;
    int ch4 = lane & 7;
    const __half* vb = Valh + (size_t)b * S_TOTAL * 256 + h * 32 + ch4 * 4;
    float4 acc = make_float4(0.f, 0.f, 0.f, 0.f);
#pragma unroll
    for (int j = 0; j < 16; j++) {
        int2 ee = tab[wpb][j][t];
        uint2 u = *(const uint2*)(vb + (size_t)ee.x * 256);
        __half2 p0 = *(__half2*)&u.x;
        __half2 p1 = *(__half2*)&u.y;
        float2 f0 = __half22float2(p0);
        float2 f1 = __half22float2(p1);
        float f = __int_as_float(ee.y);
        acc.x += f * f0.x; acc.y += f * f0.y;
        acc.z += f * f1.x; acc.w += f * f1.y;
    }
#pragma unroll
    for (int msk = 8; msk <= 16; msk <<= 1) {
        acc.x += __shfl_xor_sync(0xffffffffu, acc.x, msk);
        acc.y += __shfl_xor_sync(0xffffffffu, acc.y, msk);
        acc.z += __shfl_xor_sync(0xffffffffu, acc.z, msk);
        acc.w += __shfl_xor_sync(0xffffffffu, acc.w, msk);
    }
    if (lane < 8) {
        __half2 h0 = __halves2half2(__float2half_rn(acc.x), __float2half_rn(acc.y));
        __half2 h1 = __halves2half2(__float2half_rn(acc.z), __float2half_rn(acc.w));
        uint2 u; u.x = *(uint32_t*)&h0; u.y = *(uint32_t*)&h1;
        ((uint2*)(Samph + (size_t)tok * 256 + h * 32))[ch4] = u;
    }
}

// ---------------------------------------------------------------------------
// Host orchestration
// ---------------------------------------------------------------------------
extern "C" void kernel_launch(void* const* d_in, const int* in_sizes, int n_in,
                              void* d_out, int out_size) {
    const float* src[4];
    const float* posin[4];
    bool interleaved = (in_sizes[1] == in_sizes[0]);
    for (int l = 0; l < 4; l++) {
        if (interleaved) {
            src[l]   = (const float*)d_in[2 * l];
            posin[l] = (const float*)d_in[2 * l + 1];
        } else {
            src[l]   = (const float*)d_in[l];
            posin[l] = (const float*)d_in[4 + l];
        }
    }
    const float* lemb  = (const float*)d_in[8];
    const float* Woff  = (const float*)d_in[9];
    const float* boff  = (const float*)d_in[10];
    const float* Wattn = (const float*)d_in[11];
    const float* battn = (const float*)d_in[12];
    const float* Wval  = (const float*)d_in[13];
    const float* bval  = (const float*)d_in[14];
    const float* Wout  = (const float*)d_in[15];
    const float* bout  = (const float*)d_in[16];
    const float* ln1s  = (const float*)d_in[17];
    const float* ln1b  = (const float*)d_in[18];
    const float* W1    = (const float*)d_in[19];
    const float* b1    = (const float*)d_in[20];
    const float* W2    = (const float*)d_in[21];
    const float* b2    = (const float*)d_in[22];
    const float* ln2s  = (const float*)d_in[23];
    const float* ln2b  = (const float*)d_in[24];

    float* out = (float*)d_out;

    float *pos, *offawl, *tmp, *biasoa;
    __half *outh, *qh, *valh, *samph, *ffh, *wth;
    cudaGetSymbolAddress((void**)&pos,    g_pos);
    cudaGetSymbolAddress((void**)&outh,   g_outh);
    cudaGetSymbolAddress((void**)&qh,     g_qh);
    cudaGetSymbolAddress((void**)&valh,   g_valh);
    cudaGetSymbolAddress((void**)&offawl, g_offawl);
    cudaGetSymbolAddress((void**)&samph,  g_samph);
    cudaGetSymbolAddress((void**)&tmp,    g_tmp);
    cudaGetSymbolAddress((void**)&ffh,    g_ffh);
    cudaGetSymbolAddress((void**)&biasoa, g_biasoa);
    cudaGetSymbolAddress((void**)&wth,    g_wth);

    cudaFuncSetAttribute((tc_gemm_h<0>),      cudaFuncAttributeMaxDynamicSharedMemorySize, TCGH_SMEM);
    cudaFuncSetAttribute((tc_gemm_pers<0,0>), cudaFuncAttributeMaxDynamicSharedMemorySize, PERS_SMEM_H);
    cudaFuncSetAttribute((tc_gemm_pers<0,1>), cudaFuncAttributeMaxDynamicSharedMemorySize, PERS_SMEM_H);
    cudaFuncSetAttribute((tc_gemm_pers<1,1>), cudaFuncAttributeMaxDynamicSharedMemorySize, PERS_SMEM_H);

    // Prologue: 5 launches
    transplit_all<<<dim3(256, 6, 3), dim3(32, 32)>>>(Wval, Woff, Wattn, Wout, W1, W2,
                                                     wth, 0);
    transplit_all<<<dim3(256, 6, 3), dim3(32, 32)>>>(Wval, Woff, Wattn, Wout, W1, W2,
                                                     wth, 3);
    biascat_kernel<<<NLAYERS, 384>>>(boff, battn, biasoa);
    flatten_pair<<<dim3(16384/32 + 4096/32, 8, BATCH), dim3(32, 32)>>>(
        src[0], posin[0], 16384, 0, 0, src[1], posin[1], 4096, 16384, 1,
        lemb, out, pos, outh, qh);
    flatten_pair<<<dim3(1024/32 + 256/32, 8, BATCH), dim3(32, 32)>>>(
        src[2], posin[2], 1024, 20480, 2, src[3], posin[3], 256, 21504, 3,
        lemb, out, pos, outh, qh);

    for (int i = 0; i < NLAYERS; i++) {
        const __half* bh = wth + (size_t)i * WT_LAYER;
        // value (fp16 out) = outh @ Wval + bval      (2 cols x 148 CTAs, 2/SM)
        tc_gemm_pers<0,1><<<296, 256, PERS_SMEM_H>>>(outh, bh + WT_VAL,
                                                     bval + i * 256, (float*)valh, 256, 148);
        // [off|awl] = qh @ [Woff|Wattn] + biases     (3 cols x 98 CTAs)
        tc_gemm_pers<0,0><<<294, 256, PERS_SMEM_H>>>(qh, bh + WT_OFF,
                                                     biasoa + i * 384, offawl, 384, 98);
        // deformable sampling (fp16 values in, fp16 samp out)
        sample_kernel<<<M_TOT * NH / 8, 256>>>(valh, offawl, samph);
        // attn out = samph @ Wout + bout             (2 cols x 148 CTAs)
        tc_gemm_pers<0,0><<<296, 256, PERS_SMEM_H>>>(samph, bh + WT_OUT,
                                                     bout + i * 256, tmp, 256, 148);
        // out = LN(out + attn); emit outh
        resid_ln_kernel<<<(M_TOT + 7) / 8, 256>>>(tmp, out, ln1s + i * 256,
                                                  ln1b + i * 256, out, outh,
                                                  nullptr, nullptr, M_TOT);
        // h(fp16) = relu(outh @ W1 + b1)             (8 cols x 37 CTAs)
        tc_gemm_pers<1,1><<<296, 256, PERS_SMEM_H>>>(outh, bh + WT_W1,
                                                     b1 + i * 1024, (float*)ffh, 1024, 37);
        // ff = h(fp16) @ W2 + b2                     (K=1024: streaming)
        tc_gemm_h<0><<<dim3(M_TOT / 128, 2), 256, TCGH_SMEM>>>(ffh, bh + WT_W2,
                                                               b2 + i * 256, tmp, M_TOT, 256, 1024);
        // out = LN(out + ff); emit outh + qh for next layer
        resid_ln_kernel<<<(M_TOT + 7) / 8, 256>>>(tmp, out, ln2s + i * 256,
                                                  ln2b + i * 256, out, outh,
                                                  pos, qh, M_TOT);
    }
}

// round 15
// speedup vs baseline: 3.6871x; 1.0567x over previous
#include <cuda_runtime.h>
#include <cuda_fp16.h>
#include <math.h>
#include <stdint.h>

// ---------------------------------------------------------------------------
// MSDeformAttn transformer encoder (6 layers).
// All GEMMs full-fp16 tcgen05 kind::f16 (fp32 accum), 1 MMA per K64 chunk.
// K=256: persistent-B (B hi resident 64KB, 2 CTAs/SM). W2: streaming.
// Residual stream mirrored in fp16 (outh/qh); branch outputs (tmp) fp16.
// sm_103a arch-feature guarded; SIMT fallback otherwise.
// D=256, NH=8, NL=4, NP=4, DH=32, DFF=1024, B=2, S=21760.
// ---------------------------------------------------------------------------

#define D_MODEL 256
#define NH 8
#define DFF 1024
#define NLAYERS 6
#define BATCH 2
#define S_TOTAL 21760
#define M_TOT (BATCH * S_TOTAL)   // 43520 rows; 340 M-tiles of 128

#if defined(__CUDA_ARCH_FEAT_SM103_ALL) || defined(__CUDA_ARCH_FEAT_SM100_ALL) || defined(__CUDA_ARCH_FEAT_SM101_ALL)
#define HAS_TCGEN05 1
#else
#define HAS_TCGEN05 0
#endif

// Scratch (allocation-free: __device__ globals)
__device__ __half g_posh[M_TOT * D_MODEL];        // fp16 positional stream
__device__ __half g_outh[M_TOT * D_MODEL];        // fp16 residual stream
__device__ __half g_qh[M_TOT * D_MODEL];          // fp16 (out + pos)
__device__ __half g_valh[M_TOT * D_MODEL];        // fp16 value tensor
__device__ float  g_offawl[M_TOT * 384];          // [off 256 | awl 128] per row
__device__ __half g_samph[M_TOT * D_MODEL];       // fp16 sampled tensor
__device__ __half g_tmph[M_TOT * D_MODEL];        // fp16 branch output
__device__ __half g_ffh[M_TOT * DFF];             // fp16 FF hidden
__device__ float  g_biasoa[NLAYERS * 384];        // [boff 256 | battn 128]

// Transposed fp16 weights: per layer 753664 elements
#define WT_LAYER 753664
__device__ __half g_wth[NLAYERS * WT_LAYER];
#define WT_VAL  0
#define WT_OFF  65536      // rows 0..255 of combined [384,256] (attn follows)
#define WT_ATTN 131072
#define WT_OUT  163840
#define WT_W1   229376
#define WT_W2   491520

// ---------------------------------------------------------------------------
// PTX helpers
// ---------------------------------------------------------------------------
__device__ __forceinline__ uint32_t elect_one_pred() {
    uint32_t pred;
    asm volatile(
        "{\n\t.reg .pred p;\n\telect.sync _|p, 0xFFFFFFFF;\n\t"
        "selp.b32 %0, 1, 0, p;\n\t}" : "=r"(pred));
    return pred;
}
__device__ __forceinline__ uint32_t smem_to_u32(const void* p) {
    uint32_t a;
    asm("{ .reg .u64 t; cvta.to.shared.u64 t, %1; cvt.u32.u64 %0, t; }"
        : "=r"(a) : "l"(p));
    return a;
}

#define TCGEN05_ALLOC(addr, n) \
    asm volatile("tcgen05.alloc.cta_group::1.sync.aligned.shared::cta.b32 [%0], %1;" \
                 :: "r"((uint32_t)(addr)), "r"((uint32_t)(n)) : "memory")
#define TCGEN05_DEALLOC(tmem, n) \
    asm volatile("tcgen05.dealloc.cta_group::1.sync.aligned.b32 %0, %1;" \
                 :: "r"(tmem), "r"((uint32_t)(n)))
#define TCGEN05_RELINQ() \
    asm volatile("tcgen05.relinquish_alloc_permit.cta_group::1.sync.aligned;")
#define TCGEN05_COMMIT(mbar) \
    asm volatile("tcgen05.commit.cta_group::1.mbarrier::arrive::one.shared::cluster.b64 [%0];" \
                 :: "r"((uint32_t)(mbar)) : "memory")
#define TCGEN05_FENCE_AFTER() \
    asm volatile("tcgen05.fence::after_thread_sync;" ::: "memory")
#define TCGEN05_FENCE_BEFORE() \
    asm volatile("tcgen05.fence::before_thread_sync;" ::: "memory")
#define TCGEN05_WAIT_LD() \
    asm volatile("tcgen05.wait::ld.sync.aligned;" ::: "memory")
#define FENCE_PROXY_ASYNC() \
    asm volatile("fence.proxy.async.shared::cta;" ::: "memory")
#define MBARRIER_INIT(mbar, cnt) \
    asm volatile("mbarrier.init.shared.b64 [%0], %1;" \
                 :: "r"((uint32_t)(mbar)), "r"((uint32_t)(cnt)) : "memory")
#define MBARRIER_INVAL(mbar) \
    asm volatile("mbarrier.inval.shared.b64 [%0];" :: "r"((uint32_t)(mbar)) : "memory")

#define MBARRIER_WAIT_PARITY(mbar, parity) do {                               \
    uint32_t _m = (uint32_t)(mbar);                                           \
    uint32_t _p = (uint32_t)(parity);                                         \
    asm volatile(                                                             \
        "{\n\t.reg .pred P1;\n\t"                                             \
        "WAIT_LOOP_%=:\n\t"                                                   \
        "mbarrier.try_wait.parity.acquire.cta.shared::cta.b64 P1, [%0], %1, 0x989680;\n\t" \
        "@P1 bra.uni WAIT_DONE_%=;\n\t"                                       \
        "bra.uni WAIT_LOOP_%=;\n\t"                                           \
        "WAIT_DONE_%=:\n\t}"                                                  \
        :: "r"(_m), "r"(_p) : "memory");                                      \
} while (0)

// fp16 SS MMA (fp32 accum), cta_group::1
#define TCGEN05_MMA_F16_SS(d, ad, bd, id, en) do {                            \
    uint32_t _e = (en) ? 1u : 0u; uint32_t _z = 0;                            \
    asm volatile(                                                             \
        "{\n\t.reg .pred p;\n\tsetp.ne.u32 p, %5, 0;\n\t"                     \
        "tcgen05.mma.cta_group::1.kind::f16 [%0], %1, %2, %3, {%4,%4,%4,%4}, p;\n\t}" \
        :: "r"(d), "l"(ad), "l"(bd), "r"(id), "r"(_z), "r"(_e) : "memory");   \
} while (0)

#define TCGEN05_LD32(r, addr)                                                 \
    asm volatile(                                                             \
        "tcgen05.ld.sync.aligned.32x32b.x32.b32 "                             \
        "{%0, %1, %2, %3, %4, %5, %6, %7, "                                   \
        " %8, %9, %10, %11, %12, %13, %14, %15, "                             \
        " %16, %17, %18, %19, %20, %21, %22, %23, "                           \
        " %24, %25, %26, %27, %28, %29, %30, %31}, [%32];"                    \
        : "=r"((r)[0]),  "=r"((r)[1]),  "=r"((r)[2]),  "=r"((r)[3]),          \
          "=r"((r)[4]),  "=r"((r)[5]),  "=r"((r)[6]),  "=r"((r)[7]),          \
          "=r"((r)[8]),  "=r"((r)[9]),  "=r"((r)[10]), "=r"((r)[11]),         \
          "=r"((r)[12]), "=r"((r)[13]), "=r"((r)[14]), "=r"((r)[15]),         \
          "=r"((r)[16]), "=r"((r)[17]), "=r"((r)[18]), "=r"((r)[19]),         \
          "=r"((r)[20]), "=r"((r)[21]), "=r"((r)[22]), "=r"((r)[23]),         \
          "=r"((r)[24]), "=r"((r)[25]), "=r"((r)[26]), "=r"((r)[27]),         \
          "=r"((r)[28]), "=r"((r)[29]), "=r"((r)[30]), "=r"((r)[31])          \
        : "r"(addr))

// SW128 K-major smem descriptor: layout=2, version=1, SBO=64, LBO=1
__device__ __forceinline__ uint64_t make_sw128_desc(uint32_t addr) {
    const uint64_t base = (uint64_t(2) << 61) | (uint64_t(1) << 46)
                        | (uint64_t(64) << 32) | (uint64_t(1) << 16);
    return base | ((uint64_t)(addr >> 4) & 0x3FFF);
}

#define TCG_IDESC 0x8200010u

// Epilogue store of 4 consecutive cols (float or half)
template <int RELU, int OUTH>
__device__ __forceinline__ void epi_store4(float* Cf, size_t idx, float4 o) {
    if (RELU) {
        o.x = fmaxf(o.x, 0.f); o.y = fmaxf(o.y, 0.f);
        o.z = fmaxf(o.z, 0.f); o.w = fmaxf(o.w, 0.f);
    }
    if (OUTH) {
        __half2 h0 = __halves2half2(__float2half_rn(o.x), __float2half_rn(o.y));
        __half2 h1 = __halves2half2(__float2half_rn(o.z), __float2half_rn(o.w));
        uint2 u; u.x = *(uint32_t*)&h0; u.y = *(uint32_t*)&h1;
        *(uint2*)((__half*)Cf + idx) = u;
    } else {
        *(float4*)(Cf + idx) = o;
    }
}

// ---------------------------------------------------------------------------
// Streaming GEMM, full fp16: used for W2 (K=1024, A = ffh half).
// Per K64 chunk: 1 MMA. Stage = AH 16K + BH 16K = 32K.
// ---------------------------------------------------------------------------
#define HOFF_AH 0
#define HOFF_BH 16384
#define HSTAGE  32768
#define TCGH_SMEM (1024 + 2 * HSTAGE)   // 66560

template <int RELU, int OUTH>
__global__ __launch_bounds__(256)
void tc_gemm_h(const __half* __restrict__ A,
               const __half* __restrict__ WH,
               const float* __restrict__ bias, float* __restrict__ C,
               int M, int N, int K) {
    extern __shared__ char smem[];
    const int tid  = threadIdx.x;
    const int brow = blockIdx.x * 128;
    const int bcol = blockIdx.y * 128;

    const int lr = tid >> 3;
    const int c8 = (tid & 7) * 8;
    const __half* Ab  = A  + (size_t)(brow + lr) * K + c8;
    const __half* BHb = WH + (size_t)(bcol + lr) * K + c8;
    const int KT = K >> 6;

    uint4 ua[4], bh[4];

#define HLDG_TILE(kt) do {                                                    \
    int _k = (kt) * 64;                                                       \
    _Pragma("unroll")                                                         \
    for (int i = 0; i < 4; i++) {                                             \
        size_t ro = (size_t)(i * 32) * K + _k;                                \
        ua[i] = *(const uint4*)(Ab + ro);                                     \
        bh[i] = *(const uint4*)(BHb + ro);                                    \
    }                                                                         \
} while (0)

#if HAS_TCGEN05
    const uint32_t sbase = smem_to_u32(smem);
    const int wid  = tid >> 5;
    const int lane = tid & 31;

    const uint32_t TMEMP = sbase;
    const uint32_t MBAR0 = sbase + 8;
    const uint32_t MBAR1 = sbase + 16;
    const uint32_t STG0  = sbase + 1024;

    if (wid == 0) TCGEN05_ALLOC(TMEMP, 128);
    if (tid == 0) { MBARRIER_INIT(MBAR0, 1); MBARRIER_INIT(MBAR1, 1); }
    __syncthreads();
    uint32_t tmem;
    asm volatile("ld.shared.b32 %0, [%1];" : "=r"(tmem) : "r"(TMEMP));
    if (wid == 0) TCGEN05_RELINQ();

    uint32_t swoff[4];
#pragma unroll
    for (int i = 0; i < 4; i++) {
        uint32_t off = (uint32_t)(i * 32 + lr) * 128 + (tid & 7) * 16;
        swoff[i] = off ^ ((off >> 3) & 0x70);
    }

    int ph0 = 0, ph1 = 0;

#define HSTS_TILE(stoff) do {                                                 \
    char* _sb = smem + 1024 + (stoff);                                        \
    _Pragma("unroll")                                                         \
    for (int i = 0; i < 4; i++) {                                             \
        *(uint4*)(_sb + HOFF_AH + swoff[i]) = ua[i];                          \
        *(uint4*)(_sb + HOFF_BH + swoff[i]) = bh[i];                          \
    }                                                                         \
} while (0)

    HLDG_TILE(0);
    HSTS_TILE(0);
    FENCE_PROXY_ASYNC();
    __syncthreads();

    for (int kt = 0; kt < KT; kt++) {
        int s = kt & 1;
        bool have_next = (kt + 1 < KT);
        if (have_next) HLDG_TILE(kt + 1);

        if (wid == 0) {
            if (elect_one_pred()) {
                uint32_t sb = STG0 + s * HSTAGE;
                uint64_t dah = make_sw128_desc(sb + HOFF_AH);
                uint64_t dbh = make_sw128_desc(sb + HOFF_BH);
#pragma unroll
                for (int ks = 0; ks < 4; ks++) {
                    TCGEN05_MMA_F16_SS(tmem, dah + ks * 2, dbh + ks * 2,
                                       TCG_IDESC, (kt > 0) || (ks > 0));
                }
                TCGEN05_COMMIT(s == 0 ? MBAR0 : MBAR1);
            }
        }

        if (have_next) {
            int ns = s ^ 1;
            if (kt >= 1) {
                if (ns == 0) { MBARRIER_WAIT_PARITY(MBAR0, ph0); ph0 ^= 1; }
                else         { MBARRIER_WAIT_PARITY(MBAR1, ph1); ph1 ^= 1; }
            }
            HSTS_TILE(ns * HSTAGE);
            FENCE_PROXY_ASYNC();
            __syncthreads();
        }
    }

    if (((KT - 1) & 1) == 0) { MBARRIER_WAIT_PARITY(MBAR0, ph0); }
    else                     { MBARRIER_WAIT_PARITY(MBAR1, ph1); }
    TCGEN05_FENCE_AFTER();

    {
        int colbase = (wid >> 2) * 64;
        uint32_t d0[32], d1[32];
        TCGEN05_LD32(d0, tmem + colbase);
        TCGEN05_LD32(d1, tmem + colbase + 32);
        TCGEN05_WAIT_LD();
        TCGEN05_FENCE_BEFORE();

        int r = brow + (wid & 3) * 32 + lane;
        size_t base = (size_t)r * N + bcol + colbase;
        const float* bb = bias + bcol + colbase;
#pragma unroll
        for (int c = 0; c < 32; c += 4) {
            float4 o;
            o.x = __uint_as_float(d0[c + 0]) + bb[c + 0];
            o.y = __uint_as_float(d0[c + 1]) + bb[c + 1];
            o.z = __uint_as_float(d0[c + 2]) + bb[c + 2];
            o.w = __uint_as_float(d0[c + 3]) + bb[c + 3];
            epi_store4<RELU, OUTH>(C, base + c, o);
        }
#pragma unroll
        for (int c = 0; c < 32; c += 4) {
            float4 o;
            o.x = __uint_as_float(d1[c + 0]) + bb[32 + c + 0];
            o.y = __uint_as_float(d1[c + 1]) + bb[32 + c + 1];
            o.z = __uint_as_float(d1[c + 2]) + bb[32 + c + 2];
            o.w = __uint_as_float(d1[c + 3]) + bb[32 + c + 3];
            epi_store4<RELU, OUTH>(C, base + 32 + c, o);
        }
    }

    __syncthreads();
    if (tid == 0) { MBARRIER_INVAL(MBAR0); MBARRIER_INVAL(MBAR1); }
    __syncthreads();
    if (wid == 0) TCGEN05_DEALLOC(tmem, 128);

#else  // SIMT fallback
    float (*As)[132] = (float(*)[132])(smem);
    float (*Bs)[132] = (float(*)[132])(smem + 64 * 132 * 4);

    int ty = (tid >> 4) * 8;
    int tx = (tid & 15) * 8;

    float acc[8][8];
#pragma unroll
    for (int i = 0; i < 8; i++)
#pragma unroll
        for (int j = 0; j < 8; j++) acc[i][j] = 0.f;

    for (int kt = 0; kt < KT; kt++) {
        HLDG_TILE(kt);
        __syncthreads();
#pragma unroll
        for (int i = 0; i < 4; i++) {
            int r = i * 32 + lr;
            const __half* ha = (const __half*)&ua[i];
            const __half* hh = (const __half*)&bh[i];
#pragma unroll
            for (int j = 0; j < 8; j++) {
                As[c8 + j][r] = __half2float(ha[j]);
                Bs[c8 + j][r] = __half2float(hh[j]);
            }
        }
        __syncthreads();
#pragma unroll 16
        for (int k = 0; k < 64; k++) {
            float av[8], bv[8];
#pragma unroll
            for (int i = 0; i < 8; i++) { av[i] = As[k][ty + i]; bv[i] = Bs[k][tx + i]; }
#pragma unroll
            for (int i = 0; i < 8; i++)
#pragma unroll
                for (int j = 0; j < 8; j++)
                    acc[i][j] += av[i] * bv[j];
        }
    }

    int row = brow + ty;
    int col = bcol + tx;
#pragma unroll
    for (int i = 0; i < 8; i++) {
#pragma unroll
        for (int j = 0; j < 8; j++) {
            float v = acc[i][j] + bias[col + j];
            if (RELU) v = fmaxf(v, 0.f);
            if (OUTH) ((__half*)C)[(size_t)(row + i) * N + col + j] = __float2half_rn(v);
            else      C[(size_t)(row + i) * N + col + j] = v;
        }
    }
#endif
}

// ---------------------------------------------------------------------------
// Persistent-B GEMM, full fp16, 1 MMA per K64 chunk. K=256.
// OUTH=1 emits __half output.
// SMEM: 1024 hdr + 65536 B + 2x16384 A = 99328 -> 2 CTAs/SM.
// ---------------------------------------------------------------------------
#define PERS_SMEM_H 99328
#define MT_TILES (M_TOT / 128)   // 340

template <int RELU, int OUTH>
__global__ __launch_bounds__(256)
void tc_gemm_pers(const __half* __restrict__ A,
                  const __half* __restrict__ WH,
                  const float* __restrict__ bias, float* __restrict__ C,
                  int N, int CPC) {
    extern __shared__ char smem[];
    const int tid = threadIdx.x;
    const int K = 256;
    const int col = blockIdx.x / CPC;
    const int cid = blockIdx.x % CPC;
    const int bcol = col * 128;
    constexpr int ASTAGE = 16384;

    const int lr  = tid >> 3;
    const int c16 = tid & 7;
    const uint32_t swr = (uint32_t)lr * 128 + (uint32_t)((c16 ^ (lr & 7)) * 16);

#if HAS_TCGEN05
    const uint32_t sbase = smem_to_u32(smem);
    const int wid = tid >> 5, lane = tid & 31;
    const uint32_t TMEMP = sbase;
    const uint32_t MBAR0 = sbase + 8;
    const uint32_t MBAR1 = sbase + 16;
    const uint32_t BH_S  = sbase + 1024;
    const uint32_t AST   = BH_S + 65536;

    if (wid == 0) TCGEN05_ALLOC(TMEMP, 128);
    if (tid == 0) { MBARRIER_INIT(MBAR0, 1); MBARRIER_INIT(MBAR1, 1); }
    __syncthreads();
    uint32_t tmem;
    asm volatile("ld.shared.b32 %0, [%1];" : "=r"(tmem) : "r"(TMEMP));
    if (wid == 0) TCGEN05_RELINQ();

    // Load resident B hi: 4 K64 sub-tiles of 16KB
    {
        const __half* BHb = WH + (size_t)(bcol + lr) * K + c16 * 8;
#pragma unroll
        for (int kt = 0; kt < 4; kt++) {
#pragma unroll
            for (int i = 0; i < 4; i++) {
                size_t ro = (size_t)(i * 32) * K + kt * 64;
                uint32_t so = (uint32_t)kt * 16384 + swr + (uint32_t)i * 4096;
                *(uint4*)(smem + 1024 + so) = *(const uint4*)(BHb + ro);
            }
        }
    }
    FENCE_PROXY_ASYNC();
    __syncthreads();

    int g = 0;
    for (int m = cid; m < MT_TILES; m += CPC) {
        const int brow = m * 128;
        const __half* Ahb = A + (size_t)(brow + lr) * K + c16 * 8;

#pragma unroll 1
        for (int kt = 0; kt < 4; kt++, g++) {
            const int s = g & 1;
            uint4 ua[4];
#pragma unroll
            for (int i = 0; i < 4; i++)
                ua[i] = *(const uint4*)(Ahb + (size_t)(i * 32) * K + kt * 64);

            if (g >= 2) {
                MBARRIER_WAIT_PARITY(s ? MBAR1 : MBAR0, ((g >> 1) - 1) & 1);
            }
            char* sb = smem + 1024 + 65536 + s * ASTAGE;
#pragma unroll
            for (int i = 0; i < 4; i++)
                *(uint4*)(sb + swr + i * 4096) = ua[i];
            FENCE_PROXY_ASYNC();
            __syncthreads();

            if (wid == 0) {
                if (elect_one_pred()) {
                    uint64_t dah = make_sw128_desc(AST + s * ASTAGE);
                    uint64_t dbh = make_sw128_desc(BH_S + kt * 16384);
#pragma unroll
                    for (int ks = 0; ks < 4; ks++) {
                        TCGEN05_MMA_F16_SS(tmem, dah + ks * 2, dbh + ks * 2,
                                           TCG_IDESC, (kt > 0) || (ks > 0));
                    }
                    TCGEN05_COMMIT(s ? MBAR1 : MBAR0);
                }
            }
        }

        {
            int gl = g - 1;
            MBARRIER_WAIT_PARITY((gl & 1) ? MBAR1 : MBAR0, (gl >> 1) & 1);
            TCGEN05_FENCE_AFTER();

            int colbase = (wid >> 2) * 64;
            uint32_t d0[32], d1[32];
            TCGEN05_LD32(d0, tmem + colbase);
            TCGEN05_LD32(d1, tmem + colbase + 32);
            TCGEN05_WAIT_LD();
            TCGEN05_FENCE_BEFORE();

            int r = brow + (wid & 3) * 32 + lane;
            size_t cb = (size_t)r * N + bcol + colbase;
            const float* bb = bias + bcol + colbase;
#pragma unroll
            for (int c = 0; c < 32; c += 4) {
                float4 o;
                o.x = __uint_as_float(d0[c + 0]) + bb[c + 0];
                o.y = __uint_as_float(d0[c + 1]) + bb[c + 1];
                o.z = __uint_as_float(d0[c + 2]) + bb[c + 2];
                o.w = __uint_as_float(d0[c + 3]) + bb[c + 3];
                epi_store4<RELU, OUTH>(C, cb + c, o);
            }
#pragma unroll
            for (int c = 0; c < 32; c += 4) {
                float4 o;
                o.x = __uint_as_float(d1[c + 0]) + bb[32 + c + 0];
                o.y = __uint_as_float(d1[c + 1]) + bb[32 + c + 1];
                o.z = __uint_as_float(d1[c + 2]) + bb[32 + c + 2];
                o.w = __uint_as_float(d1[c + 3]) + bb[32 + c + 3];
                epi_store4<RELU, OUTH>(C, cb + 32 + c, o);
            }
            __syncthreads();
        }
    }

    __syncthreads();
    if (tid == 0) { MBARRIER_INVAL(MBAR0); MBARRIER_INVAL(MBAR1); }
    __syncthreads();
    if (wid == 0) TCGEN05_DEALLOC(tmem, 128);

#else  // SIMT fallback
    float (*As)[132] = (float(*)[132])(smem);
    float (*Bs)[132] = (float(*)[132])(smem + 64 * 132 * 4);
    int ty = (tid >> 4) * 8;
    int tx = (tid & 15) * 8;

    for (int m = cid; m < MT_TILES; m += CPC) {
        int brow = m * 128;
        float acc[8][8];
#pragma unroll
        for (int i = 0; i < 8; i++)
#pragma unroll
            for (int j = 0; j < 8; j++) acc[i][j] = 0.f;

        for (int kt = 0; kt < 4; kt++) {
            __syncthreads();
#pragma unroll
            for (int i = 0; i < 4; i++) {
                int row = i * 32 + lr;
                size_t aro = (size_t)(brow + row) * K + kt * 64 + c16 * 8;
                size_t bro = (size_t)(bcol + row) * K + kt * 64 + c16 * 8;
#pragma unroll
                for (int j = 0; j < 8; j++) {
                    As[c16 * 8 + j][row] = __half2float(A[aro + j]);
                    Bs[c16 * 8 + j][row] = __half2float(WH[bro + j]);
                }
            }
            __syncthreads();
#pragma unroll 16
            for (int k = 0; k < 64; k++) {
                float av[8], bv[8];
#pragma unroll
                for (int i = 0; i < 8; i++) { av[i] = As[k][ty + i]; bv[i] = Bs[k][tx + i]; }
#pragma unroll
                for (int i = 0; i < 8; i++)
#pragma unroll
                    for (int j = 0; j < 8; j++)
                        acc[i][j] += av[i] * bv[j];
            }
        }
        int row = brow + ty;
        int cc  = bcol + tx;
#pragma unroll
        for (int i = 0; i < 8; i++)
#pragma unroll
            for (int j = 0; j < 8; j++) {
                float v = acc[i][j] + bias[cc + j];
                if (RELU) v = fmaxf(v, 0.f);
                if (OUTH) ((__half*)C)[(size_t)(row + i) * N + cc + j] = __float2half_rn(v);
                else      C[(size_t)(row + i) * N + cc + j] = v;
            }
        __syncthreads();
    }
#endif
}

// ---------------------------------------------------------------------------
// Fused weight transpose + fp16 convert (all 6 types, 3 layers per launch)
// ---------------------------------------------------------------------------
__global__ void transplit_all(const float* __restrict__ Wval, const float* __restrict__ Woff,
                              const float* __restrict__ Wattn, const float* __restrict__ Wout,
                              const float* __restrict__ W1, const float* __restrict__ W2,
                              __half* __restrict__ wth, int layer0) {
    int type  = blockIdx.y;
    int layer = layer0 + blockIdx.z;
    const float* W; int K, N, off;
    switch (type) {
        case 0: W = Wval  + (size_t)layer * 65536;  K = 256;  N = 256;  off = WT_VAL;  break;
        case 1: W = Woff  + (size_t)layer * 65536;  K = 256;  N = 256;  off = WT_OFF;  break;
        case 2: W = Wattn + (size_t)layer * 32768;  K = 256;  N = 128;  off = WT_ATTN; break;
        case 3: W = Wout  + (size_t)layer * 65536;  K = 256;  N = 256;  off = WT_OUT;  break;
        case 4: W = W1    + (size_t)layer * 262144; K = 256;  N = 1024; off = WT_W1;   break;
        default: W = W2   + (size_t)layer * 262144; K = 1024; N = 256;  off = WT_W2;   break;
    }
    int tK = K >> 5, tN = N >> 5;
    int t = blockIdx.x;
    if (t >= tK * tN) return;
    int k0 = (t % tK) * 32, n0 = (t / tK) * 32;

    __shared__ float tile[32][33];
    tile[threadIdx.y][threadIdx.x] = W[(size_t)(k0 + threadIdx.y) * N + n0 + threadIdx.x];
    __syncthreads();
    float v = tile[threadIdx.x][threadIdx.y];
    size_t o = (size_t)layer * WT_LAYER + off + (size_t)(n0 + threadIdx.y) * K + k0 + threadIdx.x;
    wth[o] = __float2half_rn(v);
}

// Bias concat: g_biasoa[l][0..255]=boff, [256..383]=battn
__global__ void biascat_kernel(const float* __restrict__ boff,
                               const float* __restrict__ battn,
                               float* __restrict__ dst) {
    int l = blockIdx.x, j = threadIdx.x;
    dst[l * 384 + j] = (j < 256) ? boff[l * 256 + j] : battn[l * 128 + j - 256];
}

// ---------------------------------------------------------------------------
// Flatten pair of levels: src [B, D, h, w] -> out [B, S, D]; pos(h) + level_embed.
// Also seeds the fp16 residual mirrors: outh = fp16(out), qh = fp16(out+pos).
// ---------------------------------------------------------------------------
__global__ void flatten_pair(const float* __restrict__ sA, const float* __restrict__ pA,
                             int hwA, int stA, int lvA,
                             const float* __restrict__ sB, const float* __restrict__ pB,
                             int hwB, int stB, int lvB,
                             const float* __restrict__ lemb,
                             float* __restrict__ out, __half* __restrict__ posouth,
                             __half* __restrict__ outh, __half* __restrict__ qh) {
    __shared__ float ts[32][33];
    __shared__ float tp[32][33];
    int px = blockIdx.x;
    const float *src, *pos; int hw, start, level, p0;
    int tA = hwA >> 5;
    if (px < tA) { src = sA; pos = pA; hw = hwA; start = stA; level = lvA; p0 = px * 32; }
    else         { src = sB; pos = pB; hw = hwB; start = stB; level = lvB; p0 = (px - tA) * 32; }

    int b  = blockIdx.z;
    int d0 = blockIdx.y * 32;
    int tx = threadIdx.x, ty = threadIdx.y;

    const float* sp = src + ((size_t)b * D_MODEL + d0 + ty) * hw + p0;
    const float* pp = pos + ((size_t)b * D_MODEL + d0 + ty) * hw + p0;
    ts[ty][tx] = sp[tx];
    tp[ty][tx] = pp[tx];
    __syncthreads();

    int d = d0 + tx;
    float le = lemb[level * D_MODEL + d];
    size_t srow = (size_t)b * S_TOTAL + start + p0 + ty;
    float v = ts[tx][ty];
    float p = tp[tx][ty] + le;
    out[srow * D_MODEL + d]      = v;
    posouth[srow * D_MODEL + d]  = __float2half_rn(p);
    outh[srow * D_MODEL + d]     = __float2half_rn(v);
    qh[srow * D_MODEL + d]       = __float2half_rn(v + p);
}

// ---------------------------------------------------------------------------
// Residual + LayerNorm: out = LN(xh + r) * gamma + beta. One warp per row.
// xh is fp16 branch output. Emits outh = fp16(out); if Qh != null,
// qh = fp16(out + posh).
// ---------------------------------------------------------------------------
__global__ void resid_ln_kernel(const __half* __restrict__ Xh, const float* __restrict__ R,
                                const float* __restrict__ g, const float* __restrict__ bt,
                                float* __restrict__ O, __half* __restrict__ Oh,
                                const __half* __restrict__ Ph, __half* __restrict__ Qh,
                                int rows) {
    int warp = (blockIdx.x * blockDim.x + threadIdx.x) >> 5;
    int lane = threadIdx.x & 31;
    if (warp >= rows) return;
    const __half* xr = Xh + (size_t)warp * D_MODEL;
    const float*  rr = R  + (size_t)warp * D_MODEL;

    float v[8];
    float s = 0.f, s2 = 0.f;
#pragma unroll
    for (int u = 0; u < 2; u++) {
        uint2 ux = *(const uint2*)(xr + lane * 4 + u * 128);
        float2 xa = __half22float2(*(__half2*)&ux.x);
        float2 xb = __half22float2(*(__half2*)&ux.y);
        float4 c = *(const float4*)(rr + lane * 4 + u * 128);
        float t0 = xa.x + c.x, t1 = xa.y + c.y, t2 = xb.x + c.z, t3 = xb.y + c.w;
        v[u * 4 + 0] = t0; v[u * 4 + 1] = t1; v[u * 4 + 2] = t2; v[u * 4 + 3] = t3;
        s += t0 + t1 + t2 + t3;
        s2 += t0 * t0 + t1 * t1 + t2 * t2 + t3 * t3;
    }
#pragma unroll
    for (int o = 16; o > 0; o >>= 1) {
        s  += __shfl_xor_sync(0xffffffffu, s, o);
        s2 += __shfl_xor_sync(0xffffffffu, s2, o);
    }
    float mean = s * (1.f / D_MODEL);
    float var  = s2 * (1.f / D_MODEL) - mean * mean;
    float inv  = rsqrtf(var + 1e-5f);
#pragma unroll
    for (int u = 0; u < 2; u++) {
        int d = lane * 4 + u * 128;
        float4 o4;
        o4.x = (v[u * 4 + 0] - mean) * inv * g[d + 0] + bt[d + 0];
        o4.y = (v[u * 4 + 1] - mean) * inv * g[d + 1] + bt[d + 1];
        o4.z = (v[u * 4 + 2] - mean) * inv * g[d + 2] + bt[d + 2];
        o4.w = (v[u * 4 + 3] - mean) * inv * g[d + 3] + bt[d + 3];
        *(float4*)(O + (size_t)warp * D_MODEL + d) = o4;

        __half2 h0 = __halves2half2(__float2half_rn(o4.x), __float2half_rn(o4.y));
        __half2 h1 = __halves2half2(__float2half_rn(o4.z), __float2half_rn(o4.w));
        uint2 uo; uo.x = *(uint32_t*)&h0; uo.y = *(uint32_t*)&h1;
        *(uint2*)(Oh + (size_t)warp * D_MODEL + d) = uo;

        if (Qh) {
            uint2 up = *(const uint2*)(Ph + (size_t)warp * D_MODEL + d);
            float2 pa = __half22float2(*(__half2*)&up.x);
            float2 pb = __half22float2(*(__half2*)&up.y);
            __half2 q0 = __halves2half2(__float2half_rn(o4.x + pa.x),
                                        __float2half_rn(o4.y + pa.y));
            __half2 q1 = __halves2half2(__float2half_rn(o4.z + pb.x),
                                        __float2half_rn(o4.w + pb.y));
            uint2 uq; uq.x = *(uint32_t*)&q0; uq.y = *(uint32_t*)&q1;
            *(uint2*)(Qh + (size_t)warp * D_MODEL + d) = uq;
        }
    }
}

// ---------------------------------------------------------------------------
// Deformable sampling, fp16 values in, fp16 samp out. One warp per (token, head).
// ---------------------------------------------------------------------------
__constant__ int c_lw[4]     = {128, 64, 32, 16};
__constant__ int c_lstart[4] = {0, 16384, 20480, 21504};

__global__ void sample_kernel(const __half* __restrict__ Valh,
                              const float* __restrict__ OA,
                              __half* __restrict__ Samph) {
    __shared__ int2 tab[8][16][4];
    int gw   = (blockIdx.x * blockDim.x + threadIdx.x) >> 5;
    int lane = threadIdx.x & 31;
    int wpb  = threadIdx.x >> 5;
    if (gw >= M_TOT * NH) return;
    int h   = gw & 7;
    int tok = gw >> 3;
    int s   = tok % S_TOTAL;
    int b   = tok / S_TOTAL;

    int wt, st, sh;
    if (s < 16384)      { wt = 128; st = 0;     sh = 7; }
    else if (s < 20480) { wt = 64;  st = 16384; sh = 6; }
    else if (s < 21504) { wt = 32;  st = 20480; sh = 5; }
    else                { wt = 16;  st = 21504; sh = 4; }
    int sl = s - st;
    int iy = sl >> sh;
    int ix = sl - (iy << sh);
    float refx = (ix + 0.5f) / (float)wt;
    float refy = (iy + 0.5f) / (float)wt;

    size_t rb = (size_t)tok;

    float lv = (lane < 16) ? OA[rb * 384 + 256 + h * 16 + lane] : -1e30f;
    float m = lv;
#pragma unroll
    for (int o = 8; o > 0; o >>= 1) m = fmaxf(m, __shfl_xor_sync(0xffffffffu, m, o));
    float e = (lane < 16) ? expf(lv - m) : 0.f;
    float ssum = e;
#pragma unroll
    for (int o = 8; o > 0; o >>= 1) ssum += __shfl_xor_sync(0xffffffffu, ssum, o);
    float aw = e / ssum;

    if (lane < 16) {
        int l   = lane >> 2;
        int wl  = c_lw[l];
        int stl = c_lstart[l];
        float ox = OA[rb * 384 + (size_t)(h * 16 + lane) * 2 + 0];
        float oy = OA[rb * 384 + (size_t)(h * 16 + lane) * 2 + 1];
        float x = refx * (float)wl + ox - 0.5f;
        float y = refy * (float)wl + oy - 0.5f;
        float xf = floorf(x), yf = floorf(y);
        float lx = x - xf, ly = y - yf;
        int x0 = (int)xf, y0 = (int)yf;
        int x1 = x0 + 1, y1 = y0 + 1;
        bool okx0 = (x0 >= 0) & (x0 < wl);
        bool okx1 = (x1 >= 0) & (x1 < wl);
        bool oky0 = (y0 >= 0) & (y0 < wl);
        bool oky1 = (y1 >= 0) & (y1 < wl);
        int cx0 = min(max(x0, 0), wl - 1), cx1 = min(max(x1, 0), wl - 1);
        int cy0 = min(max(y0, 0), wl - 1), cy1 = min(max(y1, 0), wl - 1);
        float w0 = (1.f - lx) * (1.f - ly) * aw * ((okx0 && oky0) ? 1.f : 0.f);
        float w1 = lx * (1.f - ly) * aw * ((okx1 && oky0) ? 1.f : 0.f);
        float w2 = (1.f - lx) * ly * aw * ((okx0 && oky1) ? 1.f : 0.f);
        float w3 = lx * ly * aw * ((okx1 && oky1) ? 1.f : 0.f);
        tab[wpb][lane][0] = make_int2(stl + cy0 * wl + cx0, __float_as_int(w0));
        tab[wpb][lane][1] = make_int2(stl + cy0 * wl + cx1, __float_as_int(w1));
        tab[wpb][lane][2] = make_int2(stl + cy1 * wl + cx0, __float_as_int(w2));
        tab[wpb][lane][3] = make_int2(stl + cy1 * wl + cx1, __float_as_int(w3));
    }
    __syncwarp();

    int t   = lane >> 3;
    int ch4 = lane & 7;
    const __half* vb = Valh + (size_t)b * S_TOTAL * 256 + h * 32 + ch4 * 4;
    float4 acc = make_float4(0.f, 0.f, 0.f, 0.f);
#pragma unroll
    for (int j = 0; j < 16; j++) {
        int2 ee = tab[wpb][j][t];
        uint2 u = *(const uint2*)(vb + (size_t)ee.x * 256);
        __half2 p0 = *(__half2*)&u.x;
        __half2 p1 = *(__half2*)&u.y;
        float2 f0 = __half22float2(p0);
        float2 f1 = __half22float2(p1);
        float f = __int_as_float(ee.y);
        acc.x += f * f0.x; acc.y += f * f0.y;
        acc.z += f * f1.x; acc.w += f * f1.y;
    }
#pragma unroll
    for (int msk = 8; msk <= 16; msk <<= 1) {
        acc.x += __shfl_xor_sync(0xffffffffu, acc.x, msk);
        acc.y += __shfl_xor_sync(0xffffffffu, acc.y, msk);
        acc.z += __shfl_xor_sync(0xffffffffu, acc.z, msk);
        acc.w += __shfl_xor_sync(0xffffffffu, acc.w, msk);
    }
    if (lane < 8) {
        __half2 h0 = __halves2half2(__float2half_rn(acc.x), __float2half_rn(acc.y));
        __half2 h1 = __halves2half2(__float2half_rn(acc.z), __float2half_rn(acc.w));
        uint2 u; u.x = *(uint32_t*)&h0; u.y = *(uint32_t*)&h1;
        ((uint2*)(Samph + (size_t)tok * 256 + h * 32))[ch4] = u;
    }
}

// ---------------------------------------------------------------------------
// Host orchestration
// ---------------------------------------------------------------------------
extern "C" void kernel_launch(void* const* d_in, const int* in_sizes, int n_in,
                              void* d_out, int out_size) {
    const float* src[4];
    const float* posin[4];
    bool interleaved = (in_sizes[1] == in_sizes[0]);
    for (int l = 0; l < 4; l++) {
        if (interleaved) {
            src[l]   = (const float*)d_in[2 * l];
            posin[l] = (const float*)d_in[2 * l + 1];
        } else {
            src[l]   = (const float*)d_in[l];
            posin[l] = (const float*)d_in[4 + l];
        }
    }
    const float* lemb  = (const float*)d_in[8];
    const float* Woff  = (const float*)d_in[9];
    const float* boff  = (const float*)d_in[10];
    const float* Wattn = (const float*)d_in[11];
    const float* battn = (const float*)d_in[12];
    const float* Wval  = (const float*)d_in[13];
    const float* bval  = (const float*)d_in[14];
    const float* Wout  = (const float*)d_in[15];
    const float* bout  = (const float*)d_in[16];
    const float* ln1s  = (const float*)d_in[17];
    const float* ln1b  = (const float*)d_in[18];
    const float* W1    = (const float*)d_in[19];
    const float* b1    = (const float*)d_in[20];
    const float* W2    = (const float*)d_in[21];
    const float* b2    = (const float*)d_in[22];
    const float* ln2s  = (const float*)d_in[23];
    const float* ln2b  = (const float*)d_in[24];

    float* out = (float*)d_out;

    float *offawl, *biasoa;
    __half *posh, *outh, *qh, *valh, *samph, *tmph, *ffh, *wth;
    cudaGetSymbolAddress((void**)&posh,   g_posh);
    cudaGetSymbolAddress((void**)&outh,   g_outh);
    cudaGetSymbolAddress((void**)&qh,     g_qh);
    cudaGetSymbolAddress((void**)&valh,   g_valh);
    cudaGetSymbolAddress((void**)&offawl, g_offawl);
    cudaGetSymbolAddress((void**)&samph,  g_samph);
    cudaGetSymbolAddress((void**)&tmph,   g_tmph);
    cudaGetSymbolAddress((void**)&ffh,    g_ffh);
    cudaGetSymbolAddress((void**)&biasoa, g_biasoa);
    cudaGetSymbolAddress((void**)&wth,    g_wth);

    cudaFuncSetAttribute((tc_gemm_h<0,1>),    cudaFuncAttributeMaxDynamicSharedMemorySize, TCGH_SMEM);
    cudaFuncSetAttribute((tc_gemm_pers<0,0>), cudaFuncAttributeMaxDynamicSharedMemorySize, PERS_SMEM_H);
    cudaFuncSetAttribute((tc_gemm_pers<0,1>), cudaFuncAttributeMaxDynamicSharedMemorySize, PERS_SMEM_H);
    cudaFuncSetAttribute((tc_gemm_pers<1,1>), cudaFuncAttributeMaxDynamicSharedMemorySize, PERS_SMEM_H);

    // Prologue: 5 launches
    transplit_all<<<dim3(256, 6, 3), dim3(32, 32)>>>(Wval, Woff, Wattn, Wout, W1, W2,
                                                     wth, 0);
    transplit_all<<<dim3(256, 6, 3), dim3(32, 32)>>>(Wval, Woff, Wattn, Wout, W1, W2,
                                                     wth, 3);
    biascat_kernel<<<NLAYERS, 384>>>(boff, battn, biasoa);
    flatten_pair<<<dim3(16384/32 + 4096/32, 8, BATCH), dim3(32, 32)>>>(
        src[0], posin[0], 16384, 0, 0, src[1], posin[1], 4096, 16384, 1,
        lemb, out, posh, outh, qh);
    flatten_pair<<<dim3(1024/32 + 256/32, 8, BATCH), dim3(32, 32)>>>(
        src[2], posin[2], 1024, 20480, 2, src[3], posin[3], 256, 21504, 3,
        lemb, out, posh, outh, qh);

    for (int i = 0; i < NLAYERS; i++) {
        const __half* bh = wth + (size_t)i * WT_LAYER;
        // value (fp16 out) = outh @ Wval + bval      (2 cols x 148 CTAs, 2/SM)
        tc_gemm_pers<0,1><<<296, 256, PERS_SMEM_H>>>(outh, bh + WT_VAL,
                                                     bval + i * 256, (float*)valh, 256, 148);
        // [off|awl] = qh @ [Woff|Wattn] + biases     (3 cols x 98 CTAs)
        tc_gemm_pers<0,0><<<294, 256, PERS_SMEM_H>>>(qh, bh + WT_OFF,
                                                     biasoa + i * 384, offawl, 384, 98);
        // deformable sampling (fp16 values in, fp16 samp out)
        sample_kernel<<<M_TOT * NH / 8, 256>>>(valh, offawl, samph);
        // attn out (fp16) = samph @ Wout + bout      (2 cols x 148 CTAs)
        tc_gemm_pers<0,1><<<296, 256, PERS_SMEM_H>>>(samph, bh + WT_OUT,
                                                     bout + i * 256, (float*)tmph, 256, 148);
        // out = LN(out + attn); emit outh
        resid_ln_kernel<<<(M_TOT + 7) / 8, 256>>>(tmph, out, ln1s + i * 256,
                                                  ln1b + i * 256, out, outh,
                                                  nullptr, nullptr, M_TOT);
        // h(fp16) = relu(outh @ W1 + b1)             (8 cols x 37 CTAs)
        tc_gemm_pers<1,1><<<296, 256, PERS_SMEM_H>>>(outh, bh + WT_W1,
                                                     b1 + i * 1024, (float*)ffh, 1024, 37);
        // ff (fp16) = h(fp16) @ W2 + b2              (K=1024: streaming)
        tc_gemm_h<0,1><<<dim3(M_TOT / 128, 2), 256, TCGH_SMEM>>>(ffh, bh + WT_W2,
                                                                 b2 + i * 256, (float*)tmph,
                                                                 M_TOT, 256, 1024);
        // out = LN(out + ff); emit outh + qh for next layer
        resid_ln_kernel<<<(M_TOT + 7) / 8, 256>>>(tmph, out, ln2s + i * 256,
                                                  ln2b + i * 256, out, outh,
                                                  posh, qh, M_TOT);
    }
}

// round 16
// speedup vs baseline: 3.7390x; 1.0141x over previous
#include <cuda_runtime.h>
#include <cuda_fp16.h>
#include <math.h>
#include <stdint.h>

// ---------------------------------------------------------------------------
// MSDeformAttn transformer encoder (6 layers).
// All GEMMs full-fp16 tcgen05 kind::f16 (fp32 accum), 1 MMA per K64 chunk.
// K=256: persistent-B (B resident 64KB, 2 CTAs/SM) with software-pipelined
// A loads. W2: streaming (already pipelined). Residual mirrored fp16.
// sm_103a arch-feature guarded; SIMT fallback otherwise.
// D=256, NH=8, NL=4, NP=4, DH=32, DFF=1024, B=2, S=21760.
// ---------------------------------------------------------------------------

#define D_MODEL 256
#define NH 8
#define DFF 1024
#define NLAYERS 6
#define BATCH 2
#define S_TOTAL 21760
#define M_TOT (BATCH * S_TOTAL)   // 43520 rows; 340 M-tiles of 128

#if defined(__CUDA_ARCH_FEAT_SM103_ALL) || defined(__CUDA_ARCH_FEAT_SM100_ALL) || defined(__CUDA_ARCH_FEAT_SM101_ALL)
#define HAS_TCGEN05 1
#else
#define HAS_TCGEN05 0
#endif

// Scratch (allocation-free: __device__ globals)
__device__ __half g_posh[M_TOT * D_MODEL];        // fp16 positional stream
__device__ __half g_outh[M_TOT * D_MODEL];        // fp16 residual stream
__device__ __half g_qh[M_TOT * D_MODEL];          // fp16 (out + pos)
__device__ __half g_valh[M_TOT * D_MODEL];        // fp16 value tensor
__device__ float  g_offawl[M_TOT * 384];          // [off 256 | awl 128] per row
__device__ __half g_samph[M_TOT * D_MODEL];       // fp16 sampled tensor
__device__ __half g_tmph[M_TOT * D_MODEL];        // fp16 branch output
__device__ __half g_ffh[M_TOT * DFF];             // fp16 FF hidden
__device__ float  g_biasoa[NLAYERS * 384];        // [boff 256 | battn 128]

// Transposed fp16 weights: per layer 753664 elements
#define WT_LAYER 753664
__device__ __half g_wth[NLAYERS * WT_LAYER];
#define WT_VAL  0
#define WT_OFF  65536      // rows 0..255 of combined [384,256] (attn follows)
#define WT_ATTN 131072
#define WT_OUT  163840
#define WT_W1   229376
#define WT_W2   491520

// ---------------------------------------------------------------------------
// PTX helpers
// ---------------------------------------------------------------------------
__device__ __forceinline__ uint32_t elect_one_pred() {
    uint32_t pred;
    asm volatile(
        "{\n\t.reg .pred p;\n\telect.sync _|p, 0xFFFFFFFF;\n\t"
        "selp.b32 %0, 1, 0, p;\n\t}" : "=r"(pred));
    return pred;
}
__device__ __forceinline__ uint32_t smem_to_u32(const void* p) {
    uint32_t a;
    asm("{ .reg .u64 t; cvta.to.shared.u64 t, %1; cvt.u32.u64 %0, t; }"
        : "=r"(a) : "l"(p));
    return a;
}

#define TCGEN05_ALLOC(addr, n) \
    asm volatile("tcgen05.alloc.cta_group::1.sync.aligned.shared::cta.b32 [%0], %1;" \
                 :: "r"((uint32_t)(addr)), "r"((uint32_t)(n)) : "memory")
#define TCGEN05_DEALLOC(tmem, n) \
    asm volatile("tcgen05.dealloc.cta_group::1.sync.aligned.b32 %0, %1;" \
                 :: "r"(tmem), "r"((uint32_t)(n)))
#define TCGEN05_RELINQ() \
    asm volatile("tcgen05.relinquish_alloc_permit.cta_group::1.sync.aligned;")
#define TCGEN05_COMMIT(mbar) \
    asm volatile("tcgen05.commit.cta_group::1.mbarrier::arrive::one.shared::cluster.b64 [%0];" \
                 :: "r"((uint32_t)(mbar)) : "memory")
#define TCGEN05_FENCE_AFTER() \
    asm volatile("tcgen05.fence::after_thread_sync;" ::: "memory")
#define TCGEN05_FENCE_BEFORE() \
    asm volatile("tcgen05.fence::before_thread_sync;" ::: "memory")
#define TCGEN05_WAIT_LD() \
    asm volatile("tcgen05.wait::ld.sync.aligned;" ::: "memory")
#define FENCE_PROXY_ASYNC() \
    asm volatile("fence.proxy.async.shared::cta;" ::: "memory")
#define MBARRIER_INIT(mbar, cnt) \
    asm volatile("mbarrier.init.shared.b64 [%0], %1;" \
                 :: "r"((uint32_t)(mbar)), "r"((uint32_t)(cnt)) : "memory")
#define MBARRIER_INVAL(mbar) \
    asm volatile("mbarrier.inval.shared.b64 [%0];" :: "r"((uint32_t)(mbar)) : "memory")

#define MBARRIER_WAIT_PARITY(mbar, parity) do {                               \
    uint32_t _m = (uint32_t)(mbar);                                           \
    uint32_t _p = (uint32_t)(parity);                                         \
    asm volatile(                                                             \
        "{\n\t.reg .pred P1;\n\t"                                             \
        "WAIT_LOOP_%=:\n\t"                                                   \
        "mbarrier.try_wait.parity.acquire.cta.shared::cta.b64 P1, [%0], %1, 0x989680;\n\t" \
        "@P1 bra.uni WAIT_DONE_%=;\n\t"                                       \
        "bra.uni WAIT_LOOP_%=;\n\t"                                           \
        "WAIT_DONE_%=:\n\t}"                                                  \
        :: "r"(_m), "r"(_p) : "memory");                                      \
} while (0)

// fp16 SS MMA (fp32 accum), cta_group::1
#define TCGEN05_MMA_F16_SS(d, ad, bd, id, en) do {                            \
    uint32_t _e = (en) ? 1u : 0u; uint32_t _z = 0;                            \
    asm volatile(                                                             \
        "{\n\t.reg .pred p;\n\tsetp.ne.u32 p, %5, 0;\n\t"                     \
        "tcgen05.mma.cta_group::1.kind::f16 [%0], %1, %2, %3, {%4,%4,%4,%4}, p;\n\t}" \
        :: "r"(d), "l"(ad), "l"(bd), "r"(id), "r"(_z), "r"(_e) : "memory");   \
} while (0)

#define TCGEN05_LD32(r, addr)                                                 \
    asm volatile(                                                             \
        "tcgen05.ld.sync.aligned.32x32b.x32.b32 "                             \
        "{%0, %1, %2, %3, %4, %5, %6, %7, "                                   \
        " %8, %9, %10, %11, %12, %13, %14, %15, "                             \
        " %16, %17, %18, %19, %20, %21, %22, %23, "                           \
        " %24, %25, %26, %27, %28, %29, %30, %31}, [%32];"                    \
        : "=r"((r)[0]),  "=r"((r)[1]),  "=r"((r)[2]),  "=r"((r)[3]),          \
          "=r"((r)[4]),  "=r"((r)[5]),  "=r"((r)[6]),  "=r"((r)[7]),          \
          "=r"((r)[8]),  "=r"((r)[9]),  "=r"((r)[10]), "=r"((r)[11]),         \
          "=r"((r)[12]), "=r"((r)[13]), "=r"((r)[14]), "=r"((r)[15]),         \
          "=r"((r)[16]), "=r"((r)[17]), "=r"((r)[18]), "=r"((r)[19]),         \
          "=r"((r)[20]), "=r"((r)[21]), "=r"((r)[22]), "=r"((r)[23]),         \
          "=r"((r)[24]), "=r"((r)[25]), "=r"((r)[26]), "=r"((r)[27]),         \
          "=r"((r)[28]), "=r"((r)[29]), "=r"((r)[30]), "=r"((r)[31])          \
        : "r"(addr))

// SW128 K-major smem descriptor: layout=2, version=1, SBO=64, LBO=1
__device__ __forceinline__ uint64_t make_sw128_desc(uint32_t addr) {
    const uint64_t base = (uint64_t(2) << 61) | (uint64_t(1) << 46)
                        | (uint64_t(64) << 32) | (uint64_t(1) << 16);
    return base | ((uint64_t)(addr >> 4) & 0x3FFF);
}

#define TCG_IDESC 0x8200010u

// Epilogue store of 4 consecutive cols (float or half)
template <int RELU, int OUTH>
__device__ __forceinline__ void epi_store4(float* Cf, size_t idx, float4 o) {
    if (RELU) {
        o.x = fmaxf(o.x, 0.f); o.y = fmaxf(o.y, 0.f);
        o.z = fmaxf(o.z, 0.f); o.w = fmaxf(o.w, 0.f);
    }
    if (OUTH) {
        __half2 h0 = __halves2half2(__float2half_rn(o.x), __float2half_rn(o.y));
        __half2 h1 = __halves2half2(__float2half_rn(o.z), __float2half_rn(o.w));
        uint2 u; u.x = *(uint32_t*)&h0; u.y = *(uint32_t*)&h1;
        *(uint2*)((__half*)Cf + idx) = u;
    } else {
        *(float4*)(Cf + idx) = o;
    }
}

// ---------------------------------------------------------------------------
// Streaming GEMM, full fp16: used for W2 (K=1024, A = ffh half).
// Per K64 chunk: 1 MMA. Stage = AH 16K + BH 16K = 32K. LDG prefetched.
// ---------------------------------------------------------------------------
#define HOFF_AH 0
#define HOFF_BH 16384
#define HSTAGE  32768
#define TCGH_SMEM (1024 + 2 * HSTAGE)   // 66560

template <int RELU, int OUTH>
__global__ __launch_bounds__(256)
void tc_gemm_h(const __half* __restrict__ A,
               const __half* __restrict__ WH,
               const float* __restrict__ bias, float* __restrict__ C,
               int M, int N, int K) {
    extern __shared__ char smem[];
    const int tid  = threadIdx.x;
    const int brow = blockIdx.x * 128;
    const int bcol = blockIdx.y * 128;

    const int lr = tid >> 3;
    const int c8 = (tid & 7) * 8;
    const __half* Ab  = A  + (size_t)(brow + lr) * K + c8;
    const __half* BHb = WH + (size_t)(bcol + lr) * K + c8;
    const int KT = K >> 6;

    uint4 ua[4], bh[4];

#define HLDG_TILE(kt) do {                                                    \
    int _k = (kt) * 64;                                                       \
    _Pragma("unroll")                                                         \
    for (int i = 0; i < 4; i++) {                                             \
        size_t ro = (size_t)(i * 32) * K + _k;                                \
        ua[i] = *(const uint4*)(Ab + ro);                                     \
        bh[i] = *(const uint4*)(BHb + ro);                                    \
    }                                                                         \
} while (0)

#if HAS_TCGEN05
    const uint32_t sbase = smem_to_u32(smem);
    const int wid  = tid >> 5;
    const int lane = tid & 31;

    const uint32_t TMEMP = sbase;
    const uint32_t MBAR0 = sbase + 8;
    const uint32_t MBAR1 = sbase + 16;
    const uint32_t STG0  = sbase + 1024;

    if (wid == 0) TCGEN05_ALLOC(TMEMP, 128);
    if (tid == 0) { MBARRIER_INIT(MBAR0, 1); MBARRIER_INIT(MBAR1, 1); }
    __syncthreads();
    uint32_t tmem;
    asm volatile("ld.shared.b32 %0, [%1];" : "=r"(tmem) : "r"(TMEMP));
    if (wid == 0) TCGEN05_RELINQ();

    uint32_t swoff[4];
#pragma unroll
    for (int i = 0; i < 4; i++) {
        uint32_t off = (uint32_t)(i * 32 + lr) * 128 + (tid & 7) * 16;
        swoff[i] = off ^ ((off >> 3) & 0x70);
    }

    int ph0 = 0, ph1 = 0;

#define HSTS_TILE(stoff) do {                                                 \
    char* _sb = smem + 1024 + (stoff);                                        \
    _Pragma("unroll")                                                         \
    for (int i = 0; i < 4; i++) {                                             \
        *(uint4*)(_sb + HOFF_AH + swoff[i]) = ua[i];                          \
        *(uint4*)(_sb + HOFF_BH + swoff[i]) = bh[i];                          \
    }                                                                         \
} while (0)

    HLDG_TILE(0);
    HSTS_TILE(0);
    FENCE_PROXY_ASYNC();
    __syncthreads();

    for (int kt = 0; kt < KT; kt++) {
        int s = kt & 1;
        bool have_next = (kt + 1 < KT);
        if (have_next) HLDG_TILE(kt + 1);

        if (wid == 0) {
            if (elect_one_pred()) {
                uint32_t sb = STG0 + s * HSTAGE;
                uint64_t dah = make_sw128_desc(sb + HOFF_AH);
                uint64_t dbh = make_sw128_desc(sb + HOFF_BH);
#pragma unroll
                for (int ks = 0; ks < 4; ks++) {
                    TCGEN05_MMA_F16_SS(tmem, dah + ks * 2, dbh + ks * 2,
                                       TCG_IDESC, (kt > 0) || (ks > 0));
                }
                TCGEN05_COMMIT(s == 0 ? MBAR0 : MBAR1);
            }
        }

        if (have_next) {
            int ns = s ^ 1;
            if (kt >= 1) {
                if (ns == 0) { MBARRIER_WAIT_PARITY(MBAR0, ph0); ph0 ^= 1; }
                else         { MBARRIER_WAIT_PARITY(MBAR1, ph1); ph1 ^= 1; }
            }
            HSTS_TILE(ns * HSTAGE);
            FENCE_PROXY_ASYNC();
            __syncthreads();
        }
    }

    if (((KT - 1) & 1) == 0) { MBARRIER_WAIT_PARITY(MBAR0, ph0); }
    else                     { MBARRIER_WAIT_PARITY(MBAR1, ph1); }
    TCGEN05_FENCE_AFTER();

    {
        int colbase = (wid >> 2) * 64;
        uint32_t d0[32], d1[32];
        TCGEN05_LD32(d0, tmem + colbase);
        TCGEN05_LD32(d1, tmem + colbase + 32);
        TCGEN05_WAIT_LD();
        TCGEN05_FENCE_BEFORE();

        int r = brow + (wid & 3) * 32 + lane;
        size_t base = (size_t)r * N + bcol + colbase;
        const float* bb = bias + bcol + colbase;
#pragma unroll
        for (int c = 0; c < 32; c += 4) {
            float4 o;
            o.x = __uint_as_float(d0[c + 0]) + bb[c + 0];
            o.y = __uint_as_float(d0[c + 1]) + bb[c + 1];
            o.z = __uint_as_float(d0[c + 2]) + bb[c + 2];
            o.w = __uint_as_float(d0[c + 3]) + bb[c + 3];
            epi_store4<RELU, OUTH>(C, base + c, o);
        }
#pragma unroll
        for (int c = 0; c < 32; c += 4) {
            float4 o;
            o.x = __uint_as_float(d1[c + 0]) + bb[32 + c + 0];
            o.y = __uint_as_float(d1[c + 1]) + bb[32 + c + 1];
            o.z = __uint_as_float(d1[c + 2]) + bb[32 + c + 2];
            o.w = __uint_as_float(d1[c + 3]) + bb[32 + c + 3];
            epi_store4<RELU, OUTH>(C, base + 32 + c, o);
        }
    }

    __syncthreads();
    if (tid == 0) { MBARRIER_INVAL(MBAR0); MBARRIER_INVAL(MBAR1); }
    __syncthreads();
    if (wid == 0) TCGEN05_DEALLOC(tmem, 128);

#else  // SIMT fallback
    float (*As)[132] = (float(*)[132])(smem);
    float (*Bs)[132] = (float(*)[132])(smem + 64 * 132 * 4);

    int ty = (tid >> 4) * 8;
    int tx = (tid & 15) * 8;

    float acc[8][8];
#pragma unroll
    for (int i = 0; i < 8; i++)
#pragma unroll
        for (int j = 0; j < 8; j++) acc[i][j] = 0.f;

    for (int kt = 0; kt < KT; kt++) {
        HLDG_TILE(kt);
        __syncthreads();
#pragma unroll
        for (int i = 0; i < 4; i++) {
            int r = i * 32 + lr;
            const __half* ha = (const __half*)&ua[i];
            const __half* hh = (const __half*)&bh[i];
#pragma unroll
            for (int j = 0; j < 8; j++) {
                As[c8 + j][r] = __half2float(ha[j]);
                Bs[c8 + j][r] = __half2float(hh[j]);
            }
        }
        __syncthreads();
#pragma unroll 16
        for (int k = 0; k < 64; k++) {
            float av[8], bv[8];
#pragma unroll
            for (int i = 0; i < 8; i++) { av[i] = As[k][ty + i]; bv[i] = Bs[k][tx + i]; }
#pragma unroll
            for (int i = 0; i < 8; i++)
#pragma unroll
                for (int j = 0; j < 8; j++)
                    acc[i][j] += av[i] * bv[j];
        }
    }

    int row = brow + ty;
    int col = bcol + tx;
#pragma unroll
    for (int i = 0; i < 8; i++) {
#pragma unroll
        for (int j = 0; j < 8; j++) {
            float v = acc[i][j] + bias[col + j];
            if (RELU) v = fmaxf(v, 0.f);
            if (OUTH) ((__half*)C)[(size_t)(row + i) * N + col + j] = __float2half_rn(v);
            else      C[(size_t)(row + i) * N + col + j] = v;
        }
    }
#endif
}

// ---------------------------------------------------------------------------
// Persistent-B GEMM, full fp16, 1 MMA per K64 chunk. K=256.
// A loads software-pipelined: next chunk's LDG issued before the stage wait
// (crosses epilogue boundaries into the next M-tile).
// SMEM: 1024 hdr + 65536 B + 2x16384 A = 99328 -> 2 CTAs/SM.
// ---------------------------------------------------------------------------
#define PERS_SMEM_H 99328
#define MT_TILES (M_TOT / 128)   // 340

template <int RELU, int OUTH>
__global__ __launch_bounds__(256)
void tc_gemm_pers(const __half* __restrict__ A,
                  const __half* __restrict__ WH,
                  const float* __restrict__ bias, float* __restrict__ C,
                  int N, int CPC) {
    extern __shared__ char smem[];
    const int tid = threadIdx.x;
    const int K = 256;
    const int col = blockIdx.x / CPC;
    const int cid = blockIdx.x % CPC;
    const int bcol = col * 128;
    constexpr int ASTAGE = 16384;

    const int lr  = tid >> 3;
    const int c16 = tid & 7;
    const uint32_t swr = (uint32_t)lr * 128 + (uint32_t)((c16 ^ (lr & 7)) * 16);

#if HAS_TCGEN05
    const uint32_t sbase = smem_to_u32(smem);
    const int wid = tid >> 5, lane = tid & 31;
    const uint32_t TMEMP = sbase;
    const uint32_t MBAR0 = sbase + 8;
    const uint32_t MBAR1 = sbase + 16;
    const uint32_t BH_S  = sbase + 1024;
    const uint32_t AST   = BH_S + 65536;

    if (wid == 0) TCGEN05_ALLOC(TMEMP, 128);
    if (tid == 0) { MBARRIER_INIT(MBAR0, 1); MBARRIER_INIT(MBAR1, 1); }
    __syncthreads();
    uint32_t tmem;
    asm volatile("ld.shared.b32 %0, [%1];" : "=r"(tmem) : "r"(TMEMP));
    if (wid == 0) TCGEN05_RELINQ();

    // Load resident B hi: 4 K64 sub-tiles of 16KB
    {
        const __half* BHb = WH + (size_t)(bcol + lr) * K + c16 * 8;
#pragma unroll
        for (int kt = 0; kt < 4; kt++) {
#pragma unroll
            for (int i = 0; i < 4; i++) {
                size_t ro = (size_t)(i * 32) * K + kt * 64;
                uint32_t so = (uint32_t)kt * 16384 + swr + (uint32_t)i * 4096;
                *(uint4*)(smem + 1024 + so) = *(const uint4*)(BHb + ro);
            }
        }
    }
    FENCE_PROXY_ASYNC();
    __syncthreads();

    // Prefetch first A chunk (m=cid, kt=0)
    uint4 ua_cur[4];
    {
        const __half* A0 = A + (size_t)(cid * 128 + lr) * K + c16 * 8;
#pragma unroll
        for (int i = 0; i < 4; i++)
            ua_cur[i] = *(const uint4*)(A0 + (size_t)(i * 32) * K);
    }

    int g = 0;
    for (int m = cid; m < MT_TILES; m += CPC) {
#pragma unroll 1
        for (int kt = 0; kt < 4; kt++, g++) {
            const int s = g & 1;

            // Issue LDG for the next chunk (possibly next tile's chunk 0)
            uint4 ua_nxt[4];
            int nm = (kt < 3) ? m : m + CPC;
            int nk = (kt < 3) ? kt + 1 : 0;
            bool have_next = (nm < MT_TILES);
            if (have_next) {
                const __half* An = A + (size_t)(nm * 128 + lr) * K + c16 * 8 + nk * 64;
#pragma unroll
                for (int i = 0; i < 4; i++)
                    ua_nxt[i] = *(const uint4*)(An + (size_t)(i * 32) * K);
            }

            if (g >= 2) {
                MBARRIER_WAIT_PARITY(s ? MBAR1 : MBAR0, ((g >> 1) - 1) & 1);
            }
            char* sb = smem + 1024 + 65536 + s * ASTAGE;
#pragma unroll
            for (int i = 0; i < 4; i++)
                *(uint4*)(sb + swr + i * 4096) = ua_cur[i];
            FENCE_PROXY_ASYNC();
            __syncthreads();

            if (wid == 0) {
                if (elect_one_pred()) {
                    uint64_t dah = make_sw128_desc(AST + s * ASTAGE);
                    uint64_t dbh = make_sw128_desc(BH_S + kt * 16384);
#pragma unroll
                    for (int ks = 0; ks < 4; ks++) {
                        TCGEN05_MMA_F16_SS(tmem, dah + ks * 2, dbh + ks * 2,
                                           TCG_IDESC, (kt > 0) || (ks > 0));
                    }
                    TCGEN05_COMMIT(s ? MBAR1 : MBAR0);
                }
            }

            if (have_next) {
#pragma unroll
                for (int i = 0; i < 4; i++) ua_cur[i] = ua_nxt[i];
            }
        }

        {
            int gl = g - 1;
            MBARRIER_WAIT_PARITY((gl & 1) ? MBAR1 : MBAR0, (gl >> 1) & 1);
            TCGEN05_FENCE_AFTER();

            int colbase = (wid >> 2) * 64;
            uint32_t d0[32], d1[32];
            TCGEN05_LD32(d0, tmem + colbase);
            TCGEN05_LD32(d1, tmem + colbase + 32);
            TCGEN05_WAIT_LD();
            TCGEN05_FENCE_BEFORE();

            int r = m * 128 + (wid & 3) * 32 + lane;
            size_t cb = (size_t)r * N + bcol + colbase;
            const float* bb = bias + bcol + colbase;
#pragma unroll
            for (int c = 0; c < 32; c += 4) {
                float4 o;
                o.x = __uint_as_float(d0[c + 0]) + bb[c + 0];
                o.y = __uint_as_float(d0[c + 1]) + bb[c + 1];
                o.z = __uint_as_float(d0[c + 2]) + bb[c + 2];
                o.w = __uint_as_float(d0[c + 3]) + bb[c + 3];
                epi_store4<RELU, OUTH>(C, cb + c, o);
            }
#pragma unroll
            for (int c = 0; c < 32; c += 4) {
                float4 o;
                o.x = __uint_as_float(d1[c + 0]) + bb[32 + c + 0];
                o.y = __uint_as_float(d1[c + 1]) + bb[32 + c + 1];
                o.z = __uint_as_float(d1[c + 2]) + bb[32 + c + 2];
                o.w = __uint_as_float(d1[c + 3]) + bb[32 + c + 3];
                epi_store4<RELU, OUTH>(C, cb + 32 + c, o);
            }
            __syncthreads();
        }
    }

    __syncthreads();
    if (tid == 0) { MBARRIER_INVAL(MBAR0); MBARRIER_INVAL(MBAR1); }
    __syncthreads();
    if (wid == 0) TCGEN05_DEALLOC(tmem, 128);

#else  // SIMT fallback
    float (*As)[132] = (float(*)[132])(smem);
    float (*Bs)[132] = (float(*)[132])(smem + 64 * 132 * 4);
    int ty = (tid >> 4) * 8;
    int tx = (tid & 15) * 8;

    for (int m = cid; m < MT_TILES; m += CPC) {
        int brow = m * 128;
        float acc[8][8];
#pragma unroll
        for (int i = 0; i < 8; i++)
#pragma unroll
            for (int j = 0; j < 8; j++) acc[i][j] = 0.f;

        for (int kt = 0; kt < 4; kt++) {
            __syncthreads();
#pragma unroll
            for (int i = 0; i < 4; i++) {
                int row = i * 32 + lr;
                size_t aro = (size_t)(brow + row) * K + kt * 64 + c16 * 8;
                size_t bro = (size_t)(bcol + row) * K + kt * 64 + c16 * 8;
#pragma unroll
                for (int j = 0; j < 8; j++) {
                    As[c16 * 8 + j][row] = __half2float(A[aro + j]);
                    Bs[c16 * 8 + j][row] = __half2float(WH[bro + j]);
                }
            }
            __syncthreads();
#pragma unroll 16
            for (int k = 0; k < 64; k++) {
                float av[8], bv[8];
#pragma unroll
                for (int i = 0; i < 8; i++) { av[i] = As[k][ty + i]; bv[i] = Bs[k][tx + i]; }
#pragma unroll
                for (int i = 0; i < 8; i++)
#pragma unroll
                    for (int j = 0; j < 8; j++)
                        acc[i][j] += av[i] * bv[j];
            }
        }
        int row = brow + ty;
        int cc  = bcol + tx;
#pragma unroll
        for (int i = 0; i < 8; i++)
#pragma unroll
            for (int j = 0; j < 8; j++) {
                float v = acc[i][j] + bias[cc + j];
                if (RELU) v = fmaxf(v, 0.f);
                if (OUTH) ((__half*)C)[(size_t)(row + i) * N + cc + j] = __float2half_rn(v);
                else      C[(size_t)(row + i) * N + cc + j] = v;
            }
        __syncthreads();
    }
#endif
}

// ---------------------------------------------------------------------------
// Fused weight transpose + fp16 convert (all 6 types, 3 layers per launch)
// ---------------------------------------------------------------------------
__global__ void transplit_all(const float* __restrict__ Wval, const float* __restrict__ Woff,
                              const float* __restrict__ Wattn, const float* __restrict__ Wout,
                              const float* __restrict__ W1, const float* __restrict__ W2,
                              __half* __restrict__ wth, int layer0) {
    int type  = blockIdx.y;
    int layer = layer0 + blockIdx.z;
    const float* W; int K, N, off;
    switch (type) {
        case 0: W = Wval  + (size_t)layer * 65536;  K = 256;  N = 256;  off = WT_VAL;  break;
        case 1: W = Woff  + (size_t)layer * 65536;  K = 256;  N = 256;  off = WT_OFF;  break;
        case 2: W = Wattn + (size_t)layer * 32768;  K = 256;  N = 128;  off = WT_ATTN; break;
        case 3: W = Wout  + (size_t)layer * 65536;  K = 256;  N = 256;  off = WT_OUT;  break;
        case 4: W = W1    + (size_t)layer * 262144; K = 256;  N = 1024; off = WT_W1;   break;
        default: W = W2   + (size_t)layer * 262144; K = 1024; N = 256;  off = WT_W2;   break;
    }
    int tK = K >> 5, tN = N >> 5;
    int t = blockIdx.x;
    if (t >= tK * tN) return;
    int k0 = (t % tK) * 32, n0 = (t / tK) * 32;

    __shared__ float tile[32][33];
    tile[threadIdx.y][threadIdx.x] = W[(size_t)(k0 + threadIdx.y) * N + n0 + threadIdx.x];
    __syncthreads();
    float v = tile[threadIdx.x][threadIdx.y];
    size_t o = (size_t)layer * WT_LAYER + off + (size_t)(n0 + threadIdx.y) * K + k0 + threadIdx.x;
    wth[o] = __float2half_rn(v);
}

// Bias concat: g_biasoa[l][0..255]=boff, [256..383]=battn
__global__ void biascat_kernel(const float* __restrict__ boff,
                               const float* __restrict__ battn,
                               float* __restrict__ dst) {
    int l = blockIdx.x, j = threadIdx.x;
    dst[l * 384 + j] = (j < 256) ? boff[l * 256 + j] : battn[l * 128 + j - 256];
}

// ---------------------------------------------------------------------------
// Flatten pair of levels: src [B, D, h, w] -> out [B, S, D]; pos(h) + level_embed.
// Also seeds the fp16 residual mirrors: outh = fp16(out), qh = fp16(out+pos).
// ---------------------------------------------------------------------------
__global__ void flatten_pair(const float* __restrict__ sA, const float* __restrict__ pA,
                             int hwA, int stA, int lvA,
                             const float* __restrict__ sB, const float* __restrict__ pB,
                             int hwB, int stB, int lvB,
                             const float* __restrict__ lemb,
                             float* __restrict__ out, __half* __restrict__ posouth,
                             __half* __restrict__ outh, __half* __restrict__ qh) {
    __shared__ float ts[32][33];
    __shared__ float tp[32][33];
    int px = blockIdx.x;
    const float *src, *pos; int hw, start, level, p0;
    int tA = hwA >> 5;
    if (px < tA) { src = sA; pos = pA; hw = hwA; start = stA; level = lvA; p0 = px * 32; }
    else         { src = sB; pos = pB; hw = hwB; start = stB; level = lvB; p0 = (px - tA) * 32; }

    int b  = blockIdx.z;
    int d0 = blockIdx.y * 32;
    int tx = threadIdx.x, ty = threadIdx.y;

    const float* sp = src + ((size_t)b * D_MODEL + d0 + ty) * hw + p0;
    const float* pp = pos + ((size_t)b * D_MODEL + d0 + ty) * hw + p0;
    ts[ty][tx] = sp[tx];
    tp[ty][tx] = pp[tx];
    __syncthreads();

    int d = d0 + tx;
    float le = lemb[level * D_MODEL + d];
    size_t srow = (size_t)b * S_TOTAL + start + p0 + ty;
    float v = ts[tx][ty];
    float p = tp[tx][ty] + le;
    out[srow * D_MODEL + d]      = v;
    posouth[srow * D_MODEL + d]  = __float2half_rn(p);
    outh[srow * D_MODEL + d]     = __float2half_rn(v);
    qh[srow * D_MODEL + d]       = __float2half_rn(v + p);
}

// ---------------------------------------------------------------------------
// Residual + LayerNorm: out = LN(xh + r) * gamma + beta. One warp per row.
// xh is fp16 branch output. Emits outh = fp16(out); if Qh != null,
// qh = fp16(out + posh).
// ---------------------------------------------------------------------------
__global__ void resid_ln_kernel(const __half* __restrict__ Xh, const float* __restrict__ R,
                                const float* __restrict__ g, const float* __restrict__ bt,
                                float* __restrict__ O, __half* __restrict__ Oh,
                                const __half* __restrict__ Ph, __half* __restrict__ Qh,
                                int rows) {
    int warp = (blockIdx.x * blockDim.x + threadIdx.x) >> 5;
    int lane = threadIdx.x & 31;
    if (warp >= rows) return;
    const __half* xr = Xh + (size_t)warp * D_MODEL;
    const float*  rr = R  + (size_t)warp * D_MODEL;

    float v[8];
    float s = 0.f, s2 = 0.f;
#pragma unroll
    for (int u = 0; u < 2; u++) {
        uint2 ux = *(const uint2*)(xr + lane * 4 + u * 128);
        float2 xa = __half22float2(*(__half2*)&ux.x);
        float2 xb = __half22float2(*(__half2*)&ux.y);
        float4 c = *(const float4*)(rr + lane * 4 + u * 128);
        float t0 = xa.x + c.x, t1 = xa.y + c.y, t2 = xb.x + c.z, t3 = xb.y + c.w;
        v[u * 4 + 0] = t0; v[u * 4 + 1] = t1; v[u * 4 + 2] = t2; v[u * 4 + 3] = t3;
        s += t0 + t1 + t2 + t3;
        s2 += t0 * t0 + t1 * t1 + t2 * t2 + t3 * t3;
    }
#pragma unroll
    for (int o = 16; o > 0; o >>= 1) {
        s  += __shfl_xor_sync(0xffffffffu, s, o);
        s2 += __shfl_xor_sync(0xffffffffu, s2, o);
    }
    float mean = s * (1.f / D_MODEL);
    float var  = s2 * (1.f / D_MODEL) - mean * mean;
    float inv  = rsqrtf(var + 1e-5f);
#pragma unroll
    for (int u = 0; u < 2; u++) {
        int d = lane * 4 + u * 128;
        float4 o4;
        o4.x = (v[u * 4 + 0] - mean) * inv * g[d + 0] + bt[d + 0];
        o4.y = (v[u * 4 + 1] - mean) * inv * g[d + 1] + bt[d + 1];
        o4.z = (v[u * 4 + 2] - mean) * inv * g[d + 2] + bt[d + 2];
        o4.w = (v[u * 4 + 3] - mean) * inv * g[d + 3] + bt[d + 3];
        *(float4*)(O + (size_t)warp * D_MODEL + d) = o4;

        __half2 h0 = __halves2half2(__float2half_rn(o4.x), __float2half_rn(o4.y));
        __half2 h1 = __halves2half2(__float2half_rn(o4.z), __float2half_rn(o4.w));
        uint2 uo; uo.x = *(uint32_t*)&h0; uo.y = *(uint32_t*)&h1;
        *(uint2*)(Oh + (size_t)warp * D_MODEL + d) = uo;

        if (Qh) {
            uint2 up = *(const uint2*)(Ph + (size_t)warp * D_MODEL + d);
            float2 pa = __half22float2(*(__half2*)&up.x);
            float2 pb = __half22float2(*(__half2*)&up.y);
            __half2 q0 = __halves2half2(__float2half_rn(o4.x + pa.x),
                                        __float2half_rn(o4.y + pa.y));
            __half2 q1 = __halves2half2(__float2half_rn(o4.z + pb.x),
                                        __float2half_rn(o4.w + pb.y));
            uint2 uq; uq.x = *(uint32_t*)&q0; uq.y = *(uint32_t*)&q1;
            *(uint2*)(Qh + (size_t)warp * D_MODEL + d) = uq;
        }
    }
}

// ---------------------------------------------------------------------------
// Deformable sampling, fp16 values in, fp16 samp out. One warp per (token, head).
// ---------------------------------------------------------------------------
__constant__ int c_lw[4]     = {128, 64, 32, 16};
__constant__ int c_lstart[4] = {0, 16384, 20480, 21504};

__global__ void sample_kernel(const __half* __restrict__ Valh,
                              const float* __restrict__ OA,
                              __half* __restrict__ Samph) {
    __shared__ int2 tab[8][16][4];
    int gw   = (blockIdx.x * blockDim.x + threadIdx.x) >> 5;
    int lane = threadIdx.x & 31;
    int wpb  = threadIdx.x >> 5;
    if (gw >= M_TOT * NH) return;
    int h   = gw & 7;
    int tok = gw >> 3;
    int s   = tok % S_TOTAL;
    int b   = tok / S_TOTAL;

    int wt, st, sh;
    if (s < 16384)      { wt = 128; st = 0;     sh = 7; }
    else if (s < 20480) { wt = 64;  st = 16384; sh = 6; }
    else if (s < 21504) { wt = 32;  st = 20480; sh = 5; }
    else                { wt = 16;  st = 21504; sh = 4; }
    int sl = s - st;
    int iy = sl >> sh;
    int ix = sl - (iy << sh);
    float refx = (ix + 0.5f) / (float)wt;
    float refy = (iy + 0.5f) / (float)wt;

    size_t rb = (size_t)tok;

    float lv = (lane < 16) ? OA[rb * 384 + 256 + h * 16 + lane] : -1e30f;
    float m = lv;
#pragma unroll
    for (int o = 8; o > 0; o >>= 1) m = fmaxf(m, __shfl_xor_sync(0xffffffffu, m, o));
    float e = (lane < 16) ? expf(lv - m) : 0.f;
    float ssum = e;
#pragma unroll
    for (int o = 8; o > 0; o >>= 1) ssum += __shfl_xor_sync(0xffffffffu, ssum, o);
    float aw = e / ssum;

    if (lane < 16) {
        int l   = lane >> 2;
        int wl  = c_lw[l];
        int stl = c_lstart[l];
        float ox = OA[rb * 384 + (size_t)(h * 16 + lane) * 2 + 0];
        float oy = OA[rb * 384 + (size_t)(h * 16 + lane) * 2 + 1];
        float x = refx * (float)wl + ox - 0.5f;
        float y = refy * (float)wl + oy - 0.5f;
        float xf = floorf(x), yf = floorf(y);
        float lx = x - xf, ly = y - yf;
        int x0 = (int)xf, y0 = (int)yf;
        int x1 = x0 + 1, y1 = y0 + 1;
        bool okx0 = (x0 >= 0) & (x0 < wl);
        bool okx1 = (x1 >= 0) & (x1 < wl);
        bool oky0 = (y0 >= 0) & (y0 < wl);
        bool oky1 = (y1 >= 0) & (y1 < wl);
        int cx0 = min(max(x0, 0), wl - 1), cx1 = min(max(x1, 0), wl - 1);
        int cy0 = min(max(y0, 0), wl - 1), cy1 = min(max(y1, 0), wl - 1);
        float w0 = (1.f - lx) * (1.f - ly) * aw * ((okx0 && oky0) ? 1.f : 0.f);
        float w1 = lx * (1.f - ly) * aw * ((okx1 && oky0) ? 1.f : 0.f);
        float w2 = (1.f - lx) * ly * aw * ((okx0 && oky1) ? 1.f : 0.f);
        float w3 = lx * ly * aw * ((okx1 && oky1) ? 1.f : 0.f);
        tab[wpb][lane][0] = make_int2(stl + cy0 * wl + cx0, __float_as_int(w0));
        tab[wpb][lane][1] = make_int2(stl + cy0 * wl + cx1, __float_as_int(w1));
        tab[wpb][lane][2] = make_int2(stl + cy1 * wl + cx0, __float_as_int(w2));
        tab[wpb][lane][3] = make_int2(stl + cy1 * wl + cx1, __float_as_int(w3));
    }
    __syncwarp();

    int t   = lane >> 3;
    int ch4 = lane & 7;
    const __half* vb = Valh + (size_t)b * S_TOTAL * 256 + h * 32 + ch4 * 4;
    float4 acc = make_float4(0.f, 0.f, 0.f, 0.f);
#pragma unroll
    for (int j = 0; j < 16; j++) {
        int2 ee = tab[wpb][j][t];
        uint2 u = *(const uint2*)(vb + (size_t)ee.x * 256);
        __half2 p0 = *(__half2*)&u.x;
        __half2 p1 = *(__half2*)&u.y;
        float2 f0 = __half22float2(p0);
        float2 f1 = __half22float2(p1);
        float f = __int_as_float(ee.y);
        acc.x += f * f0.x; acc.y += f * f0.y;
        acc.z += f * f1.x; acc.w += f * f1.y;
    }
#pragma unroll
    for (int msk = 8; msk <= 16; msk <<= 1) {
        acc.x += __shfl_xor_sync(0xffffffffu, acc.x, msk);
        acc.y += __shfl_xor_sync(0xffffffffu, acc.y, msk);
        acc.z += __shfl_xor_sync(0xffffffffu, acc.z, msk);
        acc.w += __shfl_xor_sync(0xffffffffu, acc.w, msk);
    }
    if (lane < 8) {
        __half2 h0 = __halves2half2(__float2half_rn(acc.x), __float2half_rn(acc.y));
        __half2 h1 = __halves2half2(__float2half_rn(acc.z), __float2half_rn(acc.w));
        uint2 u; u.x = *(uint32_t*)&h0; u.y = *(uint32_t*)&h1;
        ((uint2*)(Samph + (size_t)tok * 256 + h * 32))[ch4] = u;
    }
}

// ---------------------------------------------------------------------------
// Host orchestration
// ---------------------------------------------------------------------------
extern "C" void kernel_launch(void* const* d_in, const int* in_sizes, int n_in,
                              void* d_out, int out_size) {
    const float* src[4];
    const float* posin[4];
    bool interleaved = (in_sizes[1] == in_sizes[0]);
    for (int l = 0; l < 4; l++) {
        if (interleaved) {
            src[l]   = (const float*)d_in[2 * l];
            posin[l] = (const float*)d_in[2 * l + 1];
        } else {
            src[l]   = (const float*)d_in[l];
            posin[l] = (const float*)d_in[4 + l];
        }
    }
    const float* lemb  = (const float*)d_in[8];
    const float* Woff  = (const float*)d_in[9];
    const float* boff  = (const float*)d_in[10];
    const float* Wattn = (const float*)d_in[11];
    const float* battn = (const float*)d_in[12];
    const float* Wval  = (const float*)d_in[13];
    const float* bval  = (const float*)d_in[14];
    const float* Wout  = (const float*)d_in[15];
    const float* bout  = (const float*)d_in[16];
    const float* ln1s  = (const float*)d_in[17];
    const float* ln1b  = (const float*)d_in[18];
    const float* W1    = (const float*)d_in[19];
    const float* b1    = (const float*)d_in[20];
    const float* W2    = (const float*)d_in[21];
    const float* b2    = (const float*)d_in[22];
    const float* ln2s  = (const float*)d_in[23];
    const float* ln2b  = (const float*)d_in[24];

    float* out = (float*)d_out;

    float *offawl, *biasoa;
    __half *posh, *outh, *qh, *valh, *samph, *tmph, *ffh, *wth;
    cudaGetSymbolAddress((void**)&posh,   g_posh);
    cudaGetSymbolAddress((void**)&outh,   g_outh);
    cudaGetSymbolAddress((void**)&qh,     g_qh);
    cudaGetSymbolAddress((void**)&valh,   g_valh);
    cudaGetSymbolAddress((void**)&offawl, g_offawl);
    cudaGetSymbolAddress((void**)&samph,  g_samph);
    cudaGetSymbolAddress((void**)&tmph,   g_tmph);
    cudaGetSymbolAddress((void**)&ffh,    g_ffh);
    cudaGetSymbolAddress((void**)&biasoa, g_biasoa);
    cudaGetSymbolAddress((void**)&wth,    g_wth);

    cudaFuncSetAttribute((tc_gemm_h<0,1>),    cudaFuncAttributeMaxDynamicSharedMemorySize, TCGH_SMEM);
    cudaFuncSetAttribute((tc_gemm_pers<0,0>), cudaFuncAttributeMaxDynamicSharedMemorySize, PERS_SMEM_H);
    cudaFuncSetAttribute((tc_gemm_pers<0,1>), cudaFuncAttributeMaxDynamicSharedMemorySize, PERS_SMEM_H);
    cudaFuncSetAttribute((tc_gemm_pers<1,1>), cudaFuncAttributeMaxDynamicSharedMemorySize, PERS_SMEM_H);

    // Prologue: 5 launches
    transplit_all<<<dim3(256, 6, 3), dim3(32, 32)>>>(Wval, Woff, Wattn, Wout, W1, W2,
                                                     wth, 0);
    transplit_all<<<dim3(256, 6, 3), dim3(32, 32)>>>(Wval, Woff, Wattn, Wout, W1, W2,
                                                     wth, 3);
    biascat_kernel<<<NLAYERS, 384>>>(boff, battn, biasoa);
    flatten_pair<<<dim3(16384/32 + 4096/32, 8, BATCH), dim3(32, 32)>>>(
        src[0], posin[0], 16384, 0, 0, src[1], posin[1], 4096, 16384, 1,
        lemb, out, posh, outh, qh);
    flatten_pair<<<dim3(1024/32 + 256/32, 8, BATCH), dim3(32, 32)>>>(
        src[2], posin[2], 1024, 20480, 2, src[3], posin[3], 256, 21504, 3,
        lemb, out, posh, outh, qh);

    for (int i = 0; i < NLAYERS; i++) {
        const __half* bh = wth + (size_t)i * WT_LAYER;
        // value (fp16 out) = outh @ Wval + bval      (2 cols x 148 CTAs, 2/SM)
        tc_gemm_pers<0,1><<<296, 256, PERS_SMEM_H>>>(outh, bh + WT_VAL,
                                                     bval + i * 256, (float*)valh, 256, 148);
        // [off|awl] = qh @ [Woff|Wattn] + biases     (3 cols x 98 CTAs)
        tc_gemm_pers<0,0><<<294, 256, PERS_SMEM_H>>>(qh, bh + WT_OFF,
                                                     biasoa + i * 384, offawl, 384, 98);
        // deformable sampling (fp16 values in, fp16 samp out)
        sample_kernel<<<M_TOT * NH / 8, 256>>>(valh, offawl, samph);
        // attn out (fp16) = samph @ Wout + bout      (2 cols x 148 CTAs)
        tc_gemm_pers<0,1><<<296, 256, PERS_SMEM_H>>>(samph, bh + WT_OUT,
                                                     bout + i * 256, (float*)tmph, 256, 148);
        // out = LN(out + attn); emit outh
        resid_ln_kernel<<<(M_TOT + 7) / 8, 256>>>(tmph, out, ln1s + i * 256,
                                                  ln1b + i * 256, out, outh,
                                                  nullptr, nullptr, M_TOT);
        // h(fp16) = relu(outh @ W1 + b1)             (8 cols x 37 CTAs)
        tc_gemm_pers<1,1><<<296, 256, PERS_SMEM_H>>>(outh, bh + WT_W1,
                                                     b1 + i * 1024, (float*)ffh, 1024, 37);
        // ff (fp16) = h(fp16) @ W2 + b2              (K=1024: streaming)
        tc_gemm_h<0,1><<<dim3(M_TOT / 128, 2), 256, TCGH_SMEM>>>(ffh, bh + WT_W2,
                                                                 b2 + i * 256, (float*)tmph,
                                                                 M_TOT, 256, 1024);
        // out = LN(out + ff); emit outh + qh for next layer
        resid_ln_kernel<<<(M_TOT + 7) / 8, 256>>>(tmph, out, ln2s + i * 256,
                                                  ln2b + i * 256, out, outh,
                                                  posh, qh, M_TOT);
    }
}